// round 2
// baseline (speedup 1.0000x reference)
#include <cuda_runtime.h>
#include <math.h>

// ---------------------------------------------------------------------------
// Problem constants
// ---------------------------------------------------------------------------
#define Bq   4
#define TTq  512
#define TSs  512
#define Dm   512
#define Hh   8
#define Vv   32000
#define VO   32001
#define NR   2048            // B*TT rows of activations
#define HD   4096            // H*D
#define FFd  2048            // 4*D

#define LOGITS_ELEMS (2048LL * 32001LL)   // 65,538,048
#define ATT_ELEMS    (4LL * 8 * 512 * 512) // 8,388,608

// ---------------------------------------------------------------------------
// Scratch (static device globals — no runtime allocation)
// ---------------------------------------------------------------------------
__device__ float g_x [NR * Dm];          // activations
__device__ float g_q [NR * HD];          // Q all heads   [row][h*D+e]
__device__ float g_k [NR * HD];          // K all heads
__device__ float g_v [NR * HD];          // V all heads
__device__ float g_s [Bq * Hh * TTq * TSs]; // scores / attention weights
__device__ float g_o [NR * HD];          // per-head attn outputs, concat layout
__device__ float g_t [NR * Dm];          // attn/ffn projected output
__device__ float g_ff[NR * FFd];         // FFN hidden

// ---------------------------------------------------------------------------
// Embedding + sinusoidal positional encoding
// ---------------------------------------------------------------------------
__global__ void embed_pe_kernel(const int* __restrict__ target,
                                const float* __restrict__ emb,
                                float* __restrict__ x)
{
    int row = blockIdx.x;                 // b*TT + t
    int t   = row & (TTq - 1);
    int d   = threadIdx.x;                // 512 threads
    int tok = target[row];
    float e = emb[(long)tok * Dm + d];
    int   i = d >> 1;
    float denom = powf(10000.0f, (2.0f * (float)i) / (float)Dm);
    float z = (float)t / denom;
    float p = (d & 1) ? cosf(z) : sinf(z);
    x[(long)row * Dm + d] = e + p;
}

// ---------------------------------------------------------------------------
// Masked softmax over the last dim (512) of scores.
// mode 1: self-attn  (causal & tgt_pad(k) & tgt_pad(q))
// mode 2: cross-attn (src_pad(k) & tgt_pad(q))
// ---------------------------------------------------------------------------
__global__ void softmax_kernel(float* __restrict__ S,
                               const int* __restrict__ target,
                               const int* __restrict__ srcpad,
                               int mode, float scale)
{
    int row = blockIdx.x;                 // (b*H + h)*TT + q
    int q   = row & (TTq - 1);
    int b   = row / (Hh * TTq);
    float* s = S + (long)row * TSs;
    int tid = threadIdx.x;                // 256 threads, 2 elems each
    bool qpad = (target[b * TTq + q] != Vv);

    float v[2];
    float mx = -INFINITY;
#pragma unroll
    for (int e = 0; e < 2; e++) {
        int k = tid + e * 256;
        bool valid;
        if (mode == 1)
            valid = qpad && (k <= q) && (target[b * TTq + k] != Vv);
        else
            valid = qpad && (srcpad[b * TSs + k] != 0);
        float val = valid ? s[k] * scale : -1e32f;
        v[e] = val;
        mx = fmaxf(mx, val);
    }

    __shared__ float red[8];
    // ---- block max ----
#pragma unroll
    for (int o = 16; o > 0; o >>= 1) mx = fmaxf(mx, __shfl_xor_sync(0xffffffffu, mx, o));
    if ((tid & 31) == 0) red[tid >> 5] = mx;
    __syncthreads();
    if (tid < 32) {
        float r = (tid < 8) ? red[tid] : -INFINITY;
#pragma unroll
        for (int o = 4; o > 0; o >>= 1) r = fmaxf(r, __shfl_xor_sync(0xffffffffu, r, o));
        if (tid == 0) red[0] = r;
    }
    __syncthreads();
    mx = red[0];
    __syncthreads();

    // ---- exp + block sum ----
    float sum = 0.f;
#pragma unroll
    for (int e = 0; e < 2; e++) { v[e] = expf(v[e] - mx); sum += v[e]; }
#pragma unroll
    for (int o = 16; o > 0; o >>= 1) sum += __shfl_xor_sync(0xffffffffu, sum, o);
    if ((tid & 31) == 0) red[tid >> 5] = sum;
    __syncthreads();
    if (tid < 32) {
        float r = (tid < 8) ? red[tid] : 0.f;
#pragma unroll
        for (int o = 4; o > 0; o >>= 1) r += __shfl_xor_sync(0xffffffffu, r, o);
        if (tid == 0) red[0] = r;
    }
    __syncthreads();
    float inv = 1.0f / red[0];
#pragma unroll
    for (int e = 0; e < 2; e++) s[tid + e * 256] = v[e] * inv;
}

// ---------------------------------------------------------------------------
// y = LayerNorm(xin + a) * g + b    (row length 512, eps 1e-5)
// ---------------------------------------------------------------------------
__global__ void add_ln_kernel(const float* __restrict__ xin,
                              const float* __restrict__ a,
                              const float* __restrict__ gg,
                              const float* __restrict__ bb,
                              float* __restrict__ y)
{
    int row = blockIdx.x;
    int tid = threadIdx.x;                // 256 threads, 2 elems each
    long base = (long)row * Dm;
    __shared__ float red[8];

    float v[2];
    float sum = 0.f;
#pragma unroll
    for (int e = 0; e < 2; e++) {
        int d = tid + e * 256;
        v[e] = xin[base + d] + a[base + d];
        sum += v[e];
    }
    // block sum -> mean
#pragma unroll
    for (int o = 16; o > 0; o >>= 1) sum += __shfl_xor_sync(0xffffffffu, sum, o);
    if ((tid & 31) == 0) red[tid >> 5] = sum;
    __syncthreads();
    if (tid < 32) {
        float r = (tid < 8) ? red[tid] : 0.f;
#pragma unroll
        for (int o = 4; o > 0; o >>= 1) r += __shfl_xor_sync(0xffffffffu, r, o);
        if (tid == 0) red[0] = r;
    }
    __syncthreads();
    float m = red[0] * (1.0f / (float)Dm);
    __syncthreads();

    float vs = 0.f;
#pragma unroll
    for (int e = 0; e < 2; e++) { float c = v[e] - m; vs += c * c; }
#pragma unroll
    for (int o = 16; o > 0; o >>= 1) vs += __shfl_xor_sync(0xffffffffu, vs, o);
    if ((tid & 31) == 0) red[tid >> 5] = vs;
    __syncthreads();
    if (tid < 32) {
        float r = (tid < 8) ? red[tid] : 0.f;
#pragma unroll
        for (int o = 4; o > 0; o >>= 1) r += __shfl_xor_sync(0xffffffffu, r, o);
        if (tid == 0) red[0] = r;
    }
    __syncthreads();
    float var = red[0] * (1.0f / (float)Dm);
    float rs = rsqrtf(var + 1e-5f);
#pragma unroll
    for (int e = 0; e < 2; e++) {
        int d = tid + e * 256;
        y[base + d] = (v[e] - m) * rs * gg[d] + bb[d];
    }
}

// ---------------------------------------------------------------------------
// Generic batched SGEMM. C[m,n] = sum_k A[m,k] * op(B)[k,n]  (+bias, +relu)
//   TRANSB=false: B[k*ldb + n]      TRANSB=true: B[n*ldb + k]
//   EPI: 0 = none, 1 = +bias, 2 = +bias, relu
// Batch index z -> (zb = z/Hn, zh = z%Hn); per-operand (b,h) strides.
// Tiles: BM=BN=128, BK=16; 256 threads; 8x8 per-thread micro-tile.
// M must be a multiple of 128 and K a multiple of 16 (true for all calls);
// N is guarded (needed for N=32001 LM head).
// ---------------------------------------------------------------------------
#define BM 128
#define BN 128
#define BKx 16

template<bool TRANSB, int EPI>
__global__ void __launch_bounds__(256, 2)
sgemm_kernel(const float* __restrict__ A, const float* __restrict__ Bm,
             const float* __restrict__ Bias, float* __restrict__ C,
             int M, int N, int K, int lda, int ldb, int ldc,
             long sAb, long sAh, long sBb, long sBh, long sCb, long sCh,
             long sBiB, long sBiH, int Hn)
{
    __shared__ float As[BKx][BM + 4];
    __shared__ float Bs[BKx][BN + 4];

    int z  = blockIdx.z;
    int zb = z / Hn, zh = z % Hn;
    A  += zb * sAb + zh * sAh;
    Bm += zb * sBb + zh * sBh;
    C  += zb * sCb + zh * sCh;
    long biasOff = zb * sBiB + zh * sBiH;

    int m0 = blockIdx.y * BM;
    int n0 = blockIdx.x * BN;
    int tid = threadIdx.x;
    int tx = tid & 15, ty = tid >> 4;

    float acc[8][8];
#pragma unroll
    for (int i = 0; i < 8; i++)
#pragma unroll
        for (int j = 0; j < 8; j++) acc[i][j] = 0.f;

    for (int k0 = 0; k0 < K; k0 += BKx) {
        // load A tile -> As[k][m]
#pragma unroll
        for (int i = 0; i < 8; i++) {
            int idx = tid + i * 256;
            int m = idx >> 4, k = idx & 15;
            As[k][m] = A[(long)(m0 + m) * lda + (k0 + k)];
        }
        // load B tile -> Bs[k][n]
        if (TRANSB) {
#pragma unroll
            for (int i = 0; i < 8; i++) {
                int idx = tid + i * 256;
                int n = idx >> 4, k = idx & 15;
                float vv = 0.f;
                if (n0 + n < N) vv = Bm[(long)(n0 + n) * ldb + (k0 + k)];
                Bs[k][n] = vv;
            }
        } else {
#pragma unroll
            for (int i = 0; i < 8; i++) {
                int idx = tid + i * 256;
                int k = idx >> 7, n = idx & 127;
                float vv = 0.f;
                if (n0 + n < N) vv = Bm[(long)(k0 + k) * ldb + (n0 + n)];
                Bs[k][n] = vv;
            }
        }
        __syncthreads();

#pragma unroll
        for (int k = 0; k < BKx; k++) {
            float a[8], b[8];
#pragma unroll
            for (int i = 0; i < 8; i++) a[i] = As[k][ty * 8 + i];
#pragma unroll
            for (int j = 0; j < 8; j++) b[j] = Bs[k][tx * 8 + j];
#pragma unroll
            for (int i = 0; i < 8; i++)
#pragma unroll
                for (int j = 0; j < 8; j++)
                    acc[i][j] = fmaf(a[i], b[j], acc[i][j]);
        }
        __syncthreads();
    }

#pragma unroll
    for (int i = 0; i < 8; i++) {
        int m = m0 + ty * 8 + i;
#pragma unroll
        for (int j = 0; j < 8; j++) {
            int n = n0 + tx * 8 + j;
            if (n < N) {
                float vv = acc[i][j];
                if (EPI >= 1) vv += Bias[biasOff + n];
                if (EPI == 2) vv = fmaxf(vv, 0.f);
                C[(long)m * ldc + n] = vv;
            }
        }
    }
}

// ---------------------------------------------------------------------------
// Host-side dispatch
// ---------------------------------------------------------------------------
static void launch_gemm(bool transb, int epi,
                        const float* A, const float* B, const float* Bias, float* C,
                        int M, int N, int K, int lda, int ldb, int ldc,
                        long sAb, long sAh, long sBb, long sBh, long sCb, long sCh,
                        long sBiB, long sBiH, int Hn, int Z)
{
    dim3 grid((N + BN - 1) / BN, M / BM, Z), blk(256);
    if (!transb) {
        if (epi == 0)
            sgemm_kernel<false, 0><<<grid, blk>>>(A, B, Bias, C, M, N, K, lda, ldb, ldc,
                                                  sAb, sAh, sBb, sBh, sCb, sCh, sBiB, sBiH, Hn);
        else if (epi == 1)
            sgemm_kernel<false, 1><<<grid, blk>>>(A, B, Bias, C, M, N, K, lda, ldb, ldc,
                                                  sAb, sAh, sBb, sBh, sCb, sCh, sBiB, sBiH, Hn);
        else
            sgemm_kernel<false, 2><<<grid, blk>>>(A, B, Bias, C, M, N, K, lda, ldb, ldc,
                                                  sAb, sAh, sBb, sBh, sCb, sCh, sBiB, sBiH, Hn);
    } else {
        sgemm_kernel<true, 0><<<grid, blk>>>(A, B, Bias, C, M, N, K, lda, ldb, ldc,
                                             sAb, sAh, sBb, sBh, sCb, sCh, sBiB, sBiH, Hn);
    }
}

extern "C" void kernel_launch(void* const* d_in, const int* in_sizes, int n_in,
                              void* d_out, int out_size)
{
    const float* enc    = (const float*)d_in[0];
    const int*   srcpad = (const int*)  d_in[1];
    const int*   target = (const int*)  d_in[2];
    const float* emb    = (const float*)d_in[3];
    const float* Wq1 = (const float*)d_in[4],  *bq1 = (const float*)d_in[5];
    const float* Wk1 = (const float*)d_in[6],  *bk1 = (const float*)d_in[7];
    const float* Wv1 = (const float*)d_in[8],  *bv1 = (const float*)d_in[9];
    const float* Wo1 = (const float*)d_in[10], *bo1 = (const float*)d_in[11];
    const float* Wq2 = (const float*)d_in[12], *bq2 = (const float*)d_in[13];
    const float* Wk2 = (const float*)d_in[14], *bk2 = (const float*)d_in[15];
    const float* Wv2 = (const float*)d_in[16], *bv2 = (const float*)d_in[17];
    const float* Wo2 = (const float*)d_in[18], *bo2 = (const float*)d_in[19];
    // NOTE: metadata follows setup_inputs() dict-insertion order:
    //   [20]=ln1_g [21]=ln2_g [22]=ln3_g [23]=ln1_b [24]=ln2_b [25]=ln3_b
    const float* ln1g = (const float*)d_in[20];
    const float* ln2g = (const float*)d_in[21];
    const float* ln3g = (const float*)d_in[22];
    const float* ln1b = (const float*)d_in[23];
    const float* ln2b = (const float*)d_in[24];
    const float* ln3b = (const float*)d_in[25];
    const float* Wf1 = (const float*)d_in[26], *bf1 = (const float*)d_in[27];
    const float* Wf2 = (const float*)d_in[28], *bf2 = (const float*)d_in[29];
    const float* lmW = (const float*)d_in[30], *lmb = (const float*)d_in[31];
    float* out = (float*)d_out;

    float *x, *qq, *kk, *vv, *ss, *oo, *tt, *ff;
    cudaGetSymbolAddress((void**)&x,  g_x);
    cudaGetSymbolAddress((void**)&qq, g_q);
    cudaGetSymbolAddress((void**)&kk, g_k);
    cudaGetSymbolAddress((void**)&vv, g_v);
    cudaGetSymbolAddress((void**)&ss, g_s);
    cudaGetSymbolAddress((void**)&oo, g_o);
    cudaGetSymbolAddress((void**)&tt, g_t);
    cudaGetSymbolAddress((void**)&ff, g_ff);

    const float scale = 1.0f / sqrtf((float)Dm);
    const long WATT = (long)Hh * Dm * Dm;     // per-layer attn weight stride
    const long WOUT = (long)HD * Dm;          // per-layer out-proj weight stride
    const long WFF  = (long)Dm * FFd;         // per-layer ffn weight stride

    // x = emb[target] + PE
    embed_pe_kernel<<<NR, 512>>>(target, emb, x);

    for (int l = 0; l < 2; l++) {
        // ================= self attention =================
        // Q/K/V: batched over heads. M=2048,N=512,K=512, C cols packed [h*D+e]
        launch_gemm(false, 1, x, Wq1 + l * WATT, bq1 + l * HD, qq,
                    NR, Dm, Dm, Dm, Dm, HD, 0, 0, 0, (long)Dm * Dm, 0, Dm, 0, Dm, Hh, Hh);
        launch_gemm(false, 1, x, Wk1 + l * WATT, bk1 + l * HD, kk,
                    NR, Dm, Dm, Dm, Dm, HD, 0, 0, 0, (long)Dm * Dm, 0, Dm, 0, Dm, Hh, Hh);
        launch_gemm(false, 1, x, Wv1 + l * WATT, bv1 + l * HD, vv,
                    NR, Dm, Dm, Dm, Dm, HD, 0, 0, 0, (long)Dm * Dm, 0, Dm, 0, Dm, Hh, Hh);
        // scores: S[b,h] = Q[b,h] @ K[b,h]^T
        launch_gemm(true, 0, qq, kk, nullptr, ss,
                    TTq, TSs, Dm, HD, HD, TSs,
                    (long)TTq * HD, Dm, (long)TTq * HD, Dm,
                    (long)Hh * TTq * TSs, (long)TTq * TSs, 0, 0, Hh, Bq * Hh);
        softmax_kernel<<<Bq * Hh * TTq, 256>>>(ss, target, srcpad, 1, scale);
        // O[b,h] = S @ V, written into concat layout [row][h*D+e]
        launch_gemm(false, 0, ss, vv, nullptr, oo,
                    TTq, Dm, TSs, TSs, HD, HD,
                    (long)Hh * TTq * TSs, (long)TTq * TSs, (long)TTq * HD, Dm,
                    (long)TTq * HD, Dm, 0, 0, Hh, Bq * Hh);
        // out proj
        launch_gemm(false, 1, oo, Wo1 + l * WOUT, bo1 + l * Dm, tt,
                    NR, Dm, HD, HD, Dm, Dm, 0, 0, 0, 0, 0, 0, 0, 0, 1, 1);
        add_ln_kernel<<<NR, 256>>>(x, tt, ln1g + l * Dm, ln1b + l * Dm, x);

        // ================= cross attention =================
        launch_gemm(false, 1, x, Wq2 + l * WATT, bq2 + l * HD, qq,
                    NR, Dm, Dm, Dm, Dm, HD, 0, 0, 0, (long)Dm * Dm, 0, Dm, 0, Dm, Hh, Hh);
        launch_gemm(false, 1, enc, Wk2 + l * WATT, bk2 + l * HD, kk,
                    NR, Dm, Dm, Dm, Dm, HD, 0, 0, 0, (long)Dm * Dm, 0, Dm, 0, Dm, Hh, Hh);
        launch_gemm(false, 1, enc, Wv2 + l * WATT, bv2 + l * HD, vv,
                    NR, Dm, Dm, Dm, Dm, HD, 0, 0, 0, (long)Dm * Dm, 0, Dm, 0, Dm, Hh, Hh);
        launch_gemm(true, 0, qq, kk, nullptr, ss,
                    TTq, TSs, Dm, HD, HD, TSs,
                    (long)TTq * HD, Dm, (long)TSs * HD, Dm,
                    (long)Hh * TTq * TSs, (long)TTq * TSs, 0, 0, Hh, Bq * Hh);
        softmax_kernel<<<Bq * Hh * TTq, 256>>>(ss, target, srcpad, 2, scale);
        if (l == 0 && (long)out_size >= LOGITS_ELEMS + ATT_ELEMS) {
            cudaMemcpyAsync(out + LOGITS_ELEMS, ss, ATT_ELEMS * sizeof(float),
                            cudaMemcpyDeviceToDevice, 0);
        }
        launch_gemm(false, 0, ss, vv, nullptr, oo,
                    TTq, Dm, TSs, TSs, HD, HD,
                    (long)Hh * TTq * TSs, (long)TTq * TSs, (long)TSs * HD, Dm,
                    (long)TTq * HD, Dm, 0, 0, Hh, Bq * Hh);
        launch_gemm(false, 1, oo, Wo2 + l * WOUT, bo2 + l * Dm, tt,
                    NR, Dm, HD, HD, Dm, Dm, 0, 0, 0, 0, 0, 0, 0, 0, 1, 1);
        add_ln_kernel<<<NR, 256>>>(x, tt, ln2g + l * Dm, ln2b + l * Dm, x);

        // ================= FFN =================
        launch_gemm(false, 2, x, Wf1 + l * WFF, bf1 + l * FFd, ff,
                    NR, FFd, Dm, Dm, FFd, FFd, 0, 0, 0, 0, 0, 0, 0, 0, 1, 1);
        launch_gemm(false, 1, ff, Wf2 + l * WFF, bf2 + l * Dm, tt,
                    NR, Dm, FFd, FFd, Dm, Dm, 0, 0, 0, 0, 0, 0, 0, 0, 1, 1);
        add_ln_kernel<<<NR, 256>>>(x, tt, ln3g + l * Dm, ln3b + l * Dm, x);
    }

    // ================= LM head =================
    launch_gemm(false, 1, x, lmW, lmb, out,
                NR, VO, Dm, Dm, VO, VO, 0, 0, 0, 0, 0, 0, 0, 0, 1, 1);
}

// round 4
// speedup vs baseline: 2.2020x; 2.2020x over previous
#include <cuda_runtime.h>
#include <cuda_bf16.h>
#include <math.h>
#include <stdint.h>

// ---------------------------------------------------------------------------
// Problem constants
// ---------------------------------------------------------------------------
#define Bq   4
#define TTq  512
#define TSs  512
#define Dm   512
#define Hh   8
#define Vv   32000
#define VO   32001
#define NR   2048            // B*TT rows
#define HD   4096            // H*D
#define FFd  2048            // 4*D

#define LOGITS_ELEMS (2048LL * 32001LL)
#define ATT_ELEMS    (4LL * 8 * 512 * 512)

// ---------------------------------------------------------------------------
// Scratch (static device globals)
// ---------------------------------------------------------------------------
__device__ float g_x [NR * Dm];
__device__ float g_q [NR * HD];
__device__ float g_k [NR * HD];
__device__ float g_v [NR * HD];
__device__ float g_s [Bq * Hh * TTq * TSs];
__device__ float g_o [NR * HD];
__device__ float g_t [NR * Dm];
__device__ float g_ff[NR * FFd];

__device__ __nv_bfloat16 g_x3 [NR * 1536];
__device__ __nv_bfloat16 g_e3 [NR * 1536];
__device__ __nv_bfloat16 g_q3 [NR * 12288];
__device__ __nv_bfloat16 g_k3 [NR * 12288];
__device__ __nv_bfloat16 g_v3 [32 * 512 * 1536];
__device__ __nv_bfloat16 g_s3 [32 * 512 * 1536];
__device__ __nv_bfloat16 g_o3 [NR * 12288];
__device__ __nv_bfloat16 g_f3 [NR * 6144];
__device__ __nv_bfloat16 g_w3 [6291456];            // weight triple scratch (max 4096x1536)
__device__ __nv_bfloat16 g_lm3[32128 * 1536];       // LM head, rows padded to 251*128 (pads stay 0)

// ---------------------------------------------------------------------------
// Embedding + positional encoding
// ---------------------------------------------------------------------------
__global__ void embed_pe_kernel(const int* __restrict__ target,
                                const float* __restrict__ emb,
                                float* __restrict__ x)
{
    int row = blockIdx.x;
    int t   = row & (TTq - 1);
    int d   = threadIdx.x;
    int tok = target[row];
    float e = emb[(long)tok * Dm + d];
    int   i = d >> 1;
    float denom = powf(10000.0f, (2.0f * (float)i) / (float)Dm);
    float z = (float)t / denom;
    float p = (d & 1) ? cosf(z) : sinf(z);
    x[(long)row * Dm + d] = e + p;
}

// ---------------------------------------------------------------------------
// Masked softmax over the last dim (512).
// ---------------------------------------------------------------------------
__global__ void softmax_kernel(float* __restrict__ S,
                               const int* __restrict__ target,
                               const int* __restrict__ srcpad,
                               int mode, float scale)
{
    int row = blockIdx.x;
    int q   = row & (TTq - 1);
    int b   = row / (Hh * TTq);
    float* s = S + (long)row * TSs;
    int tid = threadIdx.x;
    bool qpad = (target[b * TTq + q] != Vv);

    float v[2];
    float mx = -INFINITY;
#pragma unroll
    for (int e = 0; e < 2; e++) {
        int k = tid + e * 256;
        bool valid;
        if (mode == 1)
            valid = qpad && (k <= q) && (target[b * TTq + k] != Vv);
        else
            valid = qpad && (srcpad[b * TSs + k] != 0);
        float val = valid ? s[k] * scale : -1e32f;
        v[e] = val;
        mx = fmaxf(mx, val);
    }

    __shared__ float red[8];
#pragma unroll
    for (int o = 16; o > 0; o >>= 1) mx = fmaxf(mx, __shfl_xor_sync(0xffffffffu, mx, o));
    if ((tid & 31) == 0) red[tid >> 5] = mx;
    __syncthreads();
    if (tid < 32) {
        float r = (tid < 8) ? red[tid] : -INFINITY;
#pragma unroll
        for (int o = 4; o > 0; o >>= 1) r = fmaxf(r, __shfl_xor_sync(0xffffffffu, r, o));
        if (tid == 0) red[0] = r;
    }
    __syncthreads();
    mx = red[0];
    __syncthreads();

    float sum = 0.f;
#pragma unroll
    for (int e = 0; e < 2; e++) { v[e] = expf(v[e] - mx); sum += v[e]; }
#pragma unroll
    for (int o = 16; o > 0; o >>= 1) sum += __shfl_xor_sync(0xffffffffu, sum, o);
    if ((tid & 31) == 0) red[tid >> 5] = sum;
    __syncthreads();
    if (tid < 32) {
        float r = (tid < 8) ? red[tid] : 0.f;
#pragma unroll
        for (int o = 4; o > 0; o >>= 1) r += __shfl_xor_sync(0xffffffffu, r, o);
        if (tid == 0) red[0] = r;
    }
    __syncthreads();
    float inv = 1.0f / red[0];
#pragma unroll
    for (int e = 0; e < 2; e++) s[tid + e * 256] = v[e] * inv;
}

// ---------------------------------------------------------------------------
// y = LayerNorm(xin + a) * g + b
// ---------------------------------------------------------------------------
__global__ void add_ln_kernel(const float* __restrict__ xin,
                              const float* __restrict__ a,
                              const float* __restrict__ gg,
                              const float* __restrict__ bb,
                              float* __restrict__ y)
{
    int row = blockIdx.x;
    int tid = threadIdx.x;
    long base = (long)row * Dm;
    __shared__ float red[8];

    float v[2];
    float sum = 0.f;
#pragma unroll
    for (int e = 0; e < 2; e++) {
        int d = tid + e * 256;
        v[e] = xin[base + d] + a[base + d];
        sum += v[e];
    }
#pragma unroll
    for (int o = 16; o > 0; o >>= 1) sum += __shfl_xor_sync(0xffffffffu, sum, o);
    if ((tid & 31) == 0) red[tid >> 5] = sum;
    __syncthreads();
    if (tid < 32) {
        float r = (tid < 8) ? red[tid] : 0.f;
#pragma unroll
        for (int o = 4; o > 0; o >>= 1) r += __shfl_xor_sync(0xffffffffu, r, o);
        if (tid == 0) red[0] = r;
    }
    __syncthreads();
    float m = red[0] * (1.0f / (float)Dm);
    __syncthreads();

    float vs = 0.f;
#pragma unroll
    for (int e = 0; e < 2; e++) { float c = v[e] - m; vs += c * c; }
#pragma unroll
    for (int o = 16; o > 0; o >>= 1) vs += __shfl_xor_sync(0xffffffffu, vs, o);
    if ((tid & 31) == 0) red[tid >> 5] = vs;
    __syncthreads();
    if (tid < 32) {
        float r = (tid < 8) ? red[tid] : 0.f;
#pragma unroll
        for (int o = 4; o > 0; o >>= 1) r += __shfl_xor_sync(0xffffffffu, r, o);
        if (tid == 0) red[0] = r;
    }
    __syncthreads();
    float var = red[0] * (1.0f / (float)Dm);
    float rs = rsqrtf(var + 1e-5f);
#pragma unroll
    for (int e = 0; e < 2; e++) {
        int d = tid + e * 256;
        y[base + d] = (v[e] - m) * rs * gg[d] + bb[d];
    }
}

// ---------------------------------------------------------------------------
// Split-conversions (hi/lo bf16 triple along K).
// conv_nt: fp32 [R, nseg*Ks] -> bf16 [R, nseg*3Ks]; pat0: [hi|hi|lo], pat1: [hi|lo|hi]
// ---------------------------------------------------------------------------
__global__ void conv_nt_kernel(const float* __restrict__ in, __nv_bfloat16* __restrict__ out,
                               int R, int Ks, int nseg, int in_ld, int out_ld, int patB)
{
    long idx = (long)blockIdx.x * blockDim.x + threadIdx.x;
    long half = (long)(Ks >> 1);
    long tot = (long)R * nseg * half;
    if (idx >= tot) return;
    long k2 = idx % half;
    long t  = idx / half;
    int  s  = (int)(t % nseg);
    long r  = t / nseg;
    long k  = k2 * 2;
    const float* p = in + r * (long)in_ld + (long)s * Ks + k;
    float x0 = p[0], x1 = p[1];
    __nv_bfloat16 h0 = __float2bfloat16(x0), h1 = __float2bfloat16(x1);
    __nv_bfloat16 l0 = __float2bfloat16(x0 - __bfloat162float(h0));
    __nv_bfloat16 l1 = __float2bfloat16(x1 - __bfloat162float(h1));
    __nv_bfloat162 hh; hh.x = h0; hh.y = h1;
    __nv_bfloat162 ll; ll.x = l0; ll.y = l1;
    __nv_bfloat16* ob = out + r * (long)out_ld + (long)s * 3 * Ks + k;
    if (patB) {
        *(__nv_bfloat162*)(ob)          = hh;
        *(__nv_bfloat162*)(ob + Ks)     = ll;
        *(__nv_bfloat162*)(ob + 2 * Ks) = hh;
    } else {
        *(__nv_bfloat162*)(ob)          = hh;
        *(__nv_bfloat162*)(ob + Ks)     = hh;
        *(__nv_bfloat162*)(ob + 2 * Ks) = ll;
    }
}

// conv_t: fp32 [K, N] (N-contig) -> bf16 triple [N, 3K], pattern [hi|lo|hi].
__global__ void conv_t_kernel(const float* __restrict__ in, __nv_bfloat16* __restrict__ out,
                              int K, int N, int in_ld, int out_ld,
                              long sInB, long sInH, long sOutB, long sOutH, int Hn)
{
    __shared__ float t[32][33];
    int z = blockIdx.z, zb = z / Hn, zh = z % Hn;
    in  += zb * sInB + zh * sInH;
    out += zb * sOutB + zh * sOutH;
    int k0 = blockIdx.y * 32, n0 = blockIdx.x * 32;
    int tx = threadIdx.x, ty = threadIdx.y;   // 32 x 8
#pragma unroll
    for (int i = 0; i < 4; ++i) {
        int k = k0 + ty + i * 8, n = n0 + tx;
        t[ty + i * 8][tx] = (n < N) ? in[(long)k * in_ld + n] : 0.f;
    }
    __syncthreads();
#pragma unroll
    for (int i = 0; i < 4; ++i) {
        int n = n0 + ty + i * 8, k = k0 + tx;
        if (n < N) {
            float x = t[tx][ty + i * 8];
            __nv_bfloat16 h = __float2bfloat16(x);
            __nv_bfloat16 l = __float2bfloat16(x - __bfloat162float(h));
            __nv_bfloat16* o = out + (long)n * out_ld + k;
            o[0]     = h;
            o[K]     = l;
            o[2 * K] = h;
        }
    }
}

// ---------------------------------------------------------------------------
// bf16 tensor-core GEMM via mma.sync (HMMA, legal on sm_103 non-'a').
// C[m,n] (+bias,+relu) = sum_k A3[m,k] * B3[n,k]
// A3: [M, K3] K-contig; B3: [N, K3] K-contig (rows padded to multiple of 128).
// CTA 128x128, BK=32, 8 warps (2x4), warp tile 64x32 (4x4 m16n8k16 frags),
// cp.async 2-stage pipeline, 80B-padded smem rows (conflict-free ldmatrix).
// ---------------------------------------------------------------------------
#define GBM 128
#define GBN 128
#define GBK 32
#define LDS_PAD 40                 // elements per smem row (80 bytes)
#define STAGE_ELEMS (128 * LDS_PAD)
#define STAGE_BYTES (STAGE_ELEMS * 2)

__device__ __forceinline__ uint32_t smem_u32(const void* p) {
    uint32_t a;
    asm("{ .reg .u64 t; cvta.to.shared.u64 t, %1; cvt.u32.u64 %0, t; }" : "=r"(a) : "l"(p));
    return a;
}
#define CP16(dst, src) \
    asm volatile("cp.async.cg.shared.global [%0], [%1], 16;" :: "r"(dst), "l"(src))
#define CP_COMMIT() asm volatile("cp.async.commit_group;" ::: "memory")
#define CP_WAIT1()  asm volatile("cp.async.wait_group 1;" ::: "memory")
#define CP_WAIT0()  asm volatile("cp.async.wait_group 0;" ::: "memory")
#define LDSM_X4(r0, r1, r2, r3, addr) \
    asm volatile("ldmatrix.sync.aligned.m8n8.x4.shared.b16 {%0,%1,%2,%3}, [%4];" \
                 : "=r"(r0), "=r"(r1), "=r"(r2), "=r"(r3) : "r"(addr))
#define MMA_BF16(c, a0, a1, a2, a3, b0, b1) \
    asm volatile("mma.sync.aligned.m16n8k16.row.col.f32.bf16.bf16.f32 " \
                 "{%0,%1,%2,%3}, {%4,%5,%6,%7}, {%8,%9}, {%0,%1,%2,%3};" \
                 : "+f"((c)[0]), "+f"((c)[1]), "+f"((c)[2]), "+f"((c)[3]) \
                 : "r"(a0), "r"(a1), "r"(a2), "r"(a3), "r"(b0), "r"(b1))

template<int EPI>
__global__ void __launch_bounds__(256)
hgemm_kernel(const __nv_bfloat16* __restrict__ A3, const __nv_bfloat16* __restrict__ B3,
             const float* __restrict__ Bias, float* __restrict__ C,
             int Nstore, int K3, int lda, int ldb, int ldc,
             long sAb, long sAh, long sBb, long sBh, long sCb, long sCh,
             long sBiB, long sBiH, int Hn)
{
    __shared__ __align__(16) __nv_bfloat16 As[2][STAGE_ELEMS];
    __shared__ __align__(16) __nv_bfloat16 Bs[2][STAGE_ELEMS];

    int tid = threadIdx.x;
    int wid = tid >> 5, lane = tid & 31;

    int z = blockIdx.z, zb = z / Hn, zh = z % Hn;
    A3 += zb * sAb + zh * sAh;
    B3 += zb * sBb + zh * sBh;
    C  += zb * sCb + zh * sCh;
    long biasOff = zb * sBiB + zh * sBiH;

    long m0 = (long)blockIdx.x * GBM;
    long n0 = (long)blockIdx.y * GBN;

    const int wm = (wid >> 2) * 64;   // warp M offset in tile
    const int wn = (wid & 3) * 32;    // warp N offset in tile

    const uint32_t aBase = smem_u32(As);
    const uint32_t bBase = smem_u32(Bs);

    float acc[4][4][4];
#pragma unroll
    for (int i = 0; i < 4; i++)
#pragma unroll
        for (int j = 0; j < 4; j++)
#pragma unroll
            for (int q = 0; q < 4; q++) acc[i][j][q] = 0.f;

    const int nIter = K3 / GBK;

    // ---- stage loader ----
    auto loadStage = [&](int s, long k0) {
        uint32_t aD = aBase + s * STAGE_BYTES;
        uint32_t bD = bBase + s * STAGE_BYTES;
#pragma unroll
        for (int i = 0; i < 2; i++) {
            int c = tid + i * 256;
            int r = c >> 2, seg = c & 3;
            const __nv_bfloat16* src = A3 + (m0 + r) * (long)lda + k0 + seg * 8;
            CP16(aD + (uint32_t)(r * 80 + seg * 16), src);
        }
#pragma unroll
        for (int i = 0; i < 2; i++) {
            int c = tid + i * 256;
            int r = c >> 2, seg = c & 3;
            const __nv_bfloat16* src = B3 + (n0 + r) * (long)ldb + k0 + seg * 8;
            CP16(bD + (uint32_t)(r * 80 + seg * 16), src);
        }
        CP_COMMIT();
    };

    loadStage(0, 0);

    for (int it = 0; it < nIter; ++it) {
        int s = it & 1;
        if (it + 1 < nIter) {
            loadStage((it + 1) & 1, (long)(it + 1) * GBK);
            CP_WAIT1();
        } else {
            CP_WAIT0();
        }
        __syncthreads();

        uint32_t aS = aBase + s * STAGE_BYTES;
        uint32_t bS = bBase + s * STAGE_BYTES;
#pragma unroll
        for (int ks = 0; ks < 2; ks++) {
            int col = ks * 16 + (lane >> 4) * 8;
            uint32_t a[4][4], bf[4][2];
#pragma unroll
            for (int mi = 0; mi < 4; mi++) {
                int row = wm + mi * 16 + (lane & 15);
                uint32_t addr = aS + (uint32_t)(row * 80 + col * 2);
                LDSM_X4(a[mi][0], a[mi][1], a[mi][2], a[mi][3], addr);
            }
#pragma unroll
            for (int p = 0; p < 2; p++) {
                int row = wn + p * 16 + (lane & 15);
                uint32_t addr = bS + (uint32_t)(row * 80 + col * 2);
                uint32_t r0, r1, r2, r3;
                LDSM_X4(r0, r1, r2, r3, addr);
                bf[2 * p][0] = r0;     bf[2 * p][1] = r2;
                bf[2 * p + 1][0] = r1; bf[2 * p + 1][1] = r3;
            }
#pragma unroll
            for (int mi = 0; mi < 4; mi++)
#pragma unroll
                for (int ni = 0; ni < 4; ni++)
                    MMA_BF16(acc[mi][ni], a[mi][0], a[mi][1], a[mi][2], a[mi][3],
                             bf[ni][0], bf[ni][1]);
        }
        __syncthreads();
    }

    // ---- epilogue ----
#pragma unroll
    for (int mi = 0; mi < 4; mi++) {
        long mrow = m0 + wm + mi * 16 + (lane >> 2);
        float* c0p = C + mrow * (long)ldc;
        float* c1p = c0p + 8L * ldc;
#pragma unroll
        for (int ni = 0; ni < 4; ni++) {
            long n = n0 + wn + ni * 8 + (lane & 3) * 2;
#pragma unroll
            for (int e = 0; e < 2; e++) {
                long nn = n + e;
                if (nn < (long)Nstore) {
                    float v0 = acc[mi][ni][e];
                    float v1 = acc[mi][ni][2 + e];
                    if (EPI >= 1) {
                        float bsv = Bias[biasOff + nn];
                        v0 += bsv; v1 += bsv;
                    }
                    if (EPI == 2) { v0 = fmaxf(v0, 0.f); v1 = fmaxf(v1, 0.f); }
                    c0p[nn] = v0;
                    c1p[nn] = v1;
                }
            }
        }
    }
}

// ---------------------------------------------------------------------------
// Host dispatch
// ---------------------------------------------------------------------------
static void tg(int epi, const __nv_bfloat16* A, const __nv_bfloat16* B, const float* Bias,
               float* C, int M, int N, int K3, int lda, int ldb, int ldc,
               long sAb, long sAh, long sBb, long sBh, long sCb, long sCh,
               long sBiB, long sBiH, int Hn, int Z)
{
    dim3 g(M / GBM, (N + GBN - 1) / GBN, Z), b(256);
    switch (epi) {
    case 0: hgemm_kernel<0><<<g, b>>>(A, B, Bias, C, N, K3, lda, ldb, ldc,
                                      sAb, sAh, sBb, sBh, sCb, sCh, sBiB, sBiH, Hn); break;
    case 1: hgemm_kernel<1><<<g, b>>>(A, B, Bias, C, N, K3, lda, ldb, ldc,
                                      sAb, sAh, sBb, sBh, sCb, sCh, sBiB, sBiH, Hn); break;
    default: hgemm_kernel<2><<<g, b>>>(A, B, Bias, C, N, K3, lda, ldb, ldc,
                                       sAb, sAh, sBb, sBh, sCb, sCh, sBiB, sBiH, Hn); break;
    }
}

static void conv_nt(const float* in, __nv_bfloat16* out, int R, int Ks, int nseg,
                    int in_ld, int out_ld, int patB)
{
    long tot = (long)R * nseg * (Ks / 2);
    int blocks = (int)((tot + 255) / 256);
    conv_nt_kernel<<<blocks, 256>>>(in, out, R, Ks, nseg, in_ld, out_ld, patB);
}

extern "C" void kernel_launch(void* const* d_in, const int* in_sizes, int n_in,
                              void* d_out, int out_size)
{
    const float* enc    = (const float*)d_in[0];
    const int*   srcpad = (const int*)  d_in[1];
    const int*   target = (const int*)  d_in[2];
    const float* emb    = (const float*)d_in[3];
    const float* Wq1 = (const float*)d_in[4],  *bq1 = (const float*)d_in[5];
    const float* Wk1 = (const float*)d_in[6],  *bk1 = (const float*)d_in[7];
    const float* Wv1 = (const float*)d_in[8],  *bv1 = (const float*)d_in[9];
    const float* Wo1 = (const float*)d_in[10], *bo1 = (const float*)d_in[11];
    const float* Wq2 = (const float*)d_in[12], *bq2 = (const float*)d_in[13];
    const float* Wk2 = (const float*)d_in[14], *bk2 = (const float*)d_in[15];
    const float* Wv2 = (const float*)d_in[16], *bv2 = (const float*)d_in[17];
    const float* Wo2 = (const float*)d_in[18], *bo2 = (const float*)d_in[19];
    // dict-insertion order: g,g,g then b,b,b
    const float* ln1g = (const float*)d_in[20];
    const float* ln2g = (const float*)d_in[21];
    const float* ln3g = (const float*)d_in[22];
    const float* ln1b = (const float*)d_in[23];
    const float* ln2b = (const float*)d_in[24];
    const float* ln3b = (const float*)d_in[25];
    const float* Wf1 = (const float*)d_in[26], *bf1 = (const float*)d_in[27];
    const float* Wf2 = (const float*)d_in[28], *bf2 = (const float*)d_in[29];
    const float* lmW = (const float*)d_in[30], *lmb = (const float*)d_in[31];
    float* out = (float*)d_out;

    float *x, *qq, *kk, *vv, *ss, *oo, *tt, *ff;
    cudaGetSymbolAddress((void**)&x,  g_x);
    cudaGetSymbolAddress((void**)&qq, g_q);
    cudaGetSymbolAddress((void**)&kk, g_k);
    cudaGetSymbolAddress((void**)&vv, g_v);
    cudaGetSymbolAddress((void**)&ss, g_s);
    cudaGetSymbolAddress((void**)&oo, g_o);
    cudaGetSymbolAddress((void**)&tt, g_t);
    cudaGetSymbolAddress((void**)&ff, g_ff);
    __nv_bfloat16 *x3, *e3, *q3, *k3, *v3, *s3, *o3, *f3, *w3, *lm3;
    cudaGetSymbolAddress((void**)&x3, g_x3);
    cudaGetSymbolAddress((void**)&e3, g_e3);
    cudaGetSymbolAddress((void**)&q3, g_q3);
    cudaGetSymbolAddress((void**)&k3, g_k3);
    cudaGetSymbolAddress((void**)&v3, g_v3);
    cudaGetSymbolAddress((void**)&s3, g_s3);
    cudaGetSymbolAddress((void**)&o3, g_o3);
    cudaGetSymbolAddress((void**)&f3, g_f3);
    cudaGetSymbolAddress((void**)&w3, g_w3);
    cudaGetSymbolAddress((void**)&lm3, g_lm3);

    const float scale = 1.0f / sqrtf((float)Dm);
    const long WATT = (long)Hh * Dm * Dm;
    const long WOUT = (long)HD * Dm;
    const long WFF  = (long)Dm * FFd;
    const dim3 tb(32, 8);

    // x = emb[target] + PE;  triples of x and enc
    embed_pe_kernel<<<NR, 512>>>(target, emb, x);
    conv_nt(x,   x3, NR, Dm, 1, Dm, 1536, 0);
    conv_nt(enc, e3, NR, Dm, 1, Dm, 1536, 0);

    for (int l = 0; l < 2; l++) {
        const float *WQ[2] = {Wq1 + l * WATT, Wq2 + l * WATT};
        const float *WK[2] = {Wk1 + l * WATT, Wk2 + l * WATT};
        const float *WV[2] = {Wv1 + l * WATT, Wv2 + l * WATT};
        const float *WO[2] = {Wo1 + l * WOUT, Wo2 + l * WOUT};
        const float *BQ[2] = {bq1 + l * HD, bq2 + l * HD};
        const float *BK[2] = {bk1 + l * HD, bk2 + l * HD};
        const float *BV[2] = {bv1 + l * HD, bv2 + l * HD};
        const float *BO[2] = {bo1 + l * Dm, bo2 + l * Dm};
        const float *LG[2] = {ln1g + l * Dm, ln2g + l * Dm};
        const float *LB[2] = {ln1b + l * Dm, ln2b + l * Dm};

        for (int att = 0; att < 2; att++) {   // 0 = self, 1 = cross
            const __nv_bfloat16* kvA = (att == 0) ? x3 : e3;
            // ---- Q/K/V projections (batched over 8 heads) ----
            conv_t_kernel<<<dim3(16, 16, 8), tb>>>(WQ[att], w3, Dm, Dm, Dm, 1536,
                                                   0, (long)Dm * Dm, 0, (long)Dm * 1536, 8);
            tg(1, x3, w3, BQ[att], qq, NR, Dm, 1536, 1536, 1536, HD,
               0, 0, 0, (long)Dm * 1536, 0, Dm, 0, Dm, 8, 8);
            conv_nt(qq, q3, NR, Dm, 8, HD, 12288, 0);

            conv_t_kernel<<<dim3(16, 16, 8), tb>>>(WK[att], w3, Dm, Dm, Dm, 1536,
                                                   0, (long)Dm * Dm, 0, (long)Dm * 1536, 8);
            tg(1, kvA, w3, BK[att], kk, NR, Dm, 1536, 1536, 1536, HD,
               0, 0, 0, (long)Dm * 1536, 0, Dm, 0, Dm, 8, 8);
            conv_nt(kk, k3, NR, Dm, 8, HD, 12288, 1);

            conv_t_kernel<<<dim3(16, 16, 8), tb>>>(WV[att], w3, Dm, Dm, Dm, 1536,
                                                   0, (long)Dm * Dm, 0, (long)Dm * 1536, 8);
            tg(1, kvA, w3, BV[att], vv, NR, Dm, 1536, 1536, 1536, HD,
               0, 0, 0, (long)Dm * 1536, 0, Dm, 0, Dm, 8, 8);
            conv_t_kernel<<<dim3(16, 16, 32), tb>>>(vv, v3, TSs, Dm, HD, 1536,
                                                    (long)TSs * HD, Dm,
                                                    (long)Hh * TSs * 1536, (long)TSs * 1536, 8);

            // ---- scores = Q K^T (batched over 32 (b,h)) ----
            tg(0, q3, k3, nullptr, ss, TTq, TSs, 1536, 12288, 12288, TSs,
               (long)TTq * 12288, 1536, (long)TSs * 12288, 1536,
               (long)Hh * TTq * TSs, (long)TTq * TSs, 0, 0, 8, 32);

            softmax_kernel<<<Bq * Hh * TTq, 256>>>(ss, target, srcpad, att == 0 ? 1 : 2, scale);
            if (att == 1 && l == 0 && (long)out_size >= LOGITS_ELEMS + ATT_ELEMS) {
                cudaMemcpyAsync(out + LOGITS_ELEMS, ss, ATT_ELEMS * sizeof(float),
                                cudaMemcpyDeviceToDevice, 0);
            }
            conv_nt(ss, s3, Bq * Hh * TTq, TSs, 1, TSs, 1536, 0);

            // ---- O = S V ----
            tg(0, s3, v3, nullptr, oo, TTq, Dm, 1536, 1536, 1536, HD,
               (long)Hh * TTq * 1536, (long)TTq * 1536,
               (long)Hh * TSs * 1536, (long)TSs * 1536,
               (long)TTq * HD, Dm, 0, 0, 8, 32);
            conv_nt(oo, o3, NR, HD, 1, HD, 12288, 0);

            // ---- output projection + add&norm ----
            conv_t_kernel<<<dim3(16, 128, 1), tb>>>(WO[att], w3, HD, Dm, Dm, 12288,
                                                    0, 0, 0, 0, 1);
            tg(1, o3, w3, BO[att], tt, NR, Dm, 12288, 12288, 12288, Dm,
               0, 0, 0, 0, 0, 0, 0, 0, 1, 1);
            add_ln_kernel<<<NR, 256>>>(x, tt, LG[att], LB[att], x);
            conv_nt(x, x3, NR, Dm, 1, Dm, 1536, 0);
        }

        // ---- FFN ----
        conv_t_kernel<<<dim3(64, 16, 1), tb>>>(Wf1 + l * WFF, w3, Dm, FFd, FFd, 1536,
                                               0, 0, 0, 0, 1);
        tg(2, x3, w3, bf1 + l * FFd, ff, NR, FFd, 1536, 1536, 1536, FFd,
           0, 0, 0, 0, 0, 0, 0, 0, 1, 1);
        conv_nt(ff, f3, NR, FFd, 1, FFd, 6144, 0);
        conv_t_kernel<<<dim3(16, 64, 1), tb>>>(Wf2 + l * WFF, w3, FFd, Dm, Dm, 6144,
                                               0, 0, 0, 0, 1);
        tg(1, f3, w3, bf2 + l * Dm, tt, NR, Dm, 6144, 6144, 6144, Dm,
           0, 0, 0, 0, 0, 0, 0, 0, 1, 1);
        add_ln_kernel<<<NR, 256>>>(x, tt, ln3g + l * Dm, ln3b + l * Dm, x);
        conv_nt(x, x3, NR, Dm, 1, Dm, 1536, 0);
    }

    // ---- LM head ----
    conv_t_kernel<<<dim3(1001, 16, 1), tb>>>(lmW, lm3, Dm, VO, VO, 1536, 0, 0, 0, 0, 1);
    tg(1, x3, lm3, lmb, out, NR, VO, 1536, 1536, 1536, VO,
       0, 0, 0, 0, 0, 0, 0, 0, 1, 1);
}

// round 5
// speedup vs baseline: 2.3043x; 1.0465x over previous
#include <cuda_runtime.h>
#include <cuda_bf16.h>
#include <math.h>
#include <stdint.h>

// ---------------------------------------------------------------------------
// Problem constants
// ---------------------------------------------------------------------------
#define Bq   4
#define TTq  512
#define TSs  512
#define Dm   512
#define Hh   8
#define Vv   32000
#define VO   32001
#define NR   2048
#define HD   4096
#define FFd  2048

#define LOGITS_ELEMS (2048LL * 32001LL)
#define ATT_ELEMS    (4LL * 8 * 512 * 512)

// ---------------------------------------------------------------------------
// Scratch (static device globals)
// ---------------------------------------------------------------------------
__device__ float g_x [NR * Dm];          // residual stream (fp32)
__device__ float g_v [NR * HD];          // V projection (fp32, pre-transpose)
__device__ float g_s [Bq * Hh * TTq * TSs]; // scores / att weights (fp32)
__device__ float g_t [NR * Dm];          // block output before add+LN

__device__ __nv_bfloat16 g_x3 [NR * 1536];
__device__ __nv_bfloat16 g_e3 [NR * 1536];
__device__ __nv_bfloat16 g_q3 [NR * 12288];
__device__ __nv_bfloat16 g_k3 [NR * 12288];
__device__ __nv_bfloat16 g_v3 [32 * 512 * 1536];
__device__ __nv_bfloat16 g_s3 [32 * 512 * 1536];
__device__ __nv_bfloat16 g_o3 [NR * 12288];
__device__ __nv_bfloat16 g_f3 [NR * 6144];
__device__ __nv_bfloat16 g_w3 [6291456];        // weight triple scratch (max 512x12288)
__device__ __nv_bfloat16 g_lm3[32128 * 1536];   // LM head triple, rows padded to 251*128

// ---------------------------------------------------------------------------
// hi/lo split helpers
// ---------------------------------------------------------------------------
__device__ __forceinline__ void split2(float v0, float v1,
                                       __nv_bfloat162& hi, __nv_bfloat162& lo)
{
    __nv_bfloat16 h0 = __float2bfloat16(v0), h1 = __float2bfloat16(v1);
    hi.x = h0; hi.y = h1;
    lo.x = __float2bfloat16(v0 - __bfloat162float(h0));
    lo.y = __float2bfloat16(v1 - __bfloat162float(h1));
}

// ---------------------------------------------------------------------------
// Embedding + positional encoding -> x (fp32) and x3 (triple patA)
// ---------------------------------------------------------------------------
__global__ void embed_pe_kernel(const int* __restrict__ target,
                                const float* __restrict__ emb,
                                float* __restrict__ x,
                                __nv_bfloat16* __restrict__ x3)
{
    int row = blockIdx.x;
    int t   = row & (TTq - 1);
    int d   = threadIdx.x;
    int tok = target[row];
    float e = emb[(long)tok * Dm + d];
    int   i = d >> 1;
    float denom = powf(10000.0f, (2.0f * (float)i) / (float)Dm);
    float z = (float)t / denom;
    float p = (d & 1) ? cosf(z) : sinf(z);
    float v = e + p;
    x[(long)row * Dm + d] = v;
    __nv_bfloat16 h = __float2bfloat16(v);
    __nv_bfloat16 l = __float2bfloat16(v - __bfloat162float(h));
    __nv_bfloat16* ob = x3 + (long)row * 1536 + d;
    ob[0] = h; ob[512] = h; ob[1024] = l;
}

// ---------------------------------------------------------------------------
// enc fp32 -> e3 triple (patA)
// ---------------------------------------------------------------------------
__global__ void conv_enc_kernel(const float* __restrict__ in, __nv_bfloat16* __restrict__ out)
{
    long idx = (long)blockIdx.x * blockDim.x + threadIdx.x;  // NR*256 threads
    long r = idx >> 8;
    long k = (idx & 255) * 2;
    const float* p = in + r * Dm + k;
    __nv_bfloat162 hi, lo;
    split2(p[0], p[1], hi, lo);
    __nv_bfloat16* ob = out + r * 1536 + k;
    *(__nv_bfloat162*)(ob)        = hi;
    *(__nv_bfloat162*)(ob + 512)  = hi;
    *(__nv_bfloat162*)(ob + 1024) = lo;
}

// ---------------------------------------------------------------------------
// Masked softmax over last dim (512): writes normalized fp32 AND s3 triple patA.
// ---------------------------------------------------------------------------
__global__ void softmax_kernel(float* __restrict__ S, __nv_bfloat16* __restrict__ S3,
                               const int* __restrict__ target,
                               const int* __restrict__ srcpad,
                               int mode, float scale)
{
    int row = blockIdx.x;
    int q   = row & (TTq - 1);
    int b   = row / (Hh * TTq);
    float* s = S + (long)row * TSs;
    int tid = threadIdx.x;
    bool qpad = (target[b * TTq + q] != Vv);

    float v[2];
    float mx = -INFINITY;
#pragma unroll
    for (int e = 0; e < 2; e++) {
        int k = tid + e * 256;
        bool valid;
        if (mode == 1)
            valid = qpad && (k <= q) && (target[b * TTq + k] != Vv);
        else
            valid = qpad && (srcpad[b * TSs + k] != 0);
        float val = valid ? s[k] * scale : -1e32f;
        v[e] = val;
        mx = fmaxf(mx, val);
    }

    __shared__ float red[8];
#pragma unroll
    for (int o = 16; o > 0; o >>= 1) mx = fmaxf(mx, __shfl_xor_sync(0xffffffffu, mx, o));
    if ((tid & 31) == 0) red[tid >> 5] = mx;
    __syncthreads();
    if (tid < 32) {
        float r = (tid < 8) ? red[tid] : -INFINITY;
#pragma unroll
        for (int o = 4; o > 0; o >>= 1) r = fmaxf(r, __shfl_xor_sync(0xffffffffu, r, o));
        if (tid == 0) red[0] = r;
    }
    __syncthreads();
    mx = red[0];
    __syncthreads();

    float sum = 0.f;
#pragma unroll
    for (int e = 0; e < 2; e++) { v[e] = expf(v[e] - mx); sum += v[e]; }
#pragma unroll
    for (int o = 16; o > 0; o >>= 1) sum += __shfl_xor_sync(0xffffffffu, sum, o);
    if ((tid & 31) == 0) red[tid >> 5] = sum;
    __syncthreads();
    if (tid < 32) {
        float r = (tid < 8) ? red[tid] : 0.f;
#pragma unroll
        for (int o = 4; o > 0; o >>= 1) r += __shfl_xor_sync(0xffffffffu, r, o);
        if (tid == 0) red[0] = r;
    }
    __syncthreads();
    float inv = 1.0f / red[0];
    __nv_bfloat16* s3r = S3 + (long)row * 1536;
#pragma unroll
    for (int e = 0; e < 2; e++) {
        int k = tid + e * 256;
        float val = v[e] * inv;
        s[k] = val;
        __nv_bfloat16 h = __float2bfloat16(val);
        __nv_bfloat16 l = __float2bfloat16(val - __bfloat162float(h));
        s3r[k] = h; s3r[k + 512] = h; s3r[k + 1024] = l;
    }
}

// ---------------------------------------------------------------------------
// y = LayerNorm(xin + a) * g + b  -> y fp32 and y3 triple patA
// ---------------------------------------------------------------------------
__global__ void add_ln_kernel(const float* __restrict__ xin,
                              const float* __restrict__ a,
                              const float* __restrict__ gg,
                              const float* __restrict__ bb,
                              float* __restrict__ y,
                              __nv_bfloat16* __restrict__ y3)
{
    int row = blockIdx.x;
    int tid = threadIdx.x;
    long base = (long)row * Dm;
    __shared__ float red[8];

    float v[2];
    float sum = 0.f;
#pragma unroll
    for (int e = 0; e < 2; e++) {
        int d = tid + e * 256;
        v[e] = xin[base + d] + a[base + d];
        sum += v[e];
    }
#pragma unroll
    for (int o = 16; o > 0; o >>= 1) sum += __shfl_xor_sync(0xffffffffu, sum, o);
    if ((tid & 31) == 0) red[tid >> 5] = sum;
    __syncthreads();
    if (tid < 32) {
        float r = (tid < 8) ? red[tid] : 0.f;
#pragma unroll
        for (int o = 4; o > 0; o >>= 1) r += __shfl_xor_sync(0xffffffffu, r, o);
        if (tid == 0) red[0] = r;
    }
    __syncthreads();
    float m = red[0] * (1.0f / (float)Dm);
    __syncthreads();

    float vs = 0.f;
#pragma unroll
    for (int e = 0; e < 2; e++) { float c = v[e] - m; vs += c * c; }
#pragma unroll
    for (int o = 16; o > 0; o >>= 1) vs += __shfl_xor_sync(0xffffffffu, vs, o);
    if ((tid & 31) == 0) red[tid >> 5] = vs;
    __syncthreads();
    if (tid < 32) {
        float r = (tid < 8) ? red[tid] : 0.f;
#pragma unroll
        for (int o = 4; o > 0; o >>= 1) r += __shfl_xor_sync(0xffffffffu, r, o);
        if (tid == 0) red[0] = r;
    }
    __syncthreads();
    float var = red[0] * (1.0f / (float)Dm);
    float rs = rsqrtf(var + 1e-5f);
    __nv_bfloat16* y3r = y3 + (long)row * 1536;
#pragma unroll
    for (int e = 0; e < 2; e++) {
        int d = tid + e * 256;
        float val = (v[e] - m) * rs * gg[d] + bb[d];
        y[base + d] = val;
        __nv_bfloat16 h = __float2bfloat16(val);
        __nv_bfloat16 l = __float2bfloat16(val - __bfloat162float(h));
        y3r[d] = h; y3r[d + 512] = h; y3r[d + 1024] = l;
    }
}

// ---------------------------------------------------------------------------
// conv_t: fp32 [K, N] (N-contig) -> bf16 triple [N, 3K], pattern B [hi|lo|hi].
// Used for all weights (B operands) and the V transpose.
// ---------------------------------------------------------------------------
__global__ void conv_t_kernel(const float* __restrict__ in, __nv_bfloat16* __restrict__ out,
                              int K, int N, int in_ld, int out_ld,
                              long sInB, long sInH, long sOutB, long sOutH, int Hn)
{
    __shared__ float t[32][33];
    int z = blockIdx.z, zb = z / Hn, zh = z % Hn;
    in  += zb * sInB + zh * sInH;
    out += zb * sOutB + zh * sOutH;
    int k0 = blockIdx.y * 32, n0 = blockIdx.x * 32;
    int tx = threadIdx.x, ty = threadIdx.y;   // 32 x 8
#pragma unroll
    for (int i = 0; i < 4; ++i) {
        int k = k0 + ty + i * 8, n = n0 + tx;
        t[ty + i * 8][tx] = (n < N) ? in[(long)k * in_ld + n] : 0.f;
    }
    __syncthreads();
#pragma unroll
    for (int i = 0; i < 4; ++i) {
        int n = n0 + ty + i * 8, k = k0 + tx;
        if (n < N) {
            float x = t[tx][ty + i * 8];
            __nv_bfloat16 h = __float2bfloat16(x);
            __nv_bfloat16 l = __float2bfloat16(x - __bfloat162float(h));
            __nv_bfloat16* o = out + (long)n * out_ld + k;
            o[0]     = h;
            o[K]     = l;
            o[2 * K] = h;
        }
    }
}

// ---------------------------------------------------------------------------
// bf16 tensor-core GEMM (mma.sync m16n8k16) with fused epilogues.
//   acc[m,n] = sum_k A3[m,k]*B3[n,k]
// EPI: 0 fp32 | 1 fp32+bias | 2 fp32+bias+relu
//      3 triple patA+bias | 4 triple patB+bias | 5 triple patA
//      6 triple patA+bias+relu
// Triple modes: Cv is bf16*, ldc/sCb/sCh in bf16 elements; stores hi at +0 and
// at +d1/+d2 the (hi,lo) [patA] or (lo,hi) [patB].
// CTA 128x128, BK=32, 8 warps (64x32 warp tile), 3-stage cp.async pipeline.
// ---------------------------------------------------------------------------
#define GBM 128
#define GBN 128
#define GBK 32
#define STAGE_BYTES 20480            // (128*80)*2 arrays
#define HG_SMEM (3 * STAGE_BYTES)    // 61440

__device__ __forceinline__ uint32_t smem_u32(const void* p) {
    uint32_t a;
    asm("{ .reg .u64 t; cvta.to.shared.u64 t, %1; cvt.u32.u64 %0, t; }" : "=r"(a) : "l"(p));
    return a;
}
#define CP16(dst, src) \
    asm volatile("cp.async.cg.shared.global [%0], [%1], 16;" :: "r"(dst), "l"(src))
#define CP_COMMIT() asm volatile("cp.async.commit_group;" ::: "memory")
#define CP_WAIT1()  asm volatile("cp.async.wait_group 1;" ::: "memory")
#define CP_WAIT0()  asm volatile("cp.async.wait_group 0;" ::: "memory")
#define LDSM_X4(r0, r1, r2, r3, addr) \
    asm volatile("ldmatrix.sync.aligned.m8n8.x4.shared.b16 {%0,%1,%2,%3}, [%4];" \
                 : "=r"(r0), "=r"(r1), "=r"(r2), "=r"(r3) : "r"(addr))
#define MMA_BF16(c, a0, a1, a2, a3, b0, b1) \
    asm volatile("mma.sync.aligned.m16n8k16.row.col.f32.bf16.bf16.f32 " \
                 "{%0,%1,%2,%3}, {%4,%5,%6,%7}, {%8,%9}, {%0,%1,%2,%3};" \
                 : "+f"((c)[0]), "+f"((c)[1]), "+f"((c)[2]), "+f"((c)[3]) \
                 : "r"(a0), "r"(a1), "r"(a2), "r"(a3), "r"(b0), "r"(b1))

template<int EPI>
__global__ void __launch_bounds__(256)
hgemm_kernel(const __nv_bfloat16* __restrict__ A3, const __nv_bfloat16* __restrict__ B3,
             const float* __restrict__ Bias, void* __restrict__ Cv,
             int Nstore, int K3, int lda, int ldb, int ldc,
             long sAb, long sAh, long sBb, long sBh, long sCb, long sCh,
             long sBiB, long sBiH, int Hn, int d1, int d2)
{
    extern __shared__ __align__(16) char dsm[];
    const uint32_t base = smem_u32(dsm);

    int tid = threadIdx.x;
    int wid = tid >> 5, lane = tid & 31;

    int z = blockIdx.z, zb = z / Hn, zh = z % Hn;
    A3 += zb * sAb + zh * sAh;
    B3 += zb * sBb + zh * sBh;
    long cOff = zb * sCb + zh * sCh;
    long biasOff = zb * sBiB + zh * sBiH;

    long m0 = (long)blockIdx.x * GBM;
    long n0 = (long)blockIdx.y * GBN;

    const int wm = (wid >> 2) * 64;
    const int wn = (wid & 3) * 32;

    float acc[4][4][4];
#pragma unroll
    for (int i = 0; i < 4; i++)
#pragma unroll
        for (int j = 0; j < 4; j++)
#pragma unroll
            for (int q = 0; q < 4; q++) acc[i][j][q] = 0.f;

    const int nIter = K3 / GBK;

    auto loadStage = [&](int s, long k0) {
        uint32_t aD = base + s * STAGE_BYTES;
        uint32_t bD = aD + 10240;
#pragma unroll
        for (int i = 0; i < 2; i++) {
            int c = tid + i * 256;
            int r = c >> 2, seg = c & 3;
            CP16(aD + (uint32_t)(r * 80 + seg * 16), A3 + (m0 + r) * (long)lda + k0 + seg * 8);
        }
#pragma unroll
        for (int i = 0; i < 2; i++) {
            int c = tid + i * 256;
            int r = c >> 2, seg = c & 3;
            CP16(bD + (uint32_t)(r * 80 + seg * 16), B3 + (n0 + r) * (long)ldb + k0 + seg * 8);
        }
        CP_COMMIT();
    };

    loadStage(0, 0);

    for (int it = 0; it < nIter; ++it) {
        if (it + 1 < nIter) {
            loadStage((it + 1) % 3, (long)(it + 1) * GBK);
            CP_WAIT1();
        } else {
            CP_WAIT0();
        }
        __syncthreads();

        uint32_t aS = base + (it % 3) * STAGE_BYTES;
        uint32_t bS = aS + 10240;
#pragma unroll
        for (int ks = 0; ks < 2; ks++) {
            int col = ks * 16 + (lane >> 4) * 8;
            uint32_t a[4][4], bf[4][2];
#pragma unroll
            for (int mi = 0; mi < 4; mi++) {
                int row = wm + mi * 16 + (lane & 15);
                LDSM_X4(a[mi][0], a[mi][1], a[mi][2], a[mi][3],
                        aS + (uint32_t)(row * 80 + col * 2));
            }
#pragma unroll
            for (int p = 0; p < 2; p++) {
                int row = wn + p * 16 + (lane & 15);
                uint32_t r0, r1, r2, r3;
                LDSM_X4(r0, r1, r2, r3, bS + (uint32_t)(row * 80 + col * 2));
                bf[2 * p][0] = r0;     bf[2 * p][1] = r2;
                bf[2 * p + 1][0] = r1; bf[2 * p + 1][1] = r3;
            }
#pragma unroll
            for (int mi = 0; mi < 4; mi++)
#pragma unroll
                for (int ni = 0; ni < 4; ni++)
                    MMA_BF16(acc[mi][ni], a[mi][0], a[mi][1], a[mi][2], a[mi][3],
                             bf[ni][0], bf[ni][1]);
        }
        __syncthreads();
    }

    // ---- epilogue ----
    if (EPI <= 2) {
        float* C = (float*)Cv + cOff;
#pragma unroll
        for (int mi = 0; mi < 4; mi++) {
            long mrow = m0 + wm + mi * 16 + (lane >> 2);
            float* c0p = C + mrow * (long)ldc;
            float* c1p = c0p + 8L * ldc;
#pragma unroll
            for (int ni = 0; ni < 4; ni++) {
                long n = n0 + wn + ni * 8 + (lane & 3) * 2;
#pragma unroll
                for (int e = 0; e < 2; e++) {
                    long nn = n + e;
                    if (nn < (long)Nstore) {
                        float v0 = acc[mi][ni][e];
                        float v1 = acc[mi][ni][2 + e];
                        if (EPI >= 1) {
                            float bsv = Bias[biasOff + nn];
                            v0 += bsv; v1 += bsv;
                        }
                        if (EPI == 2) { v0 = fmaxf(v0, 0.f); v1 = fmaxf(v1, 0.f); }
                        c0p[nn] = v0;
                        c1p[nn] = v1;
                    }
                }
            }
        }
    } else {
        __nv_bfloat16* C3 = (__nv_bfloat16*)Cv + cOff;
        const bool hasBias = (EPI == 3 || EPI == 4 || EPI == 6);
        const bool relu = (EPI == 6);
        const bool patB = (EPI == 4);
#pragma unroll
        for (int mi = 0; mi < 4; mi++) {
            long r0 = m0 + wm + mi * 16 + (lane >> 2);
            __nv_bfloat16* p0 = C3 + r0 * (long)ldc;
            __nv_bfloat16* p1 = p0 + 8L * ldc;
#pragma unroll
            for (int ni = 0; ni < 4; ni++) {
                long n = n0 + wn + ni * 8 + (lane & 3) * 2;
                float b0 = 0.f, b1 = 0.f;
                if (hasBias) { b0 = Bias[biasOff + n]; b1 = Bias[biasOff + n + 1]; }
                float v0 = acc[mi][ni][0] + b0, v1 = acc[mi][ni][1] + b1;
                float v2 = acc[mi][ni][2] + b0, v3 = acc[mi][ni][3] + b1;
                if (relu) {
                    v0 = fmaxf(v0, 0.f); v1 = fmaxf(v1, 0.f);
                    v2 = fmaxf(v2, 0.f); v3 = fmaxf(v3, 0.f);
                }
                __nv_bfloat162 hiA, loA, hiB, loB;
                split2(v0, v1, hiA, loA);
                split2(v2, v3, hiB, loB);
                *(__nv_bfloat162*)(p0 + n)      = hiA;
                *(__nv_bfloat162*)(p0 + n + d1) = patB ? loA : hiA;
                *(__nv_bfloat162*)(p0 + n + d2) = patB ? hiA : loA;
                *(__nv_bfloat162*)(p1 + n)      = hiB;
                *(__nv_bfloat162*)(p1 + n + d1) = patB ? loB : hiB;
                *(__nv_bfloat162*)(p1 + n + d2) = patB ? hiB : loB;
            }
        }
    }
}

// ---------------------------------------------------------------------------
// Host dispatch
// ---------------------------------------------------------------------------
static void tg(int epi, const __nv_bfloat16* A, const __nv_bfloat16* B, const float* Bias,
               void* C, int M, int N, int K3, int lda, int ldb, int ldc,
               long sAb, long sAh, long sBb, long sBh, long sCb, long sCh,
               long sBiB, long sBiH, int Hn, int Z, int d1 = 0, int d2 = 0)
{
    dim3 g(M / GBM, (N + GBN - 1) / GBN, Z), b(256);
#define HG_CALL(E) hgemm_kernel<E><<<g, b, HG_SMEM>>>(A, B, Bias, C, N, K3, lda, ldb, ldc, \
    sAb, sAh, sBb, sBh, sCb, sCh, sBiB, sBiH, Hn, d1, d2)
    switch (epi) {
    case 0: HG_CALL(0); break;
    case 1: HG_CALL(1); break;
    case 2: HG_CALL(2); break;
    case 3: HG_CALL(3); break;
    case 4: HG_CALL(4); break;
    case 5: HG_CALL(5); break;
    default: HG_CALL(6); break;
    }
#undef HG_CALL
}

extern "C" void kernel_launch(void* const* d_in, const int* in_sizes, int n_in,
                              void* d_out, int out_size)
{
    const float* enc    = (const float*)d_in[0];
    const int*   srcpad = (const int*)  d_in[1];
    const int*   target = (const int*)  d_in[2];
    const float* emb    = (const float*)d_in[3];
    const float* Wq1 = (const float*)d_in[4],  *bq1 = (const float*)d_in[5];
    const float* Wk1 = (const float*)d_in[6],  *bk1 = (const float*)d_in[7];
    const float* Wv1 = (const float*)d_in[8],  *bv1 = (const float*)d_in[9];
    const float* Wo1 = (const float*)d_in[10], *bo1 = (const float*)d_in[11];
    const float* Wq2 = (const float*)d_in[12], *bq2 = (const float*)d_in[13];
    const float* Wk2 = (const float*)d_in[14], *bk2 = (const float*)d_in[15];
    const float* Wv2 = (const float*)d_in[16], *bv2 = (const float*)d_in[17];
    const float* Wo2 = (const float*)d_in[18], *bo2 = (const float*)d_in[19];
    // dict-insertion order: g,g,g then b,b,b
    const float* ln1g = (const float*)d_in[20];
    const float* ln2g = (const float*)d_in[21];
    const float* ln3g = (const float*)d_in[22];
    const float* ln1b = (const float*)d_in[23];
    const float* ln2b = (const float*)d_in[24];
    const float* ln3b = (const float*)d_in[25];
    const float* Wf1 = (const float*)d_in[26], *bf1 = (const float*)d_in[27];
    const float* Wf2 = (const float*)d_in[28], *bf2 = (const float*)d_in[29];
    const float* lmW = (const float*)d_in[30], *lmb = (const float*)d_in[31];
    float* out = (float*)d_out;

    float *x, *vv, *ss, *tt;
    cudaGetSymbolAddress((void**)&x,  g_x);
    cudaGetSymbolAddress((void**)&vv, g_v);
    cudaGetSymbolAddress((void**)&ss, g_s);
    cudaGetSymbolAddress((void**)&tt, g_t);
    __nv_bfloat16 *x3, *e3, *q3, *k3, *v3, *s3, *o3, *f3, *w3, *lm3;
    cudaGetSymbolAddress((void**)&x3, g_x3);
    cudaGetSymbolAddress((void**)&e3, g_e3);
    cudaGetSymbolAddress((void**)&q3, g_q3);
    cudaGetSymbolAddress((void**)&k3, g_k3);
    cudaGetSymbolAddress((void**)&v3, g_v3);
    cudaGetSymbolAddress((void**)&s3, g_s3);
    cudaGetSymbolAddress((void**)&o3, g_o3);
    cudaGetSymbolAddress((void**)&f3, g_f3);
    cudaGetSymbolAddress((void**)&w3, g_w3);
    cudaGetSymbolAddress((void**)&lm3, g_lm3);

    cudaFuncSetAttribute(hgemm_kernel<0>, cudaFuncAttributeMaxDynamicSharedMemorySize, HG_SMEM);
    cudaFuncSetAttribute(hgemm_kernel<1>, cudaFuncAttributeMaxDynamicSharedMemorySize, HG_SMEM);
    cudaFuncSetAttribute(hgemm_kernel<2>, cudaFuncAttributeMaxDynamicSharedMemorySize, HG_SMEM);
    cudaFuncSetAttribute(hgemm_kernel<3>, cudaFuncAttributeMaxDynamicSharedMemorySize, HG_SMEM);
    cudaFuncSetAttribute(hgemm_kernel<4>, cudaFuncAttributeMaxDynamicSharedMemorySize, HG_SMEM);
    cudaFuncSetAttribute(hgemm_kernel<5>, cudaFuncAttributeMaxDynamicSharedMemorySize, HG_SMEM);
    cudaFuncSetAttribute(hgemm_kernel<6>, cudaFuncAttributeMaxDynamicSharedMemorySize, HG_SMEM);

    const float scale = 1.0f / sqrtf((float)Dm);
    const long WATT = (long)Hh * Dm * Dm;
    const long WOUT = (long)HD * Dm;
    const long WFF  = (long)Dm * FFd;
    const dim3 tb(32, 8);

    embed_pe_kernel<<<NR, 512>>>(target, emb, x, x3);
    conv_enc_kernel<<<NR, 256>>>(enc, e3);

    for (int l = 0; l < 2; l++) {
        const float *WQ[2] = {Wq1 + l * WATT, Wq2 + l * WATT};
        const float *WK[2] = {Wk1 + l * WATT, Wk2 + l * WATT};
        const float *WV[2] = {Wv1 + l * WATT, Wv2 + l * WATT};
        const float *WO[2] = {Wo1 + l * WOUT, Wo2 + l * WOUT};
        const float *BQ[2] = {bq1 + l * HD, bq2 + l * HD};
        const float *BK[2] = {bk1 + l * HD, bk2 + l * HD};
        const float *BV[2] = {bv1 + l * HD, bv2 + l * HD};
        const float *BO[2] = {bo1 + l * Dm, bo2 + l * Dm};
        const float *LG[2] = {ln1g + l * Dm, ln2g + l * Dm};
        const float *LB[2] = {ln1b + l * Dm, ln2b + l * Dm};

        for (int att = 0; att < 2; att++) {   // 0 = self, 1 = cross
            const __nv_bfloat16* kvA = (att == 0) ? x3 : e3;

            // ---- Q projection -> q3 triple (patA) ----
            conv_t_kernel<<<dim3(16, 16, 8), tb>>>(WQ[att], w3, Dm, Dm, Dm, 1536,
                                                   0, (long)Dm * Dm, 0, (long)Dm * 1536, 8);
            tg(3, x3, w3, BQ[att], q3, NR, Dm, 1536, 1536, 1536, 12288,
               0, 0, 0, (long)Dm * 1536, 0, 1536, 0, Dm, 8, 8, 512, 1024);

            // ---- K projection -> k3 triple (patB) ----
            conv_t_kernel<<<dim3(16, 16, 8), tb>>>(WK[att], w3, Dm, Dm, Dm, 1536,
                                                   0, (long)Dm * Dm, 0, (long)Dm * 1536, 8);
            tg(4, kvA, w3, BK[att], k3, NR, Dm, 1536, 1536, 1536, 12288,
               0, 0, 0, (long)Dm * 1536, 0, 1536, 0, Dm, 8, 8, 512, 1024);

            // ---- V projection -> vv fp32, then transpose to v3 (patB) ----
            conv_t_kernel<<<dim3(16, 16, 8), tb>>>(WV[att], w3, Dm, Dm, Dm, 1536,
                                                   0, (long)Dm * Dm, 0, (long)Dm * 1536, 8);
            tg(1, kvA, w3, BV[att], vv, NR, Dm, 1536, 1536, 1536, HD,
               0, 0, 0, (long)Dm * 1536, 0, Dm, 0, Dm, 8, 8);
            conv_t_kernel<<<dim3(16, 16, 32), tb>>>(vv, v3, TSs, Dm, HD, 1536,
                                                    (long)TSs * HD, Dm,
                                                    (long)Hh * TSs * 1536, (long)TSs * 1536, 8);

            // ---- scores = Q K^T -> ss fp32 ----
            tg(0, q3, k3, nullptr, ss, TTq, TSs, 1536, 12288, 12288, TSs,
               (long)TTq * 12288, 1536, (long)TSs * 12288, 1536,
               (long)Hh * TTq * TSs, (long)TTq * TSs, 0, 0, 8, 32);

            // ---- softmax -> ss fp32 + s3 triple ----
            softmax_kernel<<<Bq * Hh * TTq, 256>>>(ss, s3, target, srcpad,
                                                   att == 0 ? 1 : 2, scale);
            if (att == 1 && l == 0 && (long)out_size >= LOGITS_ELEMS + ATT_ELEMS) {
                cudaMemcpyAsync(out + LOGITS_ELEMS, ss, ATT_ELEMS * sizeof(float),
                                cudaMemcpyDeviceToDevice, 0);
            }

            // ---- O = S V -> o3 triple (patA, segment width 4096) ----
            tg(5, s3, v3, nullptr, o3, TTq, Dm, 1536, 1536, 1536, 12288,
               (long)Hh * TTq * 1536, (long)TTq * 1536,
               (long)Hh * TSs * 1536, (long)TSs * 1536,
               (long)TTq * 12288, 512, 0, 0, 8, 32, 4096, 8192);

            // ---- output projection -> tt fp32; add&norm -> x, x3 ----
            conv_t_kernel<<<dim3(16, 128, 1), tb>>>(WO[att], w3, HD, Dm, Dm, 12288,
                                                    0, 0, 0, 0, 1);
            tg(1, o3, w3, BO[att], tt, NR, Dm, 12288, 12288, 12288, Dm,
               0, 0, 0, 0, 0, 0, 0, 0, 1, 1);
            add_ln_kernel<<<NR, 256>>>(x, tt, LG[att], LB[att], x, x3);
        }

        // ---- FFN ----
        conv_t_kernel<<<dim3(64, 16, 1), tb>>>(Wf1 + l * WFF, w3, Dm, FFd, FFd, 1536,
                                               0, 0, 0, 0, 1);
        tg(6, x3, w3, bf1 + l * FFd, f3, NR, FFd, 1536, 1536, 1536, 6144,
           0, 0, 0, 0, 0, 0, 0, 0, 1, 1, 2048, 4096);
        conv_t_kernel<<<dim3(16, 64, 1), tb>>>(Wf2 + l * WFF, w3, FFd, Dm, Dm, 6144,
                                               0, 0, 0, 0, 1);
        tg(1, f3, w3, bf2 + l * Dm, tt, NR, Dm, 6144, 6144, 6144, Dm,
           0, 0, 0, 0, 0, 0, 0, 0, 1, 1);
        add_ln_kernel<<<NR, 256>>>(x, tt, ln3g + l * Dm, ln3b + l * Dm, x, x3);
    }

    // ---- LM head ----
    conv_t_kernel<<<dim3(1001, 16, 1), tb>>>(lmW, lm3, Dm, VO, VO, 1536, 0, 0, 0, 0, 1);
    tg(1, x3, lm3, lmb, out, NR, VO, 1536, 1536, 1536, VO,
       0, 0, 0, 0, 0, 0, 0, 0, 1, 1);
}

// round 6
// speedup vs baseline: 2.3195x; 1.0066x over previous
#include <cuda_runtime.h>
#include <cuda_bf16.h>
#include <math.h>
#include <stdint.h>

// ---------------------------------------------------------------------------
// Problem constants
// ---------------------------------------------------------------------------
#define Bq   4
#define TTq  512
#define TSs  512
#define Dm   512
#define Hh   8
#define Vv   32000
#define VO   32001
#define NR   2048
#define HD   4096
#define FFd  2048

#define LOGITS_ELEMS (2048LL * 32001LL)
#define ATT_ELEMS    (4LL * 8 * 512 * 512)

// ---------------------------------------------------------------------------
// Scratch (static device globals)
// ---------------------------------------------------------------------------
__device__ float g_x [NR * Dm];
__device__ float g_v [NR * HD];
__device__ float g_s [Bq * Hh * TTq * TSs];
__device__ float g_t [NR * Dm];

__device__ __nv_bfloat16 g_x3 [NR * 1536];
__device__ __nv_bfloat16 g_e3 [NR * 1536];
__device__ __nv_bfloat16 g_q3 [NR * 12288];
__device__ __nv_bfloat16 g_k3 [NR * 12288];
__device__ __nv_bfloat16 g_v3 [32 * 512 * 1536];
__device__ __nv_bfloat16 g_s3 [32 * 512 * 1536];
__device__ __nv_bfloat16 g_o3 [NR * 12288];
__device__ __nv_bfloat16 g_f3 [NR * 6144];
__device__ __nv_bfloat16 g_w3 [6291456];
__device__ __nv_bfloat16 g_lm3[32128 * 1536];

// ---------------------------------------------------------------------------
// hi/lo split helper
// ---------------------------------------------------------------------------
__device__ __forceinline__ void split2(float v0, float v1,
                                       __nv_bfloat162& hi, __nv_bfloat162& lo)
{
    __nv_bfloat16 h0 = __float2bfloat16(v0), h1 = __float2bfloat16(v1);
    hi.x = h0; hi.y = h1;
    lo.x = __float2bfloat16(v0 - __bfloat162float(h0));
    lo.y = __float2bfloat16(v1 - __bfloat162float(h1));
}

// ---------------------------------------------------------------------------
// Embedding + positional encoding -> x (fp32) and x3 (triple patA)
// ---------------------------------------------------------------------------
__global__ void embed_pe_kernel(const int* __restrict__ target,
                                const float* __restrict__ emb,
                                float* __restrict__ x,
                                __nv_bfloat16* __restrict__ x3)
{
    int row = blockIdx.x;
    int t   = row & (TTq - 1);
    int d   = threadIdx.x;
    int tok = target[row];
    float e = emb[(long)tok * Dm + d];
    int   i = d >> 1;
    float denom = powf(10000.0f, (2.0f * (float)i) / (float)Dm);
    float z = (float)t / denom;
    float p = (d & 1) ? cosf(z) : sinf(z);
    float v = e + p;
    x[(long)row * Dm + d] = v;
    __nv_bfloat16 h = __float2bfloat16(v);
    __nv_bfloat16 l = __float2bfloat16(v - __bfloat162float(h));
    __nv_bfloat16* ob = x3 + (long)row * 1536 + d;
    ob[0] = h; ob[512] = h; ob[1024] = l;
}

// ---------------------------------------------------------------------------
// enc fp32 -> e3 triple (patA)
// ---------------------------------------------------------------------------
__global__ void conv_enc_kernel(const float* __restrict__ in, __nv_bfloat16* __restrict__ out)
{
    long idx = (long)blockIdx.x * blockDim.x + threadIdx.x;
    long r = idx >> 8;
    long k = (idx & 255) * 2;
    const float* p = in + r * Dm + k;
    __nv_bfloat162 hi, lo;
    split2(p[0], p[1], hi, lo);
    __nv_bfloat16* ob = out + r * 1536 + k;
    *(__nv_bfloat162*)(ob)        = hi;
    *(__nv_bfloat162*)(ob + 512)  = hi;
    *(__nv_bfloat162*)(ob + 1024) = lo;
}

// ---------------------------------------------------------------------------
// Masked softmax: writes normalized fp32 AND s3 triple patA.
// ---------------------------------------------------------------------------
__global__ void softmax_kernel(float* __restrict__ S, __nv_bfloat16* __restrict__ S3,
                               const int* __restrict__ target,
                               const int* __restrict__ srcpad,
                               int mode, float scale)
{
    int row = blockIdx.x;
    int q   = row & (TTq - 1);
    int b   = row / (Hh * TTq);
    float* s = S + (long)row * TSs;
    int tid = threadIdx.x;
    bool qpad = (target[b * TTq + q] != Vv);

    float v[2];
    float mx = -INFINITY;
#pragma unroll
    for (int e = 0; e < 2; e++) {
        int k = tid + e * 256;
        bool valid;
        if (mode == 1)
            valid = qpad && (k <= q) && (target[b * TTq + k] != Vv);
        else
            valid = qpad && (srcpad[b * TSs + k] != 0);
        float val = valid ? s[k] * scale : -1e32f;
        v[e] = val;
        mx = fmaxf(mx, val);
    }

    __shared__ float red[8];
#pragma unroll
    for (int o = 16; o > 0; o >>= 1) mx = fmaxf(mx, __shfl_xor_sync(0xffffffffu, mx, o));
    if ((tid & 31) == 0) red[tid >> 5] = mx;
    __syncthreads();
    if (tid < 32) {
        float r = (tid < 8) ? red[tid] : -INFINITY;
#pragma unroll
        for (int o = 4; o > 0; o >>= 1) r = fmaxf(r, __shfl_xor_sync(0xffffffffu, r, o));
        if (tid == 0) red[0] = r;
    }
    __syncthreads();
    mx = red[0];
    __syncthreads();

    float sum = 0.f;
#pragma unroll
    for (int e = 0; e < 2; e++) { v[e] = expf(v[e] - mx); sum += v[e]; }
#pragma unroll
    for (int o = 16; o > 0; o >>= 1) sum += __shfl_xor_sync(0xffffffffu, sum, o);
    if ((tid & 31) == 0) red[tid >> 5] = sum;
    __syncthreads();
    if (tid < 32) {
        float r = (tid < 8) ? red[tid] : 0.f;
#pragma unroll
        for (int o = 4; o > 0; o >>= 1) r += __shfl_xor_sync(0xffffffffu, r, o);
        if (tid == 0) red[0] = r;
    }
    __syncthreads();
    float inv = 1.0f / red[0];
    __nv_bfloat16* s3r = S3 + (long)row * 1536;
#pragma unroll
    for (int e = 0; e < 2; e++) {
        int k = tid + e * 256;
        float val = v[e] * inv;
        s[k] = val;
        __nv_bfloat16 h = __float2bfloat16(val);
        __nv_bfloat16 l = __float2bfloat16(val - __bfloat162float(h));
        s3r[k] = h; s3r[k + 512] = h; s3r[k + 1024] = l;
    }
}

// ---------------------------------------------------------------------------
// y = LayerNorm(xin + a) * g + b  -> y fp32 and y3 triple patA
// ---------------------------------------------------------------------------
__global__ void add_ln_kernel(const float* __restrict__ xin,
                              const float* __restrict__ a,
                              const float* __restrict__ gg,
                              const float* __restrict__ bb,
                              float* __restrict__ y,
                              __nv_bfloat16* __restrict__ y3)
{
    int row = blockIdx.x;
    int tid = threadIdx.x;
    long base = (long)row * Dm;
    __shared__ float red[8];

    float v[2];
    float sum = 0.f;
#pragma unroll
    for (int e = 0; e < 2; e++) {
        int d = tid + e * 256;
        v[e] = xin[base + d] + a[base + d];
        sum += v[e];
    }
#pragma unroll
    for (int o = 16; o > 0; o >>= 1) sum += __shfl_xor_sync(0xffffffffu, sum, o);
    if ((tid & 31) == 0) red[tid >> 5] = sum;
    __syncthreads();
    if (tid < 32) {
        float r = (tid < 8) ? red[tid] : 0.f;
#pragma unroll
        for (int o = 4; o > 0; o >>= 1) r += __shfl_xor_sync(0xffffffffu, r, o);
        if (tid == 0) red[0] = r;
    }
    __syncthreads();
    float m = red[0] * (1.0f / (float)Dm);
    __syncthreads();

    float vs = 0.f;
#pragma unroll
    for (int e = 0; e < 2; e++) { float c = v[e] - m; vs += c * c; }
#pragma unroll
    for (int o = 16; o > 0; o >>= 1) vs += __shfl_xor_sync(0xffffffffu, vs, o);
    if ((tid & 31) == 0) red[tid >> 5] = vs;
    __syncthreads();
    if (tid < 32) {
        float r = (tid < 8) ? red[tid] : 0.f;
#pragma unroll
        for (int o = 4; o > 0; o >>= 1) r += __shfl_xor_sync(0xffffffffu, r, o);
        if (tid == 0) red[0] = r;
    }
    __syncthreads();
    float var = red[0] * (1.0f / (float)Dm);
    float rs = rsqrtf(var + 1e-5f);
    __nv_bfloat16* y3r = y3 + (long)row * 1536;
#pragma unroll
    for (int e = 0; e < 2; e++) {
        int d = tid + e * 256;
        float val = (v[e] - m) * rs * gg[d] + bb[d];
        y[base + d] = val;
        __nv_bfloat16 h = __float2bfloat16(val);
        __nv_bfloat16 l = __float2bfloat16(val - __bfloat162float(h));
        y3r[d] = h; y3r[d + 512] = h; y3r[d + 1024] = l;
    }
}

// ---------------------------------------------------------------------------
// conv_t: fp32 [K, N] (N-contig) -> bf16 triple [N, 3K], pattern B [hi|lo|hi].
// ---------------------------------------------------------------------------
__global__ void conv_t_kernel(const float* __restrict__ in, __nv_bfloat16* __restrict__ out,
                              int K, int N, int in_ld, int out_ld,
                              long sInB, long sInH, long sOutB, long sOutH, int Hn)
{
    __shared__ float t[32][33];
    int z = blockIdx.z, zb = z / Hn, zh = z % Hn;
    in  += zb * sInB + zh * sInH;
    out += zb * sOutB + zh * sOutH;
    int k0 = blockIdx.y * 32, n0 = blockIdx.x * 32;
    int tx = threadIdx.x, ty = threadIdx.y;
#pragma unroll
    for (int i = 0; i < 4; ++i) {
        int k = k0 + ty + i * 8, n = n0 + tx;
        t[ty + i * 8][tx] = (n < N) ? in[(long)k * in_ld + n] : 0.f;
    }
    __syncthreads();
#pragma unroll
    for (int i = 0; i < 4; ++i) {
        int n = n0 + ty + i * 8, k = k0 + tx;
        if (n < N) {
            float x = t[tx][ty + i * 8];
            __nv_bfloat16 h = __float2bfloat16(x);
            __nv_bfloat16 l = __float2bfloat16(x - __bfloat162float(h));
            __nv_bfloat16* o = out + (long)n * out_ld + k;
            o[0]     = h;
            o[K]     = l;
            o[2 * K] = h;
        }
    }
}

// ---------------------------------------------------------------------------
// bf16 tensor-core GEMM (mma.sync m16n8k16), 4-stage cp.async pipeline,
// ONE __syncthreads per K-iter. CTA 128x128, BK=32, 8 warps (64x32 warp tile).
// EPI: 0 fp32 | 1 fp32+bias | 2 fp32+bias+relu
//      3 triple patA+bias | 4 triple patB+bias | 5 triple patA
//      6 triple patA+bias+relu
// ---------------------------------------------------------------------------
#define GBM 128
#define GBN 128
#define GBK 32
#define NSTAGE 4
#define STAGE_BYTES 20480            // (128 rows * 80B) * 2 arrays
#define HG_SMEM (NSTAGE * STAGE_BYTES)   // 81920

__device__ __forceinline__ uint32_t smem_u32(const void* p) {
    uint32_t a;
    asm("{ .reg .u64 t; cvta.to.shared.u64 t, %1; cvt.u32.u64 %0, t; }" : "=r"(a) : "l"(p));
    return a;
}
#define CP16(dst, src) \
    asm volatile("cp.async.cg.shared.global [%0], [%1], 16;" :: "r"(dst), "l"(src))
#define CP_COMMIT() asm volatile("cp.async.commit_group;" ::: "memory")
#define CP_WAIT(n)  asm volatile("cp.async.wait_group %0;" :: "n"(n) : "memory")
#define LDSM_X4(r0, r1, r2, r3, addr) \
    asm volatile("ldmatrix.sync.aligned.m8n8.x4.shared.b16 {%0,%1,%2,%3}, [%4];" \
                 : "=r"(r0), "=r"(r1), "=r"(r2), "=r"(r3) : "r"(addr))
#define MMA_BF16(c, a0, a1, a2, a3, b0, b1) \
    asm volatile("mma.sync.aligned.m16n8k16.row.col.f32.bf16.bf16.f32 " \
                 "{%0,%1,%2,%3}, {%4,%5,%6,%7}, {%8,%9}, {%0,%1,%2,%3};" \
                 : "+f"((c)[0]), "+f"((c)[1]), "+f"((c)[2]), "+f"((c)[3]) \
                 : "r"(a0), "r"(a1), "r"(a2), "r"(a3), "r"(b0), "r"(b1))

template<int EPI>
__global__ void __launch_bounds__(256, 2)
hgemm_kernel(const __nv_bfloat16* __restrict__ A3, const __nv_bfloat16* __restrict__ B3,
             const float* __restrict__ Bias, void* __restrict__ Cv,
             int Nstore, int K3, int lda, int ldb, int ldc,
             long sAb, long sAh, long sBb, long sBh, long sCb, long sCh,
             long sBiB, long sBiH, int Hn, int d1, int d2)
{
    extern __shared__ __align__(16) char dsm[];
    const uint32_t base = smem_u32(dsm);

    int tid = threadIdx.x;
    int wid = tid >> 5, lane = tid & 31;

    int z = blockIdx.z, zb = z / Hn, zh = z % Hn;
    A3 += zb * sAb + zh * sAh;
    B3 += zb * sBb + zh * sBh;
    long cOff = zb * sCb + zh * sCh;
    long biasOff = zb * sBiB + zh * sBiH;

    long m0 = (long)blockIdx.x * GBM;
    long n0 = (long)blockIdx.y * GBN;

    const int wm = (wid >> 2) * 64;
    const int wn = (wid & 3) * 32;

    float acc[4][4][4];
#pragma unroll
    for (int i = 0; i < 4; i++)
#pragma unroll
        for (int j = 0; j < 4; j++)
#pragma unroll
            for (int q = 0; q < 4; q++) acc[i][j][q] = 0.f;

    const int nIter = K3 / GBK;

    // per-thread load coordinates (fixed across stages)
    const int lr  = tid >> 2;            // row 0..63 (x2 groups)
    const int lsg = tid & 3;             // 16B segment
    const long aRow0 = m0 + lr,  aRow1 = m0 + lr + 64;
    const long bRow0 = n0 + lr,  bRow1 = n0 + lr + 64;
    const uint32_t sOffA0 = (uint32_t)(lr * 80 + lsg * 16);
    const uint32_t sOffA1 = (uint32_t)((lr + 64) * 80 + lsg * 16);

    auto loadStage = [&](int slot, long k0) {
        uint32_t aD = base + slot * STAGE_BYTES;
        uint32_t bD = aD + 10240;
        long ko = k0 + lsg * 8;
        CP16(aD + sOffA0, A3 + aRow0 * (long)lda + ko);
        CP16(aD + sOffA1, A3 + aRow1 * (long)lda + ko);
        CP16(bD + sOffA0, B3 + bRow0 * (long)ldb + ko);
        CP16(bD + sOffA1, B3 + bRow1 * (long)ldb + ko);
        CP_COMMIT();
    };

    // preload stages 0..2
    loadStage(0, 0);
    if (nIter > 1) loadStage(1, GBK); else CP_COMMIT();
    if (nIter > 2) loadStage(2, 2L * GBK); else CP_COMMIT();

    for (int it = 0; it < nIter; ++it) {
        // stage `it` must be resident; allow the 2 newer groups to stay in flight
        if (it + 2 < nIter)      CP_WAIT(2);
        else if (it + 1 < nIter) CP_WAIT(1);
        else                     CP_WAIT(0);
        __syncthreads();
        if (it + 3 < nIter) loadStage((it + 3) & (NSTAGE - 1), (long)(it + 3) * GBK);

        uint32_t aS = base + (it & (NSTAGE - 1)) * STAGE_BYTES;
        uint32_t bS = aS + 10240;
#pragma unroll
        for (int ks = 0; ks < 2; ks++) {
            int col = ks * 16 + (lane >> 4) * 8;
            uint32_t a[4][4], bf[4][2];
#pragma unroll
            for (int mi = 0; mi < 4; mi++) {
                int row = wm + mi * 16 + (lane & 15);
                LDSM_X4(a[mi][0], a[mi][1], a[mi][2], a[mi][3],
                        aS + (uint32_t)(row * 80 + col * 2));
            }
#pragma unroll
            for (int p = 0; p < 2; p++) {
                int row = wn + p * 16 + (lane & 15);
                uint32_t r0, r1, r2, r3;
                LDSM_X4(r0, r1, r2, r3, bS + (uint32_t)(row * 80 + col * 2));
                bf[2 * p][0] = r0;     bf[2 * p][1] = r2;
                bf[2 * p + 1][0] = r1; bf[2 * p + 1][1] = r3;
            }
#pragma unroll
            for (int mi = 0; mi < 4; mi++)
#pragma unroll
                for (int ni = 0; ni < 4; ni++)
                    MMA_BF16(acc[mi][ni], a[mi][0], a[mi][1], a[mi][2], a[mi][3],
                             bf[ni][0], bf[ni][1]);
        }
        // NOTE: no trailing barrier. With 4-stage buffering, the buffer written
        // at iter it+? was last read two barriers ago — the single barrier above
        // (crossed by all warps after consuming iter it-1) is sufficient.
    }

    // ---- epilogue ----
    if (EPI <= 2) {
        float* C = (float*)Cv + cOff;
#pragma unroll
        for (int mi = 0; mi < 4; mi++) {
            long mrow = m0 + wm + mi * 16 + (lane >> 2);
            float* c0p = C + mrow * (long)ldc;
            float* c1p = c0p + 8L * ldc;
#pragma unroll
            for (int ni = 0; ni < 4; ni++) {
                long n = n0 + wn + ni * 8 + (lane & 3) * 2;
#pragma unroll
                for (int e = 0; e < 2; e++) {
                    long nn = n + e;
                    if (nn < (long)Nstore) {
                        float v0 = acc[mi][ni][e];
                        float v1 = acc[mi][ni][2 + e];
                        if (EPI >= 1) {
                            float bsv = Bias[biasOff + nn];
                            v0 += bsv; v1 += bsv;
                        }
                        if (EPI == 2) { v0 = fmaxf(v0, 0.f); v1 = fmaxf(v1, 0.f); }
                        c0p[nn] = v0;
                        c1p[nn] = v1;
                    }
                }
            }
        }
    } else {
        __nv_bfloat16* C3 = (__nv_bfloat16*)Cv + cOff;
        const bool hasBias = (EPI == 3 || EPI == 4 || EPI == 6);
        const bool relu = (EPI == 6);
        const bool patB = (EPI == 4);
#pragma unroll
        for (int mi = 0; mi < 4; mi++) {
            long r0 = m0 + wm + mi * 16 + (lane >> 2);
            __nv_bfloat16* p0 = C3 + r0 * (long)ldc;
            __nv_bfloat16* p1 = p0 + 8L * ldc;
#pragma unroll
            for (int ni = 0; ni < 4; ni++) {
                long n = n0 + wn + ni * 8 + (lane & 3) * 2;
                float b0 = 0.f, b1 = 0.f;
                if (hasBias) { b0 = Bias[biasOff + n]; b1 = Bias[biasOff + n + 1]; }
                float v0 = acc[mi][ni][0] + b0, v1 = acc[mi][ni][1] + b1;
                float v2 = acc[mi][ni][2] + b0, v3 = acc[mi][ni][3] + b1;
                if (relu) {
                    v0 = fmaxf(v0, 0.f); v1 = fmaxf(v1, 0.f);
                    v2 = fmaxf(v2, 0.f); v3 = fmaxf(v3, 0.f);
                }
                __nv_bfloat162 hiA, loA, hiB, loB;
                split2(v0, v1, hiA, loA);
                split2(v2, v3, hiB, loB);
                *(__nv_bfloat162*)(p0 + n)      = hiA;
                *(__nv_bfloat162*)(p0 + n + d1) = patB ? loA : hiA;
                *(__nv_bfloat162*)(p0 + n + d2) = patB ? hiA : loA;
                *(__nv_bfloat162*)(p1 + n)      = hiB;
                *(__nv_bfloat162*)(p1 + n + d1) = patB ? loB : hiB;
                *(__nv_bfloat162*)(p1 + n + d2) = patB ? hiB : loB;
            }
        }
    }
}

// ---------------------------------------------------------------------------
// Host dispatch
// ---------------------------------------------------------------------------
static void tg(int epi, const __nv_bfloat16* A, const __nv_bfloat16* B, const float* Bias,
               void* C, int M, int N, int K3, int lda, int ldb, int ldc,
               long sAb, long sAh, long sBb, long sBh, long sCb, long sCh,
               long sBiB, long sBiH, int Hn, int Z, int d1 = 0, int d2 = 0)
{
    dim3 g(M / GBM, (N + GBN - 1) / GBN, Z), b(256);
#define HG_CALL(E) hgemm_kernel<E><<<g, b, HG_SMEM>>>(A, B, Bias, C, N, K3, lda, ldb, ldc, \
    sAb, sAh, sBb, sBh, sCb, sCh, sBiB, sBiH, Hn, d1, d2)
    switch (epi) {
    case 0: HG_CALL(0); break;
    case 1: HG_CALL(1); break;
    case 2: HG_CALL(2); break;
    case 3: HG_CALL(3); break;
    case 4: HG_CALL(4); break;
    case 5: HG_CALL(5); break;
    default: HG_CALL(6); break;
    }
#undef HG_CALL
}

extern "C" void kernel_launch(void* const* d_in, const int* in_sizes, int n_in,
                              void* d_out, int out_size)
{
    const float* enc    = (const float*)d_in[0];
    const int*   srcpad = (const int*)  d_in[1];
    const int*   target = (const int*)  d_in[2];
    const float* emb    = (const float*)d_in[3];
    const float* Wq1 = (const float*)d_in[4],  *bq1 = (const float*)d_in[5];
    const float* Wk1 = (const float*)d_in[6],  *bk1 = (const float*)d_in[7];
    const float* Wv1 = (const float*)d_in[8],  *bv1 = (const float*)d_in[9];
    const float* Wo1 = (const float*)d_in[10], *bo1 = (const float*)d_in[11];
    const float* Wq2 = (const float*)d_in[12], *bq2 = (const float*)d_in[13];
    const float* Wk2 = (const float*)d_in[14], *bk2 = (const float*)d_in[15];
    const float* Wv2 = (const float*)d_in[16], *bv2 = (const float*)d_in[17];
    const float* Wo2 = (const float*)d_in[18], *bo2 = (const float*)d_in[19];
    const float* ln1g = (const float*)d_in[20];
    const float* ln2g = (const float*)d_in[21];
    const float* ln3g = (const float*)d_in[22];
    const float* ln1b = (const float*)d_in[23];
    const float* ln2b = (const float*)d_in[24];
    const float* ln3b = (const float*)d_in[25];
    const float* Wf1 = (const float*)d_in[26], *bf1 = (const float*)d_in[27];
    const float* Wf2 = (const float*)d_in[28], *bf2 = (const float*)d_in[29];
    const float* lmW = (const float*)d_in[30], *lmb = (const float*)d_in[31];
    float* out = (float*)d_out;

    float *x, *vv, *ss, *tt;
    cudaGetSymbolAddress((void**)&x,  g_x);
    cudaGetSymbolAddress((void**)&vv, g_v);
    cudaGetSymbolAddress((void**)&ss, g_s);
    cudaGetSymbolAddress((void**)&tt, g_t);
    __nv_bfloat16 *x3, *e3, *q3, *k3, *v3, *s3, *o3, *f3, *w3, *lm3;
    cudaGetSymbolAddress((void**)&x3, g_x3);
    cudaGetSymbolAddress((void**)&e3, g_e3);
    cudaGetSymbolAddress((void**)&q3, g_q3);
    cudaGetSymbolAddress((void**)&k3, g_k3);
    cudaGetSymbolAddress((void**)&v3, g_v3);
    cudaGetSymbolAddress((void**)&s3, g_s3);
    cudaGetSymbolAddress((void**)&o3, g_o3);
    cudaGetSymbolAddress((void**)&f3, g_f3);
    cudaGetSymbolAddress((void**)&w3, g_w3);
    cudaGetSymbolAddress((void**)&lm3, g_lm3);

    cudaFuncSetAttribute(hgemm_kernel<0>, cudaFuncAttributeMaxDynamicSharedMemorySize, HG_SMEM);
    cudaFuncSetAttribute(hgemm_kernel<1>, cudaFuncAttributeMaxDynamicSharedMemorySize, HG_SMEM);
    cudaFuncSetAttribute(hgemm_kernel<2>, cudaFuncAttributeMaxDynamicSharedMemorySize, HG_SMEM);
    cudaFuncSetAttribute(hgemm_kernel<3>, cudaFuncAttributeMaxDynamicSharedMemorySize, HG_SMEM);
    cudaFuncSetAttribute(hgemm_kernel<4>, cudaFuncAttributeMaxDynamicSharedMemorySize, HG_SMEM);
    cudaFuncSetAttribute(hgemm_kernel<5>, cudaFuncAttributeMaxDynamicSharedMemorySize, HG_SMEM);
    cudaFuncSetAttribute(hgemm_kernel<6>, cudaFuncAttributeMaxDynamicSharedMemorySize, HG_SMEM);

    const float scale = 1.0f / sqrtf((float)Dm);
    const long WATT = (long)Hh * Dm * Dm;
    const long WOUT = (long)HD * Dm;
    const long WFF  = (long)Dm * FFd;
    const dim3 tb(32, 8);

    embed_pe_kernel<<<NR, 512>>>(target, emb, x, x3);
    conv_enc_kernel<<<NR, 256>>>(enc, e3);

    for (int l = 0; l < 2; l++) {
        const float *WQ[2] = {Wq1 + l * WATT, Wq2 + l * WATT};
        const float *WK[2] = {Wk1 + l * WATT, Wk2 + l * WATT};
        const float *WV[2] = {Wv1 + l * WATT, Wv2 + l * WATT};
        const float *WO[2] = {Wo1 + l * WOUT, Wo2 + l * WOUT};
        const float *BQ[2] = {bq1 + l * HD, bq2 + l * HD};
        const float *BK[2] = {bk1 + l * HD, bk2 + l * HD};
        const float *BV[2] = {bv1 + l * HD, bv2 + l * HD};
        const float *BO[2] = {bo1 + l * Dm, bo2 + l * Dm};
        const float *LG[2] = {ln1g + l * Dm, ln2g + l * Dm};
        const float *LB[2] = {ln1b + l * Dm, ln2b + l * Dm};

        for (int att = 0; att < 2; att++) {
            const __nv_bfloat16* kvA = (att == 0) ? x3 : e3;

            conv_t_kernel<<<dim3(16, 16, 8), tb>>>(WQ[att], w3, Dm, Dm, Dm, 1536,
                                                   0, (long)Dm * Dm, 0, (long)Dm * 1536, 8);
            tg(3, x3, w3, BQ[att], q3, NR, Dm, 1536, 1536, 1536, 12288,
               0, 0, 0, (long)Dm * 1536, 0, 1536, 0, Dm, 8, 8, 512, 1024);

            conv_t_kernel<<<dim3(16, 16, 8), tb>>>(WK[att], w3, Dm, Dm, Dm, 1536,
                                                   0, (long)Dm * Dm, 0, (long)Dm * 1536, 8);
            tg(4, kvA, w3, BK[att], k3, NR, Dm, 1536, 1536, 1536, 12288,
               0, 0, 0, (long)Dm * 1536, 0, 1536, 0, Dm, 8, 8, 512, 1024);

            conv_t_kernel<<<dim3(16, 16, 8), tb>>>(WV[att], w3, Dm, Dm, Dm, 1536,
                                                   0, (long)Dm * Dm, 0, (long)Dm * 1536, 8);
            tg(1, kvA, w3, BV[att], vv, NR, Dm, 1536, 1536, 1536, HD,
               0, 0, 0, (long)Dm * 1536, 0, Dm, 0, Dm, 8, 8);
            conv_t_kernel<<<dim3(16, 16, 32), tb>>>(vv, v3, TSs, Dm, HD, 1536,
                                                    (long)TSs * HD, Dm,
                                                    (long)Hh * TSs * 1536, (long)TSs * 1536, 8);

            tg(0, q3, k3, nullptr, ss, TTq, TSs, 1536, 12288, 12288, TSs,
               (long)TTq * 12288, 1536, (long)TSs * 12288, 1536,
               (long)Hh * TTq * TSs, (long)TTq * TSs, 0, 0, 8, 32);

            softmax_kernel<<<Bq * Hh * TTq, 256>>>(ss, s3, target, srcpad,
                                                   att == 0 ? 1 : 2, scale);
            if (att == 1 && l == 0 && (long)out_size >= LOGITS_ELEMS + ATT_ELEMS) {
                cudaMemcpyAsync(out + LOGITS_ELEMS, ss, ATT_ELEMS * sizeof(float),
                                cudaMemcpyDeviceToDevice, 0);
            }

            tg(5, s3, v3, nullptr, o3, TTq, Dm, 1536, 1536, 1536, 12288,
               (long)Hh * TTq * 1536, (long)TTq * 1536,
               (long)Hh * TSs * 1536, (long)TSs * 1536,
               (long)TTq * 12288, 512, 0, 0, 8, 32, 4096, 8192);

            conv_t_kernel<<<dim3(16, 128, 1), tb>>>(WO[att], w3, HD, Dm, Dm, 12288,
                                                    0, 0, 0, 0, 1);
            tg(1, o3, w3, BO[att], tt, NR, Dm, 12288, 12288, 12288, Dm,
               0, 0, 0, 0, 0, 0, 0, 0, 1, 1);
            add_ln_kernel<<<NR, 256>>>(x, tt, LG[att], LB[att], x, x3);
        }

        conv_t_kernel<<<dim3(64, 16, 1), tb>>>(Wf1 + l * WFF, w3, Dm, FFd, FFd, 1536,
                                               0, 0, 0, 0, 1);
        tg(6, x3, w3, bf1 + l * FFd, f3, NR, FFd, 1536, 1536, 1536, 6144,
           0, 0, 0, 0, 0, 0, 0, 0, 1, 1, 2048, 4096);
        conv_t_kernel<<<dim3(16, 64, 1), tb>>>(Wf2 + l * WFF, w3, FFd, Dm, Dm, 6144,
                                               0, 0, 0, 0, 1);
        tg(1, f3, w3, bf2 + l * Dm, tt, NR, Dm, 6144, 6144, 6144, Dm,
           0, 0, 0, 0, 0, 0, 0, 0, 1, 1);
        add_ln_kernel<<<NR, 256>>>(x, tt, ln3g + l * Dm, ln3b + l * Dm, x, x3);
    }

    conv_t_kernel<<<dim3(1001, 16, 1), tb>>>(lmW, lm3, Dm, VO, VO, 1536, 0, 0, 0, 0, 1);
    tg(1, x3, lm3, lmb, out, NR, VO, 1536, 1536, 1536, VO,
       0, 0, 0, 0, 0, 0, 0, 0, 1, 1);
}

// round 7
// speedup vs baseline: 2.5871x; 1.1153x over previous
#include <cuda_runtime.h>
#include <cuda_bf16.h>
#include <math.h>
#include <stdint.h>

// ---------------------------------------------------------------------------
// Problem constants
// ---------------------------------------------------------------------------
#define Bq   4
#define TTq  512
#define TSs  512
#define Dm   512
#define Hh   8
#define Vv   32000
#define VO   32001
#define NR   2048
#define HD   4096
#define FFd  2048
#define SKn  8

#define LOGITS_ELEMS (2048LL * 32001LL)
#define ATT_ELEMS    (4LL * 8 * 512 * 512)

// ---------------------------------------------------------------------------
// Scratch (static device globals)
// ---------------------------------------------------------------------------
__device__ float g_x [NR * Dm];
__device__ float g_v [NR * HD];
__device__ float g_s [Bq * Hh * TTq * TSs];
__device__ float g_t [NR * Dm];
__device__ float g_part[SKn * NR * Dm];          // split-K partials

__device__ __nv_bfloat16 g_x3 [NR * 1536];
__device__ __nv_bfloat16 g_e3 [NR * 1536];
__device__ __nv_bfloat16 g_q3 [NR * 12288];
__device__ __nv_bfloat16 g_k3 [NR * 12288];
__device__ __nv_bfloat16 g_v3 [32 * 512 * 1536];
__device__ __nv_bfloat16 g_s3 [32 * 512 * 1536];
__device__ __nv_bfloat16 g_o3 [NR * 12288];
__device__ __nv_bfloat16 g_f3 [NR * 6144];
__device__ __nv_bfloat16 g_w3 [6291456];
__device__ __nv_bfloat16 g_lm3[32256 * 1536];    // rows padded to 126*256 (pads stay 0)

// ---------------------------------------------------------------------------
// hi/lo split helper
// ---------------------------------------------------------------------------
__device__ __forceinline__ void split2(float v0, float v1,
                                       __nv_bfloat162& hi, __nv_bfloat162& lo)
{
    __nv_bfloat16 h0 = __float2bfloat16(v0), h1 = __float2bfloat16(v1);
    hi.x = h0; hi.y = h1;
    lo.x = __float2bfloat16(v0 - __bfloat162float(h0));
    lo.y = __float2bfloat16(v1 - __bfloat162float(h1));
}

// ---------------------------------------------------------------------------
// Embedding + positional encoding -> x (fp32) and x3 (triple patA)
// ---------------------------------------------------------------------------
__global__ void embed_pe_kernel(const int* __restrict__ target,
                                const float* __restrict__ emb,
                                float* __restrict__ x,
                                __nv_bfloat16* __restrict__ x3)
{
    int row = blockIdx.x;
    int t   = row & (TTq - 1);
    int d   = threadIdx.x;
    int tok = target[row];
    float e = emb[(long)tok * Dm + d];
    int   i = d >> 1;
    float denom = powf(10000.0f, (2.0f * (float)i) / (float)Dm);
    float z = (float)t / denom;
    float p = (d & 1) ? cosf(z) : sinf(z);
    float v = e + p;
    x[(long)row * Dm + d] = v;
    __nv_bfloat16 h = __float2bfloat16(v);
    __nv_bfloat16 l = __float2bfloat16(v - __bfloat162float(h));
    __nv_bfloat16* ob = x3 + (long)row * 1536 + d;
    ob[0] = h; ob[512] = h; ob[1024] = l;
}

// ---------------------------------------------------------------------------
// enc fp32 -> e3 triple (patA)
// ---------------------------------------------------------------------------
__global__ void conv_enc_kernel(const float* __restrict__ in, __nv_bfloat16* __restrict__ out)
{
    long idx = (long)blockIdx.x * blockDim.x + threadIdx.x;
    long r = idx >> 8;
    long k = (idx & 255) * 2;
    const float* p = in + r * Dm + k;
    __nv_bfloat162 hi, lo;
    split2(p[0], p[1], hi, lo);
    __nv_bfloat16* ob = out + r * 1536 + k;
    *(__nv_bfloat162*)(ob)        = hi;
    *(__nv_bfloat162*)(ob + 512)  = hi;
    *(__nv_bfloat162*)(ob + 1024) = lo;
}

// ---------------------------------------------------------------------------
// Masked softmax: writes normalized fp32 AND s3 triple patA.
// ---------------------------------------------------------------------------
__global__ void softmax_kernel(float* __restrict__ S, __nv_bfloat16* __restrict__ S3,
                               const int* __restrict__ target,
                               const int* __restrict__ srcpad,
                               int mode, float scale)
{
    int row = blockIdx.x;
    int q   = row & (TTq - 1);
    int b   = row / (Hh * TTq);
    float* s = S + (long)row * TSs;
    int tid = threadIdx.x;
    bool qpad = (target[b * TTq + q] != Vv);

    float v[2];
    float mx = -INFINITY;
#pragma unroll
    for (int e = 0; e < 2; e++) {
        int k = tid + e * 256;
        bool valid;
        if (mode == 1)
            valid = qpad && (k <= q) && (target[b * TTq + k] != Vv);
        else
            valid = qpad && (srcpad[b * TSs + k] != 0);
        float val = valid ? s[k] * scale : -1e32f;
        v[e] = val;
        mx = fmaxf(mx, val);
    }

    __shared__ float red[8];
#pragma unroll
    for (int o = 16; o > 0; o >>= 1) mx = fmaxf(mx, __shfl_xor_sync(0xffffffffu, mx, o));
    if ((tid & 31) == 0) red[tid >> 5] = mx;
    __syncthreads();
    if (tid < 32) {
        float r = (tid < 8) ? red[tid] : -INFINITY;
#pragma unroll
        for (int o = 4; o > 0; o >>= 1) r = fmaxf(r, __shfl_xor_sync(0xffffffffu, r, o));
        if (tid == 0) red[0] = r;
    }
    __syncthreads();
    mx = red[0];
    __syncthreads();

    float sum = 0.f;
#pragma unroll
    for (int e = 0; e < 2; e++) { v[e] = expf(v[e] - mx); sum += v[e]; }
#pragma unroll
    for (int o = 16; o > 0; o >>= 1) sum += __shfl_xor_sync(0xffffffffu, sum, o);
    if ((tid & 31) == 0) red[tid >> 5] = sum;
    __syncthreads();
    if (tid < 32) {
        float r = (tid < 8) ? red[tid] : 0.f;
#pragma unroll
        for (int o = 4; o > 0; o >>= 1) r += __shfl_xor_sync(0xffffffffu, r, o);
        if (tid == 0) red[0] = r;
    }
    __syncthreads();
    float inv = 1.0f / red[0];
    __nv_bfloat16* s3r = S3 + (long)row * 1536;
#pragma unroll
    for (int e = 0; e < 2; e++) {
        int k = tid + e * 256;
        float val = v[e] * inv;
        s[k] = val;
        __nv_bfloat16 h = __float2bfloat16(val);
        __nv_bfloat16 l = __float2bfloat16(val - __bfloat162float(h));
        s3r[k] = h; s3r[k + 512] = h; s3r[k + 1024] = l;
    }
}

// ---------------------------------------------------------------------------
// y = LayerNorm(xin + a) * g + b  -> y fp32 and y3 triple patA
// ---------------------------------------------------------------------------
__global__ void add_ln_kernel(const float* __restrict__ xin,
                              const float* __restrict__ a,
                              const float* __restrict__ gg,
                              const float* __restrict__ bb,
                              float* __restrict__ y,
                              __nv_bfloat16* __restrict__ y3)
{
    int row = blockIdx.x;
    int tid = threadIdx.x;
    long base = (long)row * Dm;
    __shared__ float red[8];

    float v[2];
    float sum = 0.f;
#pragma unroll
    for (int e = 0; e < 2; e++) {
        int d = tid + e * 256;
        v[e] = xin[base + d] + a[base + d];
        sum += v[e];
    }
#pragma unroll
    for (int o = 16; o > 0; o >>= 1) sum += __shfl_xor_sync(0xffffffffu, sum, o);
    if ((tid & 31) == 0) red[tid >> 5] = sum;
    __syncthreads();
    if (tid < 32) {
        float r = (tid < 8) ? red[tid] : 0.f;
#pragma unroll
        for (int o = 4; o > 0; o >>= 1) r += __shfl_xor_sync(0xffffffffu, r, o);
        if (tid == 0) red[0] = r;
    }
    __syncthreads();
    float m = red[0] * (1.0f / (float)Dm);
    __syncthreads();

    float vs = 0.f;
#pragma unroll
    for (int e = 0; e < 2; e++) { float c = v[e] - m; vs += c * c; }
#pragma unroll
    for (int o = 16; o > 0; o >>= 1) vs += __shfl_xor_sync(0xffffffffu, vs, o);
    if ((tid & 31) == 0) red[tid >> 5] = vs;
    __syncthreads();
    if (tid < 32) {
        float r = (tid < 8) ? red[tid] : 0.f;
#pragma unroll
        for (int o = 4; o > 0; o >>= 1) r += __shfl_xor_sync(0xffffffffu, r, o);
        if (tid == 0) red[0] = r;
    }
    __syncthreads();
    float var = red[0] * (1.0f / (float)Dm);
    float rs = rsqrtf(var + 1e-5f);
    __nv_bfloat16* y3r = y3 + (long)row * 1536;
#pragma unroll
    for (int e = 0; e < 2; e++) {
        int d = tid + e * 256;
        float val = (v[e] - m) * rs * gg[d] + bb[d];
        y[base + d] = val;
        __nv_bfloat16 h = __float2bfloat16(val);
        __nv_bfloat16 l = __float2bfloat16(val - __bfloat162float(h));
        y3r[d] = h; y3r[d + 512] = h; y3r[d + 1024] = l;
    }
}

// ---------------------------------------------------------------------------
// conv_t: fp32 [K, N] (N-contig) -> bf16 triple [N, 3K], pattern B [hi|lo|hi].
// ---------------------------------------------------------------------------
__global__ void conv_t_kernel(const float* __restrict__ in, __nv_bfloat16* __restrict__ out,
                              int K, int N, int in_ld, int out_ld,
                              long sInB, long sInH, long sOutB, long sOutH, int Hn)
{
    __shared__ float t[32][33];
    int z = blockIdx.z, zb = z / Hn, zh = z % Hn;
    in  += zb * sInB + zh * sInH;
    out += zb * sOutB + zh * sOutH;
    int k0 = blockIdx.y * 32, n0 = blockIdx.x * 32;
    int tx = threadIdx.x, ty = threadIdx.y;
#pragma unroll
    for (int i = 0; i < 4; ++i) {
        int k = k0 + ty + i * 8, n = n0 + tx;
        t[ty + i * 8][tx] = (n < N) ? in[(long)k * in_ld + n] : 0.f;
    }
    __syncthreads();
#pragma unroll
    for (int i = 0; i < 4; ++i) {
        int n = n0 + ty + i * 8, k = k0 + tx;
        if (n < N) {
            float x = t[tx][ty + i * 8];
            __nv_bfloat16 h = __float2bfloat16(x);
            __nv_bfloat16 l = __float2bfloat16(x - __bfloat162float(h));
            __nv_bfloat16* o = out + (long)n * out_ld + k;
            o[0]     = h;
            o[K]     = l;
            o[2 * K] = h;
        }
    }
}

// ---------------------------------------------------------------------------
// split-K reduce: out = sum_c part[c] + bias (row length Dm)
// ---------------------------------------------------------------------------
__global__ void reduce_sk_kernel(const float* __restrict__ part,
                                 const float* __restrict__ bias,
                                 float* __restrict__ outp)
{
    long e = ((long)blockIdx.x * 256 + threadIdx.x) * 4;
    float4 s = make_float4(0.f, 0.f, 0.f, 0.f);
#pragma unroll
    for (int c = 0; c < SKn; c++) {
        float4 v = *(const float4*)(part + (long)c * NR * Dm + e);
        s.x += v.x; s.y += v.y; s.z += v.z; s.w += v.w;
    }
    int d = (int)(e & (Dm - 1));
    s.x += bias[d]; s.y += bias[d + 1]; s.z += bias[d + 2]; s.w += bias[d + 3];
    *(float4*)(outp + e) = s;
}

// ---------------------------------------------------------------------------
// bf16 tensor-core GEMM (mma.sync m16n8k16). CTA 128x256, 8 warps (2x4),
// warp tile 64x64. BK=32, 4-stage cp.async pipeline, one barrier per iter.
// EPI: 0 fp32 | 1 fp32+bias | 2 fp32+bias+relu
//      3 triple patA+bias | 4 triple patB+bias | 5 triple patA
//      6 triple patA+bias+relu
// ---------------------------------------------------------------------------
#define GBM 128
#define GBN 256
#define GBK 32
#define NSTAGE 4
#define A_BYTES 10240                    // 128 rows * 80B
#define STAGE_BYTES 30720                // A(10240) + B(20480)
#define HG_SMEM (NSTAGE * STAGE_BYTES)   // 122880

__device__ __forceinline__ uint32_t smem_u32(const void* p) {
    uint32_t a;
    asm("{ .reg .u64 t; cvta.to.shared.u64 t, %1; cvt.u32.u64 %0, t; }" : "=r"(a) : "l"(p));
    return a;
}
#define CP16(dst, src) \
    asm volatile("cp.async.cg.shared.global [%0], [%1], 16;" :: "r"(dst), "l"(src))
#define CP_COMMIT() asm volatile("cp.async.commit_group;" ::: "memory")
#define CP_WAIT(n)  asm volatile("cp.async.wait_group %0;" :: "n"(n) : "memory")
#define LDSM_X4(r0, r1, r2, r3, addr) \
    asm volatile("ldmatrix.sync.aligned.m8n8.x4.shared.b16 {%0,%1,%2,%3}, [%4];" \
                 : "=r"(r0), "=r"(r1), "=r"(r2), "=r"(r3) : "r"(addr))
#define MMA_BF16(c, a0, a1, a2, a3, b0, b1) \
    asm volatile("mma.sync.aligned.m16n8k16.row.col.f32.bf16.bf16.f32 " \
                 "{%0,%1,%2,%3}, {%4,%5,%6,%7}, {%8,%9}, {%0,%1,%2,%3};" \
                 : "+f"((c)[0]), "+f"((c)[1]), "+f"((c)[2]), "+f"((c)[3]) \
                 : "r"(a0), "r"(a1), "r"(a2), "r"(a3), "r"(b0), "r"(b1))

template<int EPI>
__global__ void __launch_bounds__(256, 1)
hgemm_kernel(const __nv_bfloat16* __restrict__ A3, const __nv_bfloat16* __restrict__ B3,
             const float* __restrict__ Bias, void* __restrict__ Cv,
             int Nstore, int K3, int lda, int ldb, int ldc,
             long sAb, long sAh, long sBb, long sBh, long sCb, long sCh,
             long sBiB, long sBiH, int Hn, int d1, int d2)
{
    extern __shared__ __align__(16) char dsm[];
    const uint32_t base = smem_u32(dsm);

    int tid = threadIdx.x;
    int wid = tid >> 5, lane = tid & 31;

    int z = blockIdx.z, zb = z / Hn, zh = z % Hn;
    A3 += zb * sAb + zh * sAh;
    B3 += zb * sBb + zh * sBh;
    long cOff = zb * sCb + zh * sCh;
    long biasOff = zb * sBiB + zh * sBiH;

    long m0 = (long)blockIdx.x * GBM;
    long n0 = (long)blockIdx.y * GBN;

    const int wm = (wid >> 2) * 64;      // 2 warps in M
    const int wn = (wid & 3) * 64;       // 4 warps in N

    float acc[4][8][4];
#pragma unroll
    for (int i = 0; i < 4; i++)
#pragma unroll
        for (int j = 0; j < 8; j++)
#pragma unroll
            for (int q = 0; q < 4; q++) acc[i][j][q] = 0.f;

    const int nIter = K3 / GBK;

    const int lr  = tid >> 2;            // 0..63
    const int lsg = tid & 3;
    const long aRow0 = m0 + lr,  aRow1 = m0 + lr + 64;
    const uint32_t sOff0 = (uint32_t)(lr * 80 + lsg * 16);
    const uint32_t sOff1 = (uint32_t)((lr + 64) * 80 + lsg * 16);
    const uint32_t sOff2 = (uint32_t)((lr + 128) * 80 + lsg * 16);
    const uint32_t sOff3 = (uint32_t)((lr + 192) * 80 + lsg * 16);

    auto loadStage = [&](int slot, long k0) {
        uint32_t aD = base + slot * STAGE_BYTES;
        uint32_t bD = aD + A_BYTES;
        long ko = k0 + lsg * 8;
        CP16(aD + sOff0, A3 + aRow0 * (long)lda + ko);
        CP16(aD + sOff1, A3 + aRow1 * (long)lda + ko);
        CP16(bD + sOff0, B3 + (n0 + lr) * (long)ldb + ko);
        CP16(bD + sOff1, B3 + (n0 + lr + 64) * (long)ldb + ko);
        CP16(bD + sOff2, B3 + (n0 + lr + 128) * (long)ldb + ko);
        CP16(bD + sOff3, B3 + (n0 + lr + 192) * (long)ldb + ko);
        CP_COMMIT();
    };

    loadStage(0, 0);
    if (nIter > 1) loadStage(1, GBK); else CP_COMMIT();
    if (nIter > 2) loadStage(2, 2L * GBK); else CP_COMMIT();

    for (int it = 0; it < nIter; ++it) {
        if (it + 2 < nIter)      CP_WAIT(2);
        else if (it + 1 < nIter) CP_WAIT(1);
        else                     CP_WAIT(0);
        __syncthreads();
        if (it + 3 < nIter) loadStage((it + 3) & (NSTAGE - 1), (long)(it + 3) * GBK);

        uint32_t aS = base + (it & (NSTAGE - 1)) * STAGE_BYTES;
        uint32_t bS = aS + A_BYTES;
#pragma unroll
        for (int ks = 0; ks < 2; ks++) {
            int col = ks * 16 + (lane >> 4) * 8;
            uint32_t a[4][4], bf[8][2];
#pragma unroll
            for (int mi = 0; mi < 4; mi++) {
                int row = wm + mi * 16 + (lane & 15);
                LDSM_X4(a[mi][0], a[mi][1], a[mi][2], a[mi][3],
                        aS + (uint32_t)(row * 80 + col * 2));
            }
#pragma unroll
            for (int p = 0; p < 4; p++) {
                int row = wn + p * 16 + (lane & 15);
                uint32_t r0, r1, r2, r3;
                LDSM_X4(r0, r1, r2, r3, bS + (uint32_t)(row * 80 + col * 2));
                bf[2 * p][0] = r0;     bf[2 * p][1] = r2;
                bf[2 * p + 1][0] = r1; bf[2 * p + 1][1] = r3;
            }
#pragma unroll
            for (int mi = 0; mi < 4; mi++)
#pragma unroll
                for (int ni = 0; ni < 8; ni++)
                    MMA_BF16(acc[mi][ni], a[mi][0], a[mi][1], a[mi][2], a[mi][3],
                             bf[ni][0], bf[ni][1]);
        }
    }

    // ---- epilogue ----
    if (EPI <= 2) {
        float* C = (float*)Cv + cOff;
#pragma unroll
        for (int mi = 0; mi < 4; mi++) {
            long mrow = m0 + wm + mi * 16 + (lane >> 2);
            float* c0p = C + mrow * (long)ldc;
            float* c1p = c0p + 8L * ldc;
#pragma unroll
            for (int ni = 0; ni < 8; ni++) {
                long n = n0 + wn + ni * 8 + (lane & 3) * 2;
#pragma unroll
                for (int e = 0; e < 2; e++) {
                    long nn = n + e;
                    if (nn < (long)Nstore) {
                        float v0 = acc[mi][ni][e];
                        float v1 = acc[mi][ni][2 + e];
                        if (EPI >= 1) {
                            float bsv = Bias[biasOff + nn];
                            v0 += bsv; v1 += bsv;
                        }
                        if (EPI == 2) { v0 = fmaxf(v0, 0.f); v1 = fmaxf(v1, 0.f); }
                        c0p[nn] = v0;
                        c1p[nn] = v1;
                    }
                }
            }
        }
    } else {
        __nv_bfloat16* C3 = (__nv_bfloat16*)Cv + cOff;
        const bool hasBias = (EPI == 3 || EPI == 4 || EPI == 6);
        const bool relu = (EPI == 6);
        const bool patB = (EPI == 4);
#pragma unroll
        for (int mi = 0; mi < 4; mi++) {
            long r0 = m0 + wm + mi * 16 + (lane >> 2);
            __nv_bfloat16* p0 = C3 + r0 * (long)ldc;
            __nv_bfloat16* p1 = p0 + 8L * ldc;
#pragma unroll
            for (int ni = 0; ni < 8; ni++) {
                long n = n0 + wn + ni * 8 + (lane & 3) * 2;
                float b0 = 0.f, b1 = 0.f;
                if (hasBias) { b0 = Bias[biasOff + n]; b1 = Bias[biasOff + n + 1]; }
                float v0 = acc[mi][ni][0] + b0, v1 = acc[mi][ni][1] + b1;
                float v2 = acc[mi][ni][2] + b0, v3 = acc[mi][ni][3] + b1;
                if (relu) {
                    v0 = fmaxf(v0, 0.f); v1 = fmaxf(v1, 0.f);
                    v2 = fmaxf(v2, 0.f); v3 = fmaxf(v3, 0.f);
                }
                __nv_bfloat162 hiA, loA, hiB, loB;
                split2(v0, v1, hiA, loA);
                split2(v2, v3, hiB, loB);
                *(__nv_bfloat162*)(p0 + n)      = hiA;
                *(__nv_bfloat162*)(p0 + n + d1) = patB ? loA : hiA;
                *(__nv_bfloat162*)(p0 + n + d2) = patB ? hiA : loA;
                *(__nv_bfloat162*)(p1 + n)      = hiB;
                *(__nv_bfloat162*)(p1 + n + d1) = patB ? loB : hiB;
                *(__nv_bfloat162*)(p1 + n + d2) = patB ? hiB : loB;
            }
        }
    }
}

// ---------------------------------------------------------------------------
// Host dispatch
// ---------------------------------------------------------------------------
static void tg(int epi, const __nv_bfloat16* A, const __nv_bfloat16* B, const float* Bias,
               void* C, int M, int N, int K3, int lda, int ldb, int ldc,
               long sAb, long sAh, long sBb, long sBh, long sCb, long sCh,
               long sBiB, long sBiH, int Hn, int Z, int d1 = 0, int d2 = 0)
{
    dim3 g(M / GBM, (N + GBN - 1) / GBN, Z), b(256);
#define HG_CALL(E) hgemm_kernel<E><<<g, b, HG_SMEM>>>(A, B, Bias, C, N, K3, lda, ldb, ldc, \
    sAb, sAh, sBb, sBh, sCb, sCh, sBiB, sBiH, Hn, d1, d2)
    switch (epi) {
    case 0: HG_CALL(0); break;
    case 1: HG_CALL(1); break;
    case 2: HG_CALL(2); break;
    case 3: HG_CALL(3); break;
    case 4: HG_CALL(4); break;
    case 5: HG_CALL(5); break;
    default: HG_CALL(6); break;
    }
#undef HG_CALL
}

extern "C" void kernel_launch(void* const* d_in, const int* in_sizes, int n_in,
                              void* d_out, int out_size)
{
    const float* enc    = (const float*)d_in[0];
    const int*   srcpad = (const int*)  d_in[1];
    const int*   target = (const int*)  d_in[2];
    const float* emb    = (const float*)d_in[3];
    const float* Wq1 = (const float*)d_in[4],  *bq1 = (const float*)d_in[5];
    const float* Wk1 = (const float*)d_in[6],  *bk1 = (const float*)d_in[7];
    const float* Wv1 = (const float*)d_in[8],  *bv1 = (const float*)d_in[9];
    const float* Wo1 = (const float*)d_in[10], *bo1 = (const float*)d_in[11];
    const float* Wq2 = (const float*)d_in[12], *bq2 = (const float*)d_in[13];
    const float* Wk2 = (const float*)d_in[14], *bk2 = (const float*)d_in[15];
    const float* Wv2 = (const float*)d_in[16], *bv2 = (const float*)d_in[17];
    const float* Wo2 = (const float*)d_in[18], *bo2 = (const float*)d_in[19];
    const float* ln1g = (const float*)d_in[20];
    const float* ln2g = (const float*)d_in[21];
    const float* ln3g = (const float*)d_in[22];
    const float* ln1b = (const float*)d_in[23];
    const float* ln2b = (const float*)d_in[24];
    const float* ln3b = (const float*)d_in[25];
    const float* Wf1 = (const float*)d_in[26], *bf1 = (const float*)d_in[27];
    const float* Wf2 = (const float*)d_in[28], *bf2 = (const float*)d_in[29];
    const float* lmW = (const float*)d_in[30], *lmb = (const float*)d_in[31];
    float* out = (float*)d_out;

    float *x, *vv, *ss, *tt, *part;
    cudaGetSymbolAddress((void**)&x,  g_x);
    cudaGetSymbolAddress((void**)&vv, g_v);
    cudaGetSymbolAddress((void**)&ss, g_s);
    cudaGetSymbolAddress((void**)&tt, g_t);
    cudaGetSymbolAddress((void**)&part, g_part);
    __nv_bfloat16 *x3, *e3, *q3, *k3, *v3, *s3, *o3, *f3, *w3, *lm3;
    cudaGetSymbolAddress((void**)&x3, g_x3);
    cudaGetSymbolAddress((void**)&e3, g_e3);
    cudaGetSymbolAddress((void**)&q3, g_q3);
    cudaGetSymbolAddress((void**)&k3, g_k3);
    cudaGetSymbolAddress((void**)&v3, g_v3);
    cudaGetSymbolAddress((void**)&s3, g_s3);
    cudaGetSymbolAddress((void**)&o3, g_o3);
    cudaGetSymbolAddress((void**)&f3, g_f3);
    cudaGetSymbolAddress((void**)&w3, g_w3);
    cudaGetSymbolAddress((void**)&lm3, g_lm3);

    cudaFuncSetAttribute(hgemm_kernel<0>, cudaFuncAttributeMaxDynamicSharedMemorySize, HG_SMEM);
    cudaFuncSetAttribute(hgemm_kernel<1>, cudaFuncAttributeMaxDynamicSharedMemorySize, HG_SMEM);
    cudaFuncSetAttribute(hgemm_kernel<2>, cudaFuncAttributeMaxDynamicSharedMemorySize, HG_SMEM);
    cudaFuncSetAttribute(hgemm_kernel<3>, cudaFuncAttributeMaxDynamicSharedMemorySize, HG_SMEM);
    cudaFuncSetAttribute(hgemm_kernel<4>, cudaFuncAttributeMaxDynamicSharedMemorySize, HG_SMEM);
    cudaFuncSetAttribute(hgemm_kernel<5>, cudaFuncAttributeMaxDynamicSharedMemorySize, HG_SMEM);
    cudaFuncSetAttribute(hgemm_kernel<6>, cudaFuncAttributeMaxDynamicSharedMemorySize, HG_SMEM);

    const float scale = 1.0f / sqrtf((float)Dm);
    const long WATT = (long)Hh * Dm * Dm;
    const long WOUT = (long)HD * Dm;
    const long WFF  = (long)Dm * FFd;
    const dim3 tb(32, 8);

    embed_pe_kernel<<<NR, 512>>>(target, emb, x, x3);
    conv_enc_kernel<<<NR, 256>>>(enc, e3);

    for (int l = 0; l < 2; l++) {
        const float *WQ[2] = {Wq1 + l * WATT, Wq2 + l * WATT};
        const float *WK[2] = {Wk1 + l * WATT, Wk2 + l * WATT};
        const float *WV[2] = {Wv1 + l * WATT, Wv2 + l * WATT};
        const float *WO[2] = {Wo1 + l * WOUT, Wo2 + l * WOUT};
        const float *BQ[2] = {bq1 + l * HD, bq2 + l * HD};
        const float *BK[2] = {bk1 + l * HD, bk2 + l * HD};
        const float *BV[2] = {bv1 + l * HD, bv2 + l * HD};
        const float *BO[2] = {bo1 + l * Dm, bo2 + l * Dm};
        const float *LG[2] = {ln1g + l * Dm, ln2g + l * Dm};
        const float *LB[2] = {ln1b + l * Dm, ln2b + l * Dm};

        for (int att = 0; att < 2; att++) {
            const __nv_bfloat16* kvA = (att == 0) ? x3 : e3;

            conv_t_kernel<<<dim3(16, 16, 8), tb>>>(WQ[att], w3, Dm, Dm, Dm, 1536,
                                                   0, (long)Dm * Dm, 0, (long)Dm * 1536, 8);
            tg(3, x3, w3, BQ[att], q3, NR, Dm, 1536, 1536, 1536, 12288,
               0, 0, 0, (long)Dm * 1536, 0, 1536, 0, Dm, 8, 8, 512, 1024);

            conv_t_kernel<<<dim3(16, 16, 8), tb>>>(WK[att], w3, Dm, Dm, Dm, 1536,
                                                   0, (long)Dm * Dm, 0, (long)Dm * 1536, 8);
            tg(4, kvA, w3, BK[att], k3, NR, Dm, 1536, 1536, 1536, 12288,
               0, 0, 0, (long)Dm * 1536, 0, 1536, 0, Dm, 8, 8, 512, 1024);

            conv_t_kernel<<<dim3(16, 16, 8), tb>>>(WV[att], w3, Dm, Dm, Dm, 1536,
                                                   0, (long)Dm * Dm, 0, (long)Dm * 1536, 8);
            tg(1, kvA, w3, BV[att], vv, NR, Dm, 1536, 1536, 1536, HD,
               0, 0, 0, (long)Dm * 1536, 0, Dm, 0, Dm, 8, 8);
            conv_t_kernel<<<dim3(16, 16, 32), tb>>>(vv, v3, TSs, Dm, HD, 1536,
                                                    (long)TSs * HD, Dm,
                                                    (long)Hh * TSs * 1536, (long)TSs * 1536, 8);

            tg(0, q3, k3, nullptr, ss, TTq, TSs, 1536, 12288, 12288, TSs,
               (long)TTq * 12288, 1536, (long)TSs * 12288, 1536,
               (long)Hh * TTq * TSs, (long)TTq * TSs, 0, 0, 8, 32);

            softmax_kernel<<<Bq * Hh * TTq, 256>>>(ss, s3, target, srcpad,
                                                   att == 0 ? 1 : 2, scale);
            if (att == 1 && l == 0 && (long)out_size >= LOGITS_ELEMS + ATT_ELEMS) {
                cudaMemcpyAsync(out + LOGITS_ELEMS, ss, ATT_ELEMS * sizeof(float),
                                cudaMemcpyDeviceToDevice, 0);
            }

            tg(5, s3, v3, nullptr, o3, TTq, Dm, 1536, 1536, 1536, 12288,
               (long)Hh * TTq * 1536, (long)TTq * 1536,
               (long)Hh * TSs * 1536, (long)TSs * 1536,
               (long)TTq * 12288, 512, 0, 0, 8, 32, 4096, 8192);

            // ---- output projection: split-K=8 over K3=12288 (chunk 1536) ----
            conv_t_kernel<<<dim3(16, 128, 1), tb>>>(WO[att], w3, HD, Dm, Dm, 12288,
                                                    0, 0, 0, 0, 1);
            tg(0, o3, w3, nullptr, part, NR, Dm, 1536, 12288, 12288, Dm,
               0, 1536, 0, 1536, 0, (long)NR * Dm, 0, 0, SKn, SKn);
            reduce_sk_kernel<<<NR * Dm / 1024, 256>>>(part, BO[att], tt);
            add_ln_kernel<<<NR, 256>>>(x, tt, LG[att], LB[att], x, x3);
        }

        conv_t_kernel<<<dim3(64, 16, 1), tb>>>(Wf1 + l * WFF, w3, Dm, FFd, FFd, 1536,
                                               0, 0, 0, 0, 1);
        tg(6, x3, w3, bf1 + l * FFd, f3, NR, FFd, 1536, 1536, 1536, 6144,
           0, 0, 0, 0, 0, 0, 0, 0, 1, 1, 2048, 4096);

        // ---- FF2: split-K=8 over K3=6144 (chunk 768) ----
        conv_t_kernel<<<dim3(16, 64, 1), tb>>>(Wf2 + l * WFF, w3, FFd, Dm, Dm, 6144,
                                               0, 0, 0, 0, 1);
        tg(0, f3, w3, nullptr, part, NR, Dm, 768, 6144, 6144, Dm,
           0, 768, 0, 768, 0, (long)NR * Dm, 0, 0, SKn, SKn);
        reduce_sk_kernel<<<NR * Dm / 1024, 256>>>(part, bf2 + l * Dm, tt);
        add_ln_kernel<<<NR, 256>>>(x, tt, ln3g + l * Dm, ln3b + l * Dm, x, x3);
    }

    conv_t_kernel<<<dim3(1001, 16, 1), tb>>>(lmW, lm3, Dm, VO, VO, 1536, 0, 0, 0, 0, 1);
    tg(1, x3, lm3, lmb, out, NR, VO, 1536, 1536, 1536, VO,
       0, 0, 0, 0, 0, 0, 0, 0, 1, 1);
}

// round 8
// speedup vs baseline: 3.7061x; 1.4325x over previous
#include <cuda_runtime.h>
#include <cuda_fp16.h>
#include <math.h>
#include <stdint.h>

// ---------------------------------------------------------------------------
// Problem constants
// ---------------------------------------------------------------------------
#define Bq   4
#define TTq  512
#define TSs  512
#define Dm   512
#define Hh   8
#define Vv   32000
#define VO   32001
#define NR   2048
#define HD   4096
#define FFd  2048
#define SKn  8

#define LOGITS_ELEMS (2048LL * 32001LL)
#define ATT_ELEMS    (4LL * 8 * 512 * 512)

// ---------------------------------------------------------------------------
// Scratch (static device globals)
// ---------------------------------------------------------------------------
__device__ float g_x [NR * Dm];
__device__ float g_v [NR * HD];
__device__ float g_s [Bq * Hh * TTq * TSs];
__device__ float g_t [NR * Dm];
__device__ float g_part[SKn * NR * Dm];

// fp16 hi/lo doubles: patA = [hi|lo] (full value), patB = [hi|hi] (rounded)
__device__ __half g_xh [NR * 1024];
__device__ __half g_eh [NR * 1024];
__device__ __half g_qh [NR * 8192];
__device__ __half g_kh [NR * 8192];
__device__ __half g_vh [32 * 512 * 1024];
__device__ __half g_sh [32 * 512 * 1024];
__device__ __half g_oh [NR * 8192];
__device__ __half g_fh [NR * 4096];
__device__ __half g_wh [512 * 8192];
__device__ __half g_lmh[32256 * 1024];   // rows padded to 126*256; pads stay 0

// ---------------------------------------------------------------------------
// fp16 hi/lo split helper
// ---------------------------------------------------------------------------
__device__ __forceinline__ void split2(float v0, float v1, __half2& hi, __half2& lo)
{
    __half h0 = __float2half(v0), h1 = __float2half(v1);
    hi = __halves2half2(h0, h1);
    lo = __halves2half2(__float2half(v0 - __half2float(h0)),
                        __float2half(v1 - __half2float(h1)));
}

// ---------------------------------------------------------------------------
// Embedding + positional encoding -> x (fp32) and xh (patA)
// ---------------------------------------------------------------------------
__global__ void embed_pe_kernel(const int* __restrict__ target,
                                const float* __restrict__ emb,
                                float* __restrict__ x,
                                __half* __restrict__ xh)
{
    int row = blockIdx.x;
    int t   = row & (TTq - 1);
    int d   = threadIdx.x;
    int tok = target[row];
    float e = emb[(long)tok * Dm + d];
    int   i = d >> 1;
    float denom = powf(10000.0f, (2.0f * (float)i) / (float)Dm);
    float z = (float)t / denom;
    float p = (d & 1) ? cosf(z) : sinf(z);
    float v = e + p;
    x[(long)row * Dm + d] = v;
    __half h = __float2half(v);
    __half l = __float2half(v - __half2float(h));
    __half* ob = xh + (long)row * 1024 + d;
    ob[0] = h; ob[512] = l;
}

// ---------------------------------------------------------------------------
// enc fp32 -> eh (patA)
// ---------------------------------------------------------------------------
__global__ void conv_enc_kernel(const float* __restrict__ in, __half* __restrict__ out)
{
    long idx = (long)blockIdx.x * blockDim.x + threadIdx.x;
    long r = idx >> 8;
    long k = (idx & 255) * 2;
    const float* p = in + r * Dm + k;
    __half2 hi, lo;
    split2(p[0], p[1], hi, lo);
    __half* ob = out + r * 1024 + k;
    *(__half2*)(ob)       = hi;
    *(__half2*)(ob + 512) = lo;
}

// ---------------------------------------------------------------------------
// Masked softmax: writes normalized fp32 AND sh (patA).
// ---------------------------------------------------------------------------
__global__ void softmax_kernel(float* __restrict__ S, __half* __restrict__ Sh,
                               const int* __restrict__ target,
                               const int* __restrict__ srcpad,
                               int mode, float scale)
{
    int row = blockIdx.x;
    int q   = row & (TTq - 1);
    int b   = row / (Hh * TTq);
    float* s = S + (long)row * TSs;
    int tid = threadIdx.x;
    bool qpad = (target[b * TTq + q] != Vv);

    float v[2];
    float mx = -INFINITY;
#pragma unroll
    for (int e = 0; e < 2; e++) {
        int k = tid + e * 256;
        bool valid;
        if (mode == 1)
            valid = qpad && (k <= q) && (target[b * TTq + k] != Vv);
        else
            valid = qpad && (srcpad[b * TSs + k] != 0);
        float val = valid ? s[k] * scale : -1e32f;
        v[e] = val;
        mx = fmaxf(mx, val);
    }

    __shared__ float red[8];
#pragma unroll
    for (int o = 16; o > 0; o >>= 1) mx = fmaxf(mx, __shfl_xor_sync(0xffffffffu, mx, o));
    if ((tid & 31) == 0) red[tid >> 5] = mx;
    __syncthreads();
    if (tid < 32) {
        float r = (tid < 8) ? red[tid] : -INFINITY;
#pragma unroll
        for (int o = 4; o > 0; o >>= 1) r = fmaxf(r, __shfl_xor_sync(0xffffffffu, r, o));
        if (tid == 0) red[0] = r;
    }
    __syncthreads();
    mx = red[0];
    __syncthreads();

    float sum = 0.f;
#pragma unroll
    for (int e = 0; e < 2; e++) { v[e] = expf(v[e] - mx); sum += v[e]; }
#pragma unroll
    for (int o = 16; o > 0; o >>= 1) sum += __shfl_xor_sync(0xffffffffu, sum, o);
    if ((tid & 31) == 0) red[tid >> 5] = sum;
    __syncthreads();
    if (tid < 32) {
        float r = (tid < 8) ? red[tid] : 0.f;
#pragma unroll
        for (int o = 4; o > 0; o >>= 1) r += __shfl_xor_sync(0xffffffffu, r, o);
        if (tid == 0) red[0] = r;
    }
    __syncthreads();
    float inv = 1.0f / red[0];
    __half* shr = Sh + (long)row * 1024;
#pragma unroll
    for (int e = 0; e < 2; e++) {
        int k = tid + e * 256;
        float val = v[e] * inv;
        s[k] = val;
        __half h = __float2half(val);
        __half l = __float2half(val - __half2float(h));
        shr[k] = h; shr[k + 512] = l;
    }
}

// ---------------------------------------------------------------------------
// y = LayerNorm(xin + a) * g + b  -> y fp32 and yh (patA)
// ---------------------------------------------------------------------------
__global__ void add_ln_kernel(const float* __restrict__ xin,
                              const float* __restrict__ a,
                              const float* __restrict__ gg,
                              const float* __restrict__ bb,
                              float* __restrict__ y,
                              __half* __restrict__ yh)
{
    int row = blockIdx.x;
    int tid = threadIdx.x;
    long base = (long)row * Dm;
    __shared__ float red[8];

    float v[2];
    float sum = 0.f;
#pragma unroll
    for (int e = 0; e < 2; e++) {
        int d = tid + e * 256;
        v[e] = xin[base + d] + a[base + d];
        sum += v[e];
    }
#pragma unroll
    for (int o = 16; o > 0; o >>= 1) sum += __shfl_xor_sync(0xffffffffu, sum, o);
    if ((tid & 31) == 0) red[tid >> 5] = sum;
    __syncthreads();
    if (tid < 32) {
        float r = (tid < 8) ? red[tid] : 0.f;
#pragma unroll
        for (int o = 4; o > 0; o >>= 1) r += __shfl_xor_sync(0xffffffffu, r, o);
        if (tid == 0) red[0] = r;
    }
    __syncthreads();
    float m = red[0] * (1.0f / (float)Dm);
    __syncthreads();

    float vs = 0.f;
#pragma unroll
    for (int e = 0; e < 2; e++) { float c = v[e] - m; vs += c * c; }
#pragma unroll
    for (int o = 16; o > 0; o >>= 1) vs += __shfl_xor_sync(0xffffffffu, vs, o);
    if ((tid & 31) == 0) red[tid >> 5] = vs;
    __syncthreads();
    if (tid < 32) {
        float r = (tid < 8) ? red[tid] : 0.f;
#pragma unroll
        for (int o = 4; o > 0; o >>= 1) r += __shfl_xor_sync(0xffffffffu, r, o);
        if (tid == 0) red[0] = r;
    }
    __syncthreads();
    float var = red[0] * (1.0f / (float)Dm);
    float rs = rsqrtf(var + 1e-5f);
    __half* yhr = yh + (long)row * 1024;
#pragma unroll
    for (int e = 0; e < 2; e++) {
        int d = tid + e * 256;
        float val = (v[e] - m) * rs * gg[d] + bb[d];
        y[base + d] = val;
        __half h = __float2half(val);
        __half l = __float2half(val - __half2float(h));
        yhr[d] = h; yhr[d + 512] = l;
    }
}

// ---------------------------------------------------------------------------
// conv_t: fp32 [K, N] (N-contig) -> fp16 double [N, 2K], patB [hi|hi].
// ---------------------------------------------------------------------------
__global__ void conv_t_kernel(const float* __restrict__ in, __half* __restrict__ out,
                              int K, int N, int in_ld, int out_ld,
                              long sInB, long sInH, long sOutB, long sOutH, int Hn)
{
    __shared__ float t[32][33];
    int z = blockIdx.z, zb = z / Hn, zh = z % Hn;
    in  += zb * sInB + zh * sInH;
    out += zb * sOutB + zh * sOutH;
    int k0 = blockIdx.y * 32, n0 = blockIdx.x * 32;
    int tx = threadIdx.x, ty = threadIdx.y;
#pragma unroll
    for (int i = 0; i < 4; ++i) {
        int k = k0 + ty + i * 8, n = n0 + tx;
        t[ty + i * 8][tx] = (n < N) ? in[(long)k * in_ld + n] : 0.f;
    }
    __syncthreads();
#pragma unroll
    for (int i = 0; i < 4; ++i) {
        int n = n0 + ty + i * 8, k = k0 + tx;
        if (n < N) {
            __half h = __float2half(t[tx][ty + i * 8]);
            __half* o = out + (long)n * out_ld + k;
            o[0] = h;
            o[K] = h;
        }
    }
}

// ---------------------------------------------------------------------------
// split-K reduce: out = sum_c part[c] + bias (row length Dm)
// ---------------------------------------------------------------------------
__global__ void reduce_sk_kernel(const float* __restrict__ part,
                                 const float* __restrict__ bias,
                                 float* __restrict__ outp)
{
    long e = ((long)blockIdx.x * 256 + threadIdx.x) * 4;
    float4 s = make_float4(0.f, 0.f, 0.f, 0.f);
#pragma unroll
    for (int c = 0; c < SKn; c++) {
        float4 v = *(const float4*)(part + (long)c * NR * Dm + e);
        s.x += v.x; s.y += v.y; s.z += v.z; s.w += v.w;
    }
    int d = (int)(e & (Dm - 1));
    s.x += bias[d]; s.y += bias[d + 1]; s.z += bias[d + 2]; s.w += bias[d + 3];
    *(float4*)(outp + e) = s;
}

// ---------------------------------------------------------------------------
// fp16 tensor-core GEMM (mma.sync m16n8k16 f16). CTA 128x256, 8 warps (2x4),
// warp tile 64x64, BK=32, 4-stage cp.async pipeline, one barrier per iter.
// EPI: 0 fp32 | 1 fp32+bias | 2 fp32+bias+relu
//      3 half patA+bias | 4 half patB+bias | 5 half patA | 6 half patA+bias+relu
// Half modes: Cv is __half*; stores hi at +0 and at +d1 lo (patA) / hi (patB).
// ---------------------------------------------------------------------------
#define GBM 128
#define GBN 256
#define GBK 32
#define NSTAGE 4
#define A_BYTES 10240
#define STAGE_BYTES 30720
#define HG_SMEM (NSTAGE * STAGE_BYTES)

__device__ __forceinline__ uint32_t smem_u32(const void* p) {
    uint32_t a;
    asm("{ .reg .u64 t; cvta.to.shared.u64 t, %1; cvt.u32.u64 %0, t; }" : "=r"(a) : "l"(p));
    return a;
}
#define CP16(dst, src) \
    asm volatile("cp.async.cg.shared.global [%0], [%1], 16;" :: "r"(dst), "l"(src))
#define CP_COMMIT() asm volatile("cp.async.commit_group;" ::: "memory")
#define CP_WAIT(n)  asm volatile("cp.async.wait_group %0;" :: "n"(n) : "memory")
#define LDSM_X4(r0, r1, r2, r3, addr) \
    asm volatile("ldmatrix.sync.aligned.m8n8.x4.shared.b16 {%0,%1,%2,%3}, [%4];" \
                 : "=r"(r0), "=r"(r1), "=r"(r2), "=r"(r3) : "r"(addr))
#define MMA_F16(c, a0, a1, a2, a3, b0, b1) \
    asm volatile("mma.sync.aligned.m16n8k16.row.col.f32.f16.f16.f32 " \
                 "{%0,%1,%2,%3}, {%4,%5,%6,%7}, {%8,%9}, {%0,%1,%2,%3};" \
                 : "+f"((c)[0]), "+f"((c)[1]), "+f"((c)[2]), "+f"((c)[3]) \
                 : "r"(a0), "r"(a1), "r"(a2), "r"(a3), "r"(b0), "r"(b1))

template<int EPI>
__global__ void __launch_bounds__(256, 1)
hgemm_kernel(const __half* __restrict__ A2, const __half* __restrict__ B2,
             const float* __restrict__ Bias, void* __restrict__ Cv,
             int Nstore, int K2, int lda, int ldb, int ldc,
             long sAb, long sAh, long sBb, long sBh, long sCb, long sCh,
             long sBiB, long sBiH, int Hn, int d1)
{
    extern __shared__ __align__(16) char dsm[];
    const uint32_t base = smem_u32(dsm);

    int tid = threadIdx.x;
    int wid = tid >> 5, lane = tid & 31;

    int z = blockIdx.z, zb = z / Hn, zh = z % Hn;
    A2 += zb * sAb + zh * sAh;
    B2 += zb * sBb + zh * sBh;
    long cOff = zb * sCb + zh * sCh;
    long biasOff = zb * sBiB + zh * sBiH;

    long m0 = (long)blockIdx.x * GBM;
    long n0 = (long)blockIdx.y * GBN;

    const int wm = (wid >> 2) * 64;
    const int wn = (wid & 3) * 64;

    float acc[4][8][4];
#pragma unroll
    for (int i = 0; i < 4; i++)
#pragma unroll
        for (int j = 0; j < 8; j++)
#pragma unroll
            for (int q = 0; q < 4; q++) acc[i][j][q] = 0.f;

    const int nIter = K2 / GBK;

    const int lr  = tid >> 2;
    const int lsg = tid & 3;
    const long aRow0 = m0 + lr,  aRow1 = m0 + lr + 64;
    const uint32_t sOff0 = (uint32_t)(lr * 80 + lsg * 16);
    const uint32_t sOff1 = (uint32_t)((lr + 64) * 80 + lsg * 16);
    const uint32_t sOff2 = (uint32_t)((lr + 128) * 80 + lsg * 16);
    const uint32_t sOff3 = (uint32_t)((lr + 192) * 80 + lsg * 16);

    auto loadStage = [&](int slot, long k0) {
        uint32_t aD = base + slot * STAGE_BYTES;
        uint32_t bD = aD + A_BYTES;
        long ko = k0 + lsg * 8;
        CP16(aD + sOff0, A2 + aRow0 * (long)lda + ko);
        CP16(aD + sOff1, A2 + aRow1 * (long)lda + ko);
        CP16(bD + sOff0, B2 + (n0 + lr) * (long)ldb + ko);
        CP16(bD + sOff1, B2 + (n0 + lr + 64) * (long)ldb + ko);
        CP16(bD + sOff2, B2 + (n0 + lr + 128) * (long)ldb + ko);
        CP16(bD + sOff3, B2 + (n0 + lr + 192) * (long)ldb + ko);
        CP_COMMIT();
    };

    loadStage(0, 0);
    if (nIter > 1) loadStage(1, GBK); else CP_COMMIT();
    if (nIter > 2) loadStage(2, 2L * GBK); else CP_COMMIT();

    for (int it = 0; it < nIter; ++it) {
        if (it + 2 < nIter)      CP_WAIT(2);
        else if (it + 1 < nIter) CP_WAIT(1);
        else                     CP_WAIT(0);
        __syncthreads();
        if (it + 3 < nIter) loadStage((it + 3) & (NSTAGE - 1), (long)(it + 3) * GBK);

        uint32_t aS = base + (it & (NSTAGE - 1)) * STAGE_BYTES;
        uint32_t bS = aS + A_BYTES;
#pragma unroll
        for (int ks = 0; ks < 2; ks++) {
            int col = ks * 16 + (lane >> 4) * 8;
            uint32_t a[4][4], bf[8][2];
#pragma unroll
            for (int mi = 0; mi < 4; mi++) {
                int row = wm + mi * 16 + (lane & 15);
                LDSM_X4(a[mi][0], a[mi][1], a[mi][2], a[mi][3],
                        aS + (uint32_t)(row * 80 + col * 2));
            }
#pragma unroll
            for (int p = 0; p < 4; p++) {
                int row = wn + p * 16 + (lane & 15);
                uint32_t r0, r1, r2, r3;
                LDSM_X4(r0, r1, r2, r3, bS + (uint32_t)(row * 80 + col * 2));
                bf[2 * p][0] = r0;     bf[2 * p][1] = r2;
                bf[2 * p + 1][0] = r1; bf[2 * p + 1][1] = r3;
            }
#pragma unroll
            for (int mi = 0; mi < 4; mi++)
#pragma unroll
                for (int ni = 0; ni < 8; ni++)
                    MMA_F16(acc[mi][ni], a[mi][0], a[mi][1], a[mi][2], a[mi][3],
                            bf[ni][0], bf[ni][1]);
        }
    }

    // ---- epilogue ----
    if (EPI <= 2) {
        float* C = (float*)Cv + cOff;
#pragma unroll
        for (int mi = 0; mi < 4; mi++) {
            long mrow = m0 + wm + mi * 16 + (lane >> 2);
            float* c0p = C + mrow * (long)ldc;
            float* c1p = c0p + 8L * ldc;
#pragma unroll
            for (int ni = 0; ni < 8; ni++) {
                long n = n0 + wn + ni * 8 + (lane & 3) * 2;
#pragma unroll
                for (int e = 0; e < 2; e++) {
                    long nn = n + e;
                    if (nn < (long)Nstore) {
                        float v0 = acc[mi][ni][e];
                        float v1 = acc[mi][ni][2 + e];
                        if (EPI >= 1) {
                            float bsv = Bias[biasOff + nn];
                            v0 += bsv; v1 += bsv;
                        }
                        if (EPI == 2) { v0 = fmaxf(v0, 0.f); v1 = fmaxf(v1, 0.f); }
                        c0p[nn] = v0;
                        c1p[nn] = v1;
                    }
                }
            }
        }
    } else {
        __half* C2 = (__half*)Cv + cOff;
        const bool hasBias = (EPI == 3 || EPI == 4 || EPI == 6);
        const bool relu = (EPI == 6);
        const bool patB = (EPI == 4);
#pragma unroll
        for (int mi = 0; mi < 4; mi++) {
            long r0 = m0 + wm + mi * 16 + (lane >> 2);
            __half* p0 = C2 + r0 * (long)ldc;
            __half* p1 = p0 + 8L * ldc;
#pragma unroll
            for (int ni = 0; ni < 8; ni++) {
                long n = n0 + wn + ni * 8 + (lane & 3) * 2;
                float b0 = 0.f, b1 = 0.f;
                if (hasBias) { b0 = Bias[biasOff + n]; b1 = Bias[biasOff + n + 1]; }
                float v0 = acc[mi][ni][0] + b0, v1 = acc[mi][ni][1] + b1;
                float v2 = acc[mi][ni][2] + b0, v3 = acc[mi][ni][3] + b1;
                if (relu) {
                    v0 = fmaxf(v0, 0.f); v1 = fmaxf(v1, 0.f);
                    v2 = fmaxf(v2, 0.f); v3 = fmaxf(v3, 0.f);
                }
                __half2 hiA, loA, hiB, loB;
                split2(v0, v1, hiA, loA);
                split2(v2, v3, hiB, loB);
                *(__half2*)(p0 + n)      = hiA;
                *(__half2*)(p0 + n + d1) = patB ? hiA : loA;
                *(__half2*)(p1 + n)      = hiB;
                *(__half2*)(p1 + n + d1) = patB ? hiB : loB;
            }
        }
    }
}

// ---------------------------------------------------------------------------
// Host dispatch
// ---------------------------------------------------------------------------
static void tg(int epi, const __half* A, const __half* B, const float* Bias,
               void* C, int M, int N, int K2, int lda, int ldb, int ldc,
               long sAb, long sAh, long sBb, long sBh, long sCb, long sCh,
               long sBiB, long sBiH, int Hn, int Z, int d1 = 0)
{
    dim3 g(M / GBM, (N + GBN - 1) / GBN, Z), b(256);
#define HG_CALL(E) hgemm_kernel<E><<<g, b, HG_SMEM>>>(A, B, Bias, C, N, K2, lda, ldb, ldc, \
    sAb, sAh, sBb, sBh, sCb, sCh, sBiB, sBiH, Hn, d1)
    switch (epi) {
    case 0: HG_CALL(0); break;
    case 1: HG_CALL(1); break;
    case 2: HG_CALL(2); break;
    case 3: HG_CALL(3); break;
    case 4: HG_CALL(4); break;
    case 5: HG_CALL(5); break;
    default: HG_CALL(6); break;
    }
#undef HG_CALL
}

extern "C" void kernel_launch(void* const* d_in, const int* in_sizes, int n_in,
                              void* d_out, int out_size)
{
    const float* enc    = (const float*)d_in[0];
    const int*   srcpad = (const int*)  d_in[1];
    const int*   target = (const int*)  d_in[2];
    const float* emb    = (const float*)d_in[3];
    const float* Wq1 = (const float*)d_in[4],  *bq1 = (const float*)d_in[5];
    const float* Wk1 = (const float*)d_in[6],  *bk1 = (const float*)d_in[7];
    const float* Wv1 = (const float*)d_in[8],  *bv1 = (const float*)d_in[9];
    const float* Wo1 = (const float*)d_in[10], *bo1 = (const float*)d_in[11];
    const float* Wq2 = (const float*)d_in[12], *bq2 = (const float*)d_in[13];
    const float* Wk2 = (const float*)d_in[14], *bk2 = (const float*)d_in[15];
    const float* Wv2 = (const float*)d_in[16], *bv2 = (const float*)d_in[17];
    const float* Wo2 = (const float*)d_in[18], *bo2 = (const float*)d_in[19];
    const float* ln1g = (const float*)d_in[20];
    const float* ln2g = (const float*)d_in[21];
    const float* ln3g = (const float*)d_in[22];
    const float* ln1b = (const float*)d_in[23];
    const float* ln2b = (const float*)d_in[24];
    const float* ln3b = (const float*)d_in[25];
    const float* Wf1 = (const float*)d_in[26], *bf1 = (const float*)d_in[27];
    const float* Wf2 = (const float*)d_in[28], *bf2 = (const float*)d_in[29];
    const float* lmW = (const float*)d_in[30], *lmb = (const float*)d_in[31];
    float* out = (float*)d_out;

    float *x, *vv, *ss, *tt, *part;
    cudaGetSymbolAddress((void**)&x,  g_x);
    cudaGetSymbolAddress((void**)&vv, g_v);
    cudaGetSymbolAddress((void**)&ss, g_s);
    cudaGetSymbolAddress((void**)&tt, g_t);
    cudaGetSymbolAddress((void**)&part, g_part);
    __half *xh, *eh, *qh, *kh, *vh, *sh, *oh, *fh, *wh, *lmh;
    cudaGetSymbolAddress((void**)&xh, g_xh);
    cudaGetSymbolAddress((void**)&eh, g_eh);
    cudaGetSymbolAddress((void**)&qh, g_qh);
    cudaGetSymbolAddress((void**)&kh, g_kh);
    cudaGetSymbolAddress((void**)&vh, g_vh);
    cudaGetSymbolAddress((void**)&sh, g_sh);
    cudaGetSymbolAddress((void**)&oh, g_oh);
    cudaGetSymbolAddress((void**)&fh, g_fh);
    cudaGetSymbolAddress((void**)&wh, g_wh);
    cudaGetSymbolAddress((void**)&lmh, g_lmh);

    cudaFuncSetAttribute(hgemm_kernel<0>, cudaFuncAttributeMaxDynamicSharedMemorySize, HG_SMEM);
    cudaFuncSetAttribute(hgemm_kernel<1>, cudaFuncAttributeMaxDynamicSharedMemorySize, HG_SMEM);
    cudaFuncSetAttribute(hgemm_kernel<2>, cudaFuncAttributeMaxDynamicSharedMemorySize, HG_SMEM);
    cudaFuncSetAttribute(hgemm_kernel<3>, cudaFuncAttributeMaxDynamicSharedMemorySize, HG_SMEM);
    cudaFuncSetAttribute(hgemm_kernel<4>, cudaFuncAttributeMaxDynamicSharedMemorySize, HG_SMEM);
    cudaFuncSetAttribute(hgemm_kernel<5>, cudaFuncAttributeMaxDynamicSharedMemorySize, HG_SMEM);
    cudaFuncSetAttribute(hgemm_kernel<6>, cudaFuncAttributeMaxDynamicSharedMemorySize, HG_SMEM);

    const float scale = 1.0f / sqrtf((float)Dm);
    const long WATT = (long)Hh * Dm * Dm;
    const long WOUT = (long)HD * Dm;
    const long WFF  = (long)Dm * FFd;
    const dim3 tb(32, 8);

    embed_pe_kernel<<<NR, 512>>>(target, emb, x, xh);
    conv_enc_kernel<<<NR, 256>>>(enc, eh);

    for (int l = 0; l < 2; l++) {
        const float *WQ[2] = {Wq1 + l * WATT, Wq2 + l * WATT};
        const float *WK[2] = {Wk1 + l * WATT, Wk2 + l * WATT};
        const float *WV[2] = {Wv1 + l * WATT, Wv2 + l * WATT};
        const float *WO[2] = {Wo1 + l * WOUT, Wo2 + l * WOUT};
        const float *BQ[2] = {bq1 + l * HD, bq2 + l * HD};
        const float *BK[2] = {bk1 + l * HD, bk2 + l * HD};
        const float *BV[2] = {bv1 + l * HD, bv2 + l * HD};
        const float *BO[2] = {bo1 + l * Dm, bo2 + l * Dm};
        const float *LG[2] = {ln1g + l * Dm, ln2g + l * Dm};
        const float *LB[2] = {ln1b + l * Dm, ln2b + l * Dm};

        for (int att = 0; att < 2; att++) {
            const __half* kvA = (att == 0) ? xh : eh;

            // ---- Q projection -> qh patA [hi|lo] per head ----
            conv_t_kernel<<<dim3(16, 16, 8), tb>>>(WQ[att], wh, Dm, Dm, Dm, 1024,
                                                   0, (long)Dm * Dm, 0, (long)Dm * 1024, 8);
            tg(3, xh, wh, BQ[att], qh, NR, Dm, 1024, 1024, 1024, 8192,
               0, 0, 0, (long)Dm * 1024, 0, 1024, 0, Dm, 8, 8, 512);

            // ---- K projection -> kh patB [hi|hi] per head ----
            conv_t_kernel<<<dim3(16, 16, 8), tb>>>(WK[att], wh, Dm, Dm, Dm, 1024,
                                                   0, (long)Dm * Dm, 0, (long)Dm * 1024, 8);
            tg(4, kvA, wh, BK[att], kh, NR, Dm, 1024, 1024, 1024, 8192,
               0, 0, 0, (long)Dm * 1024, 0, 1024, 0, Dm, 8, 8, 512);

            // ---- V projection -> vv fp32 -> vh patB (transposed) ----
            conv_t_kernel<<<dim3(16, 16, 8), tb>>>(WV[att], wh, Dm, Dm, Dm, 1024,
                                                   0, (long)Dm * Dm, 0, (long)Dm * 1024, 8);
            tg(1, kvA, wh, BV[att], vv, NR, Dm, 1024, 1024, 1024, HD,
               0, 0, 0, (long)Dm * 1024, 0, Dm, 0, Dm, 8, 8);
            conv_t_kernel<<<dim3(16, 16, 32), tb>>>(vv, vh, TSs, Dm, HD, 1024,
                                                    (long)TSs * HD, Dm,
                                                    (long)Hh * TSs * 1024, (long)TSs * 1024, 8);

            // ---- scores = Q K^T ----
            tg(0, qh, kh, nullptr, ss, TTq, TSs, 1024, 8192, 8192, TSs,
               (long)TTq * 8192, 1024, (long)TSs * 8192, 1024,
               (long)Hh * TTq * TSs, (long)TTq * TSs, 0, 0, 8, 32);

            softmax_kernel<<<Bq * Hh * TTq, 256>>>(ss, sh, target, srcpad,
                                                   att == 0 ? 1 : 2, scale);
            if (att == 1 && l == 0 && (long)out_size >= LOGITS_ELEMS + ATT_ELEMS) {
                cudaMemcpyAsync(out + LOGITS_ELEMS, ss, ATT_ELEMS * sizeof(float),
                                cudaMemcpyDeviceToDevice, 0);
            }

            // ---- O = S V -> oh patA [allhi(4096)|alllo(4096)] ----
            tg(5, sh, vh, nullptr, oh, TTq, Dm, 1024, 1024, 1024, 8192,
               (long)Hh * TTq * 1024, (long)TTq * 1024,
               (long)Hh * TSs * 1024, (long)TSs * 1024,
               (long)TTq * 8192, 512, 0, 0, 8, 32, 4096);

            // ---- output projection: split-K=8 over K2=8192 (chunk 1024) ----
            conv_t_kernel<<<dim3(16, 128, 1), tb>>>(WO[att], wh, HD, Dm, Dm, 8192,
                                                    0, 0, 0, 0, 1);
            tg(0, oh, wh, nullptr, part, NR, Dm, 1024, 8192, 8192, Dm,
               0, 1024, 0, 1024, 0, (long)NR * Dm, 0, 0, SKn, SKn);
            reduce_sk_kernel<<<NR * Dm / 1024, 256>>>(part, BO[att], tt);
            add_ln_kernel<<<NR, 256>>>(x, tt, LG[att], LB[att], x, xh);
        }

        // ---- FFN ----
        conv_t_kernel<<<dim3(64, 16, 1), tb>>>(Wf1 + l * WFF, wh, Dm, FFd, FFd, 1024,
                                               0, 0, 0, 0, 1);
        tg(6, xh, wh, bf1 + l * FFd, fh, NR, FFd, 1024, 1024, 1024, 4096,
           0, 0, 0, 0, 0, 0, 0, 0, 1, 1, 2048);

        // ---- FF2: split-K=8 over K2=4096 (chunk 512) ----
        conv_t_kernel<<<dim3(16, 64, 1), tb>>>(Wf2 + l * WFF, wh, FFd, Dm, Dm, 4096,
                                               0, 0, 0, 0, 1);
        tg(0, fh, wh, nullptr, part, NR, Dm, 512, 4096, 4096, Dm,
           0, 512, 0, 512, 0, (long)NR * Dm, 0, 0, SKn, SKn);
        reduce_sk_kernel<<<NR * Dm / 1024, 256>>>(part, bf2 + l * Dm, tt);
        add_ln_kernel<<<NR, 256>>>(x, tt, ln3g + l * Dm, ln3b + l * Dm, x, xh);
    }

    // ---- LM head (2-way fp16) ----
    conv_t_kernel<<<dim3(1001, 16, 1), tb>>>(lmW, lmh, Dm, VO, VO, 1024, 0, 0, 0, 0, 1);
    tg(1, xh, lmh, lmb, out, NR, VO, 1024, 1024, 1024, VO,
       0, 0, 0, 0, 0, 0, 0, 0, 1, 1);
}

// round 9
// speedup vs baseline: 6.1322x; 1.6546x over previous
#include <cuda_runtime.h>
#include <cuda_fp16.h>
#include <math.h>
#include <stdint.h>

// ---------------------------------------------------------------------------
// Problem constants
// ---------------------------------------------------------------------------
#define Bq   4
#define TTq  512
#define TSs  512
#define Dm   512
#define Hh   8
#define Vv   32000
#define VO   32001
#define NR   2048
#define HD   4096
#define FFd  2048
#define SKn  8

#define LOGITS_ELEMS (2048LL * 32001LL)
#define ATT_ELEMS    (4LL * 8 * 512 * 512)

// ---------------------------------------------------------------------------
// Scratch (static device globals)
// ---------------------------------------------------------------------------
__device__ float g_x [NR * Dm];
__device__ float g_v [NR * HD];
__device__ float g_s [Bq * Hh * TTq * TSs];
__device__ float g_t [NR * Dm];
__device__ float g_part[SKn * NR * Dm];

// plain fp16 operands
__device__ __half g_xh [NR * 512];
__device__ __half g_eh [NR * 512];
__device__ __half g_qh [NR * 4096];
__device__ __half g_kh [NR * 4096];
__device__ __half g_vh [32 * 512 * 512];
__device__ __half g_sh [32 * 512 * 512];
__device__ __half g_oh [NR * 4096];
__device__ __half g_fh [NR * 2048];
__device__ __half g_wh [512 * 4096];
__device__ __half g_lmh[32256 * 512];    // rows padded to 126*256; pads stay 0

// ---------------------------------------------------------------------------
// Embedding + positional encoding -> x (fp32) and xh (fp16)
// ---------------------------------------------------------------------------
__global__ void embed_pe_kernel(const int* __restrict__ target,
                                const float* __restrict__ emb,
                                float* __restrict__ x,
                                __half* __restrict__ xh)
{
    int row = blockIdx.x;
    int t   = row & (TTq - 1);
    int d   = threadIdx.x;
    int tok = target[row];
    float e = emb[(long)tok * Dm + d];
    int   i = d >> 1;
    float denom = powf(10000.0f, (2.0f * (float)i) / (float)Dm);
    float z = (float)t / denom;
    float p = (d & 1) ? cosf(z) : sinf(z);
    float v = e + p;
    x[(long)row * Dm + d] = v;
    xh[(long)row * 512 + d] = __float2half(v);
}

// ---------------------------------------------------------------------------
// enc fp32 -> eh fp16
// ---------------------------------------------------------------------------
__global__ void conv_enc_kernel(const float* __restrict__ in, __half* __restrict__ out)
{
    long idx = (long)blockIdx.x * blockDim.x + threadIdx.x;
    long r = idx >> 8;
    long k = (idx & 255) * 2;
    const float* p = in + r * Dm + k;
    __half2 h = __halves2half2(__float2half(p[0]), __float2half(p[1]));
    *(__half2*)(out + r * 512 + k) = h;
}

// ---------------------------------------------------------------------------
// Masked softmax: writes normalized fp32 AND sh fp16.
// ---------------------------------------------------------------------------
__global__ void softmax_kernel(float* __restrict__ S, __half* __restrict__ Sh,
                               const int* __restrict__ target,
                               const int* __restrict__ srcpad,
                               int mode, float scale)
{
    int row = blockIdx.x;
    int q   = row & (TTq - 1);
    int b   = row / (Hh * TTq);
    float* s = S + (long)row * TSs;
    int tid = threadIdx.x;
    bool qpad = (target[b * TTq + q] != Vv);

    float v[2];
    float mx = -INFINITY;
#pragma unroll
    for (int e = 0; e < 2; e++) {
        int k = tid + e * 256;
        bool valid;
        if (mode == 1)
            valid = qpad && (k <= q) && (target[b * TTq + k] != Vv);
        else
            valid = qpad && (srcpad[b * TSs + k] != 0);
        float val = valid ? s[k] * scale : -1e32f;
        v[e] = val;
        mx = fmaxf(mx, val);
    }

    __shared__ float red[8];
#pragma unroll
    for (int o = 16; o > 0; o >>= 1) mx = fmaxf(mx, __shfl_xor_sync(0xffffffffu, mx, o));
    if ((tid & 31) == 0) red[tid >> 5] = mx;
    __syncthreads();
    if (tid < 32) {
        float r = (tid < 8) ? red[tid] : -INFINITY;
#pragma unroll
        for (int o = 4; o > 0; o >>= 1) r = fmaxf(r, __shfl_xor_sync(0xffffffffu, r, o));
        if (tid == 0) red[0] = r;
    }
    __syncthreads();
    mx = red[0];
    __syncthreads();

    float sum = 0.f;
#pragma unroll
    for (int e = 0; e < 2; e++) { v[e] = expf(v[e] - mx); sum += v[e]; }
#pragma unroll
    for (int o = 16; o > 0; o >>= 1) sum += __shfl_xor_sync(0xffffffffu, sum, o);
    if ((tid & 31) == 0) red[tid >> 5] = sum;
    __syncthreads();
    if (tid < 32) {
        float r = (tid < 8) ? red[tid] : 0.f;
#pragma unroll
        for (int o = 4; o > 0; o >>= 1) r += __shfl_xor_sync(0xffffffffu, r, o);
        if (tid == 0) red[0] = r;
    }
    __syncthreads();
    float inv = 1.0f / red[0];
    __half* shr = Sh + (long)row * 512;
#pragma unroll
    for (int e = 0; e < 2; e++) {
        int k = tid + e * 256;
        float val = v[e] * inv;
        s[k] = val;
        shr[k] = __float2half(val);
    }
}

// ---------------------------------------------------------------------------
// y = LayerNorm(xin + a) * g + b  -> y fp32 and yh fp16
// ---------------------------------------------------------------------------
__global__ void add_ln_kernel(const float* __restrict__ xin,
                              const float* __restrict__ a,
                              const float* __restrict__ gg,
                              const float* __restrict__ bb,
                              float* __restrict__ y,
                              __half* __restrict__ yh)
{
    int row = blockIdx.x;
    int tid = threadIdx.x;
    long base = (long)row * Dm;
    __shared__ float red[8];

    float v[2];
    float sum = 0.f;
#pragma unroll
    for (int e = 0; e < 2; e++) {
        int d = tid + e * 256;
        v[e] = xin[base + d] + a[base + d];
        sum += v[e];
    }
#pragma unroll
    for (int o = 16; o > 0; o >>= 1) sum += __shfl_xor_sync(0xffffffffu, sum, o);
    if ((tid & 31) == 0) red[tid >> 5] = sum;
    __syncthreads();
    if (tid < 32) {
        float r = (tid < 8) ? red[tid] : 0.f;
#pragma unroll
        for (int o = 4; o > 0; o >>= 1) r += __shfl_xor_sync(0xffffffffu, r, o);
        if (tid == 0) red[0] = r;
    }
    __syncthreads();
    float m = red[0] * (1.0f / (float)Dm);
    __syncthreads();

    float vs = 0.f;
#pragma unroll
    for (int e = 0; e < 2; e++) { float c = v[e] - m; vs += c * c; }
#pragma unroll
    for (int o = 16; o > 0; o >>= 1) vs += __shfl_xor_sync(0xffffffffu, vs, o);
    if ((tid & 31) == 0) red[tid >> 5] = vs;
    __syncthreads();
    if (tid < 32) {
        float r = (tid < 8) ? red[tid] : 0.f;
#pragma unroll
        for (int o = 4; o > 0; o >>= 1) r += __shfl_xor_sync(0xffffffffu, r, o);
        if (tid == 0) red[0] = r;
    }
    __syncthreads();
    float var = red[0] * (1.0f / (float)Dm);
    float rs = rsqrtf(var + 1e-5f);
    __half* yhr = yh + (long)row * 512;
#pragma unroll
    for (int e = 0; e < 2; e++) {
        int d = tid + e * 256;
        float val = (v[e] - m) * rs * gg[d] + bb[d];
        y[base + d] = val;
        yhr[d] = __float2half(val);
    }
}

// ---------------------------------------------------------------------------
// conv_t: fp32 [K, N] (N-contig) -> fp16 [N, K] transposed.
// ---------------------------------------------------------------------------
__global__ void conv_t_kernel(const float* __restrict__ in, __half* __restrict__ out,
                              int K, int N, int in_ld, int out_ld,
                              long sInB, long sInH, long sOutB, long sOutH, int Hn)
{
    __shared__ float t[32][33];
    int z = blockIdx.z, zb = z / Hn, zh = z % Hn;
    in  += zb * sInB + zh * sInH;
    out += zb * sOutB + zh * sOutH;
    int k0 = blockIdx.y * 32, n0 = blockIdx.x * 32;
    int tx = threadIdx.x, ty = threadIdx.y;
#pragma unroll
    for (int i = 0; i < 4; ++i) {
        int k = k0 + ty + i * 8, n = n0 + tx;
        t[ty + i * 8][tx] = (n < N) ? in[(long)k * in_ld + n] : 0.f;
    }
    __syncthreads();
#pragma unroll
    for (int i = 0; i < 4; ++i) {
        int n = n0 + ty + i * 8, k = k0 + tx;
        if (n < N)
            out[(long)n * out_ld + k] = __float2half(t[tx][ty + i * 8]);
    }
}

// ---------------------------------------------------------------------------
// split-K reduce: out = sum_c part[c] + bias (row length Dm)
// ---------------------------------------------------------------------------
__global__ void reduce_sk_kernel(const float* __restrict__ part,
                                 const float* __restrict__ bias,
                                 float* __restrict__ outp)
{
    long e = ((long)blockIdx.x * 256 + threadIdx.x) * 4;
    float4 s = make_float4(0.f, 0.f, 0.f, 0.f);
#pragma unroll
    for (int c = 0; c < SKn; c++) {
        float4 v = *(const float4*)(part + (long)c * NR * Dm + e);
        s.x += v.x; s.y += v.y; s.z += v.z; s.w += v.w;
    }
    int d = (int)(e & (Dm - 1));
    s.x += bias[d]; s.y += bias[d + 1]; s.z += bias[d + 2]; s.w += bias[d + 3];
    *(float4*)(outp + e) = s;
}

// ---------------------------------------------------------------------------
// fp16 tensor-core GEMM (mma.sync m16n8k16 f16). CTA 128x256, 8 warps (2x4),
// warp tile 64x64, BK=32, 4-stage cp.async pipeline, one barrier per iter.
// EPI: 0 fp32 | 1 fp32+bias | 2 fp32+bias+relu
//      3 half+bias | 5 half | 6 half+bias+relu
// ---------------------------------------------------------------------------
#define GBM 128
#define GBN 256
#define GBK 32
#define NSTAGE 4
#define A_BYTES 10240
#define STAGE_BYTES 30720
#define HG_SMEM (NSTAGE * STAGE_BYTES)

__device__ __forceinline__ uint32_t smem_u32(const void* p) {
    uint32_t a;
    asm("{ .reg .u64 t; cvta.to.shared.u64 t, %1; cvt.u32.u64 %0, t; }" : "=r"(a) : "l"(p));
    return a;
}
#define CP16(dst, src) \
    asm volatile("cp.async.cg.shared.global [%0], [%1], 16;" :: "r"(dst), "l"(src))
#define CP_COMMIT() asm volatile("cp.async.commit_group;" ::: "memory")
#define CP_WAIT(n)  asm volatile("cp.async.wait_group %0;" :: "n"(n) : "memory")
#define LDSM_X4(r0, r1, r2, r3, addr) \
    asm volatile("ldmatrix.sync.aligned.m8n8.x4.shared.b16 {%0,%1,%2,%3}, [%4];" \
                 : "=r"(r0), "=r"(r1), "=r"(r2), "=r"(r3) : "r"(addr))
#define MMA_F16(c, a0, a1, a2, a3, b0, b1) \
    asm volatile("mma.sync.aligned.m16n8k16.row.col.f32.f16.f16.f32 " \
                 "{%0,%1,%2,%3}, {%4,%5,%6,%7}, {%8,%9}, {%0,%1,%2,%3};" \
                 : "+f"((c)[0]), "+f"((c)[1]), "+f"((c)[2]), "+f"((c)[3]) \
                 : "r"(a0), "r"(a1), "r"(a2), "r"(a3), "r"(b0), "r"(b1))

template<int EPI>
__global__ void __launch_bounds__(256, 1)
hgemm_kernel(const __half* __restrict__ A2, const __half* __restrict__ B2,
             const float* __restrict__ Bias, void* __restrict__ Cv,
             int Nstore, int Kd, int lda, int ldb, int ldc,
             long sAb, long sAh, long sBb, long sBh, long sCb, long sCh,
             long sBiB, long sBiH, int Hn)
{
    extern __shared__ __align__(16) char dsm[];
    const uint32_t base = smem_u32(dsm);

    int tid = threadIdx.x;
    int wid = tid >> 5, lane = tid & 31;

    int z = blockIdx.z, zb = z / Hn, zh = z % Hn;
    A2 += zb * sAb + zh * sAh;
    B2 += zb * sBb + zh * sBh;
    long cOff = zb * sCb + zh * sCh;
    long biasOff = zb * sBiB + zh * sBiH;

    long m0 = (long)blockIdx.x * GBM;
    long n0 = (long)blockIdx.y * GBN;

    const int wm = (wid >> 2) * 64;
    const int wn = (wid & 3) * 64;

    float acc[4][8][4];
#pragma unroll
    for (int i = 0; i < 4; i++)
#pragma unroll
        for (int j = 0; j < 8; j++)
#pragma unroll
            for (int q = 0; q < 4; q++) acc[i][j][q] = 0.f;

    const int nIter = Kd / GBK;

    const int lr  = tid >> 2;
    const int lsg = tid & 3;
    const long aRow0 = m0 + lr,  aRow1 = m0 + lr + 64;
    const uint32_t sOff0 = (uint32_t)(lr * 80 + lsg * 16);
    const uint32_t sOff1 = (uint32_t)((lr + 64) * 80 + lsg * 16);
    const uint32_t sOff2 = (uint32_t)((lr + 128) * 80 + lsg * 16);
    const uint32_t sOff3 = (uint32_t)((lr + 192) * 80 + lsg * 16);

    auto loadStage = [&](int slot, long k0) {
        uint32_t aD = base + slot * STAGE_BYTES;
        uint32_t bD = aD + A_BYTES;
        long ko = k0 + lsg * 8;
        CP16(aD + sOff0, A2 + aRow0 * (long)lda + ko);
        CP16(aD + sOff1, A2 + aRow1 * (long)lda + ko);
        CP16(bD + sOff0, B2 + (n0 + lr) * (long)ldb + ko);
        CP16(bD + sOff1, B2 + (n0 + lr + 64) * (long)ldb + ko);
        CP16(bD + sOff2, B2 + (n0 + lr + 128) * (long)ldb + ko);
        CP16(bD + sOff3, B2 + (n0 + lr + 192) * (long)ldb + ko);
        CP_COMMIT();
    };

    loadStage(0, 0);
    if (nIter > 1) loadStage(1, GBK); else CP_COMMIT();
    if (nIter > 2) loadStage(2, 2L * GBK); else CP_COMMIT();

    for (int it = 0; it < nIter; ++it) {
        if (it + 2 < nIter)      CP_WAIT(2);
        else if (it + 1 < nIter) CP_WAIT(1);
        else                     CP_WAIT(0);
        __syncthreads();
        if (it + 3 < nIter) loadStage((it + 3) & (NSTAGE - 1), (long)(it + 3) * GBK);

        uint32_t aS = base + (it & (NSTAGE - 1)) * STAGE_BYTES;
        uint32_t bS = aS + A_BYTES;
#pragma unroll
        for (int ks = 0; ks < 2; ks++) {
            int col = ks * 16 + (lane >> 4) * 8;
            uint32_t a[4][4], bf[8][2];
#pragma unroll
            for (int mi = 0; mi < 4; mi++) {
                int row = wm + mi * 16 + (lane & 15);
                LDSM_X4(a[mi][0], a[mi][1], a[mi][2], a[mi][3],
                        aS + (uint32_t)(row * 80 + col * 2));
            }
#pragma unroll
            for (int p = 0; p < 4; p++) {
                int row = wn + p * 16 + (lane & 15);
                uint32_t r0, r1, r2, r3;
                LDSM_X4(r0, r1, r2, r3, bS + (uint32_t)(row * 80 + col * 2));
                bf[2 * p][0] = r0;     bf[2 * p][1] = r2;
                bf[2 * p + 1][0] = r1; bf[2 * p + 1][1] = r3;
            }
#pragma unroll
            for (int mi = 0; mi < 4; mi++)
#pragma unroll
                for (int ni = 0; ni < 8; ni++)
                    MMA_F16(acc[mi][ni], a[mi][0], a[mi][1], a[mi][2], a[mi][3],
                            bf[ni][0], bf[ni][1]);
        }
    }

    // ---- epilogue ----
    if (EPI <= 2) {
        float* C = (float*)Cv + cOff;
#pragma unroll
        for (int mi = 0; mi < 4; mi++) {
            long mrow = m0 + wm + mi * 16 + (lane >> 2);
            float* c0p = C + mrow * (long)ldc;
            float* c1p = c0p + 8L * ldc;
#pragma unroll
            for (int ni = 0; ni < 8; ni++) {
                long n = n0 + wn + ni * 8 + (lane & 3) * 2;
#pragma unroll
                for (int e = 0; e < 2; e++) {
                    long nn = n + e;
                    if (nn < (long)Nstore) {
                        float v0 = acc[mi][ni][e];
                        float v1 = acc[mi][ni][2 + e];
                        if (EPI >= 1) {
                            float bsv = Bias[biasOff + nn];
                            v0 += bsv; v1 += bsv;
                        }
                        if (EPI == 2) { v0 = fmaxf(v0, 0.f); v1 = fmaxf(v1, 0.f); }
                        c0p[nn] = v0;
                        c1p[nn] = v1;
                    }
                }
            }
        }
    } else {
        __half* C2 = (__half*)Cv + cOff;
        const bool hasBias = (EPI == 3 || EPI == 6);
        const bool relu = (EPI == 6);
#pragma unroll
        for (int mi = 0; mi < 4; mi++) {
            long r0 = m0 + wm + mi * 16 + (lane >> 2);
            __half* p0 = C2 + r0 * (long)ldc;
            __half* p1 = p0 + 8L * ldc;
#pragma unroll
            for (int ni = 0; ni < 8; ni++) {
                long n = n0 + wn + ni * 8 + (lane & 3) * 2;
                float b0 = 0.f, b1 = 0.f;
                if (hasBias) { b0 = Bias[biasOff + n]; b1 = Bias[biasOff + n + 1]; }
                float v0 = acc[mi][ni][0] + b0, v1 = acc[mi][ni][1] + b1;
                float v2 = acc[mi][ni][2] + b0, v3 = acc[mi][ni][3] + b1;
                if (relu) {
                    v0 = fmaxf(v0, 0.f); v1 = fmaxf(v1, 0.f);
                    v2 = fmaxf(v2, 0.f); v3 = fmaxf(v3, 0.f);
                }
                *(__half2*)(p0 + n) = __halves2half2(__float2half(v0), __float2half(v1));
                *(__half2*)(p1 + n) = __halves2half2(__float2half(v2), __float2half(v3));
            }
        }
    }
}

// ---------------------------------------------------------------------------
// Host dispatch
// ---------------------------------------------------------------------------
static void tg(int epi, const __half* A, const __half* B, const float* Bias,
               void* C, int M, int N, int Kd, int lda, int ldb, int ldc,
               long sAb, long sAh, long sBb, long sBh, long sCb, long sCh,
               long sBiB, long sBiH, int Hn, int Z)
{
    dim3 g(M / GBM, (N + GBN - 1) / GBN, Z), b(256);
#define HG_CALL(E) hgemm_kernel<E><<<g, b, HG_SMEM>>>(A, B, Bias, C, N, Kd, lda, ldb, ldc, \
    sAb, sAh, sBb, sBh, sCb, sCh, sBiB, sBiH, Hn)
    switch (epi) {
    case 0: HG_CALL(0); break;
    case 1: HG_CALL(1); break;
    case 2: HG_CALL(2); break;
    case 3: HG_CALL(3); break;
    case 5: HG_CALL(5); break;
    default: HG_CALL(6); break;
    }
#undef HG_CALL
}

extern "C" void kernel_launch(void* const* d_in, const int* in_sizes, int n_in,
                              void* d_out, int out_size)
{
    const float* enc    = (const float*)d_in[0];
    const int*   srcpad = (const int*)  d_in[1];
    const int*   target = (const int*)  d_in[2];
    const float* emb    = (const float*)d_in[3];
    const float* Wq1 = (const float*)d_in[4],  *bq1 = (const float*)d_in[5];
    const float* Wk1 = (const float*)d_in[6],  *bk1 = (const float*)d_in[7];
    const float* Wv1 = (const float*)d_in[8],  *bv1 = (const float*)d_in[9];
    const float* Wo1 = (const float*)d_in[10], *bo1 = (const float*)d_in[11];
    const float* Wq2 = (const float*)d_in[12], *bq2 = (const float*)d_in[13];
    const float* Wk2 = (const float*)d_in[14], *bk2 = (const float*)d_in[15];
    const float* Wv2 = (const float*)d_in[16], *bv2 = (const float*)d_in[17];
    const float* Wo2 = (const float*)d_in[18], *bo2 = (const float*)d_in[19];
    const float* ln1g = (const float*)d_in[20];
    const float* ln2g = (const float*)d_in[21];
    const float* ln3g = (const float*)d_in[22];
    const float* ln1b = (const float*)d_in[23];
    const float* ln2b = (const float*)d_in[24];
    const float* ln3b = (const float*)d_in[25];
    const float* Wf1 = (const float*)d_in[26], *bf1 = (const float*)d_in[27];
    const float* Wf2 = (const float*)d_in[28], *bf2 = (const float*)d_in[29];
    const float* lmW = (const float*)d_in[30], *lmb = (const float*)d_in[31];
    float* out = (float*)d_out;

    float *x, *vv, *ss, *tt, *part;
    cudaGetSymbolAddress((void**)&x,  g_x);
    cudaGetSymbolAddress((void**)&vv, g_v);
    cudaGetSymbolAddress((void**)&ss, g_s);
    cudaGetSymbolAddress((void**)&tt, g_t);
    cudaGetSymbolAddress((void**)&part, g_part);
    __half *xh, *eh, *qh, *kh, *vh, *sh, *oh, *fh, *wh, *lmh;
    cudaGetSymbolAddress((void**)&xh, g_xh);
    cudaGetSymbolAddress((void**)&eh, g_eh);
    cudaGetSymbolAddress((void**)&qh, g_qh);
    cudaGetSymbolAddress((void**)&kh, g_kh);
    cudaGetSymbolAddress((void**)&vh, g_vh);
    cudaGetSymbolAddress((void**)&sh, g_sh);
    cudaGetSymbolAddress((void**)&oh, g_oh);
    cudaGetSymbolAddress((void**)&fh, g_fh);
    cudaGetSymbolAddress((void**)&wh, g_wh);
    cudaGetSymbolAddress((void**)&lmh, g_lmh);

    cudaFuncSetAttribute(hgemm_kernel<0>, cudaFuncAttributeMaxDynamicSharedMemorySize, HG_SMEM);
    cudaFuncSetAttribute(hgemm_kernel<1>, cudaFuncAttributeMaxDynamicSharedMemorySize, HG_SMEM);
    cudaFuncSetAttribute(hgemm_kernel<2>, cudaFuncAttributeMaxDynamicSharedMemorySize, HG_SMEM);
    cudaFuncSetAttribute(hgemm_kernel<3>, cudaFuncAttributeMaxDynamicSharedMemorySize, HG_SMEM);
    cudaFuncSetAttribute(hgemm_kernel<5>, cudaFuncAttributeMaxDynamicSharedMemorySize, HG_SMEM);
    cudaFuncSetAttribute(hgemm_kernel<6>, cudaFuncAttributeMaxDynamicSharedMemorySize, HG_SMEM);

    const float scale = 1.0f / sqrtf((float)Dm);
    const long WATT = (long)Hh * Dm * Dm;
    const long WOUT = (long)HD * Dm;
    const long WFF  = (long)Dm * FFd;
    const dim3 tb(32, 8);

    embed_pe_kernel<<<NR, 512>>>(target, emb, x, xh);
    conv_enc_kernel<<<NR, 256>>>(enc, eh);

    for (int l = 0; l < 2; l++) {
        const float *WQ[2] = {Wq1 + l * WATT, Wq2 + l * WATT};
        const float *WK[2] = {Wk1 + l * WATT, Wk2 + l * WATT};
        const float *WV[2] = {Wv1 + l * WATT, Wv2 + l * WATT};
        const float *WO[2] = {Wo1 + l * WOUT, Wo2 + l * WOUT};
        const float *BQ[2] = {bq1 + l * HD, bq2 + l * HD};
        const float *BK[2] = {bk1 + l * HD, bk2 + l * HD};
        const float *BV[2] = {bv1 + l * HD, bv2 + l * HD};
        const float *BO[2] = {bo1 + l * Dm, bo2 + l * Dm};
        const float *LG[2] = {ln1g + l * Dm, ln2g + l * Dm};
        const float *LB[2] = {ln1b + l * Dm, ln2b + l * Dm};

        for (int att = 0; att < 2; att++) {
            const __half* kvA = (att == 0) ? xh : eh;

            // ---- Q projection -> qh fp16 ----
            conv_t_kernel<<<dim3(16, 16, 8), tb>>>(WQ[att], wh, Dm, Dm, Dm, 512,
                                                   0, (long)Dm * Dm, 0, (long)Dm * 512, 8);
            tg(3, xh, wh, BQ[att], qh, NR, Dm, 512, 512, 512, 4096,
               0, 0, 0, (long)Dm * 512, 0, 512, 0, Dm, 8, 8);

            // ---- K projection -> kh fp16 ----
            conv_t_kernel<<<dim3(16, 16, 8), tb>>>(WK[att], wh, Dm, Dm, Dm, 512,
                                                   0, (long)Dm * Dm, 0, (long)Dm * 512, 8);
            tg(3, kvA, wh, BK[att], kh, NR, Dm, 512, 512, 512, 4096,
               0, 0, 0, (long)Dm * 512, 0, 512, 0, Dm, 8, 8);

            // ---- V projection -> vv fp32 -> vh fp16 (transposed) ----
            conv_t_kernel<<<dim3(16, 16, 8), tb>>>(WV[att], wh, Dm, Dm, Dm, 512,
                                                   0, (long)Dm * Dm, 0, (long)Dm * 512, 8);
            tg(1, kvA, wh, BV[att], vv, NR, Dm, 512, 512, 512, HD,
               0, 0, 0, (long)Dm * 512, 0, Dm, 0, Dm, 8, 8);
            conv_t_kernel<<<dim3(16, 16, 32), tb>>>(vv, vh, TSs, Dm, HD, 512,
                                                    (long)TSs * HD, Dm,
                                                    (long)Hh * TSs * 512, (long)TSs * 512, 8);

            // ---- scores = Q K^T ----
            tg(0, qh, kh, nullptr, ss, TTq, TSs, 512, 4096, 4096, TSs,
               (long)TTq * 4096, 512, (long)TSs * 4096, 512,
               (long)Hh * TTq * TSs, (long)TTq * TSs, 0, 0, 8, 32);

            softmax_kernel<<<Bq * Hh * TTq, 256>>>(ss, sh, target, srcpad,
                                                   att == 0 ? 1 : 2, scale);
            if (att == 1 && l == 0 && (long)out_size >= LOGITS_ELEMS + ATT_ELEMS) {
                cudaMemcpyAsync(out + LOGITS_ELEMS, ss, ATT_ELEMS * sizeof(float),
                                cudaMemcpyDeviceToDevice, 0);
            }

            // ---- O = S V -> oh fp16 (concat layout, head col offset 512) ----
            tg(5, sh, vh, nullptr, oh, TTq, Dm, 512, 512, 512, 4096,
               (long)Hh * TTq * 512, (long)TTq * 512,
               (long)Hh * TSs * 512, (long)TSs * 512,
               (long)TTq * 4096, 512, 0, 0, 8, 32);

            // ---- output projection: split-K=8 over K=4096 (chunk 512) ----
            conv_t_kernel<<<dim3(16, 128, 1), tb>>>(WO[att], wh, HD, Dm, Dm, 4096,
                                                    0, 0, 0, 0, 1);
            tg(0, oh, wh, nullptr, part, NR, Dm, 512, 4096, 4096, Dm,
               0, 512, 0, 512, 0, (long)NR * Dm, 0, 0, SKn, SKn);
            reduce_sk_kernel<<<NR * Dm / 1024, 256>>>(part, BO[att], tt);
            add_ln_kernel<<<NR, 256>>>(x, tt, LG[att], LB[att], x, xh);
        }

        // ---- FFN ----
        conv_t_kernel<<<dim3(64, 16, 1), tb>>>(Wf1 + l * WFF, wh, Dm, FFd, FFd, 512,
                                               0, 0, 0, 0, 1);
        tg(6, xh, wh, bf1 + l * FFd, fh, NR, FFd, 512, 512, 512, 2048,
           0, 0, 0, 0, 0, 0, 0, 0, 1, 1);

        // ---- FF2: split-K=8 over K=2048 (chunk 256) ----
        conv_t_kernel<<<dim3(16, 64, 1), tb>>>(Wf2 + l * WFF, wh, FFd, Dm, Dm, 2048,
                                               0, 0, 0, 0, 1);
        tg(0, fh, wh, nullptr, part, NR, Dm, 256, 2048, 2048, Dm,
           0, 256, 0, 256, 0, (long)NR * Dm, 0, 0, SKn, SKn);
        reduce_sk_kernel<<<NR * Dm / 1024, 256>>>(part, bf2 + l * Dm, tt);
        add_ln_kernel<<<NR, 256>>>(x, tt, ln3g + l * Dm, ln3b + l * Dm, x, xh);
    }

    // ---- LM head (plain fp16) ----
    conv_t_kernel<<<dim3(1001, 16, 1), tb>>>(lmW, lmh, Dm, VO, VO, 512, 0, 0, 0, 0, 1);
    tg(1, xh, lmh, lmb, out, NR, VO, 512, 512, 512, VO,
       0, 0, 0, 0, 0, 0, 0, 0, 1, 1);
}

// round 10
// speedup vs baseline: 6.3910x; 1.0422x over previous
#include <cuda_runtime.h>
#include <cuda_fp16.h>
#include <math.h>
#include <stdint.h>

// ---------------------------------------------------------------------------
// Problem constants
// ---------------------------------------------------------------------------
#define Bq   4
#define TTq  512
#define TSs  512
#define Dm   512
#define Hh   8
#define Vv   32000
#define VO   32001
#define NR   2048
#define HD   4096
#define FFd  2048
#define SKn  8

#define LOGITS_ELEMS (2048LL * 32001LL)
#define ATT_ELEMS    (4LL * 8 * 512 * 512)

// ---------------------------------------------------------------------------
// Scratch (static device globals)
// ---------------------------------------------------------------------------
__device__ float g_x [NR * Dm];
__device__ float g_s [Bq * Hh * TTq * TSs];
__device__ float g_part[SKn * NR * Dm];

__device__ __half g_xh [NR * 512];
__device__ __half g_eh [NR * 512];
__device__ __half g_qh [NR * 4096];
__device__ __half g_kh [NR * 4096];
__device__ __half g_vh [32 * 512 * 512];
__device__ __half g_sh [32 * 512 * 512];
__device__ __half g_oh [NR * 4096];
__device__ __half g_fh [NR * 2048];
__device__ __half g_wh [512 * 4096];
__device__ __half g_lmh[32256 * 512];    // rows padded to 126*256; pads stay 0

// ---------------------------------------------------------------------------
// Embedding + positional encoding -> x (fp32) and xh (fp16)
// ---------------------------------------------------------------------------
__global__ void embed_pe_kernel(const int* __restrict__ target,
                                const float* __restrict__ emb,
                                float* __restrict__ x,
                                __half* __restrict__ xh)
{
    int row = blockIdx.x;
    int t   = row & (TTq - 1);
    int d   = threadIdx.x;
    int tok = target[row];
    float e = emb[(long)tok * Dm + d];
    int   i = d >> 1;
    float denom = powf(10000.0f, (2.0f * (float)i) / (float)Dm);
    float z = (float)t / denom;
    float p = (d & 1) ? cosf(z) : sinf(z);
    float v = e + p;
    x[(long)row * Dm + d] = v;
    xh[(long)row * 512 + d] = __float2half(v);
}

// ---------------------------------------------------------------------------
// enc fp32 -> eh fp16
// ---------------------------------------------------------------------------
__global__ void conv_enc_kernel(const float* __restrict__ in, __half* __restrict__ out)
{
    long idx = (long)blockIdx.x * blockDim.x + threadIdx.x;
    long r = idx >> 8;
    long k = (idx & 255) * 2;
    const float* p = in + r * Dm + k;
    __half2 h = __halves2half2(__float2half(p[0]), __float2half(p[1]));
    *(__half2*)(out + r * 512 + k) = h;
}

// ---------------------------------------------------------------------------
// Masked softmax: writes normalized fp32 AND sh fp16.
// ---------------------------------------------------------------------------
__global__ void softmax_kernel(float* __restrict__ S, __half* __restrict__ Sh,
                               const int* __restrict__ target,
                               const int* __restrict__ srcpad,
                               int mode, float scale)
{
    int row = blockIdx.x;
    int q   = row & (TTq - 1);
    int b   = row / (Hh * TTq);
    float* s = S + (long)row * TSs;
    int tid = threadIdx.x;
    bool qpad = (target[b * TTq + q] != Vv);

    float v[2];
    float mx = -INFINITY;
#pragma unroll
    for (int e = 0; e < 2; e++) {
        int k = tid + e * 256;
        bool valid;
        if (mode == 1)
            valid = qpad && (k <= q) && (target[b * TTq + k] != Vv);
        else
            valid = qpad && (srcpad[b * TSs + k] != 0);
        float val = valid ? s[k] * scale : -1e32f;
        v[e] = val;
        mx = fmaxf(mx, val);
    }

    __shared__ float red[8];
#pragma unroll
    for (int o = 16; o > 0; o >>= 1) mx = fmaxf(mx, __shfl_xor_sync(0xffffffffu, mx, o));
    if ((tid & 31) == 0) red[tid >> 5] = mx;
    __syncthreads();
    if (tid < 32) {
        float r = (tid < 8) ? red[tid] : -INFINITY;
#pragma unroll
        for (int o = 4; o > 0; o >>= 1) r = fmaxf(r, __shfl_xor_sync(0xffffffffu, r, o));
        if (tid == 0) red[0] = r;
    }
    __syncthreads();
    mx = red[0];
    __syncthreads();

    float sum = 0.f;
#pragma unroll
    for (int e = 0; e < 2; e++) { v[e] = expf(v[e] - mx); sum += v[e]; }
#pragma unroll
    for (int o = 16; o > 0; o >>= 1) sum += __shfl_xor_sync(0xffffffffu, sum, o);
    if ((tid & 31) == 0) red[tid >> 5] = sum;
    __syncthreads();
    if (tid < 32) {
        float r = (tid < 8) ? red[tid] : 0.f;
#pragma unroll
        for (int o = 4; o > 0; o >>= 1) r += __shfl_xor_sync(0xffffffffu, r, o);
        if (tid == 0) red[0] = r;
    }
    __syncthreads();
    float inv = 1.0f / red[0];
    __half* shr = Sh + (long)row * 512;
#pragma unroll
    for (int e = 0; e < 2; e++) {
        int k = tid + e * 256;
        float val = v[e] * inv;
        s[k] = val;
        shr[k] = __float2half(val);
    }
}

// ---------------------------------------------------------------------------
// Fused split-K reduce + residual + LayerNorm:
//   y = LN(xin + sum_c part[c] + bias) * g + b   -> y fp32, yh fp16
// ---------------------------------------------------------------------------
__global__ void reduce_ln_kernel(const float* __restrict__ part,
                                 const float* __restrict__ bias,
                                 const float* __restrict__ xin,
                                 const float* __restrict__ gg,
                                 const float* __restrict__ bb,
                                 float* __restrict__ y,
                                 __half* __restrict__ yh)
{
    int row = blockIdx.x;
    int tid = threadIdx.x;
    long base = (long)row * Dm;
    __shared__ float red[8];

    float v[2];
    float sum = 0.f;
#pragma unroll
    for (int e = 0; e < 2; e++) {
        int d = tid + e * 256;
        float s = xin[base + d] + bias[d];
#pragma unroll
        for (int c = 0; c < SKn; c++)
            s += part[(long)c * NR * Dm + base + d];
        v[e] = s;
        sum += s;
    }
#pragma unroll
    for (int o = 16; o > 0; o >>= 1) sum += __shfl_xor_sync(0xffffffffu, sum, o);
    if ((tid & 31) == 0) red[tid >> 5] = sum;
    __syncthreads();
    if (tid < 32) {
        float r = (tid < 8) ? red[tid] : 0.f;
#pragma unroll
        for (int o = 4; o > 0; o >>= 1) r += __shfl_xor_sync(0xffffffffu, r, o);
        if (tid == 0) red[0] = r;
    }
    __syncthreads();
    float m = red[0] * (1.0f / (float)Dm);
    __syncthreads();

    float vs = 0.f;
#pragma unroll
    for (int e = 0; e < 2; e++) { float c = v[e] - m; vs += c * c; }
#pragma unroll
    for (int o = 16; o > 0; o >>= 1) vs += __shfl_xor_sync(0xffffffffu, vs, o);
    if ((tid & 31) == 0) red[tid >> 5] = vs;
    __syncthreads();
    if (tid < 32) {
        float r = (tid < 8) ? red[tid] : 0.f;
#pragma unroll
        for (int o = 4; o > 0; o >>= 1) r += __shfl_xor_sync(0xffffffffu, r, o);
        if (tid == 0) red[0] = r;
    }
    __syncthreads();
    float var = red[0] * (1.0f / (float)Dm);
    float rs = rsqrtf(var + 1e-5f);
    __half* yhr = yh + (long)row * 512;
#pragma unroll
    for (int e = 0; e < 2; e++) {
        int d = tid + e * 256;
        float val = (v[e] - m) * rs * gg[d] + bb[d];
        y[base + d] = val;
        yhr[d] = __float2half(val);
    }
}

// ---------------------------------------------------------------------------
// conv_t: fp32 [K, N] (N-contig) -> fp16 [N, K] transposed. (weights)
// ---------------------------------------------------------------------------
__global__ void conv_t_kernel(const float* __restrict__ in, __half* __restrict__ out,
                              int K, int N, int in_ld, int out_ld,
                              long sInB, long sInH, long sOutB, long sOutH, int Hn)
{
    __shared__ float t[32][33];
    int z = blockIdx.z, zb = z / Hn, zh = z % Hn;
    in  += zb * sInB + zh * sInH;
    out += zb * sOutB + zh * sOutH;
    int k0 = blockIdx.y * 32, n0 = blockIdx.x * 32;
    int tx = threadIdx.x, ty = threadIdx.y;
#pragma unroll
    for (int i = 0; i < 4; ++i) {
        int k = k0 + ty + i * 8, n = n0 + tx;
        t[ty + i * 8][tx] = (n < N) ? in[(long)k * in_ld + n] : 0.f;
    }
    __syncthreads();
#pragma unroll
    for (int i = 0; i < 4; ++i) {
        int n = n0 + ty + i * 8, k = k0 + tx;
        if (n < N)
            out[(long)n * out_ld + k] = __float2half(t[tx][ty + i * 8]);
    }
}

// ---------------------------------------------------------------------------
// fp16 tensor-core GEMM (mma.sync m16n8k16 f16). CTA 128x256, 8 warps (2x4),
// warp tile 64x64, BK=32, 4-stage cp.async pipeline, one barrier per iter.
// EPI: 0 fp32 | 1 fp32+bias | 3 half+bias | 5 half | 6 half+bias+relu
//      7 half+bias TRANSPOSED store (C[n*ldc+m])  -- for V projection
// causal: CTAs with n0 > m0+127 exit (fully masked self-att score tiles).
// ---------------------------------------------------------------------------
#define GBM 128
#define GBN 256
#define GBK 32
#define NSTAGE 4
#define A_BYTES 10240
#define STAGE_BYTES 30720
#define HG_SMEM (NSTAGE * STAGE_BYTES)

__device__ __forceinline__ uint32_t smem_u32(const void* p) {
    uint32_t a;
    asm("{ .reg .u64 t; cvta.to.shared.u64 t, %1; cvt.u32.u64 %0, t; }" : "=r"(a) : "l"(p));
    return a;
}
#define CP16(dst, src) \
    asm volatile("cp.async.cg.shared.global [%0], [%1], 16;" :: "r"(dst), "l"(src))
#define CP_COMMIT() asm volatile("cp.async.commit_group;" ::: "memory")
#define CP_WAIT(n)  asm volatile("cp.async.wait_group %0;" :: "n"(n) : "memory")
#define LDSM_X4(r0, r1, r2, r3, addr) \
    asm volatile("ldmatrix.sync.aligned.m8n8.x4.shared.b16 {%0,%1,%2,%3}, [%4];" \
                 : "=r"(r0), "=r"(r1), "=r"(r2), "=r"(r3) : "r"(addr))
#define MMA_F16(c, a0, a1, a2, a3, b0, b1) \
    asm volatile("mma.sync.aligned.m16n8k16.row.col.f32.f16.f16.f32 " \
                 "{%0,%1,%2,%3}, {%4,%5,%6,%7}, {%8,%9}, {%0,%1,%2,%3};" \
                 : "+f"((c)[0]), "+f"((c)[1]), "+f"((c)[2]), "+f"((c)[3]) \
                 : "r"(a0), "r"(a1), "r"(a2), "r"(a3), "r"(b0), "r"(b1))

template<int EPI>
__global__ void __launch_bounds__(256, 1)
hgemm_kernel(const __half* __restrict__ A2, const __half* __restrict__ B2,
             const float* __restrict__ Bias, void* __restrict__ Cv,
             int Nstore, int Kd, int lda, int ldb, int ldc,
             long sAb, long sAh, long sBb, long sBh, long sCb, long sCh,
             long sBiB, long sBiH, int Hn, int causal)
{
    extern __shared__ __align__(16) char dsm[];
    const uint32_t base = smem_u32(dsm);

    int tid = threadIdx.x;
    int wid = tid >> 5, lane = tid & 31;

    long m0 = (long)blockIdx.x * GBM;
    long n0 = (long)blockIdx.y * GBN;
    if (causal && n0 > m0 + (GBM - 1)) return;   // fully-masked causal tile

    int z = blockIdx.z, zb = z / Hn, zh = z % Hn;
    A2 += zb * sAb + zh * sAh;
    B2 += zb * sBb + zh * sBh;
    long cOff = zb * sCb + zh * sCh;
    long biasOff = zb * sBiB + zh * sBiH;

    const int wm = (wid >> 2) * 64;
    const int wn = (wid & 3) * 64;

    float acc[4][8][4];
#pragma unroll
    for (int i = 0; i < 4; i++)
#pragma unroll
        for (int j = 0; j < 8; j++)
#pragma unroll
            for (int q = 0; q < 4; q++) acc[i][j][q] = 0.f;

    const int nIter = Kd / GBK;

    const int lr  = tid >> 2;
    const int lsg = tid & 3;
    const long aRow0 = m0 + lr,  aRow1 = m0 + lr + 64;
    const uint32_t sOff0 = (uint32_t)(lr * 80 + lsg * 16);
    const uint32_t sOff1 = (uint32_t)((lr + 64) * 80 + lsg * 16);
    const uint32_t sOff2 = (uint32_t)((lr + 128) * 80 + lsg * 16);
    const uint32_t sOff3 = (uint32_t)((lr + 192) * 80 + lsg * 16);

    auto loadStage = [&](int slot, long k0) {
        uint32_t aD = base + slot * STAGE_BYTES;
        uint32_t bD = aD + A_BYTES;
        long ko = k0 + lsg * 8;
        CP16(aD + sOff0, A2 + aRow0 * (long)lda + ko);
        CP16(aD + sOff1, A2 + aRow1 * (long)lda + ko);
        CP16(bD + sOff0, B2 + (n0 + lr) * (long)ldb + ko);
        CP16(bD + sOff1, B2 + (n0 + lr + 64) * (long)ldb + ko);
        CP16(bD + sOff2, B2 + (n0 + lr + 128) * (long)ldb + ko);
        CP16(bD + sOff3, B2 + (n0 + lr + 192) * (long)ldb + ko);
        CP_COMMIT();
    };

    loadStage(0, 0);
    if (nIter > 1) loadStage(1, GBK); else CP_COMMIT();
    if (nIter > 2) loadStage(2, 2L * GBK); else CP_COMMIT();

    for (int it = 0; it < nIter; ++it) {
        if (it + 2 < nIter)      CP_WAIT(2);
        else if (it + 1 < nIter) CP_WAIT(1);
        else                     CP_WAIT(0);
        __syncthreads();
        if (it + 3 < nIter) loadStage((it + 3) & (NSTAGE - 1), (long)(it + 3) * GBK);

        uint32_t aS = base + (it & (NSTAGE - 1)) * STAGE_BYTES;
        uint32_t bS = aS + A_BYTES;
#pragma unroll
        for (int ks = 0; ks < 2; ks++) {
            int col = ks * 16 + (lane >> 4) * 8;
            uint32_t a[4][4], bf[8][2];
#pragma unroll
            for (int mi = 0; mi < 4; mi++) {
                int row = wm + mi * 16 + (lane & 15);
                LDSM_X4(a[mi][0], a[mi][1], a[mi][2], a[mi][3],
                        aS + (uint32_t)(row * 80 + col * 2));
            }
#pragma unroll
            for (int p = 0; p < 4; p++) {
                int row = wn + p * 16 + (lane & 15);
                uint32_t r0, r1, r2, r3;
                LDSM_X4(r0, r1, r2, r3, bS + (uint32_t)(row * 80 + col * 2));
                bf[2 * p][0] = r0;     bf[2 * p][1] = r2;
                bf[2 * p + 1][0] = r1; bf[2 * p + 1][1] = r3;
            }
#pragma unroll
            for (int mi = 0; mi < 4; mi++)
#pragma unroll
                for (int ni = 0; ni < 8; ni++)
                    MMA_F16(acc[mi][ni], a[mi][0], a[mi][1], a[mi][2], a[mi][3],
                            bf[ni][0], bf[ni][1]);
        }
    }

    // ---- epilogue ----
    if (EPI <= 1) {
        float* C = (float*)Cv + cOff;
#pragma unroll
        for (int mi = 0; mi < 4; mi++) {
            long mrow = m0 + wm + mi * 16 + (lane >> 2);
            float* c0p = C + mrow * (long)ldc;
            float* c1p = c0p + 8L * ldc;
#pragma unroll
            for (int ni = 0; ni < 8; ni++) {
                long n = n0 + wn + ni * 8 + (lane & 3) * 2;
#pragma unroll
                for (int e = 0; e < 2; e++) {
                    long nn = n + e;
                    if (nn < (long)Nstore) {
                        float v0 = acc[mi][ni][e];
                        float v1 = acc[mi][ni][2 + e];
                        if (EPI >= 1) {
                            float bsv = Bias[biasOff + nn];
                            v0 += bsv; v1 += bsv;
                        }
                        c0p[nn] = v0;
                        c1p[nn] = v1;
                    }
                }
            }
        }
    } else if (EPI == 7) {
        // transposed fp16 store: C[n * ldc + m], bias over n
        __half* C2 = (__half*)Cv + cOff;
#pragma unroll
        for (int mi = 0; mi < 4; mi++) {
            long m = m0 + wm + mi * 16 + (lane >> 2);
#pragma unroll
            for (int ni = 0; ni < 8; ni++) {
                long n = n0 + wn + ni * 8 + (lane & 3) * 2;
                float b0 = Bias[biasOff + n];
                float b1 = Bias[biasOff + n + 1];
                C2[n * (long)ldc + m]           = __float2half(acc[mi][ni][0] + b0);
                C2[(n + 1) * (long)ldc + m]     = __float2half(acc[mi][ni][1] + b1);
                C2[n * (long)ldc + m + 8]       = __float2half(acc[mi][ni][2] + b0);
                C2[(n + 1) * (long)ldc + m + 8] = __float2half(acc[mi][ni][3] + b1);
            }
        }
    } else {
        __half* C2 = (__half*)Cv + cOff;
        const bool hasBias = (EPI == 3 || EPI == 6);
        const bool relu = (EPI == 6);
#pragma unroll
        for (int mi = 0; mi < 4; mi++) {
            long r0 = m0 + wm + mi * 16 + (lane >> 2);
            __half* p0 = C2 + r0 * (long)ldc;
            __half* p1 = p0 + 8L * ldc;
#pragma unroll
            for (int ni = 0; ni < 8; ni++) {
                long n = n0 + wn + ni * 8 + (lane & 3) * 2;
                float b0 = 0.f, b1 = 0.f;
                if (hasBias) { b0 = Bias[biasOff + n]; b1 = Bias[biasOff + n + 1]; }
                float v0 = acc[mi][ni][0] + b0, v1 = acc[mi][ni][1] + b1;
                float v2 = acc[mi][ni][2] + b0, v3 = acc[mi][ni][3] + b1;
                if (relu) {
                    v0 = fmaxf(v0, 0.f); v1 = fmaxf(v1, 0.f);
                    v2 = fmaxf(v2, 0.f); v3 = fmaxf(v3, 0.f);
                }
                *(__half2*)(p0 + n) = __halves2half2(__float2half(v0), __float2half(v1));
                *(__half2*)(p1 + n) = __halves2half2(__float2half(v2), __float2half(v3));
            }
        }
    }
}

// ---------------------------------------------------------------------------
// Host dispatch
// ---------------------------------------------------------------------------
static void tg(int epi, const __half* A, const __half* B, const float* Bias,
               void* C, int M, int N, int Kd, int lda, int ldb, int ldc,
               long sAb, long sAh, long sBb, long sBh, long sCb, long sCh,
               long sBiB, long sBiH, int Hn, int Z, int causal = 0)
{
    dim3 g(M / GBM, (N + GBN - 1) / GBN, Z), b(256);
#define HG_CALL(E) hgemm_kernel<E><<<g, b, HG_SMEM>>>(A, B, Bias, C, N, Kd, lda, ldb, ldc, \
    sAb, sAh, sBb, sBh, sCb, sCh, sBiB, sBiH, Hn, causal)
    switch (epi) {
    case 0: HG_CALL(0); break;
    case 1: HG_CALL(1); break;
    case 3: HG_CALL(3); break;
    case 5: HG_CALL(5); break;
    case 7: HG_CALL(7); break;
    default: HG_CALL(6); break;
    }
#undef HG_CALL
}

extern "C" void kernel_launch(void* const* d_in, const int* in_sizes, int n_in,
                              void* d_out, int out_size)
{
    const float* enc    = (const float*)d_in[0];
    const int*   srcpad = (const int*)  d_in[1];
    const int*   target = (const int*)  d_in[2];
    const float* emb    = (const float*)d_in[3];
    const float* Wq1 = (const float*)d_in[4],  *bq1 = (const float*)d_in[5];
    const float* Wk1 = (const float*)d_in[6],  *bk1 = (const float*)d_in[7];
    const float* Wv1 = (const float*)d_in[8],  *bv1 = (const float*)d_in[9];
    const float* Wo1 = (const float*)d_in[10], *bo1 = (const float*)d_in[11];
    const float* Wq2 = (const float*)d_in[12], *bq2 = (const float*)d_in[13];
    const float* Wk2 = (const float*)d_in[14], *bk2 = (const float*)d_in[15];
    const float* Wv2 = (const float*)d_in[16], *bv2 = (const float*)d_in[17];
    const float* Wo2 = (const float*)d_in[18], *bo2 = (const float*)d_in[19];
    const float* ln1g = (const float*)d_in[20];
    const float* ln2g = (const float*)d_in[21];
    const float* ln3g = (const float*)d_in[22];
    const float* ln1b = (const float*)d_in[23];
    const float* ln2b = (const float*)d_in[24];
    const float* ln3b = (const float*)d_in[25];
    const float* Wf1 = (const float*)d_in[26], *bf1 = (const float*)d_in[27];
    const float* Wf2 = (const float*)d_in[28], *bf2 = (const float*)d_in[29];
    const float* lmW = (const float*)d_in[30], *lmb = (const float*)d_in[31];
    float* out = (float*)d_out;

    float *x, *ss, *part;
    cudaGetSymbolAddress((void**)&x,  g_x);
    cudaGetSymbolAddress((void**)&ss, g_s);
    cudaGetSymbolAddress((void**)&part, g_part);
    __half *xh, *eh, *qh, *kh, *vh, *sh, *oh, *fh, *wh, *lmh;
    cudaGetSymbolAddress((void**)&xh, g_xh);
    cudaGetSymbolAddress((void**)&eh, g_eh);
    cudaGetSymbolAddress((void**)&qh, g_qh);
    cudaGetSymbolAddress((void**)&kh, g_kh);
    cudaGetSymbolAddress((void**)&vh, g_vh);
    cudaGetSymbolAddress((void**)&sh, g_sh);
    cudaGetSymbolAddress((void**)&oh, g_oh);
    cudaGetSymbolAddress((void**)&fh, g_fh);
    cudaGetSymbolAddress((void**)&wh, g_wh);
    cudaGetSymbolAddress((void**)&lmh, g_lmh);

    cudaFuncSetAttribute(hgemm_kernel<0>, cudaFuncAttributeMaxDynamicSharedMemorySize, HG_SMEM);
    cudaFuncSetAttribute(hgemm_kernel<1>, cudaFuncAttributeMaxDynamicSharedMemorySize, HG_SMEM);
    cudaFuncSetAttribute(hgemm_kernel<3>, cudaFuncAttributeMaxDynamicSharedMemorySize, HG_SMEM);
    cudaFuncSetAttribute(hgemm_kernel<5>, cudaFuncAttributeMaxDynamicSharedMemorySize, HG_SMEM);
    cudaFuncSetAttribute(hgemm_kernel<6>, cudaFuncAttributeMaxDynamicSharedMemorySize, HG_SMEM);
    cudaFuncSetAttribute(hgemm_kernel<7>, cudaFuncAttributeMaxDynamicSharedMemorySize, HG_SMEM);

    const float scale = 1.0f / sqrtf((float)Dm);
    const long WATT = (long)Hh * Dm * Dm;
    const long WOUT = (long)HD * Dm;
    const long WFF  = (long)Dm * FFd;
    const dim3 tb(32, 8);

    embed_pe_kernel<<<NR, 512>>>(target, emb, x, xh);
    conv_enc_kernel<<<NR, 256>>>(enc, eh);

    for (int l = 0; l < 2; l++) {
        const float *WQ[2] = {Wq1 + l * WATT, Wq2 + l * WATT};
        const float *WK[2] = {Wk1 + l * WATT, Wk2 + l * WATT};
        const float *WV[2] = {Wv1 + l * WATT, Wv2 + l * WATT};
        const float *WO[2] = {Wo1 + l * WOUT, Wo2 + l * WOUT};
        const float *BQ[2] = {bq1 + l * HD, bq2 + l * HD};
        const float *BK[2] = {bk1 + l * HD, bk2 + l * HD};
        const float *BV[2] = {bv1 + l * HD, bv2 + l * HD};
        const float *BO[2] = {bo1 + l * Dm, bo2 + l * Dm};
        const float *LG[2] = {ln1g + l * Dm, ln2g + l * Dm};
        const float *LB[2] = {ln1b + l * Dm, ln2b + l * Dm};

        for (int att = 0; att < 2; att++) {
            const __half* kvA = (att == 0) ? xh : eh;

            // ---- Q projection -> qh fp16 ----
            conv_t_kernel<<<dim3(16, 16, 8), tb>>>(WQ[att], wh, Dm, Dm, Dm, 512,
                                                   0, (long)Dm * Dm, 0, (long)Dm * 512, 8);
            tg(3, xh, wh, BQ[att], qh, NR, Dm, 512, 512, 512, 4096,
               0, 0, 0, (long)Dm * 512, 0, 512, 0, Dm, 8, 8);

            // ---- K projection -> kh fp16 ----
            conv_t_kernel<<<dim3(16, 16, 8), tb>>>(WK[att], wh, Dm, Dm, Dm, 512,
                                                   0, (long)Dm * Dm, 0, (long)Dm * 512, 8);
            tg(3, kvA, wh, BK[att], kh, NR, Dm, 512, 512, 512, 4096,
               0, 0, 0, (long)Dm * 512, 0, 512, 0, Dm, 8, 8);

            // ---- V projection -> vh fp16, TRANSPOSED store (batched z=32) ----
            conv_t_kernel<<<dim3(16, 16, 8), tb>>>(WV[att], wh, Dm, Dm, Dm, 512,
                                                   0, (long)Dm * Dm, 0, (long)Dm * 512, 8);
            tg(7, kvA, wh, BV[att], vh, 512, Dm, 512, 512, 512, 512,
               (long)512 * 512, 0, 0, (long)Dm * 512,
               (long)Hh * 512 * 512, (long)512 * 512, 0, Dm, 8, 32);

            // ---- scores = Q K^T (causal tile-skip for self-att) ----
            tg(0, qh, kh, nullptr, ss, TTq, TSs, 512, 4096, 4096, TSs,
               (long)TTq * 4096, 512, (long)TSs * 4096, 512,
               (long)Hh * TTq * TSs, (long)TTq * TSs, 0, 0, 8, 32,
               att == 0 ? 1 : 0);

            softmax_kernel<<<Bq * Hh * TTq, 256>>>(ss, sh, target, srcpad,
                                                   att == 0 ? 1 : 2, scale);
            if (att == 1 && l == 0 && (long)out_size >= LOGITS_ELEMS + ATT_ELEMS) {
                cudaMemcpyAsync(out + LOGITS_ELEMS, ss, ATT_ELEMS * sizeof(float),
                                cudaMemcpyDeviceToDevice, 0);
            }

            // ---- O = S V -> oh fp16 (concat layout) ----
            tg(5, sh, vh, nullptr, oh, TTq, Dm, 512, 512, 512, 4096,
               (long)Hh * TTq * 512, (long)TTq * 512,
               (long)Hh * TSs * 512, (long)TSs * 512,
               (long)TTq * 4096, 512, 0, 0, 8, 32);

            // ---- output projection: split-K=8 + fused reduce+add+LN ----
            conv_t_kernel<<<dim3(16, 128, 1), tb>>>(WO[att], wh, HD, Dm, Dm, 4096,
                                                    0, 0, 0, 0, 1);
            tg(0, oh, wh, nullptr, part, NR, Dm, 512, 4096, 4096, Dm,
               0, 512, 0, 512, 0, (long)NR * Dm, 0, 0, SKn, SKn);
            reduce_ln_kernel<<<NR, 256>>>(part, BO[att], x, LG[att], LB[att], x, xh);
        }

        // ---- FFN ----
        conv_t_kernel<<<dim3(64, 16, 1), tb>>>(Wf1 + l * WFF, wh, Dm, FFd, FFd, 512,
                                               0, 0, 0, 0, 1);
        tg(6, xh, wh, bf1 + l * FFd, fh, NR, FFd, 512, 512, 512, 2048,
           0, 0, 0, 0, 0, 0, 0, 0, 1, 1);

        // ---- FF2: split-K=8 + fused reduce+add+LN ----
        conv_t_kernel<<<dim3(16, 64, 1), tb>>>(Wf2 + l * WFF, wh, FFd, Dm, Dm, 2048,
                                               0, 0, 0, 0, 1);
        tg(0, fh, wh, nullptr, part, NR, Dm, 256, 2048, 2048, Dm,
           0, 256, 0, 256, 0, (long)NR * Dm, 0, 0, SKn, SKn);
        reduce_ln_kernel<<<NR, 256>>>(part, bf2 + l * Dm, x, ln3g + l * Dm, ln3b + l * Dm, x, xh);
    }

    // ---- LM head (plain fp16) ----
    conv_t_kernel<<<dim3(1001, 16, 1), tb>>>(lmW, lmh, Dm, VO, VO, 512, 0, 0, 0, 0, 1);
    tg(1, xh, lmh, lmb, out, NR, VO, 512, 512, 512, VO,
       0, 0, 0, 0, 0, 0, 0, 0, 1, 1);
}

// round 11
// speedup vs baseline: 6.4247x; 1.0053x over previous
#include <cuda_runtime.h>
#include <cuda_fp16.h>
#include <math.h>
#include <stdint.h>

// ---------------------------------------------------------------------------
// Problem constants
// ---------------------------------------------------------------------------
#define Bq   4
#define TTq  512
#define TSs  512
#define Dm   512
#define Hh   8
#define Vv   32000
#define VO   32001
#define NR   2048
#define HD   4096
#define FFd  2048
#define SKn  8

#define LOGITS_ELEMS (2048LL * 32001LL)
#define ATT_ELEMS    (4LL * 8 * 512 * 512)

// ---------------------------------------------------------------------------
// Scratch (static device globals)
// ---------------------------------------------------------------------------
__device__ float g_x [NR * Dm];
__device__ float g_s [Bq * Hh * TTq * TSs];     // fp32 att weights (att0 only)
__device__ float g_part[SKn * NR * Dm];
__device__ float g_bqk[2 * HD];                  // staged Q||K bias

__device__ __half g_xeh[2 * NR * 512];           // xh (0..) and eh (NR*512..)
__device__ __half g_qh [NR * 8192];              // Q cols 0-4095, K cols 4096-8191
__device__ __half g_vh [32 * 512 * 512];
__device__ __half g_sh [32 * 512 * 512];         // raw scores then att weights (fp16)
__device__ __half g_oh [NR * 4096];
__device__ __half g_fh [NR * 2048];
__device__ __half g_wh [4194304];                // Q-weights (0..) K-weights (2M..)
__device__ __half g_lmh[32256 * 512];            // rows padded to 126*256; pads stay 0

// ---------------------------------------------------------------------------
// Embedding + positional encoding -> x (fp32) and xh (fp16)
// ---------------------------------------------------------------------------
__global__ void embed_pe_kernel(const int* __restrict__ target,
                                const float* __restrict__ emb,
                                float* __restrict__ x,
                                __half* __restrict__ xh)
{
    int row = blockIdx.x;
    int t   = row & (TTq - 1);
    int d   = threadIdx.x;
    int tok = target[row];
    float e = emb[(long)tok * Dm + d];
    int   i = d >> 1;
    float denom = powf(10000.0f, (2.0f * (float)i) / (float)Dm);
    float z = (float)t / denom;
    float p = (d & 1) ? cosf(z) : sinf(z);
    float v = e + p;
    x[(long)row * Dm + d] = v;
    xh[(long)row * 512 + d] = __float2half(v);
}

// ---------------------------------------------------------------------------
// enc fp32 -> eh fp16
// ---------------------------------------------------------------------------
__global__ void conv_enc_kernel(const float* __restrict__ in, __half* __restrict__ out)
{
    long idx = (long)blockIdx.x * blockDim.x + threadIdx.x;
    long r = idx >> 8;
    long k = (idx & 255) * 2;
    const float* p = in + r * Dm + k;
    __half2 h = __halves2half2(__float2half(p[0]), __float2half(p[1]));
    *(__half2*)(out + r * 512 + k) = h;
}

// ---------------------------------------------------------------------------
// Masked softmax, fp16 in-place; optional fp32 copy (att0).
// ---------------------------------------------------------------------------
__global__ void softmax_kernel(__half* __restrict__ Sh, float* __restrict__ S,
                               int writeS,
                               const int* __restrict__ target,
                               const int* __restrict__ srcpad,
                               int mode, float scale)
{
    int row = blockIdx.x;
    int q   = row & (TTq - 1);
    int b   = row / (Hh * TTq);
    __half* sr = Sh + (long)row * 512;
    int tid = threadIdx.x;
    bool qpad = (target[b * TTq + q] != Vv);

    float v[2];
    float mx = -INFINITY;
#pragma unroll
    for (int e = 0; e < 2; e++) {
        int k = tid + e * 256;
        bool valid;
        if (mode == 1)
            valid = qpad && (k <= q) && (target[b * TTq + k] != Vv);
        else
            valid = qpad && (srcpad[b * TSs + k] != 0);
        float val = valid ? __half2float(sr[k]) * scale : -1e32f;
        v[e] = val;
        mx = fmaxf(mx, val);
    }

    __shared__ float red[8];
#pragma unroll
    for (int o = 16; o > 0; o >>= 1) mx = fmaxf(mx, __shfl_xor_sync(0xffffffffu, mx, o));
    if ((tid & 31) == 0) red[tid >> 5] = mx;
    __syncthreads();
    if (tid < 32) {
        float r = (tid < 8) ? red[tid] : -INFINITY;
#pragma unroll
        for (int o = 4; o > 0; o >>= 1) r = fmaxf(r, __shfl_xor_sync(0xffffffffu, r, o));
        if (tid == 0) red[0] = r;
    }
    __syncthreads();
    mx = red[0];
    __syncthreads();

    float sum = 0.f;
#pragma unroll
    for (int e = 0; e < 2; e++) { v[e] = expf(v[e] - mx); sum += v[e]; }
#pragma unroll
    for (int o = 16; o > 0; o >>= 1) sum += __shfl_xor_sync(0xffffffffu, sum, o);
    if ((tid & 31) == 0) red[tid >> 5] = sum;
    __syncthreads();
    if (tid < 32) {
        float r = (tid < 8) ? red[tid] : 0.f;
#pragma unroll
        for (int o = 4; o > 0; o >>= 1) r += __shfl_xor_sync(0xffffffffu, r, o);
        if (tid == 0) red[0] = r;
    }
    __syncthreads();
    float inv = 1.0f / red[0];
    float* s32 = S + (long)row * TSs;
#pragma unroll
    for (int e = 0; e < 2; e++) {
        int k = tid + e * 256;
        float val = v[e] * inv;
        sr[k] = __float2half(val);
        if (writeS) s32[k] = val;
    }
}

// ---------------------------------------------------------------------------
// Fused split-K reduce + residual + LayerNorm:
//   y = LN(xin + sum_c part[c] + bias) * g + b   -> y fp32, yh fp16
// ---------------------------------------------------------------------------
__global__ void reduce_ln_kernel(const float* __restrict__ part,
                                 const float* __restrict__ bias,
                                 const float* __restrict__ xin,
                                 const float* __restrict__ gg,
                                 const float* __restrict__ bb,
                                 float* __restrict__ y,
                                 __half* __restrict__ yh)
{
    int row = blockIdx.x;
    int tid = threadIdx.x;
    long base = (long)row * Dm;
    __shared__ float red[8];

    float v[2];
    float sum = 0.f;
#pragma unroll
    for (int e = 0; e < 2; e++) {
        int d = tid + e * 256;
        float s = xin[base + d] + bias[d];
#pragma unroll
        for (int c = 0; c < SKn; c++)
            s += part[(long)c * NR * Dm + base + d];
        v[e] = s;
        sum += s;
    }
#pragma unroll
    for (int o = 16; o > 0; o >>= 1) sum += __shfl_xor_sync(0xffffffffu, sum, o);
    if ((tid & 31) == 0) red[tid >> 5] = sum;
    __syncthreads();
    if (tid < 32) {
        float r = (tid < 8) ? red[tid] : 0.f;
#pragma unroll
        for (int o = 4; o > 0; o >>= 1) r += __shfl_xor_sync(0xffffffffu, r, o);
        if (tid == 0) red[0] = r;
    }
    __syncthreads();
    float m = red[0] * (1.0f / (float)Dm);
    __syncthreads();

    float vs = 0.f;
#pragma unroll
    for (int e = 0; e < 2; e++) { float c = v[e] - m; vs += c * c; }
#pragma unroll
    for (int o = 16; o > 0; o >>= 1) vs += __shfl_xor_sync(0xffffffffu, vs, o);
    if ((tid & 31) == 0) red[tid >> 5] = vs;
    __syncthreads();
    if (tid < 32) {
        float r = (tid < 8) ? red[tid] : 0.f;
#pragma unroll
        for (int o = 4; o > 0; o >>= 1) r += __shfl_xor_sync(0xffffffffu, r, o);
        if (tid == 0) red[0] = r;
    }
    __syncthreads();
    float var = red[0] * (1.0f / (float)Dm);
    float rs = rsqrtf(var + 1e-5f);
    __half* yhr = yh + (long)row * 512;
#pragma unroll
    for (int e = 0; e < 2; e++) {
        int d = tid + e * 256;
        float val = (v[e] - m) * rs * gg[d] + bb[d];
        y[base + d] = val;
        yhr[d] = __float2half(val);
    }
}

// ---------------------------------------------------------------------------
// conv_t: fp32 [K, N] (N-contig) -> fp16 [N, K] transposed. (weights)
// ---------------------------------------------------------------------------
__global__ void conv_t_kernel(const float* __restrict__ in, __half* __restrict__ out,
                              int K, int N, int in_ld, int out_ld,
                              long sInB, long sInH, long sOutB, long sOutH, int Hn)
{
    __shared__ float t[32][33];
    int z = blockIdx.z, zb = z / Hn, zh = z % Hn;
    in  += zb * sInB + zh * sInH;
    out += zb * sOutB + zh * sOutH;
    int k0 = blockIdx.y * 32, n0 = blockIdx.x * 32;
    int tx = threadIdx.x, ty = threadIdx.y;
#pragma unroll
    for (int i = 0; i < 4; ++i) {
        int k = k0 + ty + i * 8, n = n0 + tx;
        t[ty + i * 8][tx] = (n < N) ? in[(long)k * in_ld + n] : 0.f;
    }
    __syncthreads();
#pragma unroll
    for (int i = 0; i < 4; ++i) {
        int n = n0 + ty + i * 8, k = k0 + tx;
        if (n < N)
            out[(long)n * out_ld + k] = __float2half(t[tx][ty + i * 8]);
    }
}

// ---------------------------------------------------------------------------
// fp16 tensor-core GEMM (mma.sync m16n8k16 f16). CTA 128x256, 8 warps (2x4),
// warp tile 64x64, BK=32, 4-stage cp.async pipeline, one barrier per iter.
// EPI: 0 fp32 | 1 fp32+bias | 3 half+bias | 5 half | 6 half+bias+relu
//      7 half+bias TRANSPOSED store (C[n*ldc+m])  -- for V projection
// causal: CTAs with n0 > m0+127 exit (fully masked self-att score tiles).
// ---------------------------------------------------------------------------
#define GBM 128
#define GBN 256
#define GBK 32
#define NSTAGE 4
#define A_BYTES 10240
#define STAGE_BYTES 30720
#define HG_SMEM (NSTAGE * STAGE_BYTES)

__device__ __forceinline__ uint32_t smem_u32(const void* p) {
    uint32_t a;
    asm("{ .reg .u64 t; cvta.to.shared.u64 t, %1; cvt.u32.u64 %0, t; }" : "=r"(a) : "l"(p));
    return a;
}
#define CP16(dst, src) \
    asm volatile("cp.async.cg.shared.global [%0], [%1], 16;" :: "r"(dst), "l"(src))
#define CP_COMMIT() asm volatile("cp.async.commit_group;" ::: "memory")
#define CP_WAIT(n)  asm volatile("cp.async.wait_group %0;" :: "n"(n) : "memory")
#define LDSM_X4(r0, r1, r2, r3, addr) \
    asm volatile("ldmatrix.sync.aligned.m8n8.x4.shared.b16 {%0,%1,%2,%3}, [%4];" \
                 : "=r"(r0), "=r"(r1), "=r"(r2), "=r"(r3) : "r"(addr))
#define MMA_F16(c, a0, a1, a2, a3, b0, b1) \
    asm volatile("mma.sync.aligned.m16n8k16.row.col.f32.f16.f16.f32 " \
                 "{%0,%1,%2,%3}, {%4,%5,%6,%7}, {%8,%9}, {%0,%1,%2,%3};" \
                 : "+f"((c)[0]), "+f"((c)[1]), "+f"((c)[2]), "+f"((c)[3]) \
                 : "r"(a0), "r"(a1), "r"(a2), "r"(a3), "r"(b0), "r"(b1))

template<int EPI>
__global__ void __launch_bounds__(256, 1)
hgemm_kernel(const __half* __restrict__ A2, const __half* __restrict__ B2,
             const float* __restrict__ Bias, void* __restrict__ Cv,
             int Nstore, int Kd, int lda, int ldb, int ldc,
             long sAb, long sAh, long sBb, long sBh, long sCb, long sCh,
             long sBiB, long sBiH, int Hn, int causal)
{
    extern __shared__ __align__(16) char dsm[];
    const uint32_t base = smem_u32(dsm);

    int tid = threadIdx.x;
    int wid = tid >> 5, lane = tid & 31;

    long m0 = (long)blockIdx.x * GBM;
    long n0 = (long)blockIdx.y * GBN;
    if (causal && n0 > m0 + (GBM - 1)) return;

    int z = blockIdx.z, zb = z / Hn, zh = z % Hn;
    A2 += zb * sAb + zh * sAh;
    B2 += zb * sBb + zh * sBh;
    long cOff = zb * sCb + zh * sCh;
    long biasOff = zb * sBiB + zh * sBiH;

    const int wm = (wid >> 2) * 64;
    const int wn = (wid & 3) * 64;

    float acc[4][8][4];
#pragma unroll
    for (int i = 0; i < 4; i++)
#pragma unroll
        for (int j = 0; j < 8; j++)
#pragma unroll
            for (int q = 0; q < 4; q++) acc[i][j][q] = 0.f;

    const int nIter = Kd / GBK;

    const int lr  = tid >> 2;
    const int lsg = tid & 3;
    const long aRow0 = m0 + lr,  aRow1 = m0 + lr + 64;
    const uint32_t sOff0 = (uint32_t)(lr * 80 + lsg * 16);
    const uint32_t sOff1 = (uint32_t)((lr + 64) * 80 + lsg * 16);
    const uint32_t sOff2 = (uint32_t)((lr + 128) * 80 + lsg * 16);
    const uint32_t sOff3 = (uint32_t)((lr + 192) * 80 + lsg * 16);

    auto loadStage = [&](int slot, long k0) {
        uint32_t aD = base + slot * STAGE_BYTES;
        uint32_t bD = aD + A_BYTES;
        long ko = k0 + lsg * 8;
        CP16(aD + sOff0, A2 + aRow0 * (long)lda + ko);
        CP16(aD + sOff1, A2 + aRow1 * (long)lda + ko);
        CP16(bD + sOff0, B2 + (n0 + lr) * (long)ldb + ko);
        CP16(bD + sOff1, B2 + (n0 + lr + 64) * (long)ldb + ko);
        CP16(bD + sOff2, B2 + (n0 + lr + 128) * (long)ldb + ko);
        CP16(bD + sOff3, B2 + (n0 + lr + 192) * (long)ldb + ko);
        CP_COMMIT();
    };

    loadStage(0, 0);
    if (nIter > 1) loadStage(1, GBK); else CP_COMMIT();
    if (nIter > 2) loadStage(2, 2L * GBK); else CP_COMMIT();

    for (int it = 0; it < nIter; ++it) {
        if (it + 2 < nIter)      CP_WAIT(2);
        else if (it + 1 < nIter) CP_WAIT(1);
        else                     CP_WAIT(0);
        __syncthreads();
        if (it + 3 < nIter) loadStage((it + 3) & (NSTAGE - 1), (long)(it + 3) * GBK);

        uint32_t aS = base + (it & (NSTAGE - 1)) * STAGE_BYTES;
        uint32_t bS = aS + A_BYTES;
#pragma unroll
        for (int ks = 0; ks < 2; ks++) {
            int col = ks * 16 + (lane >> 4) * 8;
            uint32_t a[4][4], bf[8][2];
#pragma unroll
            for (int mi = 0; mi < 4; mi++) {
                int row = wm + mi * 16 + (lane & 15);
                LDSM_X4(a[mi][0], a[mi][1], a[mi][2], a[mi][3],
                        aS + (uint32_t)(row * 80 + col * 2));
            }
#pragma unroll
            for (int p = 0; p < 4; p++) {
                int row = wn + p * 16 + (lane & 15);
                uint32_t r0, r1, r2, r3;
                LDSM_X4(r0, r1, r2, r3, bS + (uint32_t)(row * 80 + col * 2));
                bf[2 * p][0] = r0;     bf[2 * p][1] = r2;
                bf[2 * p + 1][0] = r1; bf[2 * p + 1][1] = r3;
            }
#pragma unroll
            for (int mi = 0; mi < 4; mi++)
#pragma unroll
                for (int ni = 0; ni < 8; ni++)
                    MMA_F16(acc[mi][ni], a[mi][0], a[mi][1], a[mi][2], a[mi][3],
                            bf[ni][0], bf[ni][1]);
        }
    }

    // ---- epilogue ----
    if (EPI <= 1) {
        float* C = (float*)Cv + cOff;
#pragma unroll
        for (int mi = 0; mi < 4; mi++) {
            long mrow = m0 + wm + mi * 16 + (lane >> 2);
            float* c0p = C + mrow * (long)ldc;
            float* c1p = c0p + 8L * ldc;
#pragma unroll
            for (int ni = 0; ni < 8; ni++) {
                long n = n0 + wn + ni * 8 + (lane & 3) * 2;
#pragma unroll
                for (int e = 0; e < 2; e++) {
                    long nn = n + e;
                    if (nn < (long)Nstore) {
                        float v0 = acc[mi][ni][e];
                        float v1 = acc[mi][ni][2 + e];
                        if (EPI >= 1) {
                            float bsv = Bias[biasOff + nn];
                            v0 += bsv; v1 += bsv;
                        }
                        c0p[nn] = v0;
                        c1p[nn] = v1;
                    }
                }
            }
        }
    } else if (EPI == 7) {
        __half* C2 = (__half*)Cv + cOff;
#pragma unroll
        for (int mi = 0; mi < 4; mi++) {
            long m = m0 + wm + mi * 16 + (lane >> 2);
#pragma unroll
            for (int ni = 0; ni < 8; ni++) {
                long n = n0 + wn + ni * 8 + (lane & 3) * 2;
                float b0 = Bias[biasOff + n];
                float b1 = Bias[biasOff + n + 1];
                C2[n * (long)ldc + m]           = __float2half(acc[mi][ni][0] + b0);
                C2[(n + 1) * (long)ldc + m]     = __float2half(acc[mi][ni][1] + b1);
                C2[n * (long)ldc + m + 8]       = __float2half(acc[mi][ni][2] + b0);
                C2[(n + 1) * (long)ldc + m + 8] = __float2half(acc[mi][ni][3] + b1);
            }
        }
    } else {
        __half* C2 = (__half*)Cv + cOff;
        const bool hasBias = (EPI == 3 || EPI == 6);
        const bool relu = (EPI == 6);
#pragma unroll
        for (int mi = 0; mi < 4; mi++) {
            long r0 = m0 + wm + mi * 16 + (lane >> 2);
            __half* p0 = C2 + r0 * (long)ldc;
            __half* p1 = p0 + 8L * ldc;
#pragma unroll
            for (int ni = 0; ni < 8; ni++) {
                long n = n0 + wn + ni * 8 + (lane & 3) * 2;
                float b0 = 0.f, b1 = 0.f;
                if (hasBias) { b0 = Bias[biasOff + n]; b1 = Bias[biasOff + n + 1]; }
                float v0 = acc[mi][ni][0] + b0, v1 = acc[mi][ni][1] + b1;
                float v2 = acc[mi][ni][2] + b0, v3 = acc[mi][ni][3] + b1;
                if (relu) {
                    v0 = fmaxf(v0, 0.f); v1 = fmaxf(v1, 0.f);
                    v2 = fmaxf(v2, 0.f); v3 = fmaxf(v3, 0.f);
                }
                *(__half2*)(p0 + n) = __halves2half2(__float2half(v0), __float2half(v1));
                *(__half2*)(p1 + n) = __halves2half2(__float2half(v2), __float2half(v3));
            }
        }
    }
}

// ---------------------------------------------------------------------------
// Host dispatch
// ---------------------------------------------------------------------------
static void tg(int epi, const __half* A, const __half* B, const float* Bias,
               void* C, int M, int N, int Kd, int lda, int ldb, int ldc,
               long sAb, long sAh, long sBb, long sBh, long sCb, long sCh,
               long sBiB, long sBiH, int Hn, int Z, int causal = 0)
{
    dim3 g(M / GBM, (N + GBN - 1) / GBN, Z), b(256);
#define HG_CALL(E) hgemm_kernel<E><<<g, b, HG_SMEM>>>(A, B, Bias, C, N, Kd, lda, ldb, ldc, \
    sAb, sAh, sBb, sBh, sCb, sCh, sBiB, sBiH, Hn, causal)
    switch (epi) {
    case 0: HG_CALL(0); break;
    case 1: HG_CALL(1); break;
    case 3: HG_CALL(3); break;
    case 5: HG_CALL(5); break;
    case 7: HG_CALL(7); break;
    default: HG_CALL(6); break;
    }
#undef HG_CALL
}

extern "C" void kernel_launch(void* const* d_in, const int* in_sizes, int n_in,
                              void* d_out, int out_size)
{
    const float* enc    = (const float*)d_in[0];
    const int*   srcpad = (const int*)  d_in[1];
    const int*   target = (const int*)  d_in[2];
    const float* emb    = (const float*)d_in[3];
    const float* Wq1 = (const float*)d_in[4],  *bq1 = (const float*)d_in[5];
    const float* Wk1 = (const float*)d_in[6],  *bk1 = (const float*)d_in[7];
    const float* Wv1 = (const float*)d_in[8],  *bv1 = (const float*)d_in[9];
    const float* Wo1 = (const float*)d_in[10], *bo1 = (const float*)d_in[11];
    const float* Wq2 = (const float*)d_in[12], *bq2 = (const float*)d_in[13];
    const float* Wk2 = (const float*)d_in[14], *bk2 = (const float*)d_in[15];
    const float* Wv2 = (const float*)d_in[16], *bv2 = (const float*)d_in[17];
    const float* Wo2 = (const float*)d_in[18], *bo2 = (const float*)d_in[19];
    const float* ln1g = (const float*)d_in[20];
    const float* ln2g = (const float*)d_in[21];
    const float* ln3g = (const float*)d_in[22];
    const float* ln1b = (const float*)d_in[23];
    const float* ln2b = (const float*)d_in[24];
    const float* ln3b = (const float*)d_in[25];
    const float* Wf1 = (const float*)d_in[26], *bf1 = (const float*)d_in[27];
    const float* Wf2 = (const float*)d_in[28], *bf2 = (const float*)d_in[29];
    const float* lmW = (const float*)d_in[30], *lmb = (const float*)d_in[31];
    float* out = (float*)d_out;

    float *x, *ss, *part, *bqk;
    cudaGetSymbolAddress((void**)&x,  g_x);
    cudaGetSymbolAddress((void**)&ss, g_s);
    cudaGetSymbolAddress((void**)&part, g_part);
    cudaGetSymbolAddress((void**)&bqk, g_bqk);
    __half *xeh, *qh, *vh, *sh, *oh, *fh, *wh, *lmh;
    cudaGetSymbolAddress((void**)&xeh, g_xeh);
    cudaGetSymbolAddress((void**)&qh, g_qh);
    cudaGetSymbolAddress((void**)&vh, g_vh);
    cudaGetSymbolAddress((void**)&sh, g_sh);
    cudaGetSymbolAddress((void**)&oh, g_oh);
    cudaGetSymbolAddress((void**)&fh, g_fh);
    cudaGetSymbolAddress((void**)&wh, g_wh);
    cudaGetSymbolAddress((void**)&lmh, g_lmh);
    __half* xh = xeh;
    __half* eh = xeh + (long)NR * 512;
    __half* kh = qh + 4096;

    cudaFuncSetAttribute(hgemm_kernel<0>, cudaFuncAttributeMaxDynamicSharedMemorySize, HG_SMEM);
    cudaFuncSetAttribute(hgemm_kernel<1>, cudaFuncAttributeMaxDynamicSharedMemorySize, HG_SMEM);
    cudaFuncSetAttribute(hgemm_kernel<3>, cudaFuncAttributeMaxDynamicSharedMemorySize, HG_SMEM);
    cudaFuncSetAttribute(hgemm_kernel<5>, cudaFuncAttributeMaxDynamicSharedMemorySize, HG_SMEM);
    cudaFuncSetAttribute(hgemm_kernel<6>, cudaFuncAttributeMaxDynamicSharedMemorySize, HG_SMEM);
    cudaFuncSetAttribute(hgemm_kernel<7>, cudaFuncAttributeMaxDynamicSharedMemorySize, HG_SMEM);

    const float scale = 1.0f / sqrtf((float)Dm);
    const long WATT = (long)Hh * Dm * Dm;
    const long WOUT = (long)HD * Dm;
    const long WFF  = (long)Dm * FFd;
    const dim3 tb(32, 8);

    embed_pe_kernel<<<NR, 512>>>(target, emb, x, xh);
    conv_enc_kernel<<<NR, 256>>>(enc, eh);

    for (int l = 0; l < 2; l++) {
        const float *WQ[2] = {Wq1 + l * WATT, Wq2 + l * WATT};
        const float *WK[2] = {Wk1 + l * WATT, Wk2 + l * WATT};
        const float *WV[2] = {Wv1 + l * WATT, Wv2 + l * WATT};
        const float *WO[2] = {Wo1 + l * WOUT, Wo2 + l * WOUT};
        const float *BQ[2] = {bq1 + l * HD, bq2 + l * HD};
        const float *BK[2] = {bk1 + l * HD, bk2 + l * HD};
        const float *BV[2] = {bv1 + l * HD, bv2 + l * HD};
        const float *BO[2] = {bo1 + l * Dm, bo2 + l * Dm};
        const float *LG[2] = {ln1g + l * Dm, ln2g + l * Dm};
        const float *LB[2] = {ln1b + l * Dm, ln2b + l * Dm};

        for (int att = 0; att < 2; att++) {
            const __half* kvA = (att == 0) ? xh : eh;

            // ---- stage Q||K bias ----
            cudaMemcpyAsync(bqk,      BQ[att], HD * sizeof(float), cudaMemcpyDeviceToDevice, 0);
            cudaMemcpyAsync(bqk + HD, BK[att], HD * sizeof(float), cudaMemcpyDeviceToDevice, 0);

            // ---- Q+K weight conversions into wh [Q at 0, K at 2M] ----
            conv_t_kernel<<<dim3(16, 16, 8), tb>>>(WQ[att], wh, Dm, Dm, Dm, 512,
                                                   0, (long)Dm * Dm, 0, (long)Dm * 512, 8);
            conv_t_kernel<<<dim3(16, 16, 8), tb>>>(WK[att], wh + 2097152, Dm, Dm, Dm, 512,
                                                   0, (long)Dm * Dm, 0, (long)Dm * 512, 8);

            // ---- merged Q+K projection: z=16 (zb: 0=Q from xh, 1=K from kvA) ----
            tg(3, xh, wh, bqk, qh, NR, Dm, 512, 512, 512, 8192,
               (att == 0) ? 0 : (long)NR * 512, 0,       // A: Q<-xh, K<-xh/eh
               2097152, (long)Dm * 512,                  // B: Q-block / K-block, per-head
               4096, 512,                                // C: Q cols / K cols
               HD, 512, 8, 16);

            // ---- V projection -> vh fp16, TRANSPOSED store (batched z=32) ----
            conv_t_kernel<<<dim3(16, 16, 8), tb>>>(WV[att], wh, Dm, Dm, Dm, 512,
                                                   0, (long)Dm * Dm, 0, (long)Dm * 512, 8);
            tg(7, kvA, wh, BV[att], vh, 512, Dm, 512, 512, 512, 512,
               (long)512 * 512, 0, 0, (long)Dm * 512,
               (long)Hh * 512 * 512, (long)512 * 512, 0, Dm, 8, 32);

            // ---- scores = Q K^T -> sh fp16 (causal tile-skip for self-att) ----
            tg(5, qh, kh, nullptr, sh, TTq, TSs, 512, 8192, 8192, 512,
               (long)TTq * 8192, 512, (long)TSs * 8192, 512,
               (long)Hh * TTq * 512, (long)TTq * 512, 0, 0, 8, 32,
               att == 0 ? 1 : 0);

            // ---- softmax in-place fp16; fp32 copy only for att0 ----
            int writeS = (att == 1 && l == 0) ? 1 : 0;
            softmax_kernel<<<Bq * Hh * TTq, 256>>>(sh, ss, writeS, target, srcpad,
                                                   att == 0 ? 1 : 2, scale);
            if (writeS && (long)out_size >= LOGITS_ELEMS + ATT_ELEMS) {
                cudaMemcpyAsync(out + LOGITS_ELEMS, ss, ATT_ELEMS * sizeof(float),
                                cudaMemcpyDeviceToDevice, 0);
            }

            // ---- O = S V -> oh fp16 (concat layout) ----
            tg(5, sh, vh, nullptr, oh, TTq, Dm, 512, 512, 512, 4096,
               (long)Hh * TTq * 512, (long)TTq * 512,
               (long)Hh * TSs * 512, (long)TSs * 512,
               (long)TTq * 4096, 512, 0, 0, 8, 32);

            // ---- output projection: split-K=8 + fused reduce+add+LN ----
            conv_t_kernel<<<dim3(16, 128, 1), tb>>>(WO[att], wh, HD, Dm, Dm, 4096,
                                                    0, 0, 0, 0, 1);
            tg(0, oh, wh, nullptr, part, NR, Dm, 512, 4096, 4096, Dm,
               0, 512, 0, 512, 0, (long)NR * Dm, 0, 0, SKn, SKn);
            reduce_ln_kernel<<<NR, 256>>>(part, BO[att], x, LG[att], LB[att], x, xh);
        }

        // ---- FFN ----
        conv_t_kernel<<<dim3(64, 16, 1), tb>>>(Wf1 + l * WFF, wh, Dm, FFd, FFd, 512,
                                               0, 0, 0, 0, 1);
        tg(6, xh, wh, bf1 + l * FFd, fh, NR, FFd, 512, 512, 512, 2048,
           0, 0, 0, 0, 0, 0, 0, 0, 1, 1);

        // ---- FF2: split-K=8 + fused reduce+add+LN ----
        conv_t_kernel<<<dim3(16, 64, 1), tb>>>(Wf2 + l * WFF, wh, FFd, Dm, Dm, 2048,
                                               0, 0, 0, 0, 1);
        tg(0, fh, wh, nullptr, part, NR, Dm, 256, 2048, 2048, Dm,
           0, 256, 0, 256, 0, (long)NR * Dm, 0, 0, SKn, SKn);
        reduce_ln_kernel<<<NR, 256>>>(part, bf2 + l * Dm, x, ln3g + l * Dm, ln3b + l * Dm, x, xh);
    }

    // ---- LM head (plain fp16) ----
    conv_t_kernel<<<dim3(1001, 16, 1), tb>>>(lmW, lmh, Dm, VO, VO, 512, 0, 0, 0, 0, 1);
    tg(1, xh, lmh, lmb, out, NR, VO, 512, 512, 512, VO,
       0, 0, 0, 0, 0, 0, 0, 0, 1, 1);
}

// round 12
// speedup vs baseline: 6.6176x; 1.0300x over previous
#include <cuda_runtime.h>
#include <cuda_fp16.h>
#include <math.h>
#include <stdint.h>

// ---------------------------------------------------------------------------
// Problem constants
// ---------------------------------------------------------------------------
#define Bq   4
#define TTq  512
#define TSs  512
#define Dm   512
#define Hh   8
#define Vv   32000
#define VO   32001
#define NR   2048
#define HD   4096
#define FFd  2048
#define SKn  8

#define LOGITS_ELEMS (2048LL * 32001LL)
#define ATT_ELEMS    (4LL * 8 * 512 * 512)

// ---------------------------------------------------------------------------
// Scratch (static device globals)
// ---------------------------------------------------------------------------
__device__ float g_x [NR * Dm];
__device__ float g_s [Bq * Hh * TTq * TSs];
__device__ float g_part[SKn * NR * Dm];
__device__ float g_bqk4[4 * 2 * HD];             // staged Q||K bias per block

__device__ __half g_xeh[2 * NR * 512];           // xh | eh
__device__ __half g_qh [NR * 8192];              // Q cols 0-4095, K cols 4096-8191
__device__ __half g_vh [32 * 512 * 512];
__device__ __half g_sh [32 * 512 * 512];
__device__ __half g_oh [NR * 4096];
__device__ __half g_fh [NR * 2048];
__device__ __half g_lmh[32256 * 512];            // rows padded; pads stay 0

// dedicated converted-weight buffers (block b = l*2 + att)
__device__ __half g_qkw[4 * 4194304];            // per block: Q 2M | K 2M halves
__device__ __half g_vw [4 * 2097152];
__device__ __half g_ow [4 * 2097152];
__device__ __half g_f1w[2 * 1048576];
__device__ __half g_f2w[2 * 1048576];

// ---------------------------------------------------------------------------
// Embedding + positional encoding -> x (fp32) and xh (fp16)
// ---------------------------------------------------------------------------
__global__ void embed_pe_kernel(const int* __restrict__ target,
                                const float* __restrict__ emb,
                                float* __restrict__ x,
                                __half* __restrict__ xh)
{
    int row = blockIdx.x;
    int t   = row & (TTq - 1);
    int d   = threadIdx.x;
    int tok = target[row];
    float e = emb[(long)tok * Dm + d];
    int   i = d >> 1;
    float denom = powf(10000.0f, (2.0f * (float)i) / (float)Dm);
    float z = (float)t / denom;
    float p = (d & 1) ? cosf(z) : sinf(z);
    float v = e + p;
    x[(long)row * Dm + d] = v;
    xh[(long)row * 512 + d] = __float2half(v);
}

__global__ void conv_enc_kernel(const float* __restrict__ in, __half* __restrict__ out)
{
    long idx = (long)blockIdx.x * blockDim.x + threadIdx.x;
    long r = idx >> 8;
    long k = (idx & 255) * 2;
    const float* p = in + r * Dm + k;
    __half2 h = __halves2half2(__float2half(p[0]), __float2half(p[1]));
    *(__half2*)(out + r * 512 + k) = h;
}

// ---------------------------------------------------------------------------
// Masked softmax, fp16 in-place; optional fp32 copy (att0).
// ---------------------------------------------------------------------------
__global__ void softmax_kernel(__half* __restrict__ Sh, float* __restrict__ S,
                               int writeS,
                               const int* __restrict__ target,
                               const int* __restrict__ srcpad,
                               int mode, float scale)
{
    int row = blockIdx.x;
    int q   = row & (TTq - 1);
    int b   = row / (Hh * TTq);
    __half* sr = Sh + (long)row * 512;
    int tid = threadIdx.x;
    bool qpad = (target[b * TTq + q] != Vv);

    float v[2];
    float mx = -INFINITY;
#pragma unroll
    for (int e = 0; e < 2; e++) {
        int k = tid + e * 256;
        bool valid;
        if (mode == 1)
            valid = qpad && (k <= q) && (target[b * TTq + k] != Vv);
        else
            valid = qpad && (srcpad[b * TSs + k] != 0);
        float val = valid ? __half2float(sr[k]) * scale : -1e32f;
        v[e] = val;
        mx = fmaxf(mx, val);
    }

    __shared__ float red[8];
#pragma unroll
    for (int o = 16; o > 0; o >>= 1) mx = fmaxf(mx, __shfl_xor_sync(0xffffffffu, mx, o));
    if ((tid & 31) == 0) red[tid >> 5] = mx;
    __syncthreads();
    if (tid < 32) {
        float r = (tid < 8) ? red[tid] : -INFINITY;
#pragma unroll
        for (int o = 4; o > 0; o >>= 1) r = fmaxf(r, __shfl_xor_sync(0xffffffffu, r, o));
        if (tid == 0) red[0] = r;
    }
    __syncthreads();
    mx = red[0];
    __syncthreads();

    float sum = 0.f;
#pragma unroll
    for (int e = 0; e < 2; e++) { v[e] = expf(v[e] - mx); sum += v[e]; }
#pragma unroll
    for (int o = 16; o > 0; o >>= 1) sum += __shfl_xor_sync(0xffffffffu, sum, o);
    if ((tid & 31) == 0) red[tid >> 5] = sum;
    __syncthreads();
    if (tid < 32) {
        float r = (tid < 8) ? red[tid] : 0.f;
#pragma unroll
        for (int o = 4; o > 0; o >>= 1) r += __shfl_xor_sync(0xffffffffu, r, o);
        if (tid == 0) red[0] = r;
    }
    __syncthreads();
    float inv = 1.0f / red[0];
    float* s32 = S + (long)row * TSs;
#pragma unroll
    for (int e = 0; e < 2; e++) {
        int k = tid + e * 256;
        float val = v[e] * inv;
        sr[k] = __float2half(val);
        if (writeS) s32[k] = val;
    }
}

// ---------------------------------------------------------------------------
// Fused split-K reduce + residual + LayerNorm
// ---------------------------------------------------------------------------
__global__ void reduce_ln_kernel(const float* __restrict__ part,
                                 const float* __restrict__ bias,
                                 const float* __restrict__ xin,
                                 const float* __restrict__ gg,
                                 const float* __restrict__ bb,
                                 float* __restrict__ y,
                                 __half* __restrict__ yh)
{
    int row = blockIdx.x;
    int tid = threadIdx.x;
    long base = (long)row * Dm;
    __shared__ float red[8];

    float v[2];
    float sum = 0.f;
#pragma unroll
    for (int e = 0; e < 2; e++) {
        int d = tid + e * 256;
        float s = xin[base + d] + bias[d];
#pragma unroll
        for (int c = 0; c < SKn; c++)
            s += part[(long)c * NR * Dm + base + d];
        v[e] = s;
        sum += s;
    }
#pragma unroll
    for (int o = 16; o > 0; o >>= 1) sum += __shfl_xor_sync(0xffffffffu, sum, o);
    if ((tid & 31) == 0) red[tid >> 5] = sum;
    __syncthreads();
    if (tid < 32) {
        float r = (tid < 8) ? red[tid] : 0.f;
#pragma unroll
        for (int o = 4; o > 0; o >>= 1) r += __shfl_xor_sync(0xffffffffu, r, o);
        if (tid == 0) red[0] = r;
    }
    __syncthreads();
    float m = red[0] * (1.0f / (float)Dm);
    __syncthreads();

    float vs = 0.f;
#pragma unroll
    for (int e = 0; e < 2; e++) { float c = v[e] - m; vs += c * c; }
#pragma unroll
    for (int o = 16; o > 0; o >>= 1) vs += __shfl_xor_sync(0xffffffffu, vs, o);
    if ((tid & 31) == 0) red[tid >> 5] = vs;
    __syncthreads();
    if (tid < 32) {
        float r = (tid < 8) ? red[tid] : 0.f;
#pragma unroll
        for (int o = 4; o > 0; o >>= 1) r += __shfl_xor_sync(0xffffffffu, r, o);
        if (tid == 0) red[0] = r;
    }
    __syncthreads();
    float var = red[0] * (1.0f / (float)Dm);
    float rs = rsqrtf(var + 1e-5f);
    __half* yhr = yh + (long)row * 512;
#pragma unroll
    for (int e = 0; e < 2; e++) {
        int d = tid + e * 256;
        float val = (v[e] - m) * rs * gg[d] + bb[d];
        y[base + d] = val;
        yhr[d] = __float2half(val);
    }
}

// ---------------------------------------------------------------------------
// conv_t: fp32 [K, N] (N-contig) -> fp16 [N, K] transposed. (weights)
// ---------------------------------------------------------------------------
__global__ void conv_t_kernel(const float* __restrict__ in, __half* __restrict__ out,
                              int K, int N, int in_ld, int out_ld,
                              long sInB, long sInH, long sOutB, long sOutH, int Hn)
{
    __shared__ float t[32][33];
    int z = blockIdx.z, zb = z / Hn, zh = z % Hn;
    in  += zb * sInB + zh * sInH;
    out += zb * sOutB + zh * sOutH;
    int k0 = blockIdx.y * 32, n0 = blockIdx.x * 32;
    int tx = threadIdx.x, ty = threadIdx.y;
#pragma unroll
    for (int i = 0; i < 4; ++i) {
        int k = k0 + ty + i * 8, n = n0 + tx;
        t[ty + i * 8][tx] = (n < N) ? in[(long)k * in_ld + n] : 0.f;
    }
    __syncthreads();
#pragma unroll
    for (int i = 0; i < 4; ++i) {
        int n = n0 + ty + i * 8, k = k0 + tx;
        if (n < N)
            out[(long)n * out_ld + k] = __float2half(t[tx][ty + i * 8]);
    }
}

// ---------------------------------------------------------------------------
// fp16 tensor-core GEMM (mma.sync m16n8k16 f16). CTA 128x256, 8 warps (2x4),
// warp tile 64x64, BK=32, 4-stage cp.async pipeline, one barrier per iter.
// EPI: 0 fp32 | 1 fp32+bias | 3 half+bias | 5 half | 6 half+bias+relu
//      7 half+bias TRANSPOSED store
// ---------------------------------------------------------------------------
#define GBM 128
#define GBN 256
#define GBK 32
#define NSTAGE 4
#define A_BYTES 10240
#define STAGE_BYTES 30720
#define HG_SMEM (NSTAGE * STAGE_BYTES)

__device__ __forceinline__ uint32_t smem_u32(const void* p) {
    uint32_t a;
    asm("{ .reg .u64 t; cvta.to.shared.u64 t, %1; cvt.u32.u64 %0, t; }" : "=r"(a) : "l"(p));
    return a;
}
#define CP16(dst, src) \
    asm volatile("cp.async.cg.shared.global [%0], [%1], 16;" :: "r"(dst), "l"(src))
#define CP_COMMIT() asm volatile("cp.async.commit_group;" ::: "memory")
#define CP_WAIT(n)  asm volatile("cp.async.wait_group %0;" :: "n"(n) : "memory")
#define LDSM_X4(r0, r1, r2, r3, addr) \
    asm volatile("ldmatrix.sync.aligned.m8n8.x4.shared.b16 {%0,%1,%2,%3}, [%4];" \
                 : "=r"(r0), "=r"(r1), "=r"(r2), "=r"(r3) : "r"(addr))
#define MMA_F16(c, a0, a1, a2, a3, b0, b1) \
    asm volatile("mma.sync.aligned.m16n8k16.row.col.f32.f16.f16.f32 " \
                 "{%0,%1,%2,%3}, {%4,%5,%6,%7}, {%8,%9}, {%0,%1,%2,%3};" \
                 : "+f"((c)[0]), "+f"((c)[1]), "+f"((c)[2]), "+f"((c)[3]) \
                 : "r"(a0), "r"(a1), "r"(a2), "r"(a3), "r"(b0), "r"(b1))

template<int EPI>
__global__ void __launch_bounds__(256, 1)
hgemm_kernel(const __half* __restrict__ A2, const __half* __restrict__ B2,
             const float* __restrict__ Bias, void* __restrict__ Cv,
             int Nstore, int Kd, int lda, int ldb, int ldc,
             long sAb, long sAh, long sBb, long sBh, long sCb, long sCh,
             long sBiB, long sBiH, int Hn, int causal)
{
    extern __shared__ __align__(16) char dsm[];
    const uint32_t base = smem_u32(dsm);

    int tid = threadIdx.x;
    int wid = tid >> 5, lane = tid & 31;

    long m0 = (long)blockIdx.x * GBM;
    long n0 = (long)blockIdx.y * GBN;
    if (causal && n0 > m0 + (GBM - 1)) return;

    int z = blockIdx.z, zb = z / Hn, zh = z % Hn;
    A2 += zb * sAb + zh * sAh;
    B2 += zb * sBb + zh * sBh;
    long cOff = zb * sCb + zh * sCh;
    long biasOff = zb * sBiB + zh * sBiH;

    const int wm = (wid >> 2) * 64;
    const int wn = (wid & 3) * 64;

    float acc[4][8][4];
#pragma unroll
    for (int i = 0; i < 4; i++)
#pragma unroll
        for (int j = 0; j < 8; j++)
#pragma unroll
            for (int q = 0; q < 4; q++) acc[i][j][q] = 0.f;

    const int nIter = Kd / GBK;

    const int lr  = tid >> 2;
    const int lsg = tid & 3;
    const long aRow0 = m0 + lr,  aRow1 = m0 + lr + 64;
    const uint32_t sOff0 = (uint32_t)(lr * 80 + lsg * 16);
    const uint32_t sOff1 = (uint32_t)((lr + 64) * 80 + lsg * 16);
    const uint32_t sOff2 = (uint32_t)((lr + 128) * 80 + lsg * 16);
    const uint32_t sOff3 = (uint32_t)((lr + 192) * 80 + lsg * 16);

    auto loadStage = [&](int slot, long k0) {
        uint32_t aD = base + slot * STAGE_BYTES;
        uint32_t bD = aD + A_BYTES;
        long ko = k0 + lsg * 8;
        CP16(aD + sOff0, A2 + aRow0 * (long)lda + ko);
        CP16(aD + sOff1, A2 + aRow1 * (long)lda + ko);
        CP16(bD + sOff0, B2 + (n0 + lr) * (long)ldb + ko);
        CP16(bD + sOff1, B2 + (n0 + lr + 64) * (long)ldb + ko);
        CP16(bD + sOff2, B2 + (n0 + lr + 128) * (long)ldb + ko);
        CP16(bD + sOff3, B2 + (n0 + lr + 192) * (long)ldb + ko);
        CP_COMMIT();
    };

    loadStage(0, 0);
    if (nIter > 1) loadStage(1, GBK); else CP_COMMIT();
    if (nIter > 2) loadStage(2, 2L * GBK); else CP_COMMIT();

    for (int it = 0; it < nIter; ++it) {
        if (it + 2 < nIter)      CP_WAIT(2);
        else if (it + 1 < nIter) CP_WAIT(1);
        else                     CP_WAIT(0);
        __syncthreads();
        if (it + 3 < nIter) loadStage((it + 3) & (NSTAGE - 1), (long)(it + 3) * GBK);

        uint32_t aS = base + (it & (NSTAGE - 1)) * STAGE_BYTES;
        uint32_t bS = aS + A_BYTES;
#pragma unroll
        for (int ks = 0; ks < 2; ks++) {
            int col = ks * 16 + (lane >> 4) * 8;
            uint32_t a[4][4], bf[8][2];
#pragma unroll
            for (int mi = 0; mi < 4; mi++) {
                int row = wm + mi * 16 + (lane & 15);
                LDSM_X4(a[mi][0], a[mi][1], a[mi][2], a[mi][3],
                        aS + (uint32_t)(row * 80 + col * 2));
            }
#pragma unroll
            for (int p = 0; p < 4; p++) {
                int row = wn + p * 16 + (lane & 15);
                uint32_t r0, r1, r2, r3;
                LDSM_X4(r0, r1, r2, r3, bS + (uint32_t)(row * 80 + col * 2));
                bf[2 * p][0] = r0;     bf[2 * p][1] = r2;
                bf[2 * p + 1][0] = r1; bf[2 * p + 1][1] = r3;
            }
#pragma unroll
            for (int mi = 0; mi < 4; mi++)
#pragma unroll
                for (int ni = 0; ni < 8; ni++)
                    MMA_F16(acc[mi][ni], a[mi][0], a[mi][1], a[mi][2], a[mi][3],
                            bf[ni][0], bf[ni][1]);
        }
    }

    // ---- epilogue ----
    if (EPI <= 1) {
        float* C = (float*)Cv + cOff;
#pragma unroll
        for (int mi = 0; mi < 4; mi++) {
            long mrow = m0 + wm + mi * 16 + (lane >> 2);
            float* c0p = C + mrow * (long)ldc;
            float* c1p = c0p + 8L * ldc;
#pragma unroll
            for (int ni = 0; ni < 8; ni++) {
                long n = n0 + wn + ni * 8 + (lane & 3) * 2;
#pragma unroll
                for (int e = 0; e < 2; e++) {
                    long nn = n + e;
                    if (nn < (long)Nstore) {
                        float v0 = acc[mi][ni][e];
                        float v1 = acc[mi][ni][2 + e];
                        if (EPI >= 1) {
                            float bsv = Bias[biasOff + nn];
                            v0 += bsv; v1 += bsv;
                        }
                        c0p[nn] = v0;
                        c1p[nn] = v1;
                    }
                }
            }
        }
    } else if (EPI == 7) {
        __half* C2 = (__half*)Cv + cOff;
#pragma unroll
        for (int mi = 0; mi < 4; mi++) {
            long m = m0 + wm + mi * 16 + (lane >> 2);
#pragma unroll
            for (int ni = 0; ni < 8; ni++) {
                long n = n0 + wn + ni * 8 + (lane & 3) * 2;
                float b0 = Bias[biasOff + n];
                float b1 = Bias[biasOff + n + 1];
                C2[n * (long)ldc + m]           = __float2half(acc[mi][ni][0] + b0);
                C2[(n + 1) * (long)ldc + m]     = __float2half(acc[mi][ni][1] + b1);
                C2[n * (long)ldc + m + 8]       = __float2half(acc[mi][ni][2] + b0);
                C2[(n + 1) * (long)ldc + m + 8] = __float2half(acc[mi][ni][3] + b1);
            }
        }
    } else {
        __half* C2 = (__half*)Cv + cOff;
        const bool hasBias = (EPI == 3 || EPI == 6);
        const bool relu = (EPI == 6);
#pragma unroll
        for (int mi = 0; mi < 4; mi++) {
            long r0 = m0 + wm + mi * 16 + (lane >> 2);
            __half* p0 = C2 + r0 * (long)ldc;
            __half* p1 = p0 + 8L * ldc;
#pragma unroll
            for (int ni = 0; ni < 8; ni++) {
                long n = n0 + wn + ni * 8 + (lane & 3) * 2;
                float b0 = 0.f, b1 = 0.f;
                if (hasBias) { b0 = Bias[biasOff + n]; b1 = Bias[biasOff + n + 1]; }
                float v0 = acc[mi][ni][0] + b0, v1 = acc[mi][ni][1] + b1;
                float v2 = acc[mi][ni][2] + b0, v3 = acc[mi][ni][3] + b1;
                if (relu) {
                    v0 = fmaxf(v0, 0.f); v1 = fmaxf(v1, 0.f);
                    v2 = fmaxf(v2, 0.f); v3 = fmaxf(v3, 0.f);
                }
                *(__half2*)(p0 + n) = __halves2half2(__float2half(v0), __float2half(v1));
                *(__half2*)(p1 + n) = __halves2half2(__float2half(v2), __float2half(v3));
            }
        }
    }
}

// ---------------------------------------------------------------------------
// Host dispatch
// ---------------------------------------------------------------------------
static void tg(int epi, const __half* A, const __half* B, const float* Bias,
               void* C, int M, int N, int Kd, int lda, int ldb, int ldc,
               long sAb, long sAh, long sBb, long sBh, long sCb, long sCh,
               long sBiB, long sBiH, int Hn, int Z, int causal = 0)
{
    dim3 g(M / GBM, (N + GBN - 1) / GBN, Z), b(256);
#define HG_CALL(E) hgemm_kernel<E><<<g, b, HG_SMEM>>>(A, B, Bias, C, N, Kd, lda, ldb, ldc, \
    sAb, sAh, sBb, sBh, sCb, sCh, sBiB, sBiH, Hn, causal)
    switch (epi) {
    case 0: HG_CALL(0); break;
    case 1: HG_CALL(1); break;
    case 3: HG_CALL(3); break;
    case 5: HG_CALL(5); break;
    case 7: HG_CALL(7); break;
    default: HG_CALL(6); break;
    }
#undef HG_CALL
}

// side-stream handles: created once on the first (uncaptured, correctness) call.
// Work enqueued is IDENTICAL on every call — determinism preserved.
static cudaStream_t g_s2 = nullptr;
static cudaEvent_t  g_ev[18];
// indices: QK[b]=b (0-3), V[b]=4+b, O[b]=8+b, F1[l]=12+l, F2[l]=14+l, LM=16, fork=17

extern "C" void kernel_launch(void* const* d_in, const int* in_sizes, int n_in,
                              void* d_out, int out_size)
{
    const float* enc    = (const float*)d_in[0];
    const int*   srcpad = (const int*)  d_in[1];
    const int*   target = (const int*)  d_in[2];
    const float* emb    = (const float*)d_in[3];
    const float* Wq1 = (const float*)d_in[4],  *bq1 = (const float*)d_in[5];
    const float* Wk1 = (const float*)d_in[6],  *bk1 = (const float*)d_in[7];
    const float* Wv1 = (const float*)d_in[8],  *bv1 = (const float*)d_in[9];
    const float* Wo1 = (const float*)d_in[10], *bo1 = (const float*)d_in[11];
    const float* Wq2 = (const float*)d_in[12], *bq2 = (const float*)d_in[13];
    const float* Wk2 = (const float*)d_in[14], *bk2 = (const float*)d_in[15];
    const float* Wv2 = (const float*)d_in[16], *bv2 = (const float*)d_in[17];
    const float* Wo2 = (const float*)d_in[18], *bo2 = (const float*)d_in[19];
    const float* ln1g = (const float*)d_in[20];
    const float* ln2g = (const float*)d_in[21];
    const float* ln3g = (const float*)d_in[22];
    const float* ln1b = (const float*)d_in[23];
    const float* ln2b = (const float*)d_in[24];
    const float* ln3b = (const float*)d_in[25];
    const float* Wf1 = (const float*)d_in[26], *bf1 = (const float*)d_in[27];
    const float* Wf2 = (const float*)d_in[28], *bf2 = (const float*)d_in[29];
    const float* lmW = (const float*)d_in[30], *lmb = (const float*)d_in[31];
    float* out = (float*)d_out;

    if (!g_s2) {
        cudaStreamCreateWithFlags(&g_s2, cudaStreamNonBlocking);
        for (int i = 0; i < 18; i++)
            cudaEventCreateWithFlags(&g_ev[i], cudaEventDisableTiming);
    }

    float *x, *ss, *part, *bqk4;
    cudaGetSymbolAddress((void**)&x,  g_x);
    cudaGetSymbolAddress((void**)&ss, g_s);
    cudaGetSymbolAddress((void**)&part, g_part);
    cudaGetSymbolAddress((void**)&bqk4, g_bqk4);
    __half *xeh, *qh, *vh, *sh, *oh, *fh, *lmh, *qkw, *vw, *ow, *f1w, *f2w;
    cudaGetSymbolAddress((void**)&xeh, g_xeh);
    cudaGetSymbolAddress((void**)&qh, g_qh);
    cudaGetSymbolAddress((void**)&vh, g_vh);
    cudaGetSymbolAddress((void**)&sh, g_sh);
    cudaGetSymbolAddress((void**)&oh, g_oh);
    cudaGetSymbolAddress((void**)&fh, g_fh);
    cudaGetSymbolAddress((void**)&lmh, g_lmh);
    cudaGetSymbolAddress((void**)&qkw, g_qkw);
    cudaGetSymbolAddress((void**)&vw, g_vw);
    cudaGetSymbolAddress((void**)&ow, g_ow);
    cudaGetSymbolAddress((void**)&f1w, g_f1w);
    cudaGetSymbolAddress((void**)&f2w, g_f2w);
    __half* xh = xeh;
    __half* eh = xeh + (long)NR * 512;
    __half* kh = qh + 4096;

    cudaFuncSetAttribute(hgemm_kernel<0>, cudaFuncAttributeMaxDynamicSharedMemorySize, HG_SMEM);
    cudaFuncSetAttribute(hgemm_kernel<1>, cudaFuncAttributeMaxDynamicSharedMemorySize, HG_SMEM);
    cudaFuncSetAttribute(hgemm_kernel<3>, cudaFuncAttributeMaxDynamicSharedMemorySize, HG_SMEM);
    cudaFuncSetAttribute(hgemm_kernel<5>, cudaFuncAttributeMaxDynamicSharedMemorySize, HG_SMEM);
    cudaFuncSetAttribute(hgemm_kernel<6>, cudaFuncAttributeMaxDynamicSharedMemorySize, HG_SMEM);
    cudaFuncSetAttribute(hgemm_kernel<7>, cudaFuncAttributeMaxDynamicSharedMemorySize, HG_SMEM);

    const float scale = 1.0f / sqrtf((float)Dm);
    const long WATT = (long)Hh * Dm * Dm;
    const long WOUT = (long)HD * Dm;
    const long WFF  = (long)Dm * FFd;
    const dim3 tb(32, 8);

    const float *WQ[2][2] = {{Wq1, Wq1 + WATT}, {Wq2, Wq2 + WATT}};
    const float *WK[2][2] = {{Wk1, Wk1 + WATT}, {Wk2, Wk2 + WATT}};
    const float *WV[2][2] = {{Wv1, Wv1 + WATT}, {Wv2, Wv2 + WATT}};
    const float *WO[2][2] = {{Wo1, Wo1 + WOUT}, {Wo2, Wo2 + WOUT}};
    const float *BQ[2][2] = {{bq1, bq1 + HD}, {bq2, bq2 + HD}};
    const float *BK[2][2] = {{bk1, bk1 + HD}, {bk2, bk2 + HD}};
    const float *BV[2][2] = {{bv1, bv1 + HD}, {bv2, bv2 + HD}};
    const float *BO[2][2] = {{bo1, bo1 + Dm}, {bo2, bo2 + Dm}};
    const float *LG[2][2] = {{ln1g, ln1g + Dm}, {ln2g, ln2g + Dm}};
    const float *LB[2][2] = {{ln1b, ln1b + Dm}, {ln2b, ln2b + Dm}};

    // ===================== side stream: all weight conversions =====================
    cudaEventRecord(g_ev[17], 0);
    cudaStreamWaitEvent(g_s2, g_ev[17], 0);
    for (int l = 0; l < 2; l++) {
        for (int att = 0; att < 2; att++) {
            int b = l * 2 + att;
            cudaMemcpyAsync(bqk4 + b * 2 * HD,      BQ[att][l], HD * sizeof(float),
                            cudaMemcpyDeviceToDevice, g_s2);
            cudaMemcpyAsync(bqk4 + b * 2 * HD + HD, BK[att][l], HD * sizeof(float),
                            cudaMemcpyDeviceToDevice, g_s2);
            conv_t_kernel<<<dim3(16, 16, 8), tb, 0, g_s2>>>(WQ[att][l], qkw + (long)b * 4194304,
                Dm, Dm, Dm, 512, 0, (long)Dm * Dm, 0, (long)Dm * 512, 8);
            conv_t_kernel<<<dim3(16, 16, 8), tb, 0, g_s2>>>(WK[att][l], qkw + (long)b * 4194304 + 2097152,
                Dm, Dm, Dm, 512, 0, (long)Dm * Dm, 0, (long)Dm * 512, 8);
            cudaEventRecord(g_ev[b], g_s2);
            conv_t_kernel<<<dim3(16, 16, 8), tb, 0, g_s2>>>(WV[att][l], vw + (long)b * 2097152,
                Dm, Dm, Dm, 512, 0, (long)Dm * Dm, 0, (long)Dm * 512, 8);
            cudaEventRecord(g_ev[4 + b], g_s2);
            conv_t_kernel<<<dim3(16, 128, 1), tb, 0, g_s2>>>(WO[att][l], ow + (long)b * 2097152,
                HD, Dm, Dm, 4096, 0, 0, 0, 0, 1);
            cudaEventRecord(g_ev[8 + b], g_s2);
        }
        conv_t_kernel<<<dim3(64, 16, 1), tb, 0, g_s2>>>(Wf1 + l * WFF, f1w + (long)l * 1048576,
            Dm, FFd, FFd, 512, 0, 0, 0, 0, 1);
        cudaEventRecord(g_ev[12 + l], g_s2);
        conv_t_kernel<<<dim3(16, 64, 1), tb, 0, g_s2>>>(Wf2 + l * WFF, f2w + (long)l * 1048576,
            FFd, Dm, Dm, 2048, 0, 0, 0, 0, 1);
        cudaEventRecord(g_ev[14 + l], g_s2);
    }
    conv_t_kernel<<<dim3(1001, 16, 1), tb, 0, g_s2>>>(lmW, lmh, Dm, VO, VO, 512, 0, 0, 0, 0, 1);
    cudaEventRecord(g_ev[16], g_s2);

    // ===================== main chain =====================
    embed_pe_kernel<<<NR, 512>>>(target, emb, x, xh);
    conv_enc_kernel<<<NR, 256>>>(enc, eh);

    for (int l = 0; l < 2; l++) {
        for (int att = 0; att < 2; att++) {
            int b = l * 2 + att;
            const __half* kvA = (att == 0) ? xh : eh;

            // ---- merged Q+K projection: z=16 (zb: 0=Q from xh, 1=K from kvA) ----
            cudaStreamWaitEvent(0, g_ev[b], 0);
            tg(3, xh, qkw + (long)b * 4194304, bqk4 + b * 2 * HD, qh,
               NR, Dm, 512, 512, 512, 8192,
               (att == 0) ? 0 : (long)NR * 512, 0,
               2097152, (long)Dm * 512,
               4096, 512,
               HD, 512, 8, 16);

            // ---- V projection -> vh fp16, TRANSPOSED (batched z=32) ----
            cudaStreamWaitEvent(0, g_ev[4 + b], 0);
            tg(7, kvA, vw + (long)b * 2097152, BV[att][l], vh, 512, Dm, 512, 512, 512, 512,
               (long)512 * 512, 0, 0, (long)Dm * 512,
               (long)Hh * 512 * 512, (long)512 * 512, 0, Dm, 8, 32);

            // ---- scores = Q K^T -> sh fp16 (causal tile-skip for self-att) ----
            tg(5, qh, kh, nullptr, sh, TTq, TSs, 512, 8192, 8192, 512,
               (long)TTq * 8192, 512, (long)TSs * 8192, 512,
               (long)Hh * TTq * 512, (long)TTq * 512, 0, 0, 8, 32,
               att == 0 ? 1 : 0);

            int writeS = (att == 1 && l == 0) ? 1 : 0;
            softmax_kernel<<<Bq * Hh * TTq, 256>>>(sh, ss, writeS, target, srcpad,
                                                   att == 0 ? 1 : 2, scale);
            if (writeS && (long)out_size >= LOGITS_ELEMS + ATT_ELEMS) {
                cudaMemcpyAsync(out + LOGITS_ELEMS, ss, ATT_ELEMS * sizeof(float),
                                cudaMemcpyDeviceToDevice, 0);
            }

            // ---- O = S V -> oh fp16 (concat layout) ----
            tg(5, sh, vh, nullptr, oh, TTq, Dm, 512, 512, 512, 4096,
               (long)Hh * TTq * 512, (long)TTq * 512,
               (long)Hh * TSs * 512, (long)TSs * 512,
               (long)TTq * 4096, 512, 0, 0, 8, 32);

            // ---- output projection: split-K=8 + fused reduce+add+LN ----
            cudaStreamWaitEvent(0, g_ev[8 + b], 0);
            tg(0, oh, ow + (long)b * 2097152, nullptr, part, NR, Dm, 512, 4096, 4096, Dm,
               0, 512, 0, 512, 0, (long)NR * Dm, 0, 0, SKn, SKn);
            reduce_ln_kernel<<<NR, 256>>>(part, BO[att][l], x, LG[att][l], LB[att][l], x, xh);
        }

        // ---- FFN ----
        cudaStreamWaitEvent(0, g_ev[12 + l], 0);
        tg(6, xh, f1w + (long)l * 1048576, bf1 + l * FFd, fh, NR, FFd, 512, 512, 512, 2048,
           0, 0, 0, 0, 0, 0, 0, 0, 1, 1);

        cudaStreamWaitEvent(0, g_ev[14 + l], 0);
        tg(0, fh, f2w + (long)l * 1048576, nullptr, part, NR, Dm, 256, 2048, 2048, Dm,
           0, 256, 0, 256, 0, (long)NR * Dm, 0, 0, SKn, SKn);
        reduce_ln_kernel<<<NR, 256>>>(part, bf2 + l * Dm, x, ln3g + l * Dm, ln3b + l * Dm, x, xh);
    }

    // ---- LM head ----
    cudaStreamWaitEvent(0, g_ev[16], 0);
    tg(1, xh, lmh, lmb, out, NR, VO, 512, 512, 512, VO,
       0, 0, 0, 0, 0, 0, 0, 0, 1, 1);
}

// round 14
// speedup vs baseline: 6.8871x; 1.0407x over previous
#include <cuda_runtime.h>
#include <cuda_fp16.h>
#include <math.h>
#include <stdint.h>

// ---------------------------------------------------------------------------
// Problem constants
// ---------------------------------------------------------------------------
#define Bq   4
#define TTq  512
#define TSs  512
#define Dm   512
#define Hh   8
#define Vv   32000
#define VO   32001
#define NR   2048
#define HD   4096
#define FFd  2048
#define SKn  8

#define LOGITS_ELEMS (2048LL * 32001LL)
#define ATT_ELEMS    (4LL * 8 * 512 * 512)
#define VHSZ (32L * 512 * 512)

// ---------------------------------------------------------------------------
// Scratch (static device globals)
// ---------------------------------------------------------------------------
__device__ float g_x [NR * Dm];
__device__ float g_s [Bq * Hh * TTq * TSs];
__device__ float g_part[SKn * NR * Dm];
__device__ float g_bqk4[4 * 2 * HD];

__device__ __half g_xeh[2 * NR * 512];           // xh | eh
__device__ __half g_qh [NR * 8192];              // Q cols 0-4095, K cols 4096-8191
__device__ __half g_vh [4 * VHSZ];               // per-block V (no reuse hazards)
__device__ __half g_sh [32 * 512 * 512];
__device__ __half g_oh [NR * 4096];
__device__ __half g_fh [NR * 2048];
__device__ __half g_lmh[32256 * 512];

// dedicated converted-weight buffers (block b = l*2 + att)
__device__ __half g_qkw[4 * 4194304];
__device__ __half g_vw [4 * 2097152];
__device__ __half g_ow [4 * 2097152];
__device__ __half g_f1w[2 * 1048576];
__device__ __half g_f2w[2 * 1048576];

// ---------------------------------------------------------------------------
// Embedding + positional encoding -> x (fp32) and xh (fp16)
// ---------------------------------------------------------------------------
__global__ void embed_pe_kernel(const int* __restrict__ target,
                                const float* __restrict__ emb,
                                float* __restrict__ x,
                                __half* __restrict__ xh)
{
    int row = blockIdx.x;
    int t   = row & (TTq - 1);
    int d   = threadIdx.x;
    int tok = target[row];
    float e = emb[(long)tok * Dm + d];
    int   i = d >> 1;
    float denom = powf(10000.0f, (2.0f * (float)i) / (float)Dm);
    float z = (float)t / denom;
    float p = (d & 1) ? cosf(z) : sinf(z);
    float v = e + p;
    x[(long)row * Dm + d] = v;
    xh[(long)row * 512 + d] = __float2half(v);
}

__global__ void conv_enc_kernel(const float* __restrict__ in, __half* __restrict__ out)
{
    long idx = (long)blockIdx.x * blockDim.x + threadIdx.x;
    long r = idx >> 8;
    long k = (idx & 255) * 2;
    const float* p = in + r * Dm + k;
    __half2 h = __halves2half2(__float2half(p[0]), __float2half(p[1]));
    *(__half2*)(out + r * 512 + k) = h;
}

// ---------------------------------------------------------------------------
// Masked softmax, fp16 in-place; optional fp32 copy (att0).
// ---------------------------------------------------------------------------
__global__ void softmax_kernel(__half* __restrict__ Sh, float* __restrict__ S,
                               int writeS,
                               const int* __restrict__ target,
                               const int* __restrict__ srcpad,
                               int mode, float scale)
{
    int row = blockIdx.x;
    int q   = row & (TTq - 1);
    int b   = row / (Hh * TTq);
    __half* sr = Sh + (long)row * 512;
    int tid = threadIdx.x;
    bool qpad = (target[b * TTq + q] != Vv);

    float v[2];
    float mx = -INFINITY;
#pragma unroll
    for (int e = 0; e < 2; e++) {
        int k = tid + e * 256;
        bool valid;
        if (mode == 1)
            valid = qpad && (k <= q) && (target[b * TTq + k] != Vv);
        else
            valid = qpad && (srcpad[b * TSs + k] != 0);
        float val = valid ? __half2float(sr[k]) * scale : -1e32f;
        v[e] = val;
        mx = fmaxf(mx, val);
    }

    __shared__ float red[8];
#pragma unroll
    for (int o = 16; o > 0; o >>= 1) mx = fmaxf(mx, __shfl_xor_sync(0xffffffffu, mx, o));
    if ((tid & 31) == 0) red[tid >> 5] = mx;
    __syncthreads();
    if (tid < 32) {
        float r = (tid < 8) ? red[tid] : -INFINITY;
#pragma unroll
        for (int o = 4; o > 0; o >>= 1) r = fmaxf(r, __shfl_xor_sync(0xffffffffu, r, o));
        if (tid == 0) red[0] = r;
    }
    __syncthreads();
    mx = red[0];
    __syncthreads();

    float sum = 0.f;
#pragma unroll
    for (int e = 0; e < 2; e++) { v[e] = expf(v[e] - mx); sum += v[e]; }
#pragma unroll
    for (int o = 16; o > 0; o >>= 1) sum += __shfl_xor_sync(0xffffffffu, sum, o);
    if ((tid & 31) == 0) red[tid >> 5] = sum;
    __syncthreads();
    if (tid < 32) {
        float r = (tid < 8) ? red[tid] : 0.f;
#pragma unroll
        for (int o = 4; o > 0; o >>= 1) r += __shfl_xor_sync(0xffffffffu, r, o);
        if (tid == 0) red[0] = r;
    }
    __syncthreads();
    float inv = 1.0f / red[0];
    float* s32 = S + (long)row * TSs;
#pragma unroll
    for (int e = 0; e < 2; e++) {
        int k = tid + e * 256;
        float val = v[e] * inv;
        sr[k] = __float2half(val);
        if (writeS) s32[k] = val;
    }
}

// ---------------------------------------------------------------------------
// Fused split-K reduce + residual + LayerNorm
// ---------------------------------------------------------------------------
__global__ void reduce_ln_kernel(const float* __restrict__ part,
                                 const float* __restrict__ bias,
                                 const float* __restrict__ xin,
                                 const float* __restrict__ gg,
                                 const float* __restrict__ bb,
                                 float* __restrict__ y,
                                 __half* __restrict__ yh)
{
    int row = blockIdx.x;
    int tid = threadIdx.x;
    long base = (long)row * Dm;
    __shared__ float red[8];

    float v[2];
    float sum = 0.f;
#pragma unroll
    for (int e = 0; e < 2; e++) {
        int d = tid + e * 256;
        float s = xin[base + d] + bias[d];
#pragma unroll
        for (int c = 0; c < SKn; c++)
            s += part[(long)c * NR * Dm + base + d];
        v[e] = s;
        sum += s;
    }
#pragma unroll
    for (int o = 16; o > 0; o >>= 1) sum += __shfl_xor_sync(0xffffffffu, sum, o);
    if ((tid & 31) == 0) red[tid >> 5] = sum;
    __syncthreads();
    if (tid < 32) {
        float r = (tid < 8) ? red[tid] : 0.f;
#pragma unroll
        for (int o = 4; o > 0; o >>= 1) r += __shfl_xor_sync(0xffffffffu, r, o);
        if (tid == 0) red[0] = r;
    }
    __syncthreads();
    float m = red[0] * (1.0f / (float)Dm);
    __syncthreads();

    float vs = 0.f;
#pragma unroll
    for (int e = 0; e < 2; e++) { float c = v[e] - m; vs += c * c; }
#pragma unroll
    for (int o = 16; o > 0; o >>= 1) vs += __shfl_xor_sync(0xffffffffu, vs, o);
    if ((tid & 31) == 0) red[tid >> 5] = vs;
    __syncthreads();
    if (tid < 32) {
        float r = (tid < 8) ? red[tid] : 0.f;
#pragma unroll
        for (int o = 4; o > 0; o >>= 1) r += __shfl_xor_sync(0xffffffffu, r, o);
        if (tid == 0) red[0] = r;
    }
    __syncthreads();
    float var = red[0] * (1.0f / (float)Dm);
    float rs = rsqrtf(var + 1e-5f);
    __half* yhr = yh + (long)row * 512;
#pragma unroll
    for (int e = 0; e < 2; e++) {
        int d = tid + e * 256;
        float val = (v[e] - m) * rs * gg[d] + bb[d];
        y[base + d] = val;
        yhr[d] = __float2half(val);
    }
}

// ---------------------------------------------------------------------------
// conv_t: fp32 [K, N] (N-contig) -> fp16 [N, K] transposed. (weights)
// ---------------------------------------------------------------------------
__global__ void conv_t_kernel(const float* __restrict__ in, __half* __restrict__ out,
                              int K, int N, int in_ld, int out_ld,
                              long sInB, long sInH, long sOutB, long sOutH, int Hn)
{
    __shared__ float t[32][33];
    int z = blockIdx.z, zb = z / Hn, zh = z % Hn;
    in  += zb * sInB + zh * sInH;
    out += zb * sOutB + zh * sOutH;
    int k0 = blockIdx.y * 32, n0 = blockIdx.x * 32;
    int tx = threadIdx.x, ty = threadIdx.y;
#pragma unroll
    for (int i = 0; i < 4; ++i) {
        int k = k0 + ty + i * 8, n = n0 + tx;
        t[ty + i * 8][tx] = (n < N) ? in[(long)k * in_ld + n] : 0.f;
    }
    __syncthreads();
#pragma unroll
    for (int i = 0; i < 4; ++i) {
        int n = n0 + ty + i * 8, k = k0 + tx;
        if (n < N)
            out[(long)n * out_ld + k] = __float2half(t[tx][ty + i * 8]);
    }
}

// ---------------------------------------------------------------------------
// fp16 tensor-core GEMM (mma.sync m16n8k16 f16). CTA 128x256, 8 warps (2x4),
// warp tile 64x64, BK=32, 4-stage cp.async pipeline, one barrier per iter.
// EPI: 0 fp32 | 1 fp32+bias | 3 half+bias | 5 half | 6 half+bias+relu
//      7 half+bias TRANSPOSED store
// ---------------------------------------------------------------------------
#define GBM 128
#define GBN 256
#define GBK 32
#define NSTAGE 4
#define A_BYTES 10240
#define STAGE_BYTES 30720
#define HG_SMEM (NSTAGE * STAGE_BYTES)

__device__ __forceinline__ uint32_t smem_u32(const void* p) {
    uint32_t a;
    asm("{ .reg .u64 t; cvta.to.shared.u64 t, %1; cvt.u32.u64 %0, t; }" : "=r"(a) : "l"(p));
    return a;
}
#define CP16(dst, src) \
    asm volatile("cp.async.cg.shared.global [%0], [%1], 16;" :: "r"(dst), "l"(src))
#define CP_COMMIT() asm volatile("cp.async.commit_group;" ::: "memory")
#define CP_WAIT(n)  asm volatile("cp.async.wait_group %0;" :: "n"(n) : "memory")
#define LDSM_X4(r0, r1, r2, r3, addr) \
    asm volatile("ldmatrix.sync.aligned.m8n8.x4.shared.b16 {%0,%1,%2,%3}, [%4];" \
                 : "=r"(r0), "=r"(r1), "=r"(r2), "=r"(r3) : "r"(addr))
#define MMA_F16(c, a0, a1, a2, a3, b0, b1) \
    asm volatile("mma.sync.aligned.m16n8k16.row.col.f32.f16.f16.f32 " \
                 "{%0,%1,%2,%3}, {%4,%5,%6,%7}, {%8,%9}, {%0,%1,%2,%3};" \
                 : "+f"((c)[0]), "+f"((c)[1]), "+f"((c)[2]), "+f"((c)[3]) \
                 : "r"(a0), "r"(a1), "r"(a2), "r"(a3), "r"(b0), "r"(b1))

template<int EPI>
__global__ void __launch_bounds__(256, 1)
hgemm_kernel(const __half* __restrict__ A2, const __half* __restrict__ B2,
             const float* __restrict__ Bias, void* __restrict__ Cv,
             int Nstore, int Kd, int lda, int ldb, int ldc,
             long sAb, long sAh, long sBb, long sBh, long sCb, long sCh,
             long sBiB, long sBiH, int Hn, int causal)
{
    extern __shared__ __align__(16) char dsm[];
    const uint32_t base = smem_u32(dsm);

    int tid = threadIdx.x;
    int wid = tid >> 5, lane = tid & 31;

    long m0 = (long)blockIdx.x * GBM;
    long n0 = (long)blockIdx.y * GBN;
    if (causal && n0 > m0 + (GBM - 1)) return;

    int z = blockIdx.z, zb = z / Hn, zh = z % Hn;
    A2 += zb * sAb + zh * sAh;
    B2 += zb * sBb + zh * sBh;
    long cOff = zb * sCb + zh * sCh;
    long biasOff = zb * sBiB + zh * sBiH;

    const int wm = (wid >> 2) * 64;
    const int wn = (wid & 3) * 64;

    float acc[4][8][4];
#pragma unroll
    for (int i = 0; i < 4; i++)
#pragma unroll
        for (int j = 0; j < 8; j++)
#pragma unroll
            for (int q = 0; q < 4; q++) acc[i][j][q] = 0.f;

    const int nIter = Kd / GBK;

    const int lr  = tid >> 2;
    const int lsg = tid & 3;
    const long aRow0 = m0 + lr,  aRow1 = m0 + lr + 64;
    const uint32_t sOff0 = (uint32_t)(lr * 80 + lsg * 16);
    const uint32_t sOff1 = (uint32_t)((lr + 64) * 80 + lsg * 16);
    const uint32_t sOff2 = (uint32_t)((lr + 128) * 80 + lsg * 16);
    const uint32_t sOff3 = (uint32_t)((lr + 192) * 80 + lsg * 16);

    auto loadStage = [&](int slot, long k0) {
        uint32_t aD = base + slot * STAGE_BYTES;
        uint32_t bD = aD + A_BYTES;
        long ko = k0 + lsg * 8;
        CP16(aD + sOff0, A2 + aRow0 * (long)lda + ko);
        CP16(aD + sOff1, A2 + aRow1 * (long)lda + ko);
        CP16(bD + sOff0, B2 + (n0 + lr) * (long)ldb + ko);
        CP16(bD + sOff1, B2 + (n0 + lr + 64) * (long)ldb + ko);
        CP16(bD + sOff2, B2 + (n0 + lr + 128) * (long)ldb + ko);
        CP16(bD + sOff3, B2 + (n0 + lr + 192) * (long)ldb + ko);
        CP_COMMIT();
    };

    loadStage(0, 0);
    if (nIter > 1) loadStage(1, GBK); else CP_COMMIT();
    if (nIter > 2) loadStage(2, 2L * GBK); else CP_COMMIT();

    for (int it = 0; it < nIter; ++it) {
        if (it + 2 < nIter)      CP_WAIT(2);
        else if (it + 1 < nIter) CP_WAIT(1);
        else                     CP_WAIT(0);
        __syncthreads();
        if (it + 3 < nIter) loadStage((it + 3) & (NSTAGE - 1), (long)(it + 3) * GBK);

        uint32_t aS = base + (it & (NSTAGE - 1)) * STAGE_BYTES;
        uint32_t bS = aS + A_BYTES;
#pragma unroll
        for (int ks = 0; ks < 2; ks++) {
            int col = ks * 16 + (lane >> 4) * 8;
            uint32_t a[4][4], bf[8][2];
#pragma unroll
            for (int mi = 0; mi < 4; mi++) {
                int row = wm + mi * 16 + (lane & 15);
                LDSM_X4(a[mi][0], a[mi][1], a[mi][2], a[mi][3],
                        aS + (uint32_t)(row * 80 + col * 2));
            }
#pragma unroll
            for (int p = 0; p < 4; p++) {
                int row = wn + p * 16 + (lane & 15);
                uint32_t r0, r1, r2, r3;
                LDSM_X4(r0, r1, r2, r3, bS + (uint32_t)(row * 80 + col * 2));
                bf[2 * p][0] = r0;     bf[2 * p][1] = r2;
                bf[2 * p + 1][0] = r1; bf[2 * p + 1][1] = r3;
            }
#pragma unroll
            for (int mi = 0; mi < 4; mi++)
#pragma unroll
                for (int ni = 0; ni < 8; ni++)
                    MMA_F16(acc[mi][ni], a[mi][0], a[mi][1], a[mi][2], a[mi][3],
                            bf[ni][0], bf[ni][1]);
        }
    }

    // ---- epilogue ----
    if (EPI <= 1) {
        float* C = (float*)Cv + cOff;
#pragma unroll
        for (int mi = 0; mi < 4; mi++) {
            long mrow = m0 + wm + mi * 16 + (lane >> 2);
            float* c0p = C + mrow * (long)ldc;
            float* c1p = c0p + 8L * ldc;
#pragma unroll
            for (int ni = 0; ni < 8; ni++) {
                long n = n0 + wn + ni * 8 + (lane & 3) * 2;
#pragma unroll
                for (int e = 0; e < 2; e++) {
                    long nn = n + e;
                    if (nn < (long)Nstore) {
                        float v0 = acc[mi][ni][e];
                        float v1 = acc[mi][ni][2 + e];
                        if (EPI >= 1) {
                            float bsv = Bias[biasOff + nn];
                            v0 += bsv; v1 += bsv;
                        }
                        c0p[nn] = v0;
                        c1p[nn] = v1;
                    }
                }
            }
        }
    } else if (EPI == 7) {
        __half* C2 = (__half*)Cv + cOff;
#pragma unroll
        for (int mi = 0; mi < 4; mi++) {
            long m = m0 + wm + mi * 16 + (lane >> 2);
#pragma unroll
            for (int ni = 0; ni < 8; ni++) {
                long n = n0 + wn + ni * 8 + (lane & 3) * 2;
                float b0 = Bias[biasOff + n];
                float b1 = Bias[biasOff + n + 1];
                C2[n * (long)ldc + m]           = __float2half(acc[mi][ni][0] + b0);
                C2[(n + 1) * (long)ldc + m]     = __float2half(acc[mi][ni][1] + b1);
                C2[n * (long)ldc + m + 8]       = __float2half(acc[mi][ni][2] + b0);
                C2[(n + 1) * (long)ldc + m + 8] = __float2half(acc[mi][ni][3] + b1);
            }
        }
    } else {
        __half* C2 = (__half*)Cv + cOff;
        const bool hasBias = (EPI == 3 || EPI == 6);
        const bool relu = (EPI == 6);
#pragma unroll
        for (int mi = 0; mi < 4; mi++) {
            long r0 = m0 + wm + mi * 16 + (lane >> 2);
            __half* p0 = C2 + r0 * (long)ldc;
            __half* p1 = p0 + 8L * ldc;
#pragma unroll
            for (int ni = 0; ni < 8; ni++) {
                long n = n0 + wn + ni * 8 + (lane & 3) * 2;
                float b0 = 0.f, b1 = 0.f;
                if (hasBias) { b0 = Bias[biasOff + n]; b1 = Bias[biasOff + n + 1]; }
                float v0 = acc[mi][ni][0] + b0, v1 = acc[mi][ni][1] + b1;
                float v2 = acc[mi][ni][2] + b0, v3 = acc[mi][ni][3] + b1;
                if (relu) {
                    v0 = fmaxf(v0, 0.f); v1 = fmaxf(v1, 0.f);
                    v2 = fmaxf(v2, 0.f); v3 = fmaxf(v3, 0.f);
                }
                *(__half2*)(p0 + n) = __halves2half2(__float2half(v0), __float2half(v1));
                *(__half2*)(p1 + n) = __halves2half2(__float2half(v2), __float2half(v3));
            }
        }
    }
}

// ---------------------------------------------------------------------------
// Host dispatch (stream-aware)
// ---------------------------------------------------------------------------
static void tg(int epi, const __half* A, const __half* B, const float* Bias,
               void* C, int M, int N, int Kd, int lda, int ldb, int ldc,
               long sAb, long sAh, long sBb, long sBh, long sCb, long sCh,
               long sBiB, long sBiH, int Hn, int Z, int causal = 0,
               cudaStream_t st = 0)
{
    dim3 g(M / GBM, (N + GBN - 1) / GBN, Z), b(256);
#define HG_CALL(E) hgemm_kernel<E><<<g, b, HG_SMEM, st>>>(A, B, Bias, C, N, Kd, lda, ldb, ldc, \
    sAb, sAh, sBb, sBh, sCb, sCh, sBiB, sBiH, Hn, causal)
    switch (epi) {
    case 0: HG_CALL(0); break;
    case 1: HG_CALL(1); break;
    case 3: HG_CALL(3); break;
    case 5: HG_CALL(5); break;
    case 7: HG_CALL(7); break;
    default: HG_CALL(6); break;
    }
#undef HG_CALL
}

// side-stream handles: created once on the first (uncaptured) call; work
// enqueued is identical every call — determinism preserved.
// NOTE: all cross-stream waits reference events recorded EARLIER in enqueue
// order (backward edges only) — required for graph capture.
static cudaStream_t g_s2 = nullptr;
static cudaEvent_t  g_ev[24];
// QKw[b]=b, Vw[b]=4+b, Ow[b]=8+b, F1[l]=12+l, F2[l]=14+l, LM=16, fork=17,
// VprojDone[b]=18+b (b=0,1,3), QK0done=22

extern "C" void kernel_launch(void* const* d_in, const int* in_sizes, int n_in,
                              void* d_out, int out_size)
{
    const float* enc    = (const float*)d_in[0];
    const int*   srcpad = (const int*)  d_in[1];
    const int*   target = (const int*)  d_in[2];
    const float* emb    = (const float*)d_in[3];
    const float* Wq1 = (const float*)d_in[4],  *bq1 = (const float*)d_in[5];
    const float* Wk1 = (const float*)d_in[6],  *bk1 = (const float*)d_in[7];
    const float* Wv1 = (const float*)d_in[8],  *bv1 = (const float*)d_in[9];
    const float* Wo1 = (const float*)d_in[10], *bo1 = (const float*)d_in[11];
    const float* Wq2 = (const float*)d_in[12], *bq2 = (const float*)d_in[13];
    const float* Wk2 = (const float*)d_in[14], *bk2 = (const float*)d_in[15];
    const float* Wv2 = (const float*)d_in[16], *bv2 = (const float*)d_in[17];
    const float* Wo2 = (const float*)d_in[18], *bo2 = (const float*)d_in[19];
    const float* ln1g = (const float*)d_in[20];
    const float* ln2g = (const float*)d_in[21];
    const float* ln3g = (const float*)d_in[22];
    const float* ln1b = (const float*)d_in[23];
    const float* ln2b = (const float*)d_in[24];
    const float* ln3b = (const float*)d_in[25];
    const float* Wf1 = (const float*)d_in[26], *bf1 = (const float*)d_in[27];
    const float* Wf2 = (const float*)d_in[28], *bf2 = (const float*)d_in[29];
    const float* lmW = (const float*)d_in[30], *lmb = (const float*)d_in[31];
    float* out = (float*)d_out;

    if (!g_s2) {
        cudaStreamCreateWithFlags(&g_s2, cudaStreamNonBlocking);
        for (int i = 0; i < 24; i++)
            cudaEventCreateWithFlags(&g_ev[i], cudaEventDisableTiming);
    }

    float *x, *ss, *part, *bqk4;
    cudaGetSymbolAddress((void**)&x,  g_x);
    cudaGetSymbolAddress((void**)&ss, g_s);
    cudaGetSymbolAddress((void**)&part, g_part);
    cudaGetSymbolAddress((void**)&bqk4, g_bqk4);
    __half *xeh, *qh, *vh, *sh, *oh, *fh, *lmh, *qkw, *vw, *ow, *f1w, *f2w;
    cudaGetSymbolAddress((void**)&xeh, g_xeh);
    cudaGetSymbolAddress((void**)&qh, g_qh);
    cudaGetSymbolAddress((void**)&vh, g_vh);
    cudaGetSymbolAddress((void**)&sh, g_sh);
    cudaGetSymbolAddress((void**)&oh, g_oh);
    cudaGetSymbolAddress((void**)&fh, g_fh);
    cudaGetSymbolAddress((void**)&lmh, g_lmh);
    cudaGetSymbolAddress((void**)&qkw, g_qkw);
    cudaGetSymbolAddress((void**)&vw, g_vw);
    cudaGetSymbolAddress((void**)&ow, g_ow);
    cudaGetSymbolAddress((void**)&f1w, g_f1w);
    cudaGetSymbolAddress((void**)&f2w, g_f2w);
    __half* xh = xeh;
    __half* eh = xeh + (long)NR * 512;
    __half* kh = qh + 4096;

    cudaFuncSetAttribute(hgemm_kernel<0>, cudaFuncAttributeMaxDynamicSharedMemorySize, HG_SMEM);
    cudaFuncSetAttribute(hgemm_kernel<1>, cudaFuncAttributeMaxDynamicSharedMemorySize, HG_SMEM);
    cudaFuncSetAttribute(hgemm_kernel<3>, cudaFuncAttributeMaxDynamicSharedMemorySize, HG_SMEM);
    cudaFuncSetAttribute(hgemm_kernel<5>, cudaFuncAttributeMaxDynamicSharedMemorySize, HG_SMEM);
    cudaFuncSetAttribute(hgemm_kernel<6>, cudaFuncAttributeMaxDynamicSharedMemorySize, HG_SMEM);
    cudaFuncSetAttribute(hgemm_kernel<7>, cudaFuncAttributeMaxDynamicSharedMemorySize, HG_SMEM);

    const float scale = 1.0f / sqrtf((float)Dm);
    const long WATT = (long)Hh * Dm * Dm;
    const long WOUT = (long)HD * Dm;
    const long WFF  = (long)Dm * FFd;
    const dim3 tb(32, 8);

    const float *WQ[2][2] = {{Wq1, Wq1 + WATT}, {Wq2, Wq2 + WATT}};
    const float *WK[2][2] = {{Wk1, Wk1 + WATT}, {Wk2, Wk2 + WATT}};
    const float *WV[2][2] = {{Wv1, Wv1 + WATT}, {Wv2, Wv2 + WATT}};
    const float *WO[2][2] = {{Wo1, Wo1 + WOUT}, {Wo2, Wo2 + WOUT}};
    const float *BQ[2][2] = {{bq1, bq1 + HD}, {bq2, bq2 + HD}};
    const float *BK[2][2] = {{bk1, bk1 + HD}, {bk2, bk2 + HD}};
    const float *BV[2][2] = {{bv1, bv1 + HD}, {bv2, bv2 + HD}};
    const float *BO[2][2] = {{bo1, bo1 + Dm}, {bo2, bo2 + Dm}};
    const float *LG[2][2] = {{ln1g, ln1g + Dm}, {ln2g, ln2g + Dm}};
    const float *LB[2][2] = {{ln1b, ln1b + Dm}, {ln2b, ln2b + Dm}};

    // ===================== main chain start =====================
    embed_pe_kernel<<<NR, 512>>>(target, emb, x, xh);
    conv_enc_kernel<<<NR, 256>>>(enc, eh);
    cudaEventRecord(g_ev[17], 0);      // fork: inputs + xh/eh ready

    // ===================== side stream =====================
    cudaStreamWaitEvent(g_s2, g_ev[17], 0);
    for (int l = 0; l < 2; l++) {
        for (int att = 0; att < 2; att++) {
            int b = l * 2 + att;
            const __half* kvA = (att == 0) ? xh : eh;
            cudaMemcpyAsync(bqk4 + b * 2 * HD,      BQ[att][l], HD * sizeof(float),
                            cudaMemcpyDeviceToDevice, g_s2);
            cudaMemcpyAsync(bqk4 + b * 2 * HD + HD, BK[att][l], HD * sizeof(float),
                            cudaMemcpyDeviceToDevice, g_s2);
            conv_t_kernel<<<dim3(16, 16, 8), tb, 0, g_s2>>>(WQ[att][l], qkw + (long)b * 4194304,
                Dm, Dm, Dm, 512, 0, (long)Dm * Dm, 0, (long)Dm * 512, 8);
            conv_t_kernel<<<dim3(16, 16, 8), tb, 0, g_s2>>>(WK[att][l], qkw + (long)b * 4194304 + 2097152,
                Dm, Dm, Dm, 512, 0, (long)Dm * Dm, 0, (long)Dm * 512, 8);
            if (b == 0) {
                // block-0 Q+K projection on side stream (inputs ready at fork)
                tg(3, xh, qkw, bqk4, qh, NR, Dm, 512, 512, 512, 8192,
                   0, 0, 2097152, (long)Dm * 512, 4096, 512,
                   HD, 512, 8, 16, 0, g_s2);
                cudaEventRecord(g_ev[22], g_s2);
            } else {
                cudaEventRecord(g_ev[b], g_s2);
            }
            conv_t_kernel<<<dim3(16, 16, 8), tb, 0, g_s2>>>(WV[att][l], vw + (long)b * 2097152,
                Dm, Dm, Dm, 512, 0, (long)Dm * Dm, 0, (long)Dm * 512, 8);
            cudaEventRecord(g_ev[4 + b], g_s2);
            if (b != 2) {
                // V projection on side stream (xh/eh ready at fork; own vh buffer)
                tg(7, kvA, vw + (long)b * 2097152, BV[att][l], vh + (long)b * VHSZ,
                   512, Dm, 512, 512, 512, 512,
                   (long)512 * 512, 0, 0, (long)Dm * 512,
                   (long)Hh * 512 * 512, (long)512 * 512, 0, Dm, 8, 32, 0, g_s2);
                cudaEventRecord(g_ev[18 + b], g_s2);
            }
            conv_t_kernel<<<dim3(16, 128, 1), tb, 0, g_s2>>>(WO[att][l], ow + (long)b * 2097152,
                HD, Dm, Dm, 4096, 0, 0, 0, 0, 1);
            cudaEventRecord(g_ev[8 + b], g_s2);
        }
        conv_t_kernel<<<dim3(64, 16, 1), tb, 0, g_s2>>>(Wf1 + l * WFF, f1w + (long)l * 1048576,
            Dm, FFd, FFd, 512, 0, 0, 0, 0, 1);
        cudaEventRecord(g_ev[12 + l], g_s2);
        conv_t_kernel<<<dim3(16, 64, 1), tb, 0, g_s2>>>(Wf2 + l * WFF, f2w + (long)l * 1048576,
            FFd, Dm, Dm, 2048, 0, 0, 0, 0, 1);
        cudaEventRecord(g_ev[14 + l], g_s2);
    }
    conv_t_kernel<<<dim3(1001, 16, 1), tb, 0, g_s2>>>(lmW, lmh, Dm, VO, VO, 512, 0, 0, 0, 0, 1);
    cudaEventRecord(g_ev[16], g_s2);

    // ===================== main chain =====================
    for (int l = 0; l < 2; l++) {
        for (int att = 0; att < 2; att++) {
            int b = l * 2 + att;
            __half* vhb = vh + (long)b * VHSZ;

            // ---- Q+K projection (block 0 done on side stream) ----
            if (b == 0) {
                cudaStreamWaitEvent(0, g_ev[22], 0);
            } else {
                cudaStreamWaitEvent(0, g_ev[b], 0);
                tg(3, xh, qkw + (long)b * 4194304, bqk4 + b * 2 * HD, qh,
                   NR, Dm, 512, 512, 512, 8192,
                   (att == 0) ? 0 : (long)NR * 512, 0,
                   2097152, (long)Dm * 512,
                   4096, 512,
                   HD, 512, 8, 16);
            }

            // ---- scores = Q K^T -> sh fp16 (causal tile-skip for self-att) ----
            tg(5, qh, kh, nullptr, sh, TTq, TSs, 512, 8192, 8192, 512,
               (long)TTq * 8192, 512, (long)TSs * 8192, 512,
               (long)Hh * TTq * 512, (long)TTq * 512, 0, 0, 8, 32,
               att == 0 ? 1 : 0);

            int writeS = (att == 1 && l == 0) ? 1 : 0;
            softmax_kernel<<<Bq * Hh * TTq, 256>>>(sh, ss, writeS, target, srcpad,
                                                   att == 0 ? 1 : 2, scale);
            if (writeS && (long)out_size >= LOGITS_ELEMS + ATT_ELEMS) {
                cudaMemcpyAsync(out + LOGITS_ELEMS, ss, ATT_ELEMS * sizeof(float),
                                cudaMemcpyDeviceToDevice, 0);
            }

            // ---- V: side-stream for b!=2; main-stream for b==2 ----
            if (b == 2) {
                cudaStreamWaitEvent(0, g_ev[4 + b], 0);
                tg(7, xh, vw + (long)b * 2097152, BV[att][l], vhb, 512, Dm, 512, 512, 512, 512,
                   (long)512 * 512, 0, 0, (long)Dm * 512,
                   (long)Hh * 512 * 512, (long)512 * 512, 0, Dm, 8, 32);
            } else {
                cudaStreamWaitEvent(0, g_ev[18 + b], 0);
            }

            // ---- O = S V ----
            tg(5, sh, vhb, nullptr, oh, TTq, Dm, 512, 512, 512, 4096,
               (long)Hh * TTq * 512, (long)TTq * 512,
               (long)Hh * TSs * 512, (long)TSs * 512,
               (long)TTq * 4096, 512, 0, 0, 8, 32);

            // ---- output projection: split-K=8 + fused reduce+add+LN ----
            cudaStreamWaitEvent(0, g_ev[8 + b], 0);
            tg(0, oh, ow + (long)b * 2097152, nullptr, part, NR, Dm, 512, 4096, 4096, Dm,
               0, 512, 0, 512, 0, (long)NR * Dm, 0, 0, SKn, SKn);
            reduce_ln_kernel<<<NR, 256>>>(part, BO[att][l], x, LG[att][l], LB[att][l], x, xh);
        }

        // ---- FFN ----
        cudaStreamWaitEvent(0, g_ev[12 + l], 0);
        tg(6, xh, f1w + (long)l * 1048576, bf1 + l * FFd, fh, NR, FFd, 512, 512, 512, 2048,
           0, 0, 0, 0, 0, 0, 0, 0, 1, 1);

        cudaStreamWaitEvent(0, g_ev[14 + l], 0);
        tg(0, fh, f2w + (long)l * 1048576, nullptr, part, NR, Dm, 256, 2048, 2048, Dm,
           0, 256, 0, 256, 0, (long)NR * Dm, 0, 0, SKn, SKn);
        reduce_ln_kernel<<<NR, 256>>>(part, bf2 + l * Dm, x, ln3g + l * Dm, ln3b + l * Dm, x, xh);
    }

    // ---- LM head ----
    cudaStreamWaitEvent(0, g_ev[16], 0);
    tg(1, xh, lmh, lmb, out, NR, VO, 512, 512, 512, VO,
       0, 0, 0, 0, 0, 0, 0, 0, 1, 1);
}

// round 16
// speedup vs baseline: 6.9453x; 1.0085x over previous
#include <cuda_runtime.h>
#include <cuda_fp16.h>
#include <math.h>
#include <stdint.h>

// ---------------------------------------------------------------------------
// Problem constants
// ---------------------------------------------------------------------------
#define Bq   4
#define TTq  512
#define TSs  512
#define Dm   512
#define Hh   8
#define Vv   32000
#define VO   32001
#define NR   2048
#define HD   4096
#define FFd  2048
#define SKn  8

#define LOGITS_ELEMS (2048LL * 32001LL)
#define ATT_ELEMS    (4LL * 8 * 512 * 512)
#define VHSZ (32L * 512 * 512)

// ---------------------------------------------------------------------------
// Scratch (static device globals)
// ---------------------------------------------------------------------------
__device__ float g_x [NR * Dm];
__device__ float g_s [Bq * Hh * TTq * TSs];
__device__ float g_part[SKn * NR * Dm];
__device__ float g_bqk4[4 * 2 * HD];

__device__ __half g_xeh[2 * NR * 512];           // xh | eh
__device__ __half g_qh [NR * 8192];              // Q cols 0-4095, K cols 4096-8191
__device__ __half g_vh [4 * VHSZ];               // per-block V (no reuse hazards)
__device__ __half g_sh [32 * 512 * 512];
__device__ __half g_oh [NR * 4096];
__device__ __half g_fh [NR * 2048];
__device__ __half g_lmh[32256 * 512];

// dedicated converted-weight buffers (block b = l*2 + att)
__device__ __half g_qkw[4 * 4194304];
__device__ __half g_vw [4 * 2097152];
__device__ __half g_ow [4 * 2097152];
__device__ __half g_f1w[2 * 1048576];
__device__ __half g_f2w[2 * 1048576];

// ---------------------------------------------------------------------------
// Embedding + positional encoding -> x (fp32) and xh (fp16)
// ---------------------------------------------------------------------------
__global__ void embed_pe_kernel(const int* __restrict__ target,
                                const float* __restrict__ emb,
                                float* __restrict__ x,
                                __half* __restrict__ xh)
{
    int row = blockIdx.x;
    int t   = row & (TTq - 1);
    int d   = threadIdx.x;
    int tok = target[row];
    float e = emb[(long)tok * Dm + d];
    int   i = d >> 1;
    // 1/10000^(2i/512) = 2^(-i * log2(10000)/256); log2(10000)/256 = 0.0519051265
    float z = (float)t * exp2f((float)i * -0.0519051267f);
    float p = (d & 1) ? cosf(z) : sinf(z);
    float v = e + p;
    x[(long)row * Dm + d] = v;
    xh[(long)row * 512 + d] = __float2half(v);
}

__global__ void conv_enc_kernel(const float* __restrict__ in, __half* __restrict__ out)
{
    long idx = (long)blockIdx.x * blockDim.x + threadIdx.x;
    long r = idx >> 8;
    long k = (idx & 255) * 2;
    const float* p = in + r * Dm + k;
    __half2 h = __halves2half2(__float2half(p[0]), __float2half(p[1]));
    *(__half2*)(out + r * 512 + k) = h;
}

// ---------------------------------------------------------------------------
// Masked softmax, fp16 in-place; optional fp32 copy (att0).
// ---------------------------------------------------------------------------
__global__ void softmax_kernel(__half* __restrict__ Sh, float* __restrict__ S,
                               int writeS,
                               const int* __restrict__ target,
                               const int* __restrict__ srcpad,
                               int mode, float scale)
{
    int row = blockIdx.x;
    int q   = row & (TTq - 1);
    int b   = row / (Hh * TTq);
    __half* sr = Sh + (long)row * 512;
    int tid = threadIdx.x;
    bool qpad = (target[b * TTq + q] != Vv);

    float v[2];
    float mx = -INFINITY;
#pragma unroll
    for (int e = 0; e < 2; e++) {
        int k = tid + e * 256;
        bool valid;
        if (mode == 1)
            valid = qpad && (k <= q) && (target[b * TTq + k] != Vv);
        else
            valid = qpad && (srcpad[b * TSs + k] != 0);
        float val = valid ? __half2float(sr[k]) * scale : -1e32f;
        v[e] = val;
        mx = fmaxf(mx, val);
    }

    __shared__ float red[8];
#pragma unroll
    for (int o = 16; o > 0; o >>= 1) mx = fmaxf(mx, __shfl_xor_sync(0xffffffffu, mx, o));
    if ((tid & 31) == 0) red[tid >> 5] = mx;
    __syncthreads();
    if (tid < 32) {
        float r = (tid < 8) ? red[tid] : -INFINITY;
#pragma unroll
        for (int o = 4; o > 0; o >>= 1) r = fmaxf(r, __shfl_xor_sync(0xffffffffu, r, o));
        if (tid == 0) red[0] = r;
    }
    __syncthreads();
    mx = red[0];
    __syncthreads();

    float sum = 0.f;
#pragma unroll
    for (int e = 0; e < 2; e++) { v[e] = expf(v[e] - mx); sum += v[e]; }
#pragma unroll
    for (int o = 16; o > 0; o >>= 1) sum += __shfl_xor_sync(0xffffffffu, sum, o);
    if ((tid & 31) == 0) red[tid >> 5] = sum;
    __syncthreads();
    if (tid < 32) {
        float r = (tid < 8) ? red[tid] : 0.f;
#pragma unroll
        for (int o = 4; o > 0; o >>= 1) r += __shfl_xor_sync(0xffffffffu, r, o);
        if (tid == 0) red[0] = r;
    }
    __syncthreads();
    float inv = 1.0f / red[0];
    float* s32 = S + (long)row * TSs;
#pragma unroll
    for (int e = 0; e < 2; e++) {
        int k = tid + e * 256;
        float val = v[e] * inv;
        sr[k] = __float2half(val);
        if (writeS) s32[k] = val;
    }
}

// ---------------------------------------------------------------------------
// Fused split-K reduce + residual + LayerNorm
// ---------------------------------------------------------------------------
__global__ void reduce_ln_kernel(const float* __restrict__ part,
                                 const float* __restrict__ bias,
                                 const float* __restrict__ xin,
                                 const float* __restrict__ gg,
                                 const float* __restrict__ bb,
                                 float* __restrict__ y,
                                 __half* __restrict__ yh)
{
    int row = blockIdx.x;
    int tid = threadIdx.x;
    long base = (long)row * Dm;
    __shared__ float red[8];

    float v[2];
    float sum = 0.f;
#pragma unroll
    for (int e = 0; e < 2; e++) {
        int d = tid + e * 256;
        float s = xin[base + d] + bias[d];
#pragma unroll
        for (int c = 0; c < SKn; c++)
            s += part[(long)c * NR * Dm + base + d];
        v[e] = s;
        sum += s;
    }
#pragma unroll
    for (int o = 16; o > 0; o >>= 1) sum += __shfl_xor_sync(0xffffffffu, sum, o);
    if ((tid & 31) == 0) red[tid >> 5] = sum;
    __syncthreads();
    if (tid < 32) {
        float r = (tid < 8) ? red[tid] : 0.f;
#pragma unroll
        for (int o = 4; o > 0; o >>= 1) r += __shfl_xor_sync(0xffffffffu, r, o);
        if (tid == 0) red[0] = r;
    }
    __syncthreads();
    float m = red[0] * (1.0f / (float)Dm);
    __syncthreads();

    float vs = 0.f;
#pragma unroll
    for (int e = 0; e < 2; e++) { float c = v[e] - m; vs += c * c; }
#pragma unroll
    for (int o = 16; o > 0; o >>= 1) vs += __shfl_xor_sync(0xffffffffu, vs, o);
    if ((tid & 31) == 0) red[tid >> 5] = vs;
    __syncthreads();
    if (tid < 32) {
        float r = (tid < 8) ? red[tid] : 0.f;
#pragma unroll
        for (int o = 4; o > 0; o >>= 1) r += __shfl_xor_sync(0xffffffffu, r, o);
        if (tid == 0) red[0] = r;
    }
    __syncthreads();
    float var = red[0] * (1.0f / (float)Dm);
    float rs = rsqrtf(var + 1e-5f);
    __half* yhr = yh + (long)row * 512;
#pragma unroll
    for (int e = 0; e < 2; e++) {
        int d = tid + e * 256;
        float val = (v[e] - m) * rs * gg[d] + bb[d];
        y[base + d] = val;
        yhr[d] = __float2half(val);
    }
}

// ---------------------------------------------------------------------------
// conv_t: fp32 [K, N] (N-contig) -> fp16 [N, K] transposed. (weights)
// ---------------------------------------------------------------------------
__global__ void conv_t_kernel(const float* __restrict__ in, __half* __restrict__ out,
                              int K, int N, int in_ld, int out_ld,
                              long sInB, long sInH, long sOutB, long sOutH, int Hn)
{
    __shared__ float t[32][33];
    int z = blockIdx.z, zb = z / Hn, zh = z % Hn;
    in  += zb * sInB + zh * sInH;
    out += zb * sOutB + zh * sOutH;
    int k0 = blockIdx.y * 32, n0 = blockIdx.x * 32;
    int tx = threadIdx.x, ty = threadIdx.y;
#pragma unroll
    for (int i = 0; i < 4; ++i) {
        int k = k0 + ty + i * 8, n = n0 + tx;
        t[ty + i * 8][tx] = (n < N) ? in[(long)k * in_ld + n] : 0.f;
    }
    __syncthreads();
#pragma unroll
    for (int i = 0; i < 4; ++i) {
        int n = n0 + ty + i * 8, k = k0 + tx;
        if (n < N)
            out[(long)n * out_ld + k] = __float2half(t[tx][ty + i * 8]);
    }
}

// ---------------------------------------------------------------------------
// fp16 tensor-core GEMM (mma.sync m16n8k16 f16). CTA 128x256, 8 warps (2x4),
// warp tile 64x64, BK=32, 4-stage cp.async pipeline, one barrier per iter.
// EPI: 0 fp32 | 1 fp32+bias | 3 half+bias | 5 half | 6 half+bias+relu
//      7 half+bias TRANSPOSED store
// causal: 1 = skip fully-masked tiles (self-att scores)
//         2 = K-cap: only K-iters with k < m0+GBM contribute (self O=S*V)
// ---------------------------------------------------------------------------
#define GBM 128
#define GBN 256
#define GBK 32
#define NSTAGE 4
#define A_BYTES 10240
#define STAGE_BYTES 30720
#define HG_SMEM (NSTAGE * STAGE_BYTES)

__device__ __forceinline__ uint32_t smem_u32(const void* p) {
    uint32_t a;
    asm("{ .reg .u64 t; cvta.to.shared.u64 t, %1; cvt.u32.u64 %0, t; }" : "=r"(a) : "l"(p));
    return a;
}
#define CP16(dst, src) \
    asm volatile("cp.async.cg.shared.global [%0], [%1], 16;" :: "r"(dst), "l"(src))
#define CP_COMMIT() asm volatile("cp.async.commit_group;" ::: "memory")
#define CP_WAIT(n)  asm volatile("cp.async.wait_group %0;" :: "n"(n) : "memory")
#define LDSM_X4(r0, r1, r2, r3, addr) \
    asm volatile("ldmatrix.sync.aligned.m8n8.x4.shared.b16 {%0,%1,%2,%3}, [%4];" \
                 : "=r"(r0), "=r"(r1), "=r"(r2), "=r"(r3) : "r"(addr))
#define MMA_F16(c, a0, a1, a2, a3, b0, b1) \
    asm volatile("mma.sync.aligned.m16n8k16.row.col.f32.f16.f16.f32 " \
                 "{%0,%1,%2,%3}, {%4,%5,%6,%7}, {%8,%9}, {%0,%1,%2,%3};" \
                 : "+f"((c)[0]), "+f"((c)[1]), "+f"((c)[2]), "+f"((c)[3]) \
                 : "r"(a0), "r"(a1), "r"(a2), "r"(a3), "r"(b0), "r"(b1))

template<int EPI>
__global__ void __launch_bounds__(256, 1)
hgemm_kernel(const __half* __restrict__ A2, const __half* __restrict__ B2,
             const float* __restrict__ Bias, void* __restrict__ Cv,
             int Nstore, int Kd, int lda, int ldb, int ldc,
             long sAb, long sAh, long sBb, long sBh, long sCb, long sCh,
             long sBiB, long sBiH, int Hn, int causal)
{
    extern __shared__ __align__(16) char dsm[];
    const uint32_t base = smem_u32(dsm);

    int tid = threadIdx.x;
    int wid = tid >> 5, lane = tid & 31;

    long m0 = (long)blockIdx.x * GBM;
    long n0 = (long)blockIdx.y * GBN;
    if (causal == 1 && n0 > m0 + (GBM - 1)) return;

    int z = blockIdx.z, zb = z / Hn, zh = z % Hn;
    A2 += zb * sAb + zh * sAh;
    B2 += zb * sBb + zh * sBh;
    long cOff = zb * sCb + zh * sCh;
    long biasOff = zb * sBiB + zh * sBiH;

    const int wm = (wid >> 2) * 64;
    const int wn = (wid & 3) * 64;

    float acc[4][8][4];
#pragma unroll
    for (int i = 0; i < 4; i++)
#pragma unroll
        for (int j = 0; j < 8; j++)
#pragma unroll
            for (int q = 0; q < 4; q++) acc[i][j][q] = 0.f;

    int nIter = Kd / GBK;
    if (causal == 2) {
        int cap = (int)((m0 + GBM) / GBK);
        if (cap < nIter) nIter = cap;
    }

    const int lr  = tid >> 2;
    const int lsg = tid & 3;
    const long aRow0 = m0 + lr,  aRow1 = m0 + lr + 64;
    const uint32_t sOff0 = (uint32_t)(lr * 80 + lsg * 16);
    const uint32_t sOff1 = (uint32_t)((lr + 64) * 80 + lsg * 16);
    const uint32_t sOff2 = (uint32_t)((lr + 128) * 80 + lsg * 16);
    const uint32_t sOff3 = (uint32_t)((lr + 192) * 80 + lsg * 16);

    auto loadStage = [&](int slot, long k0) {
        uint32_t aD = base + slot * STAGE_BYTES;
        uint32_t bD = aD + A_BYTES;
        long ko = k0 + lsg * 8;
        CP16(aD + sOff0, A2 + aRow0 * (long)lda + ko);
        CP16(aD + sOff1, A2 + aRow1 * (long)lda + ko);
        CP16(bD + sOff0, B2 + (n0 + lr) * (long)ldb + ko);
        CP16(bD + sOff1, B2 + (n0 + lr + 64) * (long)ldb + ko);
        CP16(bD + sOff2, B2 + (n0 + lr + 128) * (long)ldb + ko);
        CP16(bD + sOff3, B2 + (n0 + lr + 192) * (long)ldb + ko);
        CP_COMMIT();
    };

    loadStage(0, 0);
    if (nIter > 1) loadStage(1, GBK); else CP_COMMIT();
    if (nIter > 2) loadStage(2, 2L * GBK); else CP_COMMIT();

    for (int it = 0; it < nIter; ++it) {
        if (it + 2 < nIter)      CP_WAIT(2);
        else if (it + 1 < nIter) CP_WAIT(1);
        else                     CP_WAIT(0);
        __syncthreads();
        if (it + 3 < nIter) loadStage((it + 3) & (NSTAGE - 1), (long)(it + 3) * GBK);

        uint32_t aS = base + (it & (NSTAGE - 1)) * STAGE_BYTES;
        uint32_t bS = aS + A_BYTES;
#pragma unroll
        for (int ks = 0; ks < 2; ks++) {
            int col = ks * 16 + (lane >> 4) * 8;
            uint32_t a[4][4], bf[8][2];
#pragma unroll
            for (int mi = 0; mi < 4; mi++) {
                int row = wm + mi * 16 + (lane & 15);
                LDSM_X4(a[mi][0], a[mi][1], a[mi][2], a[mi][3],
                        aS + (uint32_t)(row * 80 + col * 2));
            }
#pragma unroll
            for (int p = 0; p < 4; p++) {
                int row = wn + p * 16 + (lane & 15);
                uint32_t r0, r1, r2, r3;
                LDSM_X4(r0, r1, r2, r3, bS + (uint32_t)(row * 80 + col * 2));
                bf[2 * p][0] = r0;     bf[2 * p][1] = r2;
                bf[2 * p + 1][0] = r1; bf[2 * p + 1][1] = r3;
            }
#pragma unroll
            for (int mi = 0; mi < 4; mi++)
#pragma unroll
                for (int ni = 0; ni < 8; ni++)
                    MMA_F16(acc[mi][ni], a[mi][0], a[mi][1], a[mi][2], a[mi][3],
                            bf[ni][0], bf[ni][1]);
        }
    }

    // ---- epilogue ----
    if (EPI <= 1) {
        float* C = (float*)Cv + cOff;
#pragma unroll
        for (int mi = 0; mi < 4; mi++) {
            long mrow = m0 + wm + mi * 16 + (lane >> 2);
            float* c0p = C + mrow * (long)ldc;
            float* c1p = c0p + 8L * ldc;
#pragma unroll
            for (int ni = 0; ni < 8; ni++) {
                long n = n0 + wn + ni * 8 + (lane & 3) * 2;
#pragma unroll
                for (int e = 0; e < 2; e++) {
                    long nn = n + e;
                    if (nn < (long)Nstore) {
                        float v0 = acc[mi][ni][e];
                        float v1 = acc[mi][ni][2 + e];
                        if (EPI >= 1) {
                            float bsv = Bias[biasOff + nn];
                            v0 += bsv; v1 += bsv;
                        }
                        c0p[nn] = v0;
                        c1p[nn] = v1;
                    }
                }
            }
        }
    } else if (EPI == 7) {
        __half* C2 = (__half*)Cv + cOff;
#pragma unroll
        for (int mi = 0; mi < 4; mi++) {
            long m = m0 + wm + mi * 16 + (lane >> 2);
#pragma unroll
            for (int ni = 0; ni < 8; ni++) {
                long n = n0 + wn + ni * 8 + (lane & 3) * 2;
                float b0 = Bias[biasOff + n];
                float b1 = Bias[biasOff + n + 1];
                C2[n * (long)ldc + m]           = __float2half(acc[mi][ni][0] + b0);
                C2[(n + 1) * (long)ldc + m]     = __float2half(acc[mi][ni][1] + b1);
                C2[n * (long)ldc + m + 8]       = __float2half(acc[mi][ni][2] + b0);
                C2[(n + 1) * (long)ldc + m + 8] = __float2half(acc[mi][ni][3] + b1);
            }
        }
    } else {
        __half* C2 = (__half*)Cv + cOff;
        const bool hasBias = (EPI == 3 || EPI == 6);
        const bool relu = (EPI == 6);
#pragma unroll
        for (int mi = 0; mi < 4; mi++) {
            long r0 = m0 + wm + mi * 16 + (lane >> 2);
            __half* p0 = C2 + r0 * (long)ldc;
            __half* p1 = p0 + 8L * ldc;
#pragma unroll
            for (int ni = 0; ni < 8; ni++) {
                long n = n0 + wn + ni * 8 + (lane & 3) * 2;
                float b0 = 0.f, b1 = 0.f;
                if (hasBias) { b0 = Bias[biasOff + n]; b1 = Bias[biasOff + n + 1]; }
                float v0 = acc[mi][ni][0] + b0, v1 = acc[mi][ni][1] + b1;
                float v2 = acc[mi][ni][2] + b0, v3 = acc[mi][ni][3] + b1;
                if (relu) {
                    v0 = fmaxf(v0, 0.f); v1 = fmaxf(v1, 0.f);
                    v2 = fmaxf(v2, 0.f); v3 = fmaxf(v3, 0.f);
                }
                *(__half2*)(p0 + n) = __halves2half2(__float2half(v0), __float2half(v1));
                *(__half2*)(p1 + n) = __halves2half2(__float2half(v2), __float2half(v3));
            }
        }
    }
}

// ---------------------------------------------------------------------------
// Host dispatch (stream-aware)
// ---------------------------------------------------------------------------
static void tg(int epi, const __half* A, const __half* B, const float* Bias,
               void* C, int M, int N, int Kd, int lda, int ldb, int ldc,
               long sAb, long sAh, long sBb, long sBh, long sCb, long sCh,
               long sBiB, long sBiH, int Hn, int Z, int causal = 0,
               cudaStream_t st = 0)
{
    dim3 g(M / GBM, (N + GBN - 1) / GBN, Z), b(256);
#define HG_CALL(E) hgemm_kernel<E><<<g, b, HG_SMEM, st>>>(A, B, Bias, C, N, Kd, lda, ldb, ldc, \
    sAb, sAh, sBb, sBh, sCb, sCh, sBiB, sBiH, Hn, causal)
    switch (epi) {
    case 0: HG_CALL(0); break;
    case 1: HG_CALL(1); break;
    case 3: HG_CALL(3); break;
    case 5: HG_CALL(5); break;
    case 7: HG_CALL(7); break;
    default: HG_CALL(6); break;
    }
#undef HG_CALL
}

// side-stream handles: created once on the first (uncaptured) call; work
// enqueued is identical every call. ALL cross-stream waits reference events
// recorded EARLIER in host enqueue order (backward edges only).
static cudaStream_t g_s2 = nullptr;
static cudaEvent_t  g_ev[24];
// QKw[b]=b, Vw[b]=4+b, Ow[b]=8+b, F1[l]=12+l, F2[l]=14+l, LM=16, fork=17,
// VprojDone[b]=18+b, QK0done=22, Xready_l1=23

extern "C" void kernel_launch(void* const* d_in, const int* in_sizes, int n_in,
                              void* d_out, int out_size)
{
    const float* enc    = (const float*)d_in[0];
    const int*   srcpad = (const int*)  d_in[1];
    const int*   target = (const int*)  d_in[2];
    const float* emb    = (const float*)d_in[3];
    const float* Wq1 = (const float*)d_in[4],  *bq1 = (const float*)d_in[5];
    const float* Wk1 = (const float*)d_in[6],  *bk1 = (const float*)d_in[7];
    const float* Wv1 = (const float*)d_in[8],  *bv1 = (const float*)d_in[9];
    const float* Wo1 = (const float*)d_in[10], *bo1 = (const float*)d_in[11];
    const float* Wq2 = (const float*)d_in[12], *bq2 = (const float*)d_in[13];
    const float* Wk2 = (const float*)d_in[14], *bk2 = (const float*)d_in[15];
    const float* Wv2 = (const float*)d_in[16], *bv2 = (const float*)d_in[17];
    const float* Wo2 = (const float*)d_in[18], *bo2 = (const float*)d_in[19];
    const float* ln1g = (const float*)d_in[20];
    const float* ln2g = (const float*)d_in[21];
    const float* ln3g = (const float*)d_in[22];
    const float* ln1b = (const float*)d_in[23];
    const float* ln2b = (const float*)d_in[24];
    const float* ln3b = (const float*)d_in[25];
    const float* Wf1 = (const float*)d_in[26], *bf1 = (const float*)d_in[27];
    const float* Wf2 = (const float*)d_in[28], *bf2 = (const float*)d_in[29];
    const float* lmW = (const float*)d_in[30], *lmb = (const float*)d_in[31];
    float* out = (float*)d_out;

    if (!g_s2) {
        cudaStreamCreateWithFlags(&g_s2, cudaStreamNonBlocking);
        for (int i = 0; i < 24; i++)
            cudaEventCreateWithFlags(&g_ev[i], cudaEventDisableTiming);
    }

    float *x, *ss, *part, *bqk4;
    cudaGetSymbolAddress((void**)&x,  g_x);
    cudaGetSymbolAddress((void**)&ss, g_s);
    cudaGetSymbolAddress((void**)&part, g_part);
    cudaGetSymbolAddress((void**)&bqk4, g_bqk4);
    __half *xeh, *qh, *vh, *sh, *oh, *fh, *lmh, *qkw, *vw, *ow, *f1w, *f2w;
    cudaGetSymbolAddress((void**)&xeh, g_xeh);
    cudaGetSymbolAddress((void**)&qh, g_qh);
    cudaGetSymbolAddress((void**)&vh, g_vh);
    cudaGetSymbolAddress((void**)&sh, g_sh);
    cudaGetSymbolAddress((void**)&oh, g_oh);
    cudaGetSymbolAddress((void**)&fh, g_fh);
    cudaGetSymbolAddress((void**)&lmh, g_lmh);
    cudaGetSymbolAddress((void**)&qkw, g_qkw);
    cudaGetSymbolAddress((void**)&vw, g_vw);
    cudaGetSymbolAddress((void**)&ow, g_ow);
    cudaGetSymbolAddress((void**)&f1w, g_f1w);
    cudaGetSymbolAddress((void**)&f2w, g_f2w);
    __half* xh = xeh;
    __half* eh = xeh + (long)NR * 512;
    __half* kh = qh + 4096;

    cudaFuncSetAttribute(hgemm_kernel<0>, cudaFuncAttributeMaxDynamicSharedMemorySize, HG_SMEM);
    cudaFuncSetAttribute(hgemm_kernel<1>, cudaFuncAttributeMaxDynamicSharedMemorySize, HG_SMEM);
    cudaFuncSetAttribute(hgemm_kernel<3>, cudaFuncAttributeMaxDynamicSharedMemorySize, HG_SMEM);
    cudaFuncSetAttribute(hgemm_kernel<5>, cudaFuncAttributeMaxDynamicSharedMemorySize, HG_SMEM);
    cudaFuncSetAttribute(hgemm_kernel<6>, cudaFuncAttributeMaxDynamicSharedMemorySize, HG_SMEM);
    cudaFuncSetAttribute(hgemm_kernel<7>, cudaFuncAttributeMaxDynamicSharedMemorySize, HG_SMEM);

    const float scale = 1.0f / sqrtf((float)Dm);
    const long WATT = (long)Hh * Dm * Dm;
    const long WOUT = (long)HD * Dm;
    const long WFF  = (long)Dm * FFd;
    const dim3 tb(32, 8);

    const float *WQ[2][2] = {{Wq1, Wq1 + WATT}, {Wq2, Wq2 + WATT}};
    const float *WK[2][2] = {{Wk1, Wk1 + WATT}, {Wk2, Wk2 + WATT}};
    const float *WV[2][2] = {{Wv1, Wv1 + WATT}, {Wv2, Wv2 + WATT}};
    const float *WO[2][2] = {{Wo1, Wo1 + WOUT}, {Wo2, Wo2 + WOUT}};
    const float *BQ[2][2] = {{bq1, bq1 + HD}, {bq2, bq2 + HD}};
    const float *BK[2][2] = {{bk1, bk1 + HD}, {bk2, bk2 + HD}};
    const float *BV[2][2] = {{bv1, bv1 + HD}, {bv2, bv2 + HD}};
    const float *BO[2][2] = {{bo1, bo1 + Dm}, {bo2, bo2 + Dm}};
    const float *LG[2][2] = {{ln1g, ln1g + Dm}, {ln2g, ln2g + Dm}};
    const float *LB[2][2] = {{ln1b, ln1b + Dm}, {ln2b, ln2b + Dm}};

    // ===================== main chain start =====================
    embed_pe_kernel<<<NR, 512>>>(target, emb, x, xh);
    conv_enc_kernel<<<NR, 256>>>(enc, eh);
    cudaEventRecord(g_ev[17], 0);      // fork: inputs + xh/eh ready

    // ===================== side stream, segment 1 =====================
    cudaStreamWaitEvent(g_s2, g_ev[17], 0);
    for (int l = 0; l < 2; l++) {
        for (int att = 0; att < 2; att++) {
            int b = l * 2 + att;
            const __half* kvA = (att == 0) ? xh : eh;
            cudaMemcpyAsync(bqk4 + b * 2 * HD,      BQ[att][l], HD * sizeof(float),
                            cudaMemcpyDeviceToDevice, g_s2);
            cudaMemcpyAsync(bqk4 + b * 2 * HD + HD, BK[att][l], HD * sizeof(float),
                            cudaMemcpyDeviceToDevice, g_s2);
            conv_t_kernel<<<dim3(16, 16, 8), tb, 0, g_s2>>>(WQ[att][l], qkw + (long)b * 4194304,
                Dm, Dm, Dm, 512, 0, (long)Dm * Dm, 0, (long)Dm * 512, 8);
            conv_t_kernel<<<dim3(16, 16, 8), tb, 0, g_s2>>>(WK[att][l], qkw + (long)b * 4194304 + 2097152,
                Dm, Dm, Dm, 512, 0, (long)Dm * Dm, 0, (long)Dm * 512, 8);
            if (b == 0) {
                tg(3, xh, qkw, bqk4, qh, NR, Dm, 512, 512, 512, 8192,
                   0, 0, 2097152, (long)Dm * 512, 4096, 512,
                   HD, 512, 8, 16, 0, g_s2);
                cudaEventRecord(g_ev[22], g_s2);
            } else {
                cudaEventRecord(g_ev[b], g_s2);
            }
            conv_t_kernel<<<dim3(16, 16, 8), tb, 0, g_s2>>>(WV[att][l], vw + (long)b * 2097152,
                Dm, Dm, Dm, 512, 0, (long)Dm * Dm, 0, (long)Dm * 512, 8);
            cudaEventRecord(g_ev[4 + b], g_s2);
            if (b != 2) {
                tg(7, kvA, vw + (long)b * 2097152, BV[att][l], vh + (long)b * VHSZ,
                   512, Dm, 512, 512, 512, 512,
                   (long)512 * 512, 0, 0, (long)Dm * 512,
                   (long)Hh * 512 * 512, (long)512 * 512, 0, Dm, 8, 32, 0, g_s2);
                cudaEventRecord(g_ev[18 + b], g_s2);
            }
            conv_t_kernel<<<dim3(16, 128, 1), tb, 0, g_s2>>>(WO[att][l], ow + (long)b * 2097152,
                HD, Dm, Dm, 4096, 0, 0, 0, 0, 1);
            cudaEventRecord(g_ev[8 + b], g_s2);
        }
        conv_t_kernel<<<dim3(64, 16, 1), tb, 0, g_s2>>>(Wf1 + l * WFF, f1w + (long)l * 1048576,
            Dm, FFd, FFd, 512, 0, 0, 0, 0, 1);
        cudaEventRecord(g_ev[12 + l], g_s2);
        conv_t_kernel<<<dim3(16, 64, 1), tb, 0, g_s2>>>(Wf2 + l * WFF, f2w + (long)l * 1048576,
            FFd, Dm, Dm, 2048, 0, 0, 0, 0, 1);
        cudaEventRecord(g_ev[14 + l], g_s2);
    }
    conv_t_kernel<<<dim3(1001, 16, 1), tb, 0, g_s2>>>(lmW, lmh, Dm, VO, VO, 512, 0, 0, 0, 0, 1);
    cudaEventRecord(g_ev[16], g_s2);

    // ===================== main chain =====================
    for (int l = 0; l < 2; l++) {
        for (int att = 0; att < 2; att++) {
            int b = l * 2 + att;
            __half* vhb = vh + (long)b * VHSZ;

            // ---- Q+K projection (block 0 done on side stream) ----
            if (b == 0) {
                cudaStreamWaitEvent(0, g_ev[22], 0);
            } else {
                cudaStreamWaitEvent(0, g_ev[b], 0);
                tg(3, xh, qkw + (long)b * 4194304, bqk4 + b * 2 * HD, qh,
                   NR, Dm, 512, 512, 512, 8192,
                   (att == 0) ? 0 : (long)NR * 512, 0,
                   2097152, (long)Dm * 512,
                   4096, 512,
                   HD, 512, 8, 16);
            }

            // ---- scores = Q K^T -> sh fp16 (causal tile-skip for self-att) ----
            tg(5, qh, kh, nullptr, sh, TTq, TSs, 512, 8192, 8192, 512,
               (long)TTq * 8192, 512, (long)TSs * 8192, 512,
               (long)Hh * TTq * 512, (long)TTq * 512, 0, 0, 8, 32,
               att == 0 ? 1 : 0);

            int writeS = (att == 1 && l == 0) ? 1 : 0;
            softmax_kernel<<<Bq * Hh * TTq, 256>>>(sh, ss, writeS, target, srcpad,
                                                   att == 0 ? 1 : 2, scale);
            if (writeS && (long)out_size >= LOGITS_ELEMS + ATT_ELEMS) {
                cudaMemcpyAsync(out + LOGITS_ELEMS, ss, ATT_ELEMS * sizeof(float),
                                cudaMemcpyDeviceToDevice, 0);
            }

            // ---- O = S V (V computed on side stream; self-att: causal K-cap) ----
            cudaStreamWaitEvent(0, g_ev[18 + b], 0);
            tg(5, sh, vhb, nullptr, oh, TTq, Dm, 512, 512, 512, 4096,
               (long)Hh * TTq * 512, (long)TTq * 512,
               (long)Hh * TSs * 512, (long)TSs * 512,
               (long)TTq * 4096, 512, 0, 0, 8, 32,
               att == 0 ? 2 : 0);

            // ---- output projection: split-K=8 + fused reduce+add+LN ----
            cudaStreamWaitEvent(0, g_ev[8 + b], 0);
            tg(0, oh, ow + (long)b * 2097152, nullptr, part, NR, Dm, 512, 4096, 4096, Dm,
               0, 512, 0, 512, 0, (long)NR * Dm, 0, 0, SKn, SKn);
            reduce_ln_kernel<<<NR, 256>>>(part, BO[att][l], x, LG[att][l], LB[att][l], x, xh);
        }

        // ---- FFN ----
        cudaStreamWaitEvent(0, g_ev[12 + l], 0);
        tg(6, xh, f1w + (long)l * 1048576, bf1 + l * FFd, fh, NR, FFd, 512, 512, 512, 2048,
           0, 0, 0, 0, 0, 0, 0, 0, 1, 1);

        cudaStreamWaitEvent(0, g_ev[14 + l], 0);
        tg(0, fh, f2w + (long)l * 1048576, nullptr, part, NR, Dm, 256, 2048, 2048, Dm,
           0, 256, 0, 256, 0, (long)NR * Dm, 0, 0, SKn, SKn);
        reduce_ln_kernel<<<NR, 256>>>(part, bf2 + l * Dm, x, ln3g + l * Dm, ln3b + l * Dm, x, xh);

        if (l == 0) {
            // xh for layer 1 is ready — enqueue V-proj(b=2) on the side stream.
            // Backward edge: ev[23] recorded here, side wait enqueued after.
            cudaEventRecord(g_ev[23], 0);
            cudaStreamWaitEvent(g_s2, g_ev[23], 0);
            tg(7, xh, vw + 2L * 2097152, BV[0][1], vh + 2L * VHSZ,
               512, Dm, 512, 512, 512, 512,
               (long)512 * 512, 0, 0, (long)Dm * 512,
               (long)Hh * 512 * 512, (long)512 * 512, 0, Dm, 8, 32, 0, g_s2);
            cudaEventRecord(g_ev[18 + 2], g_s2);
        }
    }

    // ---- LM head ----
    cudaStreamWaitEvent(0, g_ev[16], 0);
    tg(1, xh, lmh, lmb, out, NR, VO, 512, 512, 512, VO,
       0, 0, 0, 0, 0, 0, 0, 0, 1, 1);
}

// round 17
// speedup vs baseline: 7.1199x; 1.0251x over previous
#include <cuda_runtime.h>
#include <cuda_fp16.h>
#include <math.h>
#include <stdint.h>

// ---------------------------------------------------------------------------
// Problem constants
// ---------------------------------------------------------------------------
#define Bq   4
#define TTq  512
#define TSs  512
#define Dm   512
#define Hh   8
#define Vv   32000
#define VO   32001
#define NR   2048
#define HD   4096
#define FFd  2048
#define SKn  8

#define LOGITS_ELEMS (2048LL * 32001LL)
#define ATT_ELEMS    (4LL * 8 * 512 * 512)
#define VHSZ (32L * 512 * 512)

// ---------------------------------------------------------------------------
// Scratch (static device globals)
// ---------------------------------------------------------------------------
__device__ float g_x [NR * Dm];
__device__ float g_s [Bq * Hh * TTq * TSs];
__device__ float g_part[SKn * NR * Dm];
__device__ float g_bqk4[4 * 2 * HD];

__device__ __half g_xeh[2 * NR * 512];           // xh | eh
__device__ __half g_qh [NR * 8192];              // merged QK (self blocks)
__device__ __half g_qhx[NR * 4096];              // cross-block Q
__device__ __half g_khx[2L * NR * 4096];         // cross-block K (l=0 | l=1)
__device__ __half g_vh [4 * VHSZ];               // per-block V
__device__ __half g_sh [32 * 512 * 512];
__device__ __half g_oh [NR * 4096];
__device__ __half g_fh [NR * 2048];
__device__ __half g_lmh[32256 * 512];

// dedicated converted-weight buffers (block b = l*2 + att)
__device__ __half g_qkw[4 * 4194304];
__device__ __half g_vw [4 * 2097152];
__device__ __half g_ow [4 * 2097152];
__device__ __half g_f1w[2 * 1048576];
__device__ __half g_f2w[2 * 1048576];

// ---------------------------------------------------------------------------
// Embedding + positional encoding -> x (fp32) and xh (fp16)
// ---------------------------------------------------------------------------
__global__ void embed_pe_kernel(const int* __restrict__ target,
                                const float* __restrict__ emb,
                                float* __restrict__ x,
                                __half* __restrict__ xh)
{
    int row = blockIdx.x;
    int t   = row & (TTq - 1);
    int d   = threadIdx.x;
    int tok = target[row];
    float e = emb[(long)tok * Dm + d];
    int   i = d >> 1;
    // 1/10000^(2i/512) = 2^(-i * log2(10000)/256)
    float z = (float)t * exp2f((float)i * -0.0519051267f);
    float p = (d & 1) ? cosf(z) : sinf(z);
    float v = e + p;
    x[(long)row * Dm + d] = v;
    xh[(long)row * 512 + d] = __float2half(v);
}

__global__ void conv_enc_kernel(const float* __restrict__ in, __half* __restrict__ out)
{
    long idx = (long)blockIdx.x * blockDim.x + threadIdx.x;
    long r = idx >> 8;
    long k = (idx & 255) * 2;
    const float* p = in + r * Dm + k;
    __half2 h = __halves2half2(__float2half(p[0]), __float2half(p[1]));
    *(__half2*)(out + r * 512 + k) = h;
}

// ---------------------------------------------------------------------------
// Masked softmax, fp16 in-place; optional fp32 copy (att0).
// ---------------------------------------------------------------------------
__global__ void softmax_kernel(__half* __restrict__ Sh, float* __restrict__ S,
                               int writeS,
                               const int* __restrict__ target,
                               const int* __restrict__ srcpad,
                               int mode, float scale)
{
    int row = blockIdx.x;
    int q   = row & (TTq - 1);
    int b   = row / (Hh * TTq);
    __half* sr = Sh + (long)row * 512;
    int tid = threadIdx.x;
    bool qpad = (target[b * TTq + q] != Vv);

    float v[2];
    float mx = -INFINITY;
#pragma unroll
    for (int e = 0; e < 2; e++) {
        int k = tid + e * 256;
        bool valid;
        if (mode == 1)
            valid = qpad && (k <= q) && (target[b * TTq + k] != Vv);
        else
            valid = qpad && (srcpad[b * TSs + k] != 0);
        float val = valid ? __half2float(sr[k]) * scale : -1e32f;
        v[e] = val;
        mx = fmaxf(mx, val);
    }

    __shared__ float red[8];
#pragma unroll
    for (int o = 16; o > 0; o >>= 1) mx = fmaxf(mx, __shfl_xor_sync(0xffffffffu, mx, o));
    if ((tid & 31) == 0) red[tid >> 5] = mx;
    __syncthreads();
    if (tid < 32) {
        float r = (tid < 8) ? red[tid] : -INFINITY;
#pragma unroll
        for (int o = 4; o > 0; o >>= 1) r = fmaxf(r, __shfl_xor_sync(0xffffffffu, r, o));
        if (tid == 0) red[0] = r;
    }
    __syncthreads();
    mx = red[0];
    __syncthreads();

    float sum = 0.f;
#pragma unroll
    for (int e = 0; e < 2; e++) { v[e] = expf(v[e] - mx); sum += v[e]; }
#pragma unroll
    for (int o = 16; o > 0; o >>= 1) sum += __shfl_xor_sync(0xffffffffu, sum, o);
    if ((tid & 31) == 0) red[tid >> 5] = sum;
    __syncthreads();
    if (tid < 32) {
        float r = (tid < 8) ? red[tid] : 0.f;
#pragma unroll
        for (int o = 4; o > 0; o >>= 1) r += __shfl_xor_sync(0xffffffffu, r, o);
        if (tid == 0) red[0] = r;
    }
    __syncthreads();
    float inv = 1.0f / red[0];
    float* s32 = S + (long)row * TSs;
#pragma unroll
    for (int e = 0; e < 2; e++) {
        int k = tid + e * 256;
        float val = v[e] * inv;
        sr[k] = __float2half(val);
        if (writeS) s32[k] = val;
    }
}

// ---------------------------------------------------------------------------
// Fused split-K reduce + residual + LayerNorm
// ---------------------------------------------------------------------------
__global__ void reduce_ln_kernel(const float* __restrict__ part,
                                 const float* __restrict__ bias,
                                 const float* __restrict__ xin,
                                 const float* __restrict__ gg,
                                 const float* __restrict__ bb,
                                 float* __restrict__ y,
                                 __half* __restrict__ yh)
{
    int row = blockIdx.x;
    int tid = threadIdx.x;
    long base = (long)row * Dm;
    __shared__ float red[8];

    float v[2];
    float sum = 0.f;
#pragma unroll
    for (int e = 0; e < 2; e++) {
        int d = tid + e * 256;
        float s = xin[base + d] + bias[d];
#pragma unroll
        for (int c = 0; c < SKn; c++)
            s += part[(long)c * NR * Dm + base + d];
        v[e] = s;
        sum += s;
    }
#pragma unroll
    for (int o = 16; o > 0; o >>= 1) sum += __shfl_xor_sync(0xffffffffu, sum, o);
    if ((tid & 31) == 0) red[tid >> 5] = sum;
    __syncthreads();
    if (tid < 32) {
        float r = (tid < 8) ? red[tid] : 0.f;
#pragma unroll
        for (int o = 4; o > 0; o >>= 1) r += __shfl_xor_sync(0xffffffffu, r, o);
        if (tid == 0) red[0] = r;
    }
    __syncthreads();
    float m = red[0] * (1.0f / (float)Dm);
    __syncthreads();

    float vs = 0.f;
#pragma unroll
    for (int e = 0; e < 2; e++) { float c = v[e] - m; vs += c * c; }
#pragma unroll
    for (int o = 16; o > 0; o >>= 1) vs += __shfl_xor_sync(0xffffffffu, vs, o);
    if ((tid & 31) == 0) red[tid >> 5] = vs;
    __syncthreads();
    if (tid < 32) {
        float r = (tid < 8) ? red[tid] : 0.f;
#pragma unroll
        for (int o = 4; o > 0; o >>= 1) r += __shfl_xor_sync(0xffffffffu, r, o);
        if (tid == 0) red[0] = r;
    }
    __syncthreads();
    float var = red[0] * (1.0f / (float)Dm);
    float rs = rsqrtf(var + 1e-5f);
    __half* yhr = yh + (long)row * 512;
#pragma unroll
    for (int e = 0; e < 2; e++) {
        int d = tid + e * 256;
        float val = (v[e] - m) * rs * gg[d] + bb[d];
        y[base + d] = val;
        yhr[d] = __float2half(val);
    }
}

// ---------------------------------------------------------------------------
// conv_t: fp32 [K, N] (N-contig) -> fp16 [N, K] transposed. (weights)
// ---------------------------------------------------------------------------
__global__ void conv_t_kernel(const float* __restrict__ in, __half* __restrict__ out,
                              int K, int N, int in_ld, int out_ld,
                              long sInB, long sInH, long sOutB, long sOutH, int Hn)
{
    __shared__ float t[32][33];
    int z = blockIdx.z, zb = z / Hn, zh = z % Hn;
    in  += zb * sInB + zh * sInH;
    out += zb * sOutB + zh * sOutH;
    int k0 = blockIdx.y * 32, n0 = blockIdx.x * 32;
    int tx = threadIdx.x, ty = threadIdx.y;
#pragma unroll
    for (int i = 0; i < 4; ++i) {
        int k = k0 + ty + i * 8, n = n0 + tx;
        t[ty + i * 8][tx] = (n < N) ? in[(long)k * in_ld + n] : 0.f;
    }
    __syncthreads();
#pragma unroll
    for (int i = 0; i < 4; ++i) {
        int n = n0 + ty + i * 8, k = k0 + tx;
        if (n < N)
            out[(long)n * out_ld + k] = __float2half(t[tx][ty + i * 8]);
    }
}

// ---------------------------------------------------------------------------
// fp16 tensor-core GEMM (mma.sync m16n8k16 f16). CTA 128x256, 8 warps (2x4),
// warp tile 64x64, BK=32, 4-stage cp.async pipeline, one barrier per iter.
// EPI: 0 fp32 | 1 fp32+bias | 3 half+bias | 5 half | 6 half+bias+relu
//      7 half+bias TRANSPOSED store
// causal: 1 = skip fully-masked tiles (self-att scores)
//         2 = K-cap: only K-iters with k < m0+GBM contribute (self O=S*V)
// ---------------------------------------------------------------------------
#define GBM 128
#define GBN 256
#define GBK 32
#define NSTAGE 4
#define A_BYTES 10240
#define STAGE_BYTES 30720
#define HG_SMEM (NSTAGE * STAGE_BYTES)

__device__ __forceinline__ uint32_t smem_u32(const void* p) {
    uint32_t a;
    asm("{ .reg .u64 t; cvta.to.shared.u64 t, %1; cvt.u32.u64 %0, t; }" : "=r"(a) : "l"(p));
    return a;
}
#define CP16(dst, src) \
    asm volatile("cp.async.cg.shared.global [%0], [%1], 16;" :: "r"(dst), "l"(src))
#define CP_COMMIT() asm volatile("cp.async.commit_group;" ::: "memory")
#define CP_WAIT(n)  asm volatile("cp.async.wait_group %0;" :: "n"(n) : "memory")
#define LDSM_X4(r0, r1, r2, r3, addr) \
    asm volatile("ldmatrix.sync.aligned.m8n8.x4.shared.b16 {%0,%1,%2,%3}, [%4];" \
                 : "=r"(r0), "=r"(r1), "=r"(r2), "=r"(r3) : "r"(addr))
#define MMA_F16(c, a0, a1, a2, a3, b0, b1) \
    asm volatile("mma.sync.aligned.m16n8k16.row.col.f32.f16.f16.f32 " \
                 "{%0,%1,%2,%3}, {%4,%5,%6,%7}, {%8,%9}, {%0,%1,%2,%3};" \
                 : "+f"((c)[0]), "+f"((c)[1]), "+f"((c)[2]), "+f"((c)[3]) \
                 : "r"(a0), "r"(a1), "r"(a2), "r"(a3), "r"(b0), "r"(b1))

template<int EPI>
__global__ void __launch_bounds__(256, 1)
hgemm_kernel(const __half* __restrict__ A2, const __half* __restrict__ B2,
             const float* __restrict__ Bias, void* __restrict__ Cv,
             int Nstore, int Kd, int lda, int ldb, int ldc,
             long sAb, long sAh, long sBb, long sBh, long sCb, long sCh,
             long sBiB, long sBiH, int Hn, int causal)
{
    extern __shared__ __align__(16) char dsm[];
    const uint32_t base = smem_u32(dsm);

    int tid = threadIdx.x;
    int wid = tid >> 5, lane = tid & 31;

    long m0 = (long)blockIdx.x * GBM;
    long n0 = (long)blockIdx.y * GBN;
    if (causal == 1 && n0 > m0 + (GBM - 1)) return;

    int z = blockIdx.z, zb = z / Hn, zh = z % Hn;
    A2 += zb * sAb + zh * sAh;
    B2 += zb * sBb + zh * sBh;
    long cOff = zb * sCb + zh * sCh;
    long biasOff = zb * sBiB + zh * sBiH;

    const int wm = (wid >> 2) * 64;
    const int wn = (wid & 3) * 64;

    float acc[4][8][4];
#pragma unroll
    for (int i = 0; i < 4; i++)
#pragma unroll
        for (int j = 0; j < 8; j++)
#pragma unroll
            for (int q = 0; q < 4; q++) acc[i][j][q] = 0.f;

    int nIter = Kd / GBK;
    if (causal == 2) {
        int cap = (int)((m0 + GBM) / GBK);
        if (cap < nIter) nIter = cap;
    }

    const int lr  = tid >> 2;
    const int lsg = tid & 3;
    const long aRow0 = m0 + lr,  aRow1 = m0 + lr + 64;
    const uint32_t sOff0 = (uint32_t)(lr * 80 + lsg * 16);
    const uint32_t sOff1 = (uint32_t)((lr + 64) * 80 + lsg * 16);
    const uint32_t sOff2 = (uint32_t)((lr + 128) * 80 + lsg * 16);
    const uint32_t sOff3 = (uint32_t)((lr + 192) * 80 + lsg * 16);

    auto loadStage = [&](int slot, long k0) {
        uint32_t aD = base + slot * STAGE_BYTES;
        uint32_t bD = aD + A_BYTES;
        long ko = k0 + lsg * 8;
        CP16(aD + sOff0, A2 + aRow0 * (long)lda + ko);
        CP16(aD + sOff1, A2 + aRow1 * (long)lda + ko);
        CP16(bD + sOff0, B2 + (n0 + lr) * (long)ldb + ko);
        CP16(bD + sOff1, B2 + (n0 + lr + 64) * (long)ldb + ko);
        CP16(bD + sOff2, B2 + (n0 + lr + 128) * (long)ldb + ko);
        CP16(bD + sOff3, B2 + (n0 + lr + 192) * (long)ldb + ko);
        CP_COMMIT();
    };

    loadStage(0, 0);
    if (nIter > 1) loadStage(1, GBK); else CP_COMMIT();
    if (nIter > 2) loadStage(2, 2L * GBK); else CP_COMMIT();

    for (int it = 0; it < nIter; ++it) {
        if (it + 2 < nIter)      CP_WAIT(2);
        else if (it + 1 < nIter) CP_WAIT(1);
        else                     CP_WAIT(0);
        __syncthreads();
        if (it + 3 < nIter) loadStage((it + 3) & (NSTAGE - 1), (long)(it + 3) * GBK);

        uint32_t aS = base + (it & (NSTAGE - 1)) * STAGE_BYTES;
        uint32_t bS = aS + A_BYTES;
#pragma unroll
        for (int ks = 0; ks < 2; ks++) {
            int col = ks * 16 + (lane >> 4) * 8;
            uint32_t a[4][4], bf[8][2];
#pragma unroll
            for (int mi = 0; mi < 4; mi++) {
                int row = wm + mi * 16 + (lane & 15);
                LDSM_X4(a[mi][0], a[mi][1], a[mi][2], a[mi][3],
                        aS + (uint32_t)(row * 80 + col * 2));
            }
#pragma unroll
            for (int p = 0; p < 4; p++) {
                int row = wn + p * 16 + (lane & 15);
                uint32_t r0, r1, r2, r3;
                LDSM_X4(r0, r1, r2, r3, bS + (uint32_t)(row * 80 + col * 2));
                bf[2 * p][0] = r0;     bf[2 * p][1] = r2;
                bf[2 * p + 1][0] = r1; bf[2 * p + 1][1] = r3;
            }
#pragma unroll
            for (int mi = 0; mi < 4; mi++)
#pragma unroll
                for (int ni = 0; ni < 8; ni++)
                    MMA_F16(acc[mi][ni], a[mi][0], a[mi][1], a[mi][2], a[mi][3],
                            bf[ni][0], bf[ni][1]);
        }
    }

    // ---- epilogue ----
    if (EPI <= 1) {
        float* C = (float*)Cv + cOff;
#pragma unroll
        for (int mi = 0; mi < 4; mi++) {
            long mrow = m0 + wm + mi * 16 + (lane >> 2);
            float* c0p = C + mrow * (long)ldc;
            float* c1p = c0p + 8L * ldc;
#pragma unroll
            for (int ni = 0; ni < 8; ni++) {
                long n = n0 + wn + ni * 8 + (lane & 3) * 2;
#pragma unroll
                for (int e = 0; e < 2; e++) {
                    long nn = n + e;
                    if (nn < (long)Nstore) {
                        float v0 = acc[mi][ni][e];
                        float v1 = acc[mi][ni][2 + e];
                        if (EPI >= 1) {
                            float bsv = Bias[biasOff + nn];
                            v0 += bsv; v1 += bsv;
                        }
                        c0p[nn] = v0;
                        c1p[nn] = v1;
                    }
                }
            }
        }
    } else if (EPI == 7) {
        __half* C2 = (__half*)Cv + cOff;
#pragma unroll
        for (int mi = 0; mi < 4; mi++) {
            long m = m0 + wm + mi * 16 + (lane >> 2);
#pragma unroll
            for (int ni = 0; ni < 8; ni++) {
                long n = n0 + wn + ni * 8 + (lane & 3) * 2;
                float b0 = Bias[biasOff + n];
                float b1 = Bias[biasOff + n + 1];
                C2[n * (long)ldc + m]           = __float2half(acc[mi][ni][0] + b0);
                C2[(n + 1) * (long)ldc + m]     = __float2half(acc[mi][ni][1] + b1);
                C2[n * (long)ldc + m + 8]       = __float2half(acc[mi][ni][2] + b0);
                C2[(n + 1) * (long)ldc + m + 8] = __float2half(acc[mi][ni][3] + b1);
            }
        }
    } else {
        __half* C2 = (__half*)Cv + cOff;
        const bool hasBias = (EPI == 3 || EPI == 6);
        const bool relu = (EPI == 6);
#pragma unroll
        for (int mi = 0; mi < 4; mi++) {
            long r0 = m0 + wm + mi * 16 + (lane >> 2);
            __half* p0 = C2 + r0 * (long)ldc;
            __half* p1 = p0 + 8L * ldc;
#pragma unroll
            for (int ni = 0; ni < 8; ni++) {
                long n = n0 + wn + ni * 8 + (lane & 3) * 2;
                float b0 = 0.f, b1 = 0.f;
                if (hasBias) { b0 = Bias[biasOff + n]; b1 = Bias[biasOff + n + 1]; }
                float v0 = acc[mi][ni][0] + b0, v1 = acc[mi][ni][1] + b1;
                float v2 = acc[mi][ni][2] + b0, v3 = acc[mi][ni][3] + b1;
                if (relu) {
                    v0 = fmaxf(v0, 0.f); v1 = fmaxf(v1, 0.f);
                    v2 = fmaxf(v2, 0.f); v3 = fmaxf(v3, 0.f);
                }
                *(__half2*)(p0 + n) = __halves2half2(__float2half(v0), __float2half(v1));
                *(__half2*)(p1 + n) = __halves2half2(__float2half(v2), __float2half(v3));
            }
        }
    }
}

// ---------------------------------------------------------------------------
// Host dispatch (stream-aware)
// ---------------------------------------------------------------------------
static void tg(int epi, const __half* A, const __half* B, const float* Bias,
               void* C, int M, int N, int Kd, int lda, int ldb, int ldc,
               long sAb, long sAh, long sBb, long sBh, long sCb, long sCh,
               long sBiB, long sBiH, int Hn, int Z, int causal = 0,
               cudaStream_t st = 0)
{
    dim3 g(M / GBM, (N + GBN - 1) / GBN, Z), b(256);
#define HG_CALL(E) hgemm_kernel<E><<<g, b, HG_SMEM, st>>>(A, B, Bias, C, N, Kd, lda, ldb, ldc, \
    sAb, sAh, sBb, sBh, sCb, sCh, sBiB, sBiH, Hn, causal)
    switch (epi) {
    case 0: HG_CALL(0); break;
    case 1: HG_CALL(1); break;
    case 3: HG_CALL(3); break;
    case 5: HG_CALL(5); break;
    case 7: HG_CALL(7); break;
    default: HG_CALL(6); break;
    }
#undef HG_CALL
}

// side-stream handles: created once on the first (uncaptured) call; work
// enqueued is identical every call. ALL cross-stream waits reference events
// recorded EARLIER in host enqueue order (backward edges only).
static cudaStream_t g_s2 = nullptr;
static cudaEvent_t  g_ev[26];
// QKw[b]=b, Vw[b]=4+b, Ow[b]=8+b, F1[l]=12+l, F2[l]=14+l, LM=16, fork=17,
// VprojDone[b]=18+b, QK0done=22, Xready_l1=23, KXdone[l]=24+l

extern "C" void kernel_launch(void* const* d_in, const int* in_sizes, int n_in,
                              void* d_out, int out_size)
{
    const float* enc    = (const float*)d_in[0];
    const int*   srcpad = (const int*)  d_in[1];
    const int*   target = (const int*)  d_in[2];
    const float* emb    = (const float*)d_in[3];
    const float* Wq1 = (const float*)d_in[4],  *bq1 = (const float*)d_in[5];
    const float* Wk1 = (const float*)d_in[6],  *bk1 = (const float*)d_in[7];
    const float* Wv1 = (const float*)d_in[8],  *bv1 = (const float*)d_in[9];
    const float* Wo1 = (const float*)d_in[10], *bo1 = (const float*)d_in[11];
    const float* Wq2 = (const float*)d_in[12], *bq2 = (const float*)d_in[13];
    const float* Wk2 = (const float*)d_in[14], *bk2 = (const float*)d_in[15];
    const float* Wv2 = (const float*)d_in[16], *bv2 = (const float*)d_in[17];
    const float* Wo2 = (const float*)d_in[18], *bo2 = (const float*)d_in[19];
    const float* ln1g = (const float*)d_in[20];
    const float* ln2g = (const float*)d_in[21];
    const float* ln3g = (const float*)d_in[22];
    const float* ln1b = (const float*)d_in[23];
    const float* ln2b = (const float*)d_in[24];
    const float* ln3b = (const float*)d_in[25];
    const float* Wf1 = (const float*)d_in[26], *bf1 = (const float*)d_in[27];
    const float* Wf2 = (const float*)d_in[28], *bf2 = (const float*)d_in[29];
    const float* lmW = (const float*)d_in[30], *lmb = (const float*)d_in[31];
    float* out = (float*)d_out;

    if (!g_s2) {
        cudaStreamCreateWithFlags(&g_s2, cudaStreamNonBlocking);
        for (int i = 0; i < 26; i++)
            cudaEventCreateWithFlags(&g_ev[i], cudaEventDisableTiming);
    }

    float *x, *ss, *part, *bqk4;
    cudaGetSymbolAddress((void**)&x,  g_x);
    cudaGetSymbolAddress((void**)&ss, g_s);
    cudaGetSymbolAddress((void**)&part, g_part);
    cudaGetSymbolAddress((void**)&bqk4, g_bqk4);
    __half *xeh, *qh, *qhx, *khx, *vh, *sh, *oh, *fh, *lmh, *qkw, *vw, *ow, *f1w, *f2w;
    cudaGetSymbolAddress((void**)&xeh, g_xeh);
    cudaGetSymbolAddress((void**)&qh, g_qh);
    cudaGetSymbolAddress((void**)&qhx, g_qhx);
    cudaGetSymbolAddress((void**)&khx, g_khx);
    cudaGetSymbolAddress((void**)&vh, g_vh);
    cudaGetSymbolAddress((void**)&sh, g_sh);
    cudaGetSymbolAddress((void**)&oh, g_oh);
    cudaGetSymbolAddress((void**)&fh, g_fh);
    cudaGetSymbolAddress((void**)&lmh, g_lmh);
    cudaGetSymbolAddress((void**)&qkw, g_qkw);
    cudaGetSymbolAddress((void**)&vw, g_vw);
    cudaGetSymbolAddress((void**)&ow, g_ow);
    cudaGetSymbolAddress((void**)&f1w, g_f1w);
    cudaGetSymbolAddress((void**)&f2w, g_f2w);
    __half* xh = xeh;
    __half* eh = xeh + (long)NR * 512;
    __half* kh = qh + 4096;

    cudaFuncSetAttribute(hgemm_kernel<0>, cudaFuncAttributeMaxDynamicSharedMemorySize, HG_SMEM);
    cudaFuncSetAttribute(hgemm_kernel<1>, cudaFuncAttributeMaxDynamicSharedMemorySize, HG_SMEM);
    cudaFuncSetAttribute(hgemm_kernel<3>, cudaFuncAttributeMaxDynamicSharedMemorySize, HG_SMEM);
    cudaFuncSetAttribute(hgemm_kernel<5>, cudaFuncAttributeMaxDynamicSharedMemorySize, HG_SMEM);
    cudaFuncSetAttribute(hgemm_kernel<6>, cudaFuncAttributeMaxDynamicSharedMemorySize, HG_SMEM);
    cudaFuncSetAttribute(hgemm_kernel<7>, cudaFuncAttributeMaxDynamicSharedMemorySize, HG_SMEM);

    const float scale = 1.0f / sqrtf((float)Dm);
    const long WATT = (long)Hh * Dm * Dm;
    const long WOUT = (long)HD * Dm;
    const long WFF  = (long)Dm * FFd;
    const dim3 tb(32, 8);

    const float *WQ[2][2] = {{Wq1, Wq1 + WATT}, {Wq2, Wq2 + WATT}};
    const float *WK[2][2] = {{Wk1, Wk1 + WATT}, {Wk2, Wk2 + WATT}};
    const float *WV[2][2] = {{Wv1, Wv1 + WATT}, {Wv2, Wv2 + WATT}};
    const float *WO[2][2] = {{Wo1, Wo1 + WOUT}, {Wo2, Wo2 + WOUT}};
    const float *BQ[2][2] = {{bq1, bq1 + HD}, {bq2, bq2 + HD}};
    const float *BK[2][2] = {{bk1, bk1 + HD}, {bk2, bk2 + HD}};
    const float *BV[2][2] = {{bv1, bv1 + HD}, {bv2, bv2 + HD}};
    const float *BO[2][2] = {{bo1, bo1 + Dm}, {bo2, bo2 + Dm}};
    const float *LG[2][2] = {{ln1g, ln1g + Dm}, {ln2g, ln2g + Dm}};
    const float *LB[2][2] = {{ln1b, ln1b + Dm}, {ln2b, ln2b + Dm}};

    // ===================== main chain start =====================
    embed_pe_kernel<<<NR, 512>>>(target, emb, x, xh);
    conv_enc_kernel<<<NR, 256>>>(enc, eh);
    cudaEventRecord(g_ev[17], 0);      // fork: inputs + xh/eh ready

    // ===================== side stream, segment 1 =====================
    cudaStreamWaitEvent(g_s2, g_ev[17], 0);
    for (int l = 0; l < 2; l++) {
        for (int att = 0; att < 2; att++) {
            int b = l * 2 + att;
            const __half* kvA = (att == 0) ? xh : eh;
            cudaMemcpyAsync(bqk4 + b * 2 * HD,      BQ[att][l], HD * sizeof(float),
                            cudaMemcpyDeviceToDevice, g_s2);
            cudaMemcpyAsync(bqk4 + b * 2 * HD + HD, BK[att][l], HD * sizeof(float),
                            cudaMemcpyDeviceToDevice, g_s2);
            conv_t_kernel<<<dim3(16, 16, 8), tb, 0, g_s2>>>(WQ[att][l], qkw + (long)b * 4194304,
                Dm, Dm, Dm, 512, 0, (long)Dm * Dm, 0, (long)Dm * 512, 8);
            conv_t_kernel<<<dim3(16, 16, 8), tb, 0, g_s2>>>(WK[att][l], qkw + (long)b * 4194304 + 2097152,
                Dm, Dm, Dm, 512, 0, (long)Dm * Dm, 0, (long)Dm * 512, 8);
            if (b == 0) {
                // block-0 merged Q+K projection on side stream
                tg(3, xh, qkw, bqk4, qh, NR, Dm, 512, 512, 512, 8192,
                   0, 0, 2097152, (long)Dm * 512, 4096, 512,
                   HD, 512, 8, 16, 0, g_s2);
                cudaEventRecord(g_ev[22], g_s2);
            } else {
                cudaEventRecord(g_ev[b], g_s2);
            }
            if (att == 1) {
                // cross-block K projection on side stream (reads eh, ready at fork)
                tg(3, eh, qkw + (long)b * 4194304 + 2097152, BK[1][l],
                   khx + (long)l * NR * 4096, NR, Dm, 512, 512, 512, 4096,
                   0, 0, 0, (long)Dm * 512, 0, 512, 0, Dm, 8, 8, 0, g_s2);
                cudaEventRecord(g_ev[24 + l], g_s2);
            }
            conv_t_kernel<<<dim3(16, 16, 8), tb, 0, g_s2>>>(WV[att][l], vw + (long)b * 2097152,
                Dm, Dm, Dm, 512, 0, (long)Dm * Dm, 0, (long)Dm * 512, 8);
            cudaEventRecord(g_ev[4 + b], g_s2);
            if (b != 2) {
                tg(7, kvA, vw + (long)b * 2097152, BV[att][l], vh + (long)b * VHSZ,
                   512, Dm, 512, 512, 512, 512,
                   (long)512 * 512, 0, 0, (long)Dm * 512,
                   (long)Hh * 512 * 512, (long)512 * 512, 0, Dm, 8, 32, 0, g_s2);
                cudaEventRecord(g_ev[18 + b], g_s2);
            }
            conv_t_kernel<<<dim3(16, 128, 1), tb, 0, g_s2>>>(WO[att][l], ow + (long)b * 2097152,
                HD, Dm, Dm, 4096, 0, 0, 0, 0, 1);
            cudaEventRecord(g_ev[8 + b], g_s2);
        }
        conv_t_kernel<<<dim3(64, 16, 1), tb, 0, g_s2>>>(Wf1 + l * WFF, f1w + (long)l * 1048576,
            Dm, FFd, FFd, 512, 0, 0, 0, 0, 1);
        cudaEventRecord(g_ev[12 + l], g_s2);
        conv_t_kernel<<<dim3(16, 64, 1), tb, 0, g_s2>>>(Wf2 + l * WFF, f2w + (long)l * 1048576,
            FFd, Dm, Dm, 2048, 0, 0, 0, 0, 1);
        cudaEventRecord(g_ev[14 + l], g_s2);
    }
    conv_t_kernel<<<dim3(1001, 16, 1), tb, 0, g_s2>>>(lmW, lmh, Dm, VO, VO, 512, 0, 0, 0, 0, 1);
    cudaEventRecord(g_ev[16], g_s2);

    // ===================== main chain =====================
    for (int l = 0; l < 2; l++) {
        for (int att = 0; att < 2; att++) {
            int b = l * 2 + att;
            __half* vhb = vh + (long)b * VHSZ;

            if (att == 0) {
                // ---- self: merged Q+K (b0 on side stream, b2 on main) ----
                if (b == 0) {
                    cudaStreamWaitEvent(0, g_ev[22], 0);
                } else {
                    cudaStreamWaitEvent(0, g_ev[b], 0);
                    tg(3, xh, qkw + (long)b * 4194304, bqk4 + b * 2 * HD, qh,
                       NR, Dm, 512, 512, 512, 8192,
                       0, 0, 2097152, (long)Dm * 512, 4096, 512,
                       HD, 512, 8, 16);
                }
                // scores from merged buffer (causal tile-skip)
                tg(5, qh, kh, nullptr, sh, TTq, TSs, 512, 8192, 8192, 512,
                   (long)TTq * 8192, 512, (long)TSs * 8192, 512,
                   (long)Hh * TTq * 512, (long)TTq * 512, 0, 0, 8, 32, 1);
            } else {
                // ---- cross: Q-proj only on main (K done on side stream) ----
                cudaStreamWaitEvent(0, g_ev[b], 0);
                tg(3, xh, qkw + (long)b * 4194304, BQ[1][l], qhx,
                   NR, Dm, 512, 512, 512, 4096,
                   0, 0, 0, (long)Dm * 512, 0, 512, 0, Dm, 8, 8);
                cudaStreamWaitEvent(0, g_ev[24 + l], 0);
                tg(5, qhx, khx + (long)l * NR * 4096, nullptr, sh,
                   TTq, TSs, 512, 4096, 4096, 512,
                   (long)TTq * 4096, 512, (long)TSs * 4096, 512,
                   (long)Hh * TTq * 512, (long)TTq * 512, 0, 0, 8, 32, 0);
            }

            int writeS = (att == 1 && l == 0) ? 1 : 0;
            softmax_kernel<<<Bq * Hh * TTq, 256>>>(sh, ss, writeS, target, srcpad,
                                                   att == 0 ? 1 : 2, scale);
            if (writeS && (long)out_size >= LOGITS_ELEMS + ATT_ELEMS) {
                cudaMemcpyAsync(out + LOGITS_ELEMS, ss, ATT_ELEMS * sizeof(float),
                                cudaMemcpyDeviceToDevice, 0);
            }

            // ---- O = S V (self: causal K-cap) ----
            cudaStreamWaitEvent(0, g_ev[18 + b], 0);
            tg(5, sh, vhb, nullptr, oh, TTq, Dm, 512, 512, 512, 4096,
               (long)Hh * TTq * 512, (long)TTq * 512,
               (long)Hh * TSs * 512, (long)TSs * 512,
               (long)TTq * 4096, 512, 0, 0, 8, 32,
               att == 0 ? 2 : 0);

            // ---- output projection: split-K=8 + fused reduce+add+LN ----
            cudaStreamWaitEvent(0, g_ev[8 + b], 0);
            tg(0, oh, ow + (long)b * 2097152, nullptr, part, NR, Dm, 512, 4096, 4096, Dm,
               0, 512, 0, 512, 0, (long)NR * Dm, 0, 0, SKn, SKn);
            reduce_ln_kernel<<<NR, 256>>>(part, BO[att][l], x, LG[att][l], LB[att][l], x, xh);
        }

        // ---- FFN ----
        cudaStreamWaitEvent(0, g_ev[12 + l], 0);
        tg(6, xh, f1w + (long)l * 1048576, bf1 + l * FFd, fh, NR, FFd, 512, 512, 512, 2048,
           0, 0, 0, 0, 0, 0, 0, 0, 1, 1);

        cudaStreamWaitEvent(0, g_ev[14 + l], 0);
        tg(0, fh, f2w + (long)l * 1048576, nullptr, part, NR, Dm, 256, 2048, 2048, Dm,
           0, 256, 0, 256, 0, (long)NR * Dm, 0, 0, SKn, SKn);
        reduce_ln_kernel<<<NR, 256>>>(part, bf2 + l * Dm, x, ln3g + l * Dm, ln3b + l * Dm, x, xh);

        if (l == 0) {
            // xh for layer 1 is ready — enqueue V-proj(b=2) on the side stream.
            cudaEventRecord(g_ev[23], 0);
            cudaStreamWaitEvent(g_s2, g_ev[23], 0);
            tg(7, xh, vw + 2L * 2097152, BV[0][1], vh + 2L * VHSZ,
               512, Dm, 512, 512, 512, 512,
               (long)512 * 512, 0, 0, (long)Dm * 512,
               (long)Hh * 512 * 512, (long)512 * 512, 0, Dm, 8, 32, 0, g_s2);
            cudaEventRecord(g_ev[18 + 2], g_s2);
        }
    }

    // ---- LM head ----
    cudaStreamWaitEvent(0, g_ev[16], 0);
    tg(1, xh, lmh, lmb, out, NR, VO, 512, 512, 512, VO,
       0, 0, 0, 0, 0, 0, 0, 0, 1, 1);
}